// round 6
// baseline (speedup 1.0000x reference)
#include <cuda_runtime.h>
#include <cuda_fp16.h>
#include <cuda_bf16.h>
#include <mma.h>
#include <cstdint>
#include <cstddef>

#define D 128
using namespace nvcuda;

// ---------------- static scratch (device globals) ---------------------------
static __device__ float    g_T  [100000 * 128];  // T fp32; reused in-place as A
static __device__ unsigned g_T16[100000 * 64];   // T / n fp16 rows
static __device__ unsigned g_E16[50000  * 64];   // e fp16 rows
static __device__ float    g_h  [100000 * 128];  // h = prelu(n) from layer 0
static __device__ float    g_c1 [2048   * 128];
static __device__ float    g_c2 [2048   * 128];
static __device__ float    g_c3 [2048   * 128];
static __device__ unsigned g_Wb [4 * 384 * 64];  // 4 W, bf16-split [384][128] rows
static __device__ float g_invdst[50016];
static __device__ float g_invsrc[100016];
static __device__ float g_invc1[2048];
static __device__ float g_invc2[2048];
static __device__ int   g_cd [50016];
static __device__ int   g_cs [100016];
static __device__ int   g_cc1[2048];
static __device__ int   g_cc2[2048];
static __device__ int   g_offs_d[50024];
static __device__ int   g_offs_s[100024];
static __device__ int   g_perm_d[1600128];
static __device__ int   g_perm_s[1600128];
static __device__ int   g_bsum [1024];
static __device__ int   g_bscan[1024];

// ---------------- helpers ----------------------------------------------------
__device__ __forceinline__ unsigned long long pk2(float v) {
    unsigned long long r; unsigned u = __float_as_uint(v);
    asm("mov.b64 %0, {%1,%1};" : "=l"(r) : "r"(u));
    return r;
}
__device__ __forceinline__ void fma2(unsigned long long& d, unsigned long long a,
                                     unsigned long long b) {
    asm("fma.rn.f32x2 %0, %1, %2, %0;" : "+l"(d) : "l"(a), "l"(b));
}
__device__ __forceinline__ float2 up2(unsigned long long v) {
    unsigned lo, hi;
    asm("mov.b64 {%0,%1}, %2;" : "=r"(lo), "=r"(hi) : "l"(v));
    return make_float2(__uint_as_float(lo), __uint_as_float(hi));
}
__device__ __forceinline__ float prelu1(float v, float a) { return v >= 0.f ? v : a * v; }
__device__ __forceinline__ float4 prelu4(float4 v, float a) {
    return make_float4(prelu1(v.x, a), prelu1(v.y, a), prelu1(v.z, a), prelu1(v.w, a));
}
__device__ __forceinline__ void add4(float4& a, float4 b) {
    a.x += b.x; a.y += b.y; a.z += b.z; a.w += b.w;
}
__device__ __forceinline__ void addh(float4& a, uint2 v) {
    __half2 h0 = *reinterpret_cast<__half2*>(&v.x);
    __half2 h1 = *reinterpret_cast<__half2*>(&v.y);
    float2 f0 = __half22float2(h0), f1 = __half22float2(h1);
    a.x += f0.x; a.y += f0.y; a.z += f1.x; a.w += f1.y;
}
__device__ __forceinline__ uint2 h4(float4 v) {
    __half2 h0 = __float22half2_rn(make_float2(v.x, v.y));
    __half2 h1 = __float22half2_rn(make_float2(v.z, v.w));
    uint2 r;
    r.x = *reinterpret_cast<unsigned*>(&h0);
    r.y = *reinterpret_cast<unsigned*>(&h1);
    return r;
}
__device__ __forceinline__ unsigned bf2(float a, float b) {
    __nv_bfloat162 t = __floats2bfloat162_rn(a, b);
    return *reinterpret_cast<unsigned*>(&t);
}
__device__ __forceinline__ float bfres(float a) {   // a - bf16(a)
    return a - __bfloat162float(__float2bfloat16_rn(a));
}

// ---------------- W pre-split: Wb[w] = bf16 [384][128], rows [hi|hi|lo] ------
__global__ void kconvW(const float* __restrict__ W0, const float* __restrict__ W1,
                       const float* __restrict__ W2, const float* __restrict__ W3,
                       unsigned* __restrict__ Wb) {
    int idx = blockIdx.x * blockDim.x + threadIdx.x;
    if (idx >= 4 * 384 * 16) return;
    int w = idx / (384 * 16);
    int rem = idx % (384 * 16);
    int kk = rem >> 4, g = rem & 15;           // row kk, cols [g*8, g*8+8)
    const float* W = (w == 0) ? W0 : (w == 1) ? W1 : (w == 2) ? W2 : W3;
    int ksrc = (kk < 128) ? kk : (kk < 256) ? kk - 128 : kk - 256;
    bool lo = (kk >= 256);
    float4 x0 = __ldg((const float4*)(W + (size_t)ksrc * D + g * 8));
    float4 x1 = __ldg((const float4*)(W + (size_t)ksrc * D + g * 8 + 4));
    float f[8] = {x0.x, x0.y, x0.z, x0.w, x1.x, x1.y, x1.z, x1.w};
    if (lo) {
#pragma unroll
        for (int j = 0; j < 8; j++) f[j] = bfres(f[j]);
    }
    uint4 v;
    v.x = bf2(f[0], f[1]); v.y = bf2(f[2], f[3]);
    v.z = bf2(f[4], f[5]); v.w = bf2(f[6], f[7]);
    ((uint4*)(Wb + (size_t)w * 384 * 64))[kk * 16 + g] = v;
}

// ---------------- WMMA GEMM: Y[M x 128] = X @ W + b --------------------------
// 3-term bf16 emulation over K=384. out_f32 (raw or prelu), out_h16 optional.
#define AS_LD 400      // halves; 800 B row, 32B aligned
#define BS_LD 144      // halves; 288 B row, 32B aligned
#define CS_LD 136      // floats; 544 B row, 32B aligned
#define SM_AS  (128 * AS_LD * 2)              // 102400
#define SM_TOT (SM_AS + 384 * BS_LD * 2)      // 102400 + 110592 = 212992

__global__ __launch_bounds__(256, 1) void kgemm_tc(const float* __restrict__ X,
                                                   const unsigned* __restrict__ Wb,
                                                   const float* __restrict__ bias,
                                                   const float* __restrict__ pa,
                                                   float* __restrict__ out_f32,
                                                   unsigned* __restrict__ out_h16,
                                                   int prelu_f32, int M) {
    extern __shared__ char smem[];
    __nv_bfloat16* As = (__nv_bfloat16*)smem;            // 128 x AS_LD
    __nv_bfloat16* Bs = (__nv_bfloat16*)(smem + SM_AS);  // 384 x BS_LD
    float* Cs = (float*)smem;                            // reuse As: 128 x CS_LD
    const int tid = threadIdx.x;
    const int wid = tid >> 5;
    const int m0 = blockIdx.x * 128;

    // stage A: fp32 -> bf16 hi/lo split, segments [hi | lo | hi]
    for (int idx = tid; idx < 128 * 16; idx += 256) {
        int r = idx >> 4, g = idx & 15;
        int gr = m0 + r;
        float f[8];
        if (gr < M) {
            float4 x0 = __ldg((const float4*)(X + (size_t)gr * D + g * 8));
            float4 x1 = __ldg((const float4*)(X + (size_t)gr * D + g * 8 + 4));
            f[0] = x0.x; f[1] = x0.y; f[2] = x0.z; f[3] = x0.w;
            f[4] = x1.x; f[5] = x1.y; f[6] = x1.z; f[7] = x1.w;
        } else {
#pragma unroll
            for (int j = 0; j < 8; j++) f[j] = 0.f;
        }
        uint4 hi, lo;
        hi.x = bf2(f[0], f[1]); hi.y = bf2(f[2], f[3]);
        hi.z = bf2(f[4], f[5]); hi.w = bf2(f[6], f[7]);
        lo.x = bf2(bfres(f[0]), bfres(f[1])); lo.y = bf2(bfres(f[2]), bfres(f[3]));
        lo.z = bf2(bfres(f[4]), bfres(f[5])); lo.w = bf2(bfres(f[6]), bfres(f[7]));
        *(uint4*)(As + (size_t)r * AS_LD + g * 8)       = hi;
        *(uint4*)(As + (size_t)r * AS_LD + 128 + g * 8) = lo;
        *(uint4*)(As + (size_t)r * AS_LD + 256 + g * 8) = hi;
    }
    // stage B: pre-split rows, straight copy
    for (int idx = tid; idx < 384 * 16; idx += 256) {
        int kk = idx >> 4, g = idx & 15;
        uint4 v = __ldg((const uint4*)Wb + kk * 16 + g);
        *(uint4*)(Bs + (size_t)kk * BS_LD + g * 8) = v;
    }
    __syncthreads();

    wmma::fragment<wmma::accumulator, 16, 16, 16, float> acc[8];
#pragma unroll
    for (int j = 0; j < 8; j++) wmma::fill_fragment(acc[j], 0.f);
    const int row0 = wid * 16;
#pragma unroll 4
    for (int k = 0; k < 24; k++) {
        wmma::fragment<wmma::matrix_a, 16, 16, 16, __nv_bfloat16, wmma::row_major> af;
        wmma::load_matrix_sync(af, As + (size_t)row0 * AS_LD + k * 16, AS_LD);
#pragma unroll
        for (int j = 0; j < 8; j++) {
            wmma::fragment<wmma::matrix_b, 16, 16, 16, __nv_bfloat16, wmma::row_major> bf;
            wmma::load_matrix_sync(bf, Bs + (size_t)(k * 16) * BS_LD + j * 16, BS_LD);
            wmma::mma_sync(acc[j], af, bf, acc[j]);
        }
    }
    __syncthreads();   // all warps done reading As before we overwrite with Cs
#pragma unroll
    for (int j = 0; j < 8; j++)
        wmma::store_matrix_sync(Cs + (size_t)row0 * CS_LD + j * 16, acc[j], CS_LD,
                                wmma::mem_row_major);
    __syncthreads();

    // epilogue: each thread handles one row-half (64 cols)
    {
        int r = tid >> 1, h = (tid & 1) * 64;
        int gr = m0 + r;
        if (gr < M) {
            float a = __ldg(pa);
#pragma unroll
            for (int q = 0; q < 16; q++) {
                int c = h + q * 4;
                float4 v = *(float4*)(Cs + (size_t)r * CS_LD + c);
                float4 bb = __ldg((const float4*)(bias + c));
                add4(v, bb);
                if (out_h16)
                    *(uint2*)(out_h16 + (size_t)gr * 64 + c / 2) = h4(v);
                if (out_f32) {
                    float4 o = prelu_f32 ? prelu4(v, a) : v;
                    *(float4*)(out_f32 + (size_t)gr * D + c) = o;
                }
            }
        }
    }
}

// ---------------- setup kernels ----------------------------------------------
__global__ void kzero_counts(int* cd, int* cs, int* cc1, int* cc2, int E, int N, int C) {
    int i = blockIdx.x * blockDim.x + threadIdx.x;
    int tot = E + N + 2 * C;
    if (i >= tot) return;
    if (i < E) cd[i] = 0;
    else if (i < E + N) cs[i - E] = 0;
    else if (i < E + N + C) cc1[i - E - N] = 0;
    else cc2[i - E - N - C] = 0;
}

__global__ void kcountall(const int* __restrict__ src, const int* __restrict__ dst,
                          const int* __restrict__ he_c, const int* __restrict__ nc_c,
                          int* cs, int* cd, int* cc1, int* cc2,
                          int nnz, int E, int N) {
    int i = blockIdx.x * blockDim.x + threadIdx.x;
    if (i < nnz) {
        atomicAdd(&cd[dst[i]], 1);
        atomicAdd(&cs[src[i]], 1);
    } else if (i < nnz + E) {
        atomicAdd(&cc1[he_c[i - nnz]], 1);
    } else if (i < nnz + E + N) {
        atomicAdd(&cc2[nc_c[i - nnz - E]], 1);
    }
}

__global__ __launch_bounds__(1024) void kscanA(const int* __restrict__ cd,
                                               const int* __restrict__ cs,
                                               int* od, int* os, int* bsum,
                                               int nbd, int E, int N) {
    __shared__ int sh[1024];
    const int b = blockIdx.x, t = threadIdx.x;
    const bool isD = b < nbd;
    const int* in = isD ? cd : cs;
    int* out = isD ? od : os;
    const int n = isD ? E : N;
    const int i = (isD ? b : b - nbd) * 1024 + t;
    int v = (i < n) ? in[i] : 0;
    sh[t] = v;
    __syncthreads();
    for (int off = 1; off < 1024; off <<= 1) {
        int x = (t >= off) ? sh[t - off] : 0;
        __syncthreads();
        sh[t] += x;
        __syncthreads();
    }
    if (i < n) out[i] = sh[t] - v;
    if (t == 1023) bsum[b] = sh[1023];
}

__global__ __launch_bounds__(1024) void kscanB(const int* __restrict__ bsum,
                                               int* bscan, int nbd, int nbtot, int nnz) {
    __shared__ int sh[1024];
    int t = threadIdx.x;
    int v = (t < nbtot) ? bsum[t] : 0;
    sh[t] = v;
    __syncthreads();
    for (int off = 1; off < 1024; off <<= 1) {
        int x = (t >= off) ? sh[t - off] : 0;
        __syncthreads();
        sh[t] += x;
        __syncthreads();
    }
    if (t < nbtot) {
        int excl = sh[t] - v;
        bscan[t] = (t >= nbd) ? excl - nnz : excl;
    }
}

__global__ __launch_bounds__(1024) void kscanC(int* od, int* os,
                                               const int* __restrict__ bscan,
                                               int* cd, int* cs,
                                               int nbd, int E, int N, int nnz) {
    const int b = blockIdx.x, t = threadIdx.x;
    const bool isD = b < nbd;
    const int i = (isD ? b : b - nbd) * 1024 + t;
    if (isD) {
        if (i < E) { od[i] += bscan[b]; cd[i] = 0; }
        if (b == 0 && t == 0) od[E] = nnz;
    } else {
        if (i < N) { os[i] += bscan[b]; cs[i] = 0; }
        if (i == 0) os[N] = nnz;
    }
}

__global__ void kfill(const int* __restrict__ src, const int* __restrict__ dst,
                      const int* __restrict__ od, const int* __restrict__ os,
                      int* cur_d, int* cur_s, int* perm_d, int* perm_s, int nnz) {
    int k = blockIdx.x * blockDim.x + threadIdx.x;
    if (k >= nnz) return;
    int s = __ldg(&src[k]), d = __ldg(&dst[k]);
    int pd = atomicAdd(&cur_d[d], 1);
    perm_d[__ldg(&od[d]) + pd] = s;
    int ps = atomicAdd(&cur_s[s], 1);
    perm_s[__ldg(&os[s]) + ps] = d;
}

__global__ void kinvall(const int* __restrict__ od, const int* __restrict__ os,
                        const int* __restrict__ cc1, const int* __restrict__ cc2,
                        float* invd, float* invs, float* ic1, float* ic2,
                        int E, int N, int C) {
    int i = blockIdx.x * blockDim.x + threadIdx.x;
    if (i < E) {
        int c = od[i + 1] - od[i];
        invd[i] = 1.f / (float)(c > 0 ? c : 1);
    } else if (i < E + N) {
        int j = i - E;
        int c = os[j + 1] - os[j] + 1;
        invs[j] = 1.f / (float)c;
    } else if (i < E + N + C) {
        int c = cc1[i - E - N];
        ic1[i - E - N] = 1.f / (float)(c > 0 ? c : 1);
    } else if (i < E + N + 2 * C) {
        int c = cc2[i - E - N - C];
        ic2[i - E - N - C] = 1.f / (float)(c > 0 ? c : 1);
    }
}

__global__ void kzero4(float4* p, long n4) {
    long i = (long)blockIdx.x * blockDim.x + threadIdx.x;
    if (i < n4) p[i] = make_float4(0.f, 0.f, 0.f, 0.f);
}

// ---------------- SIMT GEMM (small C-row GEMMs) ------------------------------
__global__ __launch_bounds__(256) void kgemm2(const float* __restrict__ X,
                                              const float* __restrict__ W,
                                              const float* __restrict__ b,
                                              const float* __restrict__ addin,
                                              float* __restrict__ Yraw,
                                              float* __restrict__ Ypre,
                                              const float* __restrict__ pa, int M) {
    __shared__ float As[64][128];
    const int m0 = blockIdx.x * 64;
    const int t = threadIdx.x;
    {
        const int c4 = t & 31;
        const int r0 = t >> 5;
#pragma unroll
        for (int s = 0; s < 8; s++) {
            int r = r0 + 8 * s;
            int gr = m0 + r;
            float4 v = make_float4(0.f, 0.f, 0.f, 0.f);
            if (gr < M) v = ((const float4*)(X + (size_t)gr * D))[c4];
            ((float4*)(&As[r][0]))[c4] = v;
        }
    }
    __syncthreads();
    const int cg = (t & 15) * 8;
    const int rg = (t >> 4) * 4;
    unsigned long long acc[4][4];
#pragma unroll
    for (int i = 0; i < 4; i++)
#pragma unroll
        for (int j = 0; j < 4; j++) acc[i][j] = 0ULL;
#pragma unroll 4
    for (int k = 0; k < D; k += 4) {
        float4 a[4];
#pragma unroll
        for (int i = 0; i < 4; i++) a[i] = *(const float4*)&As[rg + i][k];
#pragma unroll
        for (int kk = 0; kk < 4; kk++) {
            const ulonglong2 w0 = *reinterpret_cast<const ulonglong2*>(&W[(k + kk) * D + cg]);
            const ulonglong2 w1 = *reinterpret_cast<const ulonglong2*>(&W[(k + kk) * D + cg + 4]);
#pragma unroll
            for (int i = 0; i < 4; i++) {
                float av = (kk == 0) ? a[i].x : (kk == 1) ? a[i].y
                         : (kk == 2) ? a[i].z : a[i].w;
                unsigned long long av2 = pk2(av);
                fma2(acc[i][0], av2, w0.x);
                fma2(acc[i][1], av2, w0.y);
                fma2(acc[i][2], av2, w1.x);
                fma2(acc[i][3], av2, w1.y);
            }
        }
    }
    const float4 b0 = __ldg((const float4*)&b[cg]);
    const float4 b1 = __ldg((const float4*)&b[cg + 4]);
    const float a = __ldg(pa);
#pragma unroll
    for (int i = 0; i < 4; i++) {
        int gr = m0 + rg + i;
        if (gr >= M) continue;
        float2 p0 = up2(acc[i][0]), p1 = up2(acc[i][1]);
        float2 p2 = up2(acc[i][2]), p3 = up2(acc[i][3]);
        float4 o0 = make_float4(p0.x + b0.x, p0.y + b0.y, p1.x + b0.z, p1.y + b0.w);
        float4 o1 = make_float4(p2.x + b1.x, p2.y + b1.y, p3.x + b1.z, p3.y + b1.w);
        if (addin) {
            const float4* ar = (const float4*)(addin + (size_t)gr * D);
            add4(o0, ar[cg / 4]); add4(o1, ar[cg / 4 + 1]);
        }
        if (Yraw) {
            float4* yr = (float4*)(Yraw + (size_t)gr * D);
            yr[cg / 4] = o0; yr[cg / 4 + 1] = o1;
        }
        if (Ypre) {
            float4* yp = (float4*)(Ypre + (size_t)gr * D);
            yp[cg / 4] = prelu4(o0, a); yp[cg / 4 + 1] = prelu4(o1, a);
        }
    }
}

// ---------------- CSR aggregation (warp per segment, fp16 gather) ------------
__global__ __launch_bounds__(256) void kagg_e(const unsigned* __restrict__ T16,
                                              const int* __restrict__ perm,
                                              const int* __restrict__ offs,
                                              const float* __restrict__ invd,
                                              const float* __restrict__ pa,
                                              unsigned* __restrict__ EB16,
                                              float* __restrict__ out_e, int E) {
    int w = (blockIdx.x * blockDim.x + threadIdx.x) >> 5;
    int lane = threadIdx.x & 31;
    if (w >= E) return;
    int beg = __ldg(&offs[w]), end = __ldg(&offs[w + 1]);
    float4 a0 = {0,0,0,0}, a1 = {0,0,0,0}, a2 = {0,0,0,0}, a3 = {0,0,0,0};
    int p = beg;
    for (; p + 4 <= end; p += 4) {
        int s0 = __ldg(&perm[p]),     s1 = __ldg(&perm[p + 1]);
        int s2 = __ldg(&perm[p + 2]), s3 = __ldg(&perm[p + 3]);
        addh(a0, __ldg((const uint2*)(T16 + (size_t)s0 * 64) + lane));
        addh(a1, __ldg((const uint2*)(T16 + (size_t)s1 * 64) + lane));
        addh(a2, __ldg((const uint2*)(T16 + (size_t)s2 * 64) + lane));
        addh(a3, __ldg((const uint2*)(T16 + (size_t)s3 * 64) + lane));
    }
    for (; p < end; p++)
        addh(a0, __ldg((const uint2*)(T16 + (size_t)__ldg(&perm[p]) * 64) + lane));
    add4(a0, a1); add4(a2, a3); add4(a0, a2);
    float iv = __ldg(&invd[w]);
    float a = __ldg(pa);
    a0.x *= iv; a0.y *= iv; a0.z *= iv; a0.w *= iv;
    float4 r = prelu4(a0, a);
    ((uint2*)(EB16 + (size_t)w * 64))[lane] = h4(r);
    if (out_e) ((float4*)out_e)[(size_t)w * 32 + lane] = r;
}

__global__ __launch_bounds__(256) void kagg_n(float* __restrict__ T,
                                              const unsigned* __restrict__ EB16,
                                              const int* __restrict__ perm,
                                              const int* __restrict__ offs,
                                              const float* __restrict__ invs,
                                              const float* __restrict__ pa, int N) {
    int w = (blockIdx.x * blockDim.x + threadIdx.x) >> 5;
    int lane = threadIdx.x & 31;
    if (w >= N) return;
    int beg = __ldg(&offs[w]), end = __ldg(&offs[w + 1]);
    float4 a0 = {0,0,0,0}, a1 = {0,0,0,0}, a2 = {0,0,0,0}, a3 = {0,0,0,0};
    int p = beg;
    for (; p + 4 <= end; p += 4) {
        int s0 = __ldg(&perm[p]),     s1 = __ldg(&perm[p + 1]);
        int s2 = __ldg(&perm[p + 2]), s3 = __ldg(&perm[p + 3]);
        addh(a0, __ldg((const uint2*)(EB16 + (size_t)s0 * 64) + lane));
        addh(a1, __ldg((const uint2*)(EB16 + (size_t)s1 * 64) + lane));
        addh(a2, __ldg((const uint2*)(EB16 + (size_t)s2 * 64) + lane));
        addh(a3, __ldg((const uint2*)(EB16 + (size_t)s3 * 64) + lane));
    }
    for (; p < end; p++)
        addh(a0, __ldg((const uint2*)(EB16 + (size_t)__ldg(&perm[p]) * 64) + lane));
    add4(a0, a1); add4(a2, a3); add4(a0, a2);
    float a = __ldg(pa);
    float4 t = ((float4*)T)[(size_t)w * 32 + lane];
    add4(a0, prelu4(t, a));
    float iv = __ldg(&invs[w]);
    a0.x *= iv; a0.y *= iv; a0.z *= iv; a0.w *= iv;
    ((float4*)T)[(size_t)w * 32 + lane] = a0;
}

// ---------------- component scatter (atomic; fp16 gather) --------------------
__device__ __forceinline__ void red4(float* a, float4 v) {
    asm volatile("red.global.add.v4.f32 [%0], {%1,%2,%3,%4};"
                 :: "l"(a), "f"(v.x), "f"(v.y), "f"(v.z), "f"(v.w)
                 : "memory");
}

__global__ void kscatterc(const unsigned* __restrict__ P16, const int* __restrict__ rows,
                          const int* __restrict__ comp, const float* __restrict__ inv,
                          float* __restrict__ csum, int n) {
    int w = (blockIdx.x * blockDim.x + threadIdx.x) >> 5;
    int lane = threadIdx.x & 31;
    if (w >= n) return;
    int r = __ldg(&rows[w]);
    int c = __ldg(&comp[w]);
    float sc = __ldg(&inv[c]);
    float4 v = {0,0,0,0};
    addh(v, __ldg((const uint2*)(P16 + (size_t)r * 64) + lane));
    v.x *= sc; v.y *= sc; v.z *= sc; v.w *= sc;
    red4(csum + (size_t)c * D + lane * 4, v);
}

// ---------------- host driver ------------------------------------------------
static inline int cdiv(long a, long b) { return (int)((a + b - 1) / b); }

extern "C" void kernel_launch(void* const* d_in, const int* in_sizes, int n_in,
                              void* d_out, int out_size) {
    const float* x   = (const float*)d_in[0];
    const int*   hei = (const int*)d_in[1];
    const int*   hci = (const int*)d_in[2];
    const int*   nci = (const int*)d_in[3];

    const int NNZ = in_sizes[1] / 2;
    const int E   = in_sizes[2] / 2;
    const int N   = in_sizes[0] / D;
    const int C   = out_size / D - N - E;

    int wi = -1;
    for (int i = 4; i < n_in; i++) {
        if (in_sizes[i] == D * D) { wi = i; break; }
    }
    const float* pa = (const float*)d_in[wi - 1];

    const int* src  = hei;
    const int* dst  = hei + NNZ;
    const int* he_e = hci;
    const int* he_c = hci + E;
    const int* nc_n = nci;
    const int* nc_c = nci + N;

    float *T, *HB, *CE, *CN, *CT, *invd, *invs, *ic1, *ic2;
    unsigned *T16, *E16, *Wb;
    int *cd, *cs, *cc1, *cc2, *od, *os, *pd, *ps, *bsum, *bscan;
    cudaGetSymbolAddress((void**)&T,    g_T);
    cudaGetSymbolAddress((void**)&T16,  g_T16);
    cudaGetSymbolAddress((void**)&E16,  g_E16);
    cudaGetSymbolAddress((void**)&HB,   g_h);
    cudaGetSymbolAddress((void**)&CE,   g_c1);
    cudaGetSymbolAddress((void**)&CN,   g_c2);
    cudaGetSymbolAddress((void**)&CT,   g_c3);
    cudaGetSymbolAddress((void**)&Wb,   g_Wb);
    cudaGetSymbolAddress((void**)&invd, g_invdst);
    cudaGetSymbolAddress((void**)&invs, g_invsrc);
    cudaGetSymbolAddress((void**)&ic1,  g_invc1);
    cudaGetSymbolAddress((void**)&ic2,  g_invc2);
    cudaGetSymbolAddress((void**)&cd,   g_cd);
    cudaGetSymbolAddress((void**)&cs,   g_cs);
    cudaGetSymbolAddress((void**)&cc1,  g_cc1);
    cudaGetSymbolAddress((void**)&cc2,  g_cc2);
    cudaGetSymbolAddress((void**)&od,   g_offs_d);
    cudaGetSymbolAddress((void**)&os,   g_offs_s);
    cudaGetSymbolAddress((void**)&pd,   g_perm_d);
    cudaGetSymbolAddress((void**)&ps,   g_perm_s);
    cudaGetSymbolAddress((void**)&bsum, g_bsum);
    cudaGetSymbolAddress((void**)&bscan,g_bscan);

    float* out   = (float*)d_out;
    float* out_n = out;
    float* out_e = out + (size_t)N * D;
    float* out_c = out + (size_t)(N + E) * D;

    const int TB = 256;
    const int nbd = cdiv(E, 1024);
    const int nbs = cdiv(N, 1024);
    const int nbtot = nbd + nbs;
    const int GT = cdiv(N, 128);

    const float* Wv0 = (const float*)d_in[wi + 0];
    const float* bv0 = (const float*)d_in[wi + 1];
    const float* We0 = (const float*)d_in[wi + 2];
    const float* be0 = (const float*)d_in[wi + 3];
    const float* Wv1 = (const float*)d_in[wi + 8];
    const float* bv1 = (const float*)d_in[wi + 9];
    const float* We1 = (const float*)d_in[wi + 10];
    const float* be1 = (const float*)d_in[wi + 11];

    cudaFuncSetAttribute(kgemm_tc, cudaFuncAttributeMaxDynamicSharedMemorySize, SM_TOT);

    kconvW<<<cdiv(4 * 384 * 16, TB), TB>>>(Wv0, We0, Wv1, We1, Wb);
    kzero_counts<<<cdiv(E + N + 2 * C, TB), TB>>>(cd, cs, cc1, cc2, E, N, C);
    kcountall<<<cdiv(NNZ + E + N, TB), TB>>>(src, dst, he_c, nc_c, cs, cd, cc1, cc2,
                                             NNZ, E, N);
    // G1 = v2e layer 0 -> T fp32 raw + T16 (launch index 3 for ncu capture)
    kgemm_tc<<<GT, TB, SM_TOT>>>(x, Wb + 0 * 24576, bv0, pa, T, T16, 0, N);
    kscanA<<<nbtot, 1024>>>(cd, cs, od, os, bsum, nbd, E, N);
    kscanB<<<1, 1024>>>(bsum, bscan, nbd, nbtot, NNZ);
    kscanC<<<nbtot, 1024>>>(od, os, bscan, cd, cs, nbd, E, N, NNZ);
    kfill<<<cdiv(NNZ, TB), TB>>>(src, dst, od, os, cd, cs, pd, ps, NNZ);
    kinvall<<<cdiv(E + N + 2 * C, TB), TB>>>(od, os, cc1, cc2, invd, invs, ic1, ic2,
                                             E, N, C);

    // ---- layer 0 ----
    kagg_e<<<cdiv((long)E * 32, TB), TB>>>(T16, pd, od, invd, pa, E16, nullptr, E);
    kagg_n<<<cdiv((long)N * 32, TB), TB>>>(T, E16, ps, os, invs, pa, N);
    // G2 = e2v layer 0 -> HB = prelu(A@We0+be0)
    kgemm_tc<<<GT, TB, SM_TOT>>>(T, Wb + 1 * 24576, be0, pa, HB, nullptr, 1, N);

    // ---- layer 1 ----
    kgemm_tc<<<GT, TB, SM_TOT>>>(HB, Wb + 2 * 24576, bv1, pa, T, T16, 0, N);
    kagg_e<<<cdiv((long)E * 32, TB), TB>>>(T16, pd, od, invd, pa, E16, out_e, E);
    kagg_n<<<cdiv((long)N * 32, TB), TB>>>(T, E16, ps, os, invs, pa, N);
    // G4 = e2v layer 1 -> out_n = prelu(n), T16 = raw n fp16
    kgemm_tc<<<GT, TB, SM_TOT>>>(T, Wb + 3 * 24576, be1, pa, out_n, T16, 1, N);

    // components
    kzero4<<<cdiv((long)C * 32, TB), TB>>>((float4*)CE, (long)C * 32);
    kzero4<<<cdiv((long)C * 32, TB), TB>>>((float4*)CN, (long)C * 32);
    kscatterc<<<cdiv((long)E, 8), TB>>>(E16, he_e, he_c, ic1, CE, E);
    kscatterc<<<cdiv((long)N, 8), TB>>>(T16, nc_n, nc_c, ic2, CN, N);
    kgemm2<<<cdiv(C, 64), TB>>>(CE, (const float*)d_in[wi + 12], (const float*)d_in[wi + 13],
                                nullptr, CT, nullptr, pa, C);
    kgemm2<<<cdiv(C, 64), TB>>>(CN, (const float*)d_in[wi + 14], (const float*)d_in[wi + 15],
                                CT, nullptr, out_c, pa, C);
}

// round 7
// speedup vs baseline: 1.1017x; 1.1017x over previous
#include <cuda_runtime.h>
#include <cuda_fp16.h>
#include <cuda_bf16.h>
#include <mma.h>
#include <cstdint>
#include <cstddef>

#define D 128
using namespace nvcuda;

// ---------------- static scratch (device globals) ---------------------------
static __device__ float    g_T  [100000 * 128];  // T fp32; reused in-place as A
static __device__ unsigned g_T16[100000 * 64];   // T / n fp16 rows
static __device__ unsigned g_E16[50000  * 64];   // e fp16 rows
static __device__ float    g_h  [100000 * 128];  // h = prelu(n) from layer 0
static __device__ float    g_c1 [2048   * 128];
static __device__ float    g_c2 [2048   * 128];
static __device__ float    g_c3 [2048   * 128];
static __device__ unsigned g_Wb [4 * 384 * 64];  // 4 W, bf16-split [384][128] rows
static __device__ float g_invdst[50016];
static __device__ float g_invsrc[100016];
static __device__ float g_invc1[2048];
static __device__ float g_invc2[2048];
static __device__ int   g_cd [50016];
static __device__ int   g_cs [100016];
static __device__ int   g_cc1[2048];
static __device__ int   g_cc2[2048];
static __device__ int   g_offs_d[50024];
static __device__ int   g_offs_s[100024];
static __device__ int   g_perm_d[1600128];
static __device__ int   g_perm_s[1600128];
static __device__ int   g_bsum [1024];
static __device__ int   g_bscan[1024];

// ---------------- helpers ----------------------------------------------------
__device__ __forceinline__ unsigned long long pk2(float v) {
    unsigned long long r; unsigned u = __float_as_uint(v);
    asm("mov.b64 %0, {%1,%1};" : "=l"(r) : "r"(u));
    return r;
}
__device__ __forceinline__ void fma2(unsigned long long& d, unsigned long long a,
                                     unsigned long long b) {
    asm("fma.rn.f32x2 %0, %1, %2, %0;" : "+l"(d) : "l"(a), "l"(b));
}
__device__ __forceinline__ float2 up2(unsigned long long v) {
    unsigned lo, hi;
    asm("mov.b64 {%0,%1}, %2;" : "=r"(lo), "=r"(hi) : "l"(v));
    return make_float2(__uint_as_float(lo), __uint_as_float(hi));
}
__device__ __forceinline__ float prelu1(float v, float a) { return v >= 0.f ? v : a * v; }
__device__ __forceinline__ float4 prelu4(float4 v, float a) {
    return make_float4(prelu1(v.x, a), prelu1(v.y, a), prelu1(v.z, a), prelu1(v.w, a));
}
__device__ __forceinline__ void add4(float4& a, float4 b) {
    a.x += b.x; a.y += b.y; a.z += b.z; a.w += b.w;
}
__device__ __forceinline__ void addh(float4& a, uint2 v) {
    __half2 h0 = *reinterpret_cast<__half2*>(&v.x);
    __half2 h1 = *reinterpret_cast<__half2*>(&v.y);
    float2 f0 = __half22float2(h0), f1 = __half22float2(h1);
    a.x += f0.x; a.y += f0.y; a.z += f1.x; a.w += f1.y;
}
__device__ __forceinline__ uint2 h4(float4 v) {
    __half2 h0 = __float22half2_rn(make_float2(v.x, v.y));
    __half2 h1 = __float22half2_rn(make_float2(v.z, v.w));
    uint2 r;
    r.x = *reinterpret_cast<unsigned*>(&h0);
    r.y = *reinterpret_cast<unsigned*>(&h1);
    return r;
}
__device__ __forceinline__ unsigned bf2(float a, float b) {
    __nv_bfloat162 t = __floats2bfloat162_rn(a, b);
    return *reinterpret_cast<unsigned*>(&t);
}
__device__ __forceinline__ float bfres(float a) {   // a - bf16(a)
    return a - __bfloat162float(__float2bfloat16_rn(a));
}

// ---------------- W pre-split: Wb[w] = bf16 [384][128], rows [hi|hi|lo] ------
__global__ void kconvW(const float* __restrict__ W0, const float* __restrict__ W1,
                       const float* __restrict__ W2, const float* __restrict__ W3,
                       unsigned* __restrict__ Wb) {
    int idx = blockIdx.x * blockDim.x + threadIdx.x;
    if (idx >= 4 * 384 * 16) return;
    int w = idx / (384 * 16);
    int rem = idx % (384 * 16);
    int kk = rem >> 4, g = rem & 15;
    const float* W = (w == 0) ? W0 : (w == 1) ? W1 : (w == 2) ? W2 : W3;
    int ksrc = (kk < 128) ? kk : (kk < 256) ? kk - 128 : kk - 256;
    bool lo = (kk >= 256);
    float4 x0 = __ldg((const float4*)(W + (size_t)ksrc * D + g * 8));
    float4 x1 = __ldg((const float4*)(W + (size_t)ksrc * D + g * 8 + 4));
    float f[8] = {x0.x, x0.y, x0.z, x0.w, x1.x, x1.y, x1.z, x1.w};
    if (lo) {
#pragma unroll
        for (int j = 0; j < 8; j++) f[j] = bfres(f[j]);
    }
    uint4 v;
    v.x = bf2(f[0], f[1]); v.y = bf2(f[2], f[3]);
    v.z = bf2(f[4], f[5]); v.w = bf2(f[6], f[7]);
    ((uint4*)(Wb + (size_t)w * 384 * 64))[kk * 16 + g] = v;
}

// ---------------- WMMA GEMM: Y[M x 128] = X @ W + b --------------------------
// 3-term bf16 emulation over K=384; 512 threads, warp tile 16x64.
// Conflict-free LDSM strides: AS_LD*2 = 816 B (mod128 = 48), BS_LD*2 = 272 B (mod128 = 16).
#define AS_LD 408
#define BS_LD 136
#define CS_LD 136
#define SM_AS  (128 * AS_LD * 2)              // 104448
#define SM_TOT (SM_AS + 384 * BS_LD * 2)      // 104448 + 104448 = 208896

__global__ __launch_bounds__(512, 1) void kgemm_tc(const float* __restrict__ X,
                                                   const unsigned* __restrict__ Wb,
                                                   const float* __restrict__ bias,
                                                   const float* __restrict__ pa,
                                                   float* __restrict__ out_f32,
                                                   unsigned* __restrict__ out_h16,
                                                   int prelu_f32, int M) {
    extern __shared__ char smem[];
    __nv_bfloat16* As = (__nv_bfloat16*)smem;            // 128 x AS_LD
    __nv_bfloat16* Bs = (__nv_bfloat16*)(smem + SM_AS);  // 384 x BS_LD
    float* Cs = (float*)smem;                            // reuse As: 128 x CS_LD
    const int tid = threadIdx.x;
    const int wid = tid >> 5;
    const int m0 = blockIdx.x * 128;

    // stage A: fp32 -> bf16 hi/lo split, K segments [hi | lo | hi]
    for (int idx = tid; idx < 128 * 16; idx += 512) {
        int r = idx >> 4, g = idx & 15;
        int gr = m0 + r;
        float f[8];
        if (gr < M) {
            float4 x0 = __ldg((const float4*)(X + (size_t)gr * D + g * 8));
            float4 x1 = __ldg((const float4*)(X + (size_t)gr * D + g * 8 + 4));
            f[0] = x0.x; f[1] = x0.y; f[2] = x0.z; f[3] = x0.w;
            f[4] = x1.x; f[5] = x1.y; f[6] = x1.z; f[7] = x1.w;
        } else {
#pragma unroll
            for (int j = 0; j < 8; j++) f[j] = 0.f;
        }
        uint4 hi, lo;
        hi.x = bf2(f[0], f[1]); hi.y = bf2(f[2], f[3]);
        hi.z = bf2(f[4], f[5]); hi.w = bf2(f[6], f[7]);
        lo.x = bf2(bfres(f[0]), bfres(f[1])); lo.y = bf2(bfres(f[2]), bfres(f[3]));
        lo.z = bf2(bfres(f[4]), bfres(f[5])); lo.w = bf2(bfres(f[6]), bfres(f[7]));
        *(uint4*)(As + (size_t)r * AS_LD + g * 8)       = hi;
        *(uint4*)(As + (size_t)r * AS_LD + 128 + g * 8) = lo;
        *(uint4*)(As + (size_t)r * AS_LD + 256 + g * 8) = hi;
    }
    // stage B: pre-split rows, straight copy
    for (int idx = tid; idx < 384 * 16; idx += 512) {
        int kk = idx >> 4, g = idx & 15;
        uint4 v = __ldg((const uint4*)Wb + kk * 16 + g);
        *(uint4*)(Bs + (size_t)kk * BS_LD + g * 8) = v;
    }
    __syncthreads();

    // 16 warps: 8 m-strips x 2 n-halves; warp tile 16x64
    const int row0 = (wid >> 1) * 16;
    const int n0   = (wid & 1) * 64;
    wmma::fragment<wmma::accumulator, 16, 16, 16, float> acc[4];
#pragma unroll
    for (int j = 0; j < 4; j++) wmma::fill_fragment(acc[j], 0.f);
#pragma unroll 6
    for (int k = 0; k < 24; k++) {
        wmma::fragment<wmma::matrix_a, 16, 16, 16, __nv_bfloat16, wmma::row_major> af;
        wmma::load_matrix_sync(af, As + (size_t)row0 * AS_LD + k * 16, AS_LD);
#pragma unroll
        for (int j = 0; j < 4; j++) {
            wmma::fragment<wmma::matrix_b, 16, 16, 16, __nv_bfloat16, wmma::row_major> bf;
            wmma::load_matrix_sync(bf, Bs + (size_t)(k * 16) * BS_LD + n0 + j * 16, BS_LD);
            wmma::mma_sync(acc[j], af, bf, acc[j]);
        }
    }
    __syncthreads();   // all warps done reading As before overwrite with Cs
#pragma unroll
    for (int j = 0; j < 4; j++)
        wmma::store_matrix_sync(Cs + (size_t)row0 * CS_LD + n0 + j * 16, acc[j], CS_LD,
                                wmma::mem_row_major);
    __syncthreads();

    // epilogue: each thread one quarter-row (32 cols)
    {
        int r = tid >> 2, h = (tid & 3) * 32;
        int gr = m0 + r;
        if (gr < M) {
            float a = __ldg(pa);
#pragma unroll
            for (int q = 0; q < 8; q++) {
                int c = h + q * 4;
                float4 v = *(float4*)(Cs + (size_t)r * CS_LD + c);
                float4 bb = __ldg((const float4*)(bias + c));
                add4(v, bb);
                if (out_h16)
                    *(uint2*)(out_h16 + (size_t)gr * 64 + c / 2) = h4(v);
                if (out_f32) {
                    float4 o = prelu_f32 ? prelu4(v, a) : v;
                    *(float4*)(out_f32 + (size_t)gr * D + c) = o;
                }
            }
        }
    }
}

// ---------------- setup kernels ----------------------------------------------
__global__ void kzero_counts(int* cd, int* cs, int* cc1, int* cc2, int E, int N, int C) {
    int i = blockIdx.x * blockDim.x + threadIdx.x;
    int tot = E + N + 2 * C;
    if (i >= tot) return;
    if (i < E) cd[i] = 0;
    else if (i < E + N) cs[i - E] = 0;
    else if (i < E + N + C) cc1[i - E - N] = 0;
    else cc2[i - E - N - C] = 0;
}

__global__ void kcountall(const int* __restrict__ src, const int* __restrict__ dst,
                          const int* __restrict__ he_c, const int* __restrict__ nc_c,
                          int* cs, int* cd, int* cc1, int* cc2,
                          int nnz, int E, int N) {
    int i = blockIdx.x * blockDim.x + threadIdx.x;
    if (i < nnz) {
        atomicAdd(&cd[dst[i]], 1);
        atomicAdd(&cs[src[i]], 1);
    } else if (i < nnz + E) {
        atomicAdd(&cc1[he_c[i - nnz]], 1);
    } else if (i < nnz + E + N) {
        atomicAdd(&cc2[nc_c[i - nnz - E]], 1);
    }
}

__global__ __launch_bounds__(1024) void kscanA(const int* __restrict__ cd,
                                               const int* __restrict__ cs,
                                               int* od, int* os, int* bsum,
                                               int nbd, int E, int N) {
    __shared__ int sh[1024];
    const int b = blockIdx.x, t = threadIdx.x;
    const bool isD = b < nbd;
    const int* in = isD ? cd : cs;
    int* out = isD ? od : os;
    const int n = isD ? E : N;
    const int i = (isD ? b : b - nbd) * 1024 + t;
    int v = (i < n) ? in[i] : 0;
    sh[t] = v;
    __syncthreads();
    for (int off = 1; off < 1024; off <<= 1) {
        int x = (t >= off) ? sh[t - off] : 0;
        __syncthreads();
        sh[t] += x;
        __syncthreads();
    }
    if (i < n) out[i] = sh[t] - v;
    if (t == 1023) bsum[b] = sh[1023];
}

__global__ __launch_bounds__(1024) void kscanB(const int* __restrict__ bsum,
                                               int* bscan, int nbd, int nbtot, int nnz) {
    __shared__ int sh[1024];
    int t = threadIdx.x;
    int v = (t < nbtot) ? bsum[t] : 0;
    sh[t] = v;
    __syncthreads();
    for (int off = 1; off < 1024; off <<= 1) {
        int x = (t >= off) ? sh[t - off] : 0;
        __syncthreads();
        sh[t] += x;
        __syncthreads();
    }
    if (t < nbtot) {
        int excl = sh[t] - v;
        bscan[t] = (t >= nbd) ? excl - nnz : excl;
    }
}

__global__ __launch_bounds__(1024) void kscanC(int* od, int* os,
                                               const int* __restrict__ bscan,
                                               int* cd, int* cs,
                                               int nbd, int E, int N, int nnz) {
    const int b = blockIdx.x, t = threadIdx.x;
    const bool isD = b < nbd;
    const int i = (isD ? b : b - nbd) * 1024 + t;
    if (isD) {
        if (i < E) { od[i] += bscan[b]; cd[i] = 0; }
        if (b == 0 && t == 0) od[E] = nnz;
    } else {
        if (i < N) { os[i] += bscan[b]; cs[i] = 0; }
        if (i == 0) os[N] = nnz;
    }
}

__global__ void kfill(const int* __restrict__ src, const int* __restrict__ dst,
                      const int* __restrict__ od, const int* __restrict__ os,
                      int* cur_d, int* cur_s, int* perm_d, int* perm_s, int nnz) {
    int k = blockIdx.x * blockDim.x + threadIdx.x;
    if (k >= nnz) return;
    int s = __ldg(&src[k]), d = __ldg(&dst[k]);
    int pd = atomicAdd(&cur_d[d], 1);
    perm_d[__ldg(&od[d]) + pd] = s;
    int ps = atomicAdd(&cur_s[s], 1);
    perm_s[__ldg(&os[s]) + ps] = d;
}

__global__ void kinvall(const int* __restrict__ od, const int* __restrict__ os,
                        const int* __restrict__ cc1, const int* __restrict__ cc2,
                        float* invd, float* invs, float* ic1, float* ic2,
                        int E, int N, int C) {
    int i = blockIdx.x * blockDim.x + threadIdx.x;
    if (i < E) {
        int c = od[i + 1] - od[i];
        invd[i] = 1.f / (float)(c > 0 ? c : 1);
    } else if (i < E + N) {
        int j = i - E;
        int c = os[j + 1] - os[j] + 1;
        invs[j] = 1.f / (float)c;
    } else if (i < E + N + C) {
        int c = cc1[i - E - N];
        ic1[i - E - N] = 1.f / (float)(c > 0 ? c : 1);
    } else if (i < E + N + 2 * C) {
        int c = cc2[i - E - N - C];
        ic2[i - E - N - C] = 1.f / (float)(c > 0 ? c : 1);
    }
}

__global__ void kzero4(float4* p, long n4) {
    long i = (long)blockIdx.x * blockDim.x + threadIdx.x;
    if (i < n4) p[i] = make_float4(0.f, 0.f, 0.f, 0.f);
}

// ---------------- SIMT GEMM (small C-row GEMMs) ------------------------------
__global__ __launch_bounds__(256) void kgemm2(const float* __restrict__ X,
                                              const float* __restrict__ W,
                                              const float* __restrict__ b,
                                              const float* __restrict__ addin,
                                              float* __restrict__ Yraw,
                                              float* __restrict__ Ypre,
                                              const float* __restrict__ pa, int M) {
    __shared__ float As[64][128];
    const int m0 = blockIdx.x * 64;
    const int t = threadIdx.x;
    {
        const int c4 = t & 31;
        const int r0 = t >> 5;
#pragma unroll
        for (int s = 0; s < 8; s++) {
            int r = r0 + 8 * s;
            int gr = m0 + r;
            float4 v = make_float4(0.f, 0.f, 0.f, 0.f);
            if (gr < M) v = ((const float4*)(X + (size_t)gr * D))[c4];
            ((float4*)(&As[r][0]))[c4] = v;
        }
    }
    __syncthreads();
    const int cg = (t & 15) * 8;
    const int rg = (t >> 4) * 4;
    unsigned long long acc[4][4];
#pragma unroll
    for (int i = 0; i < 4; i++)
#pragma unroll
        for (int j = 0; j < 4; j++) acc[i][j] = 0ULL;
#pragma unroll 4
    for (int k = 0; k < D; k += 4) {
        float4 a[4];
#pragma unroll
        for (int i = 0; i < 4; i++) a[i] = *(const float4*)&As[rg + i][k];
#pragma unroll
        for (int kk = 0; kk < 4; kk++) {
            const ulonglong2 w0 = *reinterpret_cast<const ulonglong2*>(&W[(k + kk) * D + cg]);
            const ulonglong2 w1 = *reinterpret_cast<const ulonglong2*>(&W[(k + kk) * D + cg + 4]);
#pragma unroll
            for (int i = 0; i < 4; i++) {
                float av = (kk == 0) ? a[i].x : (kk == 1) ? a[i].y
                         : (kk == 2) ? a[i].z : a[i].w;
                unsigned long long av2 = pk2(av);
                fma2(acc[i][0], av2, w0.x);
                fma2(acc[i][1], av2, w0.y);
                fma2(acc[i][2], av2, w1.x);
                fma2(acc[i][3], av2, w1.y);
            }
        }
    }
    const float4 b0 = __ldg((const float4*)&b[cg]);
    const float4 b1 = __ldg((const float4*)&b[cg + 4]);
    const float a = __ldg(pa);
#pragma unroll
    for (int i = 0; i < 4; i++) {
        int gr = m0 + rg + i;
        if (gr >= M) continue;
        float2 p0 = up2(acc[i][0]), p1 = up2(acc[i][1]);
        float2 p2 = up2(acc[i][2]), p3 = up2(acc[i][3]);
        float4 o0 = make_float4(p0.x + b0.x, p0.y + b0.y, p1.x + b0.z, p1.y + b0.w);
        float4 o1 = make_float4(p2.x + b1.x, p2.y + b1.y, p3.x + b1.z, p3.y + b1.w);
        if (addin) {
            const float4* ar = (const float4*)(addin + (size_t)gr * D);
            add4(o0, ar[cg / 4]); add4(o1, ar[cg / 4 + 1]);
        }
        if (Yraw) {
            float4* yr = (float4*)(Yraw + (size_t)gr * D);
            yr[cg / 4] = o0; yr[cg / 4 + 1] = o1;
        }
        if (Ypre) {
            float4* yp = (float4*)(Ypre + (size_t)gr * D);
            yp[cg / 4] = prelu4(o0, a); yp[cg / 4 + 1] = prelu4(o1, a);
        }
    }
}

// ---------------- CSR aggregation (warp per segment, fp16 gather) ------------
__global__ __launch_bounds__(256) void kagg_e(const unsigned* __restrict__ T16,
                                              const int* __restrict__ perm,
                                              const int* __restrict__ offs,
                                              const float* __restrict__ invd,
                                              const float* __restrict__ pa,
                                              unsigned* __restrict__ EB16,
                                              float* __restrict__ out_e, int E) {
    int w = (blockIdx.x * blockDim.x + threadIdx.x) >> 5;
    int lane = threadIdx.x & 31;
    if (w >= E) return;
    int beg = __ldg(&offs[w]), end = __ldg(&offs[w + 1]);
    float4 a0 = {0,0,0,0}, a1 = {0,0,0,0}, a2 = {0,0,0,0}, a3 = {0,0,0,0};
    int p = beg;
    for (; p + 4 <= end; p += 4) {
        int s0 = __ldg(&perm[p]),     s1 = __ldg(&perm[p + 1]);
        int s2 = __ldg(&perm[p + 2]), s3 = __ldg(&perm[p + 3]);
        addh(a0, __ldg((const uint2*)(T16 + (size_t)s0 * 64) + lane));
        addh(a1, __ldg((const uint2*)(T16 + (size_t)s1 * 64) + lane));
        addh(a2, __ldg((const uint2*)(T16 + (size_t)s2 * 64) + lane));
        addh(a3, __ldg((const uint2*)(T16 + (size_t)s3 * 64) + lane));
    }
    for (; p < end; p++)
        addh(a0, __ldg((const uint2*)(T16 + (size_t)__ldg(&perm[p]) * 64) + lane));
    add4(a0, a1); add4(a2, a3); add4(a0, a2);
    float iv = __ldg(&invd[w]);
    float a = __ldg(pa);
    a0.x *= iv; a0.y *= iv; a0.z *= iv; a0.w *= iv;
    float4 r = prelu4(a0, a);
    ((uint2*)(EB16 + (size_t)w * 64))[lane] = h4(r);
    if (out_e) ((float4*)out_e)[(size_t)w * 32 + lane] = r;
}

__global__ __launch_bounds__(256) void kagg_n(float* __restrict__ T,
                                              const unsigned* __restrict__ EB16,
                                              const int* __restrict__ perm,
                                              const int* __restrict__ offs,
                                              const float* __restrict__ invs,
                                              const float* __restrict__ pa, int N) {
    int w = (blockIdx.x * blockDim.x + threadIdx.x) >> 5;
    int lane = threadIdx.x & 31;
    if (w >= N) return;
    int beg = __ldg(&offs[w]), end = __ldg(&offs[w + 1]);
    float4 a0 = {0,0,0,0}, a1 = {0,0,0,0}, a2 = {0,0,0,0}, a3 = {0,0,0,0};
    int p = beg;
    for (; p + 4 <= end; p += 4) {
        int s0 = __ldg(&perm[p]),     s1 = __ldg(&perm[p + 1]);
        int s2 = __ldg(&perm[p + 2]), s3 = __ldg(&perm[p + 3]);
        addh(a0, __ldg((const uint2*)(EB16 + (size_t)s0 * 64) + lane));
        addh(a1, __ldg((const uint2*)(EB16 + (size_t)s1 * 64) + lane));
        addh(a2, __ldg((const uint2*)(EB16 + (size_t)s2 * 64) + lane));
        addh(a3, __ldg((const uint2*)(EB16 + (size_t)s3 * 64) + lane));
    }
    for (; p < end; p++)
        addh(a0, __ldg((const uint2*)(EB16 + (size_t)__ldg(&perm[p]) * 64) + lane));
    add4(a0, a1); add4(a2, a3); add4(a0, a2);
    float a = __ldg(pa);
    float4 t = ((float4*)T)[(size_t)w * 32 + lane];
    add4(a0, prelu4(t, a));
    float iv = __ldg(&invs[w]);
    a0.x *= iv; a0.y *= iv; a0.z *= iv; a0.w *= iv;
    ((float4*)T)[(size_t)w * 32 + lane] = a0;
}

// ---------------- component scatter (atomic; fp16 gather) --------------------
__device__ __forceinline__ void red4(float* a, float4 v) {
    asm volatile("red.global.add.v4.f32 [%0], {%1,%2,%3,%4};"
                 :: "l"(a), "f"(v.x), "f"(v.y), "f"(v.z), "f"(v.w)
                 : "memory");
}

__global__ void kscatterc(const unsigned* __restrict__ P16, const int* __restrict__ rows,
                          const int* __restrict__ comp, const float* __restrict__ inv,
                          float* __restrict__ csum, int n) {
    int w = (blockIdx.x * blockDim.x + threadIdx.x) >> 5;
    int lane = threadIdx.x & 31;
    if (w >= n) return;
    int r = __ldg(&rows[w]);
    int c = __ldg(&comp[w]);
    float sc = __ldg(&inv[c]);
    float4 v = {0,0,0,0};
    addh(v, __ldg((const uint2*)(P16 + (size_t)r * 64) + lane));
    v.x *= sc; v.y *= sc; v.z *= sc; v.w *= sc;
    red4(csum + (size_t)c * D + lane * 4, v);
}

// ---------------- host driver ------------------------------------------------
static inline int cdiv(long a, long b) { return (int)((a + b - 1) / b); }

extern "C" void kernel_launch(void* const* d_in, const int* in_sizes, int n_in,
                              void* d_out, int out_size) {
    const float* x   = (const float*)d_in[0];
    const int*   hei = (const int*)d_in[1];
    const int*   hci = (const int*)d_in[2];
    const int*   nci = (const int*)d_in[3];

    const int NNZ = in_sizes[1] / 2;
    const int E   = in_sizes[2] / 2;
    const int N   = in_sizes[0] / D;
    const int C   = out_size / D - N - E;

    int wi = -1;
    for (int i = 4; i < n_in; i++) {
        if (in_sizes[i] == D * D) { wi = i; break; }
    }
    const float* pa = (const float*)d_in[wi - 1];

    const int* src  = hei;
    const int* dst  = hei + NNZ;
    const int* he_e = hci;
    const int* he_c = hci + E;
    const int* nc_n = nci;
    const int* nc_c = nci + N;

    float *T, *HB, *CE, *CN, *CT, *invd, *invs, *ic1, *ic2;
    unsigned *T16, *E16, *Wb;
    int *cd, *cs, *cc1, *cc2, *od, *os, *pd, *ps, *bsum, *bscan;
    cudaGetSymbolAddress((void**)&T,    g_T);
    cudaGetSymbolAddress((void**)&T16,  g_T16);
    cudaGetSymbolAddress((void**)&E16,  g_E16);
    cudaGetSymbolAddress((void**)&HB,   g_h);
    cudaGetSymbolAddress((void**)&CE,   g_c1);
    cudaGetSymbolAddress((void**)&CN,   g_c2);
    cudaGetSymbolAddress((void**)&CT,   g_c3);
    cudaGetSymbolAddress((void**)&Wb,   g_Wb);
    cudaGetSymbolAddress((void**)&invd, g_invdst);
    cudaGetSymbolAddress((void**)&invs, g_invsrc);
    cudaGetSymbolAddress((void**)&ic1,  g_invc1);
    cudaGetSymbolAddress((void**)&ic2,  g_invc2);
    cudaGetSymbolAddress((void**)&cd,   g_cd);
    cudaGetSymbolAddress((void**)&cs,   g_cs);
    cudaGetSymbolAddress((void**)&cc1,  g_cc1);
    cudaGetSymbolAddress((void**)&cc2,  g_cc2);
    cudaGetSymbolAddress((void**)&od,   g_offs_d);
    cudaGetSymbolAddress((void**)&os,   g_offs_s);
    cudaGetSymbolAddress((void**)&pd,   g_perm_d);
    cudaGetSymbolAddress((void**)&ps,   g_perm_s);
    cudaGetSymbolAddress((void**)&bsum, g_bsum);
    cudaGetSymbolAddress((void**)&bscan,g_bscan);

    float* out   = (float*)d_out;
    float* out_n = out;
    float* out_e = out + (size_t)N * D;
    float* out_c = out + (size_t)(N + E) * D;

    const int TB = 256;
    const int nbd = cdiv(E, 1024);
    const int nbs = cdiv(N, 1024);
    const int nbtot = nbd + nbs;
    const int GT = cdiv(N, 128);

    const float* Wv0 = (const float*)d_in[wi + 0];
    const float* bv0 = (const float*)d_in[wi + 1];
    const float* We0 = (const float*)d_in[wi + 2];
    const float* be0 = (const float*)d_in[wi + 3];
    const float* Wv1 = (const float*)d_in[wi + 8];
    const float* bv1 = (const float*)d_in[wi + 9];
    const float* We1 = (const float*)d_in[wi + 10];
    const float* be1 = (const float*)d_in[wi + 11];

    cudaFuncSetAttribute(kgemm_tc, cudaFuncAttributeMaxDynamicSharedMemorySize, SM_TOT);

    kconvW<<<cdiv(4 * 384 * 16, TB), TB>>>(Wv0, We0, Wv1, We1, Wb);
    kzero_counts<<<cdiv(E + N + 2 * C, TB), TB>>>(cd, cs, cc1, cc2, E, N, C);
    kcountall<<<cdiv(NNZ + E + N, TB), TB>>>(src, dst, he_c, nc_c, cs, cd, cc1, cc2,
                                             NNZ, E, N);
    // G1 = v2e layer 0 -> T fp32 raw + T16 (launch index 3 for ncu capture)
    kgemm_tc<<<GT, 512, SM_TOT>>>(x, Wb + 0 * 24576, bv0, pa, T, T16, 0, N);
    kscanA<<<nbtot, 1024>>>(cd, cs, od, os, bsum, nbd, E, N);
    kscanB<<<1, 1024>>>(bsum, bscan, nbd, nbtot, NNZ);
    kscanC<<<nbtot, 1024>>>(od, os, bscan, cd, cs, nbd, E, N, NNZ);
    kfill<<<cdiv(NNZ, TB), TB>>>(src, dst, od, os, cd, cs, pd, ps, NNZ);
    kinvall<<<cdiv(E + N + 2 * C, TB), TB>>>(od, os, cc1, cc2, invd, invs, ic1, ic2,
                                             E, N, C);

    // ---- layer 0 ----
    kagg_e<<<cdiv((long)E * 32, TB), TB>>>(T16, pd, od, invd, pa, E16, nullptr, E);
    kagg_n<<<cdiv((long)N * 32, TB), TB>>>(T, E16, ps, os, invs, pa, N);
    // G2 = e2v layer 0 -> HB = prelu(A@We0+be0)
    kgemm_tc<<<GT, 512, SM_TOT>>>(T, Wb + 1 * 24576, be0, pa, HB, nullptr, 1, N);

    // ---- layer 1 ----
    kgemm_tc<<<GT, 512, SM_TOT>>>(HB, Wb + 2 * 24576, bv1, pa, T, T16, 0, N);
    kagg_e<<<cdiv((long)E * 32, TB), TB>>>(T16, pd, od, invd, pa, E16, out_e, E);
    kagg_n<<<cdiv((long)N * 32, TB), TB>>>(T, E16, ps, os, invs, pa, N);
    // G4 = e2v layer 1 -> out_n = prelu(n), T16 = raw n fp16
    kgemm_tc<<<GT, 512, SM_TOT>>>(T, Wb + 3 * 24576, be1, pa, out_n, T16, 1, N);

    // components
    kzero4<<<cdiv((long)C * 32, TB), TB>>>((float4*)CE, (long)C * 32);
    kzero4<<<cdiv((long)C * 32, TB), TB>>>((float4*)CN, (long)C * 32);
    kscatterc<<<cdiv((long)E, 8), TB>>>(E16, he_e, he_c, ic1, CE, E);
    kscatterc<<<cdiv((long)N, 8), TB>>>(T16, nc_n, nc_c, ic2, CN, N);
    kgemm2<<<cdiv(C, 64), TB>>>(CE, (const float*)d_in[wi + 12], (const float*)d_in[wi + 13],
                                nullptr, CT, nullptr, pa, C);
    kgemm2<<<cdiv(C, 64), TB>>>(CN, (const float*)d_in[wi + 14], (const float*)d_in[wi + 15],
                                CT, nullptr, out_c, pa, C);
}

// round 8
// speedup vs baseline: 1.2777x; 1.1597x over previous
#include <cuda_runtime.h>
#include <cuda_fp16.h>
#include <cuda_bf16.h>
#include <mma.h>
#include <cstdint>
#include <cstddef>

#define D 128
using namespace nvcuda;

// ---------------- static scratch (device globals) ---------------------------
static __device__ float    g_T  [100000 * 128];  // T fp32; reused in-place as A
static __device__ unsigned g_T16[100000 * 64];   // T / n fp16 rows
static __device__ unsigned g_E16[50000  * 64];   // e fp16 rows
static __device__ float    g_h  [100000 * 128];  // h = prelu(n) from layer 0
static __device__ float    g_c1 [2048   * 128];
static __device__ float    g_c2 [2048   * 128];
static __device__ float    g_c3 [2048   * 128];
static __device__ unsigned g_Wb [4 * 256 * 64];  // 4 W, bf16 [256][128]: hi rows | lo rows
static __device__ float g_invdst[50016];
static __device__ float g_invsrc[100016];
static __device__ float g_invc1[2048];
static __device__ float g_invc2[2048];
static __device__ int   g_cd [50016];
static __device__ int   g_cs [100016];
static __device__ int   g_cc1[2048];
static __device__ int   g_cc2[2048];
static __device__ int   g_offs_d[50024];
static __device__ int   g_offs_s[100024];
static __device__ int   g_perm_d[1600128];
static __device__ int   g_perm_s[1600128];
static __device__ int   g_bsum [1024];
static __device__ int   g_bscan[1024];

// ---------------- helpers ----------------------------------------------------
__device__ __forceinline__ unsigned long long pk2(float v) {
    unsigned long long r; unsigned u = __float_as_uint(v);
    asm("mov.b64 %0, {%1,%1};" : "=l"(r) : "r"(u));
    return r;
}
__device__ __forceinline__ void fma2(unsigned long long& d, unsigned long long a,
                                     unsigned long long b) {
    asm("fma.rn.f32x2 %0, %1, %2, %0;" : "+l"(d) : "l"(a), "l"(b));
}
__device__ __forceinline__ float2 up2(unsigned long long v) {
    unsigned lo, hi;
    asm("mov.b64 {%0,%1}, %2;" : "=r"(lo), "=r"(hi) : "l"(v));
    return make_float2(__uint_as_float(lo), __uint_as_float(hi));
}
__device__ __forceinline__ float prelu1(float v, float a) { return v >= 0.f ? v : a * v; }
__device__ __forceinline__ float4 prelu4(float4 v, float a) {
    return make_float4(prelu1(v.x, a), prelu1(v.y, a), prelu1(v.z, a), prelu1(v.w, a));
}
__device__ __forceinline__ void add4(float4& a, float4 b) {
    a.x += b.x; a.y += b.y; a.z += b.z; a.w += b.w;
}
__device__ __forceinline__ void addh(float4& a, uint2 v) {
    __half2 h0 = *reinterpret_cast<__half2*>(&v.x);
    __half2 h1 = *reinterpret_cast<__half2*>(&v.y);
    float2 f0 = __half22float2(h0), f1 = __half22float2(h1);
    a.x += f0.x; a.y += f0.y; a.z += f1.x; a.w += f1.y;
}
__device__ __forceinline__ uint2 h4(float4 v) {
    __half2 h0 = __float22half2_rn(make_float2(v.x, v.y));
    __half2 h1 = __float22half2_rn(make_float2(v.z, v.w));
    uint2 r;
    r.x = *reinterpret_cast<unsigned*>(&h0);
    r.y = *reinterpret_cast<unsigned*>(&h1);
    return r;
}
__device__ __forceinline__ unsigned bf2(float a, float b) {
    __nv_bfloat162 t = __floats2bfloat162_rn(a, b);
    return *reinterpret_cast<unsigned*>(&t);
}
__device__ __forceinline__ float bfres(float a) {   // a - bf16(a)
    return a - __bfloat162float(__float2bfloat16_rn(a));
}

// ---------------- W pre-split: Wb[w] = bf16 [256][128]: hi rows | lo rows ----
__global__ void kconvW(const float* __restrict__ W0, const float* __restrict__ W1,
                       const float* __restrict__ W2, const float* __restrict__ W3,
                       unsigned* __restrict__ Wb) {
    int idx = blockIdx.x * blockDim.x + threadIdx.x;
    if (idx >= 4 * 256 * 16) return;
    int w = idx / (256 * 16);
    int rem = idx % (256 * 16);
    int kk = rem >> 4, g = rem & 15;
    const float* W = (w == 0) ? W0 : (w == 1) ? W1 : (w == 2) ? W2 : W3;
    int ksrc = kk & 127;
    bool lo = (kk >= 128);
    float4 x0 = __ldg((const float4*)(W + (size_t)ksrc * D + g * 8));
    float4 x1 = __ldg((const float4*)(W + (size_t)ksrc * D + g * 8 + 4));
    float f[8] = {x0.x, x0.y, x0.z, x0.w, x1.x, x1.y, x1.z, x1.w};
    if (lo) {
#pragma unroll
        for (int j = 0; j < 8; j++) f[j] = bfres(f[j]);
    }
    uint4 v;
    v.x = bf2(f[0], f[1]); v.y = bf2(f[2], f[3]);
    v.z = bf2(f[4], f[5]); v.w = bf2(f[6], f[7]);
    ((uint4*)(Wb + (size_t)w * 256 * 64))[kk * 16 + g] = v;
}

// ---------------- WMMA GEMM: Y[M x 128] = X @ W + b --------------------------
// Native K=128, explicit 3-product bf16 emulation (Ahi*Bhi + Alo*Bhi + Ahi*Blo).
// CTA 64x128, 8 warps, warp tile 32x32. 2 CTAs/SM.
// Strides (halves/floats) chosen so row strides are ≡16 mod 128 (conflict-free).
#define AS_LD 264      // 528 B rows; A: 64 x 256 (hi cols 0-127, lo cols 128-255)
#define BS_LD 136      // 272 B rows; B: 256 x 128 (hi rows 0-127, lo rows 128-255)
#define CS_LD 132      // 528 B rows; C: 64 x 128, reuses A region
#define SM_AS  (64 * AS_LD * 2)               // 33792
#define SM_TOT (SM_AS + 256 * BS_LD * 2)      // 33792 + 69632 = 103424

__global__ __launch_bounds__(256, 2) void kgemm_tc(const float* __restrict__ X,
                                                   const unsigned* __restrict__ Wb,
                                                   const float* __restrict__ bias,
                                                   const float* __restrict__ pa,
                                                   float* __restrict__ out_f32,
                                                   unsigned* __restrict__ out_h16,
                                                   int prelu_f32, int M) {
    extern __shared__ char smem[];
    __nv_bfloat16* As = (__nv_bfloat16*)smem;            // 64 x AS_LD
    __nv_bfloat16* Bs = (__nv_bfloat16*)(smem + SM_AS);  // 256 x BS_LD
    float* Cs = (float*)smem;                            // reuse As: 64 x CS_LD
    const int tid = threadIdx.x;
    const int wid = tid >> 5;
    const int m0 = blockIdx.x * 64;

    // stage A: fp32 -> bf16 hi (cols 0-127) / lo (cols 128-255)
    for (int idx = tid; idx < 64 * 16; idx += 256) {
        int r = idx >> 4, g = idx & 15;
        int gr = m0 + r;
        float f[8];
        if (gr < M) {
            float4 x0 = __ldg((const float4*)(X + (size_t)gr * D + g * 8));
            float4 x1 = __ldg((const float4*)(X + (size_t)gr * D + g * 8 + 4));
            f[0] = x0.x; f[1] = x0.y; f[2] = x0.z; f[3] = x0.w;
            f[4] = x1.x; f[5] = x1.y; f[6] = x1.z; f[7] = x1.w;
        } else {
#pragma unroll
            for (int j = 0; j < 8; j++) f[j] = 0.f;
        }
        uint4 hi, lo;
        hi.x = bf2(f[0], f[1]); hi.y = bf2(f[2], f[3]);
        hi.z = bf2(f[4], f[5]); hi.w = bf2(f[6], f[7]);
        lo.x = bf2(bfres(f[0]), bfres(f[1])); lo.y = bf2(bfres(f[2]), bfres(f[3]));
        lo.z = bf2(bfres(f[4]), bfres(f[5])); lo.w = bf2(bfres(f[6]), bfres(f[7]));
        *(uint4*)(As + (size_t)r * AS_LD + g * 8)       = hi;
        *(uint4*)(As + (size_t)r * AS_LD + 128 + g * 8) = lo;
    }
    // stage B: pre-split [256][128], straight copy
    for (int idx = tid; idx < 256 * 16; idx += 256) {
        int kk = idx >> 4, g = idx & 15;
        uint4 v = __ldg((const uint4*)Wb + kk * 16 + g);
        *(uint4*)(Bs + (size_t)kk * BS_LD + g * 8) = v;
    }
    __syncthreads();

    // 8 warps: 2 m-strips (32 rows) x 4 n-strips (32 cols); warp tile 32x32
    const int row0 = (wid >> 2) * 32;
    const int n0   = (wid & 3) * 32;
    wmma::fragment<wmma::accumulator, 16, 16, 16, float> acc[2][2];
#pragma unroll
    for (int i = 0; i < 2; i++)
#pragma unroll
        for (int j = 0; j < 2; j++) wmma::fill_fragment(acc[i][j], 0.f);

#pragma unroll
    for (int k = 0; k < 8; k++) {
        wmma::fragment<wmma::matrix_a, 16, 16, 16, __nv_bfloat16, wmma::row_major> ahi[2], alo[2];
        wmma::fragment<wmma::matrix_b, 16, 16, 16, __nv_bfloat16, wmma::row_major> bhi[2], blo[2];
#pragma unroll
        for (int i = 0; i < 2; i++) {
            wmma::load_matrix_sync(ahi[i], As + (size_t)(row0 + i * 16) * AS_LD + k * 16, AS_LD);
            wmma::load_matrix_sync(alo[i], As + (size_t)(row0 + i * 16) * AS_LD + 128 + k * 16, AS_LD);
        }
#pragma unroll
        for (int j = 0; j < 2; j++) {
            wmma::load_matrix_sync(bhi[j], Bs + (size_t)(k * 16) * BS_LD + n0 + j * 16, BS_LD);
            wmma::load_matrix_sync(blo[j], Bs + (size_t)(128 + k * 16) * BS_LD + n0 + j * 16, BS_LD);
        }
#pragma unroll
        for (int i = 0; i < 2; i++)
#pragma unroll
            for (int j = 0; j < 2; j++) {
                wmma::mma_sync(acc[i][j], ahi[i], bhi[j], acc[i][j]);
                wmma::mma_sync(acc[i][j], alo[i], bhi[j], acc[i][j]);
                wmma::mma_sync(acc[i][j], ahi[i], blo[j], acc[i][j]);
            }
    }
    __syncthreads();   // all warps done reading As before overwrite with Cs
#pragma unroll
    for (int i = 0; i < 2; i++)
#pragma unroll
        for (int j = 0; j < 2; j++)
            wmma::store_matrix_sync(Cs + (size_t)(row0 + i * 16) * CS_LD + n0 + j * 16,
                                    acc[i][j], CS_LD, wmma::mem_row_major);
    __syncthreads();

    // epilogue: each thread one quarter-row (32 cols)
    {
        int r = tid >> 2, h = (tid & 3) * 32;
        int gr = m0 + r;
        if (gr < M) {
            float a = __ldg(pa);
#pragma unroll
            for (int q = 0; q < 8; q++) {
                int c = h + q * 4;
                float4 v = *(float4*)(Cs + (size_t)r * CS_LD + c);
                float4 bb = __ldg((const float4*)(bias + c));
                add4(v, bb);
                if (out_h16)
                    *(uint2*)(out_h16 + (size_t)gr * 64 + c / 2) = h4(v);
                if (out_f32) {
                    float4 o = prelu_f32 ? prelu4(v, a) : v;
                    *(float4*)(out_f32 + (size_t)gr * D + c) = o;
                }
            }
        }
    }
}

// ---------------- setup kernels ----------------------------------------------
__global__ void kzero_counts(int* cd, int* cs, int* cc1, int* cc2, int E, int N, int C) {
    int i = blockIdx.x * blockDim.x + threadIdx.x;
    int tot = E + N + 2 * C;
    if (i >= tot) return;
    if (i < E) cd[i] = 0;
    else if (i < E + N) cs[i - E] = 0;
    else if (i < E + N + C) cc1[i - E - N] = 0;
    else cc2[i - E - N - C] = 0;
}

__global__ void kcountall(const int* __restrict__ src, const int* __restrict__ dst,
                          const int* __restrict__ he_c, const int* __restrict__ nc_c,
                          int* cs, int* cd, int* cc1, int* cc2,
                          int nnz, int E, int N) {
    int i = blockIdx.x * blockDim.x + threadIdx.x;
    if (i < nnz) {
        atomicAdd(&cd[dst[i]], 1);
        atomicAdd(&cs[src[i]], 1);
    } else if (i < nnz + E) {
        atomicAdd(&cc1[he_c[i - nnz]], 1);
    } else if (i < nnz + E + N) {
        atomicAdd(&cc2[nc_c[i - nnz - E]], 1);
    }
}

__global__ __launch_bounds__(1024) void kscanA(const int* __restrict__ cd,
                                               const int* __restrict__ cs,
                                               int* od, int* os, int* bsum,
                                               int nbd, int E, int N) {
    __shared__ int sh[1024];
    const int b = blockIdx.x, t = threadIdx.x;
    const bool isD = b < nbd;
    const int* in = isD ? cd : cs;
    int* out = isD ? od : os;
    const int n = isD ? E : N;
    const int i = (isD ? b : b - nbd) * 1024 + t;
    int v = (i < n) ? in[i] : 0;
    sh[t] = v;
    __syncthreads();
    for (int off = 1; off < 1024; off <<= 1) {
        int x = (t >= off) ? sh[t - off] : 0;
        __syncthreads();
        sh[t] += x;
        __syncthreads();
    }
    if (i < n) out[i] = sh[t] - v;
    if (t == 1023) bsum[b] = sh[1023];
}

__global__ __launch_bounds__(1024) void kscanB(const int* __restrict__ bsum,
                                               int* bscan, int nbd, int nbtot, int nnz) {
    __shared__ int sh[1024];
    int t = threadIdx.x;
    int v = (t < nbtot) ? bsum[t] : 0;
    sh[t] = v;
    __syncthreads();
    for (int off = 1; off < 1024; off <<= 1) {
        int x = (t >= off) ? sh[t - off] : 0;
        __syncthreads();
        sh[t] += x;
        __syncthreads();
    }
    if (t < nbtot) {
        int excl = sh[t] - v;
        bscan[t] = (t >= nbd) ? excl - nnz : excl;
    }
}

__global__ __launch_bounds__(1024) void kscanC(int* od, int* os,
                                               const int* __restrict__ bscan,
                                               int* cd, int* cs,
                                               int nbd, int E, int N, int nnz) {
    const int b = blockIdx.x, t = threadIdx.x;
    const bool isD = b < nbd;
    const int i = (isD ? b : b - nbd) * 1024 + t;
    if (isD) {
        if (i < E) { od[i] += bscan[b]; cd[i] = 0; }
        if (b == 0 && t == 0) od[E] = nnz;
    } else {
        if (i < N) { os[i] += bscan[b]; cs[i] = 0; }
        if (i == 0) os[N] = nnz;
    }
}

__global__ void kfill(const int* __restrict__ src, const int* __restrict__ dst,
                      const int* __restrict__ od, const int* __restrict__ os,
                      int* cur_d, int* cur_s, int* perm_d, int* perm_s, int nnz) {
    int k = blockIdx.x * blockDim.x + threadIdx.x;
    if (k >= nnz) return;
    int s = __ldg(&src[k]), d = __ldg(&dst[k]);
    int pd = atomicAdd(&cur_d[d], 1);
    perm_d[__ldg(&od[d]) + pd] = s;
    int ps = atomicAdd(&cur_s[s], 1);
    perm_s[__ldg(&os[s]) + ps] = d;
}

__global__ void kinvall(const int* __restrict__ od, const int* __restrict__ os,
                        const int* __restrict__ cc1, const int* __restrict__ cc2,
                        float* invd, float* invs, float* ic1, float* ic2,
                        int E, int N, int C) {
    int i = blockIdx.x * blockDim.x + threadIdx.x;
    if (i < E) {
        int c = od[i + 1] - od[i];
        invd[i] = 1.f / (float)(c > 0 ? c : 1);
    } else if (i < E + N) {
        int j = i - E;
        int c = os[j + 1] - os[j] + 1;
        invs[j] = 1.f / (float)c;
    } else if (i < E + N + C) {
        int c = cc1[i - E - N];
        ic1[i - E - N] = 1.f / (float)(c > 0 ? c : 1);
    } else if (i < E + N + 2 * C) {
        int c = cc2[i - E - N - C];
        ic2[i - E - N - C] = 1.f / (float)(c > 0 ? c : 1);
    }
}

__global__ void kzero4(float4* p, long n4) {
    long i = (long)blockIdx.x * blockDim.x + threadIdx.x;
    if (i < n4) p[i] = make_float4(0.f, 0.f, 0.f, 0.f);
}

// ---------------- SIMT GEMM (small C-row GEMMs) ------------------------------
__global__ __launch_bounds__(256) void kgemm2(const float* __restrict__ X,
                                              const float* __restrict__ W,
                                              const float* __restrict__ b,
                                              const float* __restrict__ addin,
                                              float* __restrict__ Yraw,
                                              float* __restrict__ Ypre,
                                              const float* __restrict__ pa, int M) {
    __shared__ float As[64][128];
    const int m0 = blockIdx.x * 64;
    const int t = threadIdx.x;
    {
        const int c4 = t & 31;
        const int r0 = t >> 5;
#pragma unroll
        for (int s = 0; s < 8; s++) {
            int r = r0 + 8 * s;
            int gr = m0 + r;
            float4 v = make_float4(0.f, 0.f, 0.f, 0.f);
            if (gr < M) v = ((const float4*)(X + (size_t)gr * D))[c4];
            ((float4*)(&As[r][0]))[c4] = v;
        }
    }
    __syncthreads();
    const int cg = (t & 15) * 8;
    const int rg = (t >> 4) * 4;
    unsigned long long acc[4][4];
#pragma unroll
    for (int i = 0; i < 4; i++)
#pragma unroll
        for (int j = 0; j < 4; j++) acc[i][j] = 0ULL;
#pragma unroll 4
    for (int k = 0; k < D; k += 4) {
        float4 a[4];
#pragma unroll
        for (int i = 0; i < 4; i++) a[i] = *(const float4*)&As[rg + i][k];
#pragma unroll
        for (int kk = 0; kk < 4; kk++) {
            const ulonglong2 w0 = *reinterpret_cast<const ulonglong2*>(&W[(k + kk) * D + cg]);
            const ulonglong2 w1 = *reinterpret_cast<const ulonglong2*>(&W[(k + kk) * D + cg + 4]);
#pragma unroll
            for (int i = 0; i < 4; i++) {
                float av = (kk == 0) ? a[i].x : (kk == 1) ? a[i].y
                         : (kk == 2) ? a[i].z : a[i].w;
                unsigned long long av2 = pk2(av);
                fma2(acc[i][0], av2, w0.x);
                fma2(acc[i][1], av2, w0.y);
                fma2(acc[i][2], av2, w1.x);
                fma2(acc[i][3], av2, w1.y);
            }
        }
    }
    const float4 b0 = __ldg((const float4*)&b[cg]);
    const float4 b1 = __ldg((const float4*)&b[cg + 4]);
    const float a = __ldg(pa);
#pragma unroll
    for (int i = 0; i < 4; i++) {
        int gr = m0 + rg + i;
        if (gr >= M) continue;
        float2 p0 = up2(acc[i][0]), p1 = up2(acc[i][1]);
        float2 p2 = up2(acc[i][2]), p3 = up2(acc[i][3]);
        float4 o0 = make_float4(p0.x + b0.x, p0.y + b0.y, p1.x + b0.z, p1.y + b0.w);
        float4 o1 = make_float4(p2.x + b1.x, p2.y + b1.y, p3.x + b1.z, p3.y + b1.w);
        if (addin) {
            const float4* ar = (const float4*)(addin + (size_t)gr * D);
            add4(o0, ar[cg / 4]); add4(o1, ar[cg / 4 + 1]);
        }
        if (Yraw) {
            float4* yr = (float4*)(Yraw + (size_t)gr * D);
            yr[cg / 4] = o0; yr[cg / 4 + 1] = o1;
        }
        if (Ypre) {
            float4* yp = (float4*)(Ypre + (size_t)gr * D);
            yp[cg / 4] = prelu4(o0, a); yp[cg / 4 + 1] = prelu4(o1, a);
        }
    }
}

// ---------------- CSR aggregation (warp per segment, fp16 gather) ------------
__global__ __launch_bounds__(256) void kagg_e(const unsigned* __restrict__ T16,
                                              const int* __restrict__ perm,
                                              const int* __restrict__ offs,
                                              const float* __restrict__ invd,
                                              const float* __restrict__ pa,
                                              unsigned* __restrict__ EB16,
                                              float* __restrict__ out_e, int E) {
    int w = (blockIdx.x * blockDim.x + threadIdx.x) >> 5;
    int lane = threadIdx.x & 31;
    if (w >= E) return;
    int beg = __ldg(&offs[w]), end = __ldg(&offs[w + 1]);
    float4 a0 = {0,0,0,0}, a1 = {0,0,0,0}, a2 = {0,0,0,0}, a3 = {0,0,0,0};
    int p = beg;
    for (; p + 4 <= end; p += 4) {
        int s0 = __ldg(&perm[p]),     s1 = __ldg(&perm[p + 1]);
        int s2 = __ldg(&perm[p + 2]), s3 = __ldg(&perm[p + 3]);
        addh(a0, __ldg((const uint2*)(T16 + (size_t)s0 * 64) + lane));
        addh(a1, __ldg((const uint2*)(T16 + (size_t)s1 * 64) + lane));
        addh(a2, __ldg((const uint2*)(T16 + (size_t)s2 * 64) + lane));
        addh(a3, __ldg((const uint2*)(T16 + (size_t)s3 * 64) + lane));
    }
    for (; p < end; p++)
        addh(a0, __ldg((const uint2*)(T16 + (size_t)__ldg(&perm[p]) * 64) + lane));
    add4(a0, a1); add4(a2, a3); add4(a0, a2);
    float iv = __ldg(&invd[w]);
    float a = __ldg(pa);
    a0.x *= iv; a0.y *= iv; a0.z *= iv; a0.w *= iv;
    float4 r = prelu4(a0, a);
    ((uint2*)(EB16 + (size_t)w * 64))[lane] = h4(r);
    if (out_e) ((float4*)out_e)[(size_t)w * 32 + lane] = r;
}

__global__ __launch_bounds__(256) void kagg_n(float* __restrict__ T,
                                              const unsigned* __restrict__ EB16,
                                              const int* __restrict__ perm,
                                              const int* __restrict__ offs,
                                              const float* __restrict__ invs,
                                              const float* __restrict__ pa, int N) {
    int w = (blockIdx.x * blockDim.x + threadIdx.x) >> 5;
    int lane = threadIdx.x & 31;
    if (w >= N) return;
    int beg = __ldg(&offs[w]), end = __ldg(&offs[w + 1]);
    float4 a0 = {0,0,0,0}, a1 = {0,0,0,0}, a2 = {0,0,0,0}, a3 = {0,0,0,0};
    int p = beg;
    for (; p + 4 <= end; p += 4) {
        int s0 = __ldg(&perm[p]),     s1 = __ldg(&perm[p + 1]);
        int s2 = __ldg(&perm[p + 2]), s3 = __ldg(&perm[p + 3]);
        addh(a0, __ldg((const uint2*)(EB16 + (size_t)s0 * 64) + lane));
        addh(a1, __ldg((const uint2*)(EB16 + (size_t)s1 * 64) + lane));
        addh(a2, __ldg((const uint2*)(EB16 + (size_t)s2 * 64) + lane));
        addh(a3, __ldg((const uint2*)(EB16 + (size_t)s3 * 64) + lane));
    }
    for (; p < end; p++)
        addh(a0, __ldg((const uint2*)(EB16 + (size_t)__ldg(&perm[p]) * 64) + lane));
    add4(a0, a1); add4(a2, a3); add4(a0, a2);
    float a = __ldg(pa);
    float4 t = ((float4*)T)[(size_t)w * 32 + lane];
    add4(a0, prelu4(t, a));
    float iv = __ldg(&invs[w]);
    a0.x *= iv; a0.y *= iv; a0.z *= iv; a0.w *= iv;
    ((float4*)T)[(size_t)w * 32 + lane] = a0;
}

// ---------------- component scatter (atomic; fp16 gather) --------------------
__device__ __forceinline__ void red4(float* a, float4 v) {
    asm volatile("red.global.add.v4.f32 [%0], {%1,%2,%3,%4};"
                 :: "l"(a), "f"(v.x), "f"(v.y), "f"(v.z), "f"(v.w)
                 : "memory");
}

__global__ void kscatterc(const unsigned* __restrict__ P16, const int* __restrict__ rows,
                          const int* __restrict__ comp, const float* __restrict__ inv,
                          float* __restrict__ csum, int n) {
    int w = (blockIdx.x * blockDim.x + threadIdx.x) >> 5;
    int lane = threadIdx.x & 31;
    if (w >= n) return;
    int r = __ldg(&rows[w]);
    int c = __ldg(&comp[w]);
    float sc = __ldg(&inv[c]);
    float4 v = {0,0,0,0};
    addh(v, __ldg((const uint2*)(P16 + (size_t)r * 64) + lane));
    v.x *= sc; v.y *= sc; v.z *= sc; v.w *= sc;
    red4(csum + (size_t)c * D + lane * 4, v);
}

// ---------------- host driver ------------------------------------------------
static inline int cdiv(long a, long b) { return (int)((a + b - 1) / b); }

extern "C" void kernel_launch(void* const* d_in, const int* in_sizes, int n_in,
                              void* d_out, int out_size) {
    const float* x   = (const float*)d_in[0];
    const int*   hei = (const int*)d_in[1];
    const int*   hci = (const int*)d_in[2];
    const int*   nci = (const int*)d_in[3];

    const int NNZ = in_sizes[1] / 2;
    const int E   = in_sizes[2] / 2;
    const int N   = in_sizes[0] / D;
    const int C   = out_size / D - N - E;

    int wi = -1;
    for (int i = 4; i < n_in; i++) {
        if (in_sizes[i] == D * D) { wi = i; break; }
    }
    const float* pa = (const float*)d_in[wi - 1];

    const int* src  = hei;
    const int* dst  = hei + NNZ;
    const int* he_e = hci;
    const int* he_c = hci + E;
    const int* nc_n = nci;
    const int* nc_c = nci + N;

    float *T, *HB, *CE, *CN, *CT, *invd, *invs, *ic1, *ic2;
    unsigned *T16, *E16, *Wb;
    int *cd, *cs, *cc1, *cc2, *od, *os, *pd, *ps, *bsum, *bscan;
    cudaGetSymbolAddress((void**)&T,    g_T);
    cudaGetSymbolAddress((void**)&T16,  g_T16);
    cudaGetSymbolAddress((void**)&E16,  g_E16);
    cudaGetSymbolAddress((void**)&HB,   g_h);
    cudaGetSymbolAddress((void**)&CE,   g_c1);
    cudaGetSymbolAddress((void**)&CN,   g_c2);
    cudaGetSymbolAddress((void**)&CT,   g_c3);
    cudaGetSymbolAddress((void**)&Wb,   g_Wb);
    cudaGetSymbolAddress((void**)&invd, g_invdst);
    cudaGetSymbolAddress((void**)&invs, g_invsrc);
    cudaGetSymbolAddress((void**)&ic1,  g_invc1);
    cudaGetSymbolAddress((void**)&ic2,  g_invc2);
    cudaGetSymbolAddress((void**)&cd,   g_cd);
    cudaGetSymbolAddress((void**)&cs,   g_cs);
    cudaGetSymbolAddress((void**)&cc1,  g_cc1);
    cudaGetSymbolAddress((void**)&cc2,  g_cc2);
    cudaGetSymbolAddress((void**)&od,   g_offs_d);
    cudaGetSymbolAddress((void**)&os,   g_offs_s);
    cudaGetSymbolAddress((void**)&pd,   g_perm_d);
    cudaGetSymbolAddress((void**)&ps,   g_perm_s);
    cudaGetSymbolAddress((void**)&bsum, g_bsum);
    cudaGetSymbolAddress((void**)&bscan,g_bscan);

    float* out   = (float*)d_out;
    float* out_n = out;
    float* out_e = out + (size_t)N * D;
    float* out_c = out + (size_t)(N + E) * D;

    const int TB = 256;
    const int nbd = cdiv(E, 1024);
    const int nbs = cdiv(N, 1024);
    const int nbtot = nbd + nbs;
    const int GT = cdiv(N, 64);

    const float* Wv0 = (const float*)d_in[wi + 0];
    const float* bv0 = (const float*)d_in[wi + 1];
    const float* We0 = (const float*)d_in[wi + 2];
    const float* be0 = (const float*)d_in[wi + 3];
    const float* Wv1 = (const float*)d_in[wi + 8];
    const float* bv1 = (const float*)d_in[wi + 9];
    const float* We1 = (const float*)d_in[wi + 10];
    const float* be1 = (const float*)d_in[wi + 11];

    cudaFuncSetAttribute(kgemm_tc, cudaFuncAttributeMaxDynamicSharedMemorySize, SM_TOT);

    kconvW<<<cdiv(4 * 256 * 16, TB), TB>>>(Wv0, We0, Wv1, We1, Wb);
    kzero_counts<<<cdiv(E + N + 2 * C, TB), TB>>>(cd, cs, cc1, cc2, E, N, C);
    kcountall<<<cdiv(NNZ + E + N, TB), TB>>>(src, dst, he_c, nc_c, cs, cd, cc1, cc2,
                                             NNZ, E, N);
    // G1 = v2e layer 0 -> T fp32 raw + T16 (launch index 3 for ncu capture)
    kgemm_tc<<<GT, 256, SM_TOT>>>(x, Wb + 0 * 16384, bv0, pa, T, T16, 0, N);
    kscanA<<<nbtot, 1024>>>(cd, cs, od, os, bsum, nbd, E, N);
    kscanB<<<1, 1024>>>(bsum, bscan, nbd, nbtot, NNZ);
    kscanC<<<nbtot, 1024>>>(od, os, bscan, cd, cs, nbd, E, N, NNZ);
    kfill<<<cdiv(NNZ, TB), TB>>>(src, dst, od, os, cd, cs, pd, ps, NNZ);
    kinvall<<<cdiv(E + N + 2 * C, TB), TB>>>(od, os, cc1, cc2, invd, invs, ic1, ic2,
                                             E, N, C);

    // ---- layer 0 ----
    kagg_e<<<cdiv((long)E * 32, TB), TB>>>(T16, pd, od, invd, pa, E16, nullptr, E);
    kagg_n<<<cdiv((long)N * 32, TB), TB>>>(T, E16, ps, os, invs, pa, N);
    // G2 = e2v layer 0 -> HB = prelu(A@We0+be0)
    kgemm_tc<<<GT, 256, SM_TOT>>>(T, Wb + 1 * 16384, be0, pa, HB, nullptr, 1, N);

    // ---- layer 1 ----
    kgemm_tc<<<GT, 256, SM_TOT>>>(HB, Wb + 2 * 16384, bv1, pa, T, T16, 0, N);
    kagg_e<<<cdiv((long)E * 32, TB), TB>>>(T16, pd, od, invd, pa, E16, out_e, E);
    kagg_n<<<cdiv((long)N * 32, TB), TB>>>(T, E16, ps, os, invs, pa, N);
    // G4 = e2v layer 1 -> out_n = prelu(n), T16 = raw n fp16
    kgemm_tc<<<GT, 256, SM_TOT>>>(T, Wb + 3 * 16384, be1, pa, out_n, T16, 1, N);

    // components
    kzero4<<<cdiv((long)C * 32, TB), TB>>>((float4*)CE, (long)C * 32);
    kzero4<<<cdiv((long)C * 32, TB), TB>>>((float4*)CN, (long)C * 32);
    kscatterc<<<cdiv((long)E, 8), TB>>>(E16, he_e, he_c, ic1, CE, E);
    kscatterc<<<cdiv((long)N, 8), TB>>>(T16, nc_n, nc_c, ic2, CN, N);
    kgemm2<<<cdiv(C, 64), TB>>>(CE, (const float*)d_in[wi + 12], (const float*)d_in[wi + 13],
                                nullptr, CT, nullptr, pa, C);
    kgemm2<<<cdiv(C, 64), TB>>>(CN, (const float*)d_in[wi + 14], (const float*)d_in[wi + 15],
                                CT, nullptr, out_c, pa, C);
}

// round 9
// speedup vs baseline: 1.5592x; 1.2204x over previous
#include <cuda_runtime.h>
#include <cuda_fp16.h>
#include <cuda_bf16.h>
#include <mma.h>
#include <cstdint>
#include <cstddef>

#define D 128
using namespace nvcuda;

// ---------------- static scratch (device globals) ---------------------------
static __device__ float    g_T  [100000 * 128];  // T fp32; reused in-place as A
static __device__ unsigned g_T16[100000 * 64];   // T / n fp16 rows
static __device__ unsigned g_E16[50000  * 64];   // e fp16 rows
static __device__ float    g_h  [100000 * 128];  // h = prelu(n) from layer 0
static __device__ float    g_c1 [2048   * 128];
static __device__ float    g_c2 [2048   * 128];
static __device__ float    g_c3 [2048   * 128];
static __device__ unsigned g_Wh [4 * 128 * 64];  // 4 W, fp16 [128][128]
static __device__ float g_invdst[50016];
static __device__ float g_invsrc[100016];
static __device__ float g_invc1[2048];
static __device__ float g_invc2[2048];
static __device__ int   g_cd [50016];
static __device__ int   g_cs [100016];
static __device__ int   g_cc1[2048];
static __device__ int   g_cc2[2048];
static __device__ int   g_offs_d[50024];
static __device__ int   g_offs_s[100024];
static __device__ int   g_perm_d[1600128];
static __device__ int   g_perm_s[1600128];
static __device__ int   g_bsum [1024];
static __device__ int   g_bscan[1024];

// ---------------- helpers ----------------------------------------------------
__device__ __forceinline__ unsigned long long pk2(float v) {
    unsigned long long r; unsigned u = __float_as_uint(v);
    asm("mov.b64 %0, {%1,%1};" : "=l"(r) : "r"(u));
    return r;
}
__device__ __forceinline__ void fma2(unsigned long long& d, unsigned long long a,
                                     unsigned long long b) {
    asm("fma.rn.f32x2 %0, %1, %2, %0;" : "+l"(d) : "l"(a), "l"(b));
}
__device__ __forceinline__ float2 up2(unsigned long long v) {
    unsigned lo, hi;
    asm("mov.b64 {%0,%1}, %2;" : "=r"(lo), "=r"(hi) : "l"(v));
    return make_float2(__uint_as_float(lo), __uint_as_float(hi));
}
__device__ __forceinline__ float prelu1(float v, float a) { return v >= 0.f ? v : a * v; }
__device__ __forceinline__ float4 prelu4(float4 v, float a) {
    return make_float4(prelu1(v.x, a), prelu1(v.y, a), prelu1(v.z, a), prelu1(v.w, a));
}
__device__ __forceinline__ void add4(float4& a, float4 b) {
    a.x += b.x; a.y += b.y; a.z += b.z; a.w += b.w;
}
__device__ __forceinline__ void addh(float4& a, uint2 v) {
    __half2 h0 = *reinterpret_cast<__half2*>(&v.x);
    __half2 h1 = *reinterpret_cast<__half2*>(&v.y);
    float2 f0 = __half22float2(h0), f1 = __half22float2(h1);
    a.x += f0.x; a.y += f0.y; a.z += f1.x; a.w += f1.y;
}
__device__ __forceinline__ uint2 h4(float4 v) {
    __half2 h0 = __float22half2_rn(make_float2(v.x, v.y));
    __half2 h1 = __float22half2_rn(make_float2(v.z, v.w));
    uint2 r;
    r.x = *reinterpret_cast<unsigned*>(&h0);
    r.y = *reinterpret_cast<unsigned*>(&h1);
    return r;
}

// ---------------- W convert: Wh[w] = fp16 [128][128] -------------------------
__global__ void kconvW(const float* __restrict__ W0, const float* __restrict__ W1,
                       const float* __restrict__ W2, const float* __restrict__ W3,
                       unsigned* __restrict__ Wh) {
    int idx = blockIdx.x * blockDim.x + threadIdx.x;
    if (idx >= 4 * 128 * 16) return;
    int w = idx >> 11;
    int rem = idx & 2047;
    int kk = rem >> 4, g = rem & 15;
    const float* W = (w == 0) ? W0 : (w == 1) ? W1 : (w == 2) ? W2 : W3;
    float4 x0 = __ldg((const float4*)(W + (size_t)kk * D + g * 8));
    float4 x1 = __ldg((const float4*)(W + (size_t)kk * D + g * 8 + 4));
    uint2 p0 = h4(x0), p1 = h4(x1);
    ((uint4*)(Wh + (size_t)w * 128 * 64))[kk * 16 + g] = make_uint4(p0.x, p0.y, p1.x, p1.y);
}

// ---------------- WMMA GEMM: Y[M x 128] = X @ W + b (fp16 single product) ---
// CTA 64x128, 8 warps, warp tile 32x32, 4 CTAs/SM.
// Row strides 272 B (AS/BS) ≡ 16 mod 128 -> conflict-free LDSM phases.
#define AS_LD 136
#define BS_LD 136
#define CS_LD 132
#define SM_AS  (64 * AS_LD * 2)               // 17408
#define SM_TOT (SM_AS + 128 * BS_LD * 2)      // 17408 + 34816 = 52224

__global__ __launch_bounds__(256, 4) void kgemm_tc(const float* __restrict__ X,
                                                   const unsigned* __restrict__ Wh,
                                                   const float* __restrict__ bias,
                                                   const float* __restrict__ pa,
                                                   float* __restrict__ out_f32,
                                                   unsigned* __restrict__ out_h16,
                                                   int prelu_f32, int M) {
    extern __shared__ char smem[];
    __half* As = (__half*)smem;                  // 64 x AS_LD
    __half* Bs = (__half*)(smem + SM_AS);        // 128 x BS_LD
    float* Cs = (float*)smem;                    // reuse whole smem: 64 x CS_LD
    const int tid = threadIdx.x;
    const int wid = tid >> 5;
    const int m0 = blockIdx.x * 64;

    // stage A: fp32 -> fp16
    for (int idx = tid; idx < 64 * 16; idx += 256) {
        int r = idx >> 4, g = idx & 15;
        int gr = m0 + r;
        float4 x0 = make_float4(0.f, 0.f, 0.f, 0.f), x1 = x0;
        if (gr < M) {
            x0 = __ldg((const float4*)(X + (size_t)gr * D + g * 8));
            x1 = __ldg((const float4*)(X + (size_t)gr * D + g * 8 + 4));
        }
        uint2 p0 = h4(x0), p1 = h4(x1);
        *(uint4*)(As + (size_t)r * AS_LD + g * 8) = make_uint4(p0.x, p0.y, p1.x, p1.y);
    }
    // stage B: fp16 weights, straight copy
    for (int idx = tid; idx < 128 * 16; idx += 256) {
        int kk = idx >> 4, g = idx & 15;
        uint4 v = __ldg((const uint4*)Wh + kk * 16 + g);
        *(uint4*)(Bs + (size_t)kk * BS_LD + g * 8) = v;
    }
    __syncthreads();

    // 8 warps: 2 m-strips (32 rows) x 4 n-strips (32 cols)
    const int row0 = (wid >> 2) * 32;
    const int n0   = (wid & 3) * 32;
    wmma::fragment<wmma::accumulator, 16, 16, 16, float> acc[2][2];
#pragma unroll
    for (int i = 0; i < 2; i++)
#pragma unroll
        for (int j = 0; j < 2; j++) wmma::fill_fragment(acc[i][j], 0.f);

#pragma unroll
    for (int k = 0; k < 8; k++) {
        wmma::fragment<wmma::matrix_a, 16, 16, 16, __half, wmma::row_major> af[2];
        wmma::fragment<wmma::matrix_b, 16, 16, 16, __half, wmma::row_major> bf[2];
#pragma unroll
        for (int i = 0; i < 2; i++)
            wmma::load_matrix_sync(af[i], As + (size_t)(row0 + i * 16) * AS_LD + k * 16, AS_LD);
#pragma unroll
        for (int j = 0; j < 2; j++)
            wmma::load_matrix_sync(bf[j], Bs + (size_t)(k * 16) * BS_LD + n0 + j * 16, BS_LD);
#pragma unroll
        for (int i = 0; i < 2; i++)
#pragma unroll
            for (int j = 0; j < 2; j++)
                wmma::mma_sync(acc[i][j], af[i], bf[j], acc[i][j]);
    }
    __syncthreads();   // all warps done reading As/Bs before overwrite with Cs
#pragma unroll
    for (int i = 0; i < 2; i++)
#pragma unroll
        for (int j = 0; j < 2; j++)
            wmma::store_matrix_sync(Cs + (size_t)(row0 + i * 16) * CS_LD + n0 + j * 16,
                                    acc[i][j], CS_LD, wmma::mem_row_major);
    __syncthreads();

    // epilogue: each thread one quarter-row (32 cols)
    {
        int r = tid >> 2, h = (tid & 3) * 32;
        int gr = m0 + r;
        if (gr < M) {
            float a = __ldg(pa);
#pragma unroll
            for (int q = 0; q < 8; q++) {
                int c = h + q * 4;
                float4 v = *(float4*)(Cs + (size_t)r * CS_LD + c);
                float4 bb = __ldg((const float4*)(bias + c));
                add4(v, bb);
                if (out_h16)
                    *(uint2*)(out_h16 + (size_t)gr * 64 + c / 2) = h4(v);
                if (out_f32) {
                    float4 o = prelu_f32 ? prelu4(v, a) : v;
                    *(float4*)(out_f32 + (size_t)gr * D + c) = o;
                }
            }
        }
    }
}

// ---------------- setup kernels ----------------------------------------------
__global__ void kzero_counts(int* cd, int* cs, int* cc1, int* cc2, int E, int N, int C) {
    int i = blockIdx.x * blockDim.x + threadIdx.x;
    int tot = E + N + 2 * C;
    if (i >= tot) return;
    if (i < E) cd[i] = 0;
    else if (i < E + N) cs[i - E] = 0;
    else if (i < E + N + C) cc1[i - E - N] = 0;
    else cc2[i - E - N - C] = 0;
}

__global__ void kcountall(const int* __restrict__ src, const int* __restrict__ dst,
                          const int* __restrict__ he_c, const int* __restrict__ nc_c,
                          int* cs, int* cd, int* cc1, int* cc2,
                          int nnz, int E, int N) {
    int i = blockIdx.x * blockDim.x + threadIdx.x;
    if (i < nnz) {
        atomicAdd(&cd[dst[i]], 1);
        atomicAdd(&cs[src[i]], 1);
    } else if (i < nnz + E) {
        atomicAdd(&cc1[he_c[i - nnz]], 1);
    } else if (i < nnz + E + N) {
        atomicAdd(&cc2[nc_c[i - nnz - E]], 1);
    }
}

__global__ __launch_bounds__(1024) void kscanA(const int* __restrict__ cd,
                                               const int* __restrict__ cs,
                                               int* od, int* os, int* bsum,
                                               int nbd, int E, int N) {
    __shared__ int sh[1024];
    const int b = blockIdx.x, t = threadIdx.x;
    const bool isD = b < nbd;
    const int* in = isD ? cd : cs;
    int* out = isD ? od : os;
    const int n = isD ? E : N;
    const int i = (isD ? b : b - nbd) * 1024 + t;
    int v = (i < n) ? in[i] : 0;
    sh[t] = v;
    __syncthreads();
    for (int off = 1; off < 1024; off <<= 1) {
        int x = (t >= off) ? sh[t - off] : 0;
        __syncthreads();
        sh[t] += x;
        __syncthreads();
    }
    if (i < n) out[i] = sh[t] - v;
    if (t == 1023) bsum[b] = sh[1023];
}

__global__ __launch_bounds__(1024) void kscanB(const int* __restrict__ bsum,
                                               int* bscan, int nbd, int nbtot, int nnz) {
    __shared__ int sh[1024];
    int t = threadIdx.x;
    int v = (t < nbtot) ? bsum[t] : 0;
    sh[t] = v;
    __syncthreads();
    for (int off = 1; off < 1024; off <<= 1) {
        int x = (t >= off) ? sh[t - off] : 0;
        __syncthreads();
        sh[t] += x;
        __syncthreads();
    }
    if (t < nbtot) {
        int excl = sh[t] - v;
        bscan[t] = (t >= nbd) ? excl - nnz : excl;
    }
}

__global__ __launch_bounds__(1024) void kscanC(int* od, int* os,
                                               const int* __restrict__ bscan,
                                               int* cd, int* cs,
                                               int nbd, int E, int N, int nnz) {
    const int b = blockIdx.x, t = threadIdx.x;
    const bool isD = b < nbd;
    const int i = (isD ? b : b - nbd) * 1024 + t;
    if (isD) {
        if (i < E) { od[i] += bscan[b]; cd[i] = 0; }
        if (b == 0 && t == 0) od[E] = nnz;
    } else {
        if (i < N) { os[i] += bscan[b]; cs[i] = 0; }
        if (i == 0) os[N] = nnz;
    }
}

__global__ void kfill(const int* __restrict__ src, const int* __restrict__ dst,
                      const int* __restrict__ od, const int* __restrict__ os,
                      int* cur_d, int* cur_s, int* perm_d, int* perm_s, int nnz) {
    int k = blockIdx.x * blockDim.x + threadIdx.x;
    if (k >= nnz) return;
    int s = __ldg(&src[k]), d = __ldg(&dst[k]);
    int pd = atomicAdd(&cur_d[d], 1);
    perm_d[__ldg(&od[d]) + pd] = s;
    int ps = atomicAdd(&cur_s[s], 1);
    perm_s[__ldg(&os[s]) + ps] = d;
}

__global__ void kinvall(const int* __restrict__ od, const int* __restrict__ os,
                        const int* __restrict__ cc1, const int* __restrict__ cc2,
                        float* invd, float* invs, float* ic1, float* ic2,
                        int E, int N, int C) {
    int i = blockIdx.x * blockDim.x + threadIdx.x;
    if (i < E) {
        int c = od[i + 1] - od[i];
        invd[i] = 1.f / (float)(c > 0 ? c : 1);
    } else if (i < E + N) {
        int j = i - E;
        int c = os[j + 1] - os[j] + 1;
        invs[j] = 1.f / (float)c;
    } else if (i < E + N + C) {
        int c = cc1[i - E - N];
        ic1[i - E - N] = 1.f / (float)(c > 0 ? c : 1);
    } else if (i < E + N + 2 * C) {
        int c = cc2[i - E - N - C];
        ic2[i - E - N - C] = 1.f / (float)(c > 0 ? c : 1);
    }
}

__global__ void kzero4(float4* p, long n4) {
    long i = (long)blockIdx.x * blockDim.x + threadIdx.x;
    if (i < n4) p[i] = make_float4(0.f, 0.f, 0.f, 0.f);
}

// ---------------- SIMT GEMM (small C-row GEMMs) ------------------------------
__global__ __launch_bounds__(256) void kgemm2(const float* __restrict__ X,
                                              const float* __restrict__ W,
                                              const float* __restrict__ b,
                                              const float* __restrict__ addin,
                                              float* __restrict__ Yraw,
                                              float* __restrict__ Ypre,
                                              const float* __restrict__ pa, int M) {
    __shared__ float As[64][128];
    const int m0 = blockIdx.x * 64;
    const int t = threadIdx.x;
    {
        const int c4 = t & 31;
        const int r0 = t >> 5;
#pragma unroll
        for (int s = 0; s < 8; s++) {
            int r = r0 + 8 * s;
            int gr = m0 + r;
            float4 v = make_float4(0.f, 0.f, 0.f, 0.f);
            if (gr < M) v = ((const float4*)(X + (size_t)gr * D))[c4];
            ((float4*)(&As[r][0]))[c4] = v;
        }
    }
    __syncthreads();
    const int cg = (t & 15) * 8;
    const int rg = (t >> 4) * 4;
    unsigned long long acc[4][4];
#pragma unroll
    for (int i = 0; i < 4; i++)
#pragma unroll
        for (int j = 0; j < 4; j++) acc[i][j] = 0ULL;
#pragma unroll 4
    for (int k = 0; k < D; k += 4) {
        float4 a[4];
#pragma unroll
        for (int i = 0; i < 4; i++) a[i] = *(const float4*)&As[rg + i][k];
#pragma unroll
        for (int kk = 0; kk < 4; kk++) {
            const ulonglong2 w0 = *reinterpret_cast<const ulonglong2*>(&W[(k + kk) * D + cg]);
            const ulonglong2 w1 = *reinterpret_cast<const ulonglong2*>(&W[(k + kk) * D + cg + 4]);
#pragma unroll
            for (int i = 0; i < 4; i++) {
                float av = (kk == 0) ? a[i].x : (kk == 1) ? a[i].y
                         : (kk == 2) ? a[i].z : a[i].w;
                unsigned long long av2 = pk2(av);
                fma2(acc[i][0], av2, w0.x);
                fma2(acc[i][1], av2, w0.y);
                fma2(acc[i][2], av2, w1.x);
                fma2(acc[i][3], av2, w1.y);
            }
        }
    }
    const float4 b0 = __ldg((const float4*)&b[cg]);
    const float4 b1 = __ldg((const float4*)&b[cg + 4]);
    const float a = __ldg(pa);
#pragma unroll
    for (int i = 0; i < 4; i++) {
        int gr = m0 + rg + i;
        if (gr >= M) continue;
        float2 p0 = up2(acc[i][0]), p1 = up2(acc[i][1]);
        float2 p2 = up2(acc[i][2]), p3 = up2(acc[i][3]);
        float4 o0 = make_float4(p0.x + b0.x, p0.y + b0.y, p1.x + b0.z, p1.y + b0.w);
        float4 o1 = make_float4(p2.x + b1.x, p2.y + b1.y, p3.x + b1.z, p3.y + b1.w);
        if (addin) {
            const float4* ar = (const float4*)(addin + (size_t)gr * D);
            add4(o0, ar[cg / 4]); add4(o1, ar[cg / 4 + 1]);
        }
        if (Yraw) {
            float4* yr = (float4*)(Yraw + (size_t)gr * D);
            yr[cg / 4] = o0; yr[cg / 4 + 1] = o1;
        }
        if (Ypre) {
            float4* yp = (float4*)(Ypre + (size_t)gr * D);
            yp[cg / 4] = prelu4(o0, a); yp[cg / 4 + 1] = prelu4(o1, a);
        }
    }
}

// ---------------- CSR aggregation (warp per segment, fp16 gather) ------------
__global__ __launch_bounds__(256) void kagg_e(const unsigned* __restrict__ T16,
                                              const int* __restrict__ perm,
                                              const int* __restrict__ offs,
                                              const float* __restrict__ invd,
                                              const float* __restrict__ pa,
                                              unsigned* __restrict__ EB16,
                                              float* __restrict__ out_e, int E) {
    int w = (blockIdx.x * blockDim.x + threadIdx.x) >> 5;
    int lane = threadIdx.x & 31;
    if (w >= E) return;
    int beg = __ldg(&offs[w]), end = __ldg(&offs[w + 1]);
    float4 a0 = {0,0,0,0}, a1 = {0,0,0,0}, a2 = {0,0,0,0}, a3 = {0,0,0,0};
    int p = beg;
    for (; p + 4 <= end; p += 4) {
        int s0 = __ldg(&perm[p]),     s1 = __ldg(&perm[p + 1]);
        int s2 = __ldg(&perm[p + 2]), s3 = __ldg(&perm[p + 3]);
        addh(a0, __ldg((const uint2*)(T16 + (size_t)s0 * 64) + lane));
        addh(a1, __ldg((const uint2*)(T16 + (size_t)s1 * 64) + lane));
        addh(a2, __ldg((const uint2*)(T16 + (size_t)s2 * 64) + lane));
        addh(a3, __ldg((const uint2*)(T16 + (size_t)s3 * 64) + lane));
    }
    for (; p < end; p++)
        addh(a0, __ldg((const uint2*)(T16 + (size_t)__ldg(&perm[p]) * 64) + lane));
    add4(a0, a1); add4(a2, a3); add4(a0, a2);
    float iv = __ldg(&invd[w]);
    float a = __ldg(pa);
    a0.x *= iv; a0.y *= iv; a0.z *= iv; a0.w *= iv;
    float4 r = prelu4(a0, a);
    ((uint2*)(EB16 + (size_t)w * 64))[lane] = h4(r);
    if (out_e) ((float4*)out_e)[(size_t)w * 32 + lane] = r;
}

__global__ __launch_bounds__(256) void kagg_n(float* __restrict__ T,
                                              const unsigned* __restrict__ EB16,
                                              const int* __restrict__ perm,
                                              const int* __restrict__ offs,
                                              const float* __restrict__ invs,
                                              const float* __restrict__ pa, int N) {
    int w = (blockIdx.x * blockDim.x + threadIdx.x) >> 5;
    int lane = threadIdx.x & 31;
    if (w >= N) return;
    int beg = __ldg(&offs[w]), end = __ldg(&offs[w + 1]);
    float4 a0 = {0,0,0,0}, a1 = {0,0,0,0}, a2 = {0,0,0,0}, a3 = {0,0,0,0};
    int p = beg;
    for (; p + 4 <= end; p += 4) {
        int s0 = __ldg(&perm[p]),     s1 = __ldg(&perm[p + 1]);
        int s2 = __ldg(&perm[p + 2]), s3 = __ldg(&perm[p + 3]);
        addh(a0, __ldg((const uint2*)(EB16 + (size_t)s0 * 64) + lane));
        addh(a1, __ldg((const uint2*)(EB16 + (size_t)s1 * 64) + lane));
        addh(a2, __ldg((const uint2*)(EB16 + (size_t)s2 * 64) + lane));
        addh(a3, __ldg((const uint2*)(EB16 + (size_t)s3 * 64) + lane));
    }
    for (; p < end; p++)
        addh(a0, __ldg((const uint2*)(EB16 + (size_t)__ldg(&perm[p]) * 64) + lane));
    add4(a0, a1); add4(a2, a3); add4(a0, a2);
    float a = __ldg(pa);
    float4 t = ((float4*)T)[(size_t)w * 32 + lane];
    add4(a0, prelu4(t, a));
    float iv = __ldg(&invs[w]);
    a0.x *= iv; a0.y *= iv; a0.z *= iv; a0.w *= iv;
    ((float4*)T)[(size_t)w * 32 + lane] = a0;
}

// ---------------- component scatter (atomic; fp16 gather) --------------------
__device__ __forceinline__ void red4(float* a, float4 v) {
    asm volatile("red.global.add.v4.f32 [%0], {%1,%2,%3,%4};"
                 :: "l"(a), "f"(v.x), "f"(v.y), "f"(v.z), "f"(v.w)
                 : "memory");
}

__global__ void kscatterc(const unsigned* __restrict__ P16, const int* __restrict__ rows,
                          const int* __restrict__ comp, const float* __restrict__ inv,
                          float* __restrict__ csum, int n) {
    int w = (blockIdx.x * blockDim.x + threadIdx.x) >> 5;
    int lane = threadIdx.x & 31;
    if (w >= n) return;
    int r = __ldg(&rows[w]);
    int c = __ldg(&comp[w]);
    float sc = __ldg(&inv[c]);
    float4 v = {0,0,0,0};
    addh(v, __ldg((const uint2*)(P16 + (size_t)r * 64) + lane));
    v.x *= sc; v.y *= sc; v.z *= sc; v.w *= sc;
    red4(csum + (size_t)c * D + lane * 4, v);
}

// ---------------- host driver ------------------------------------------------
static inline int cdiv(long a, long b) { return (int)((a + b - 1) / b); }

extern "C" void kernel_launch(void* const* d_in, const int* in_sizes, int n_in,
                              void* d_out, int out_size) {
    const float* x   = (const float*)d_in[0];
    const int*   hei = (const int*)d_in[1];
    const int*   hci = (const int*)d_in[2];
    const int*   nci = (const int*)d_in[3];

    const int NNZ = in_sizes[1] / 2;
    const int E   = in_sizes[2] / 2;
    const int N   = in_sizes[0] / D;
    const int C   = out_size / D - N - E;

    int wi = -1;
    for (int i = 4; i < n_in; i++) {
        if (in_sizes[i] == D * D) { wi = i; break; }
    }
    const float* pa = (const float*)d_in[wi - 1];

    const int* src  = hei;
    const int* dst  = hei + NNZ;
    const int* he_e = hci;
    const int* he_c = hci + E;
    const int* nc_n = nci;
    const int* nc_c = nci + N;

    float *T, *HB, *CE, *CN, *CT, *invd, *invs, *ic1, *ic2;
    unsigned *T16, *E16, *Wh;
    int *cd, *cs, *cc1, *cc2, *od, *os, *pd, *ps, *bsum, *bscan;
    cudaGetSymbolAddress((void**)&T,    g_T);
    cudaGetSymbolAddress((void**)&T16,  g_T16);
    cudaGetSymbolAddress((void**)&E16,  g_E16);
    cudaGetSymbolAddress((void**)&HB,   g_h);
    cudaGetSymbolAddress((void**)&CE,   g_c1);
    cudaGetSymbolAddress((void**)&CN,   g_c2);
    cudaGetSymbolAddress((void**)&CT,   g_c3);
    cudaGetSymbolAddress((void**)&Wh,   g_Wh);
    cudaGetSymbolAddress((void**)&invd, g_invdst);
    cudaGetSymbolAddress((void**)&invs, g_invsrc);
    cudaGetSymbolAddress((void**)&ic1,  g_invc1);
    cudaGetSymbolAddress((void**)&ic2,  g_invc2);
    cudaGetSymbolAddress((void**)&cd,   g_cd);
    cudaGetSymbolAddress((void**)&cs,   g_cs);
    cudaGetSymbolAddress((void**)&cc1,  g_cc1);
    cudaGetSymbolAddress((void**)&cc2,  g_cc2);
    cudaGetSymbolAddress((void**)&od,   g_offs_d);
    cudaGetSymbolAddress((void**)&os,   g_offs_s);
    cudaGetSymbolAddress((void**)&pd,   g_perm_d);
    cudaGetSymbolAddress((void**)&ps,   g_perm_s);
    cudaGetSymbolAddress((void**)&bsum, g_bsum);
    cudaGetSymbolAddress((void**)&bscan,g_bscan);

    float* out   = (float*)d_out;
    float* out_n = out;
    float* out_e = out + (size_t)N * D;
    float* out_c = out + (size_t)(N + E) * D;

    const int TB = 256;
    const int nbd = cdiv(E, 1024);
    const int nbs = cdiv(N, 1024);
    const int nbtot = nbd + nbs;
    const int GT = cdiv(N, 64);

    const float* Wv0 = (const float*)d_in[wi + 0];
    const float* bv0 = (const float*)d_in[wi + 1];
    const float* We0 = (const float*)d_in[wi + 2];
    const float* be0 = (const float*)d_in[wi + 3];
    const float* Wv1 = (const float*)d_in[wi + 8];
    const float* bv1 = (const float*)d_in[wi + 9];
    const float* We1 = (const float*)d_in[wi + 10];
    const float* be1 = (const float*)d_in[wi + 11];

    cudaFuncSetAttribute(kgemm_tc, cudaFuncAttributeMaxDynamicSharedMemorySize, SM_TOT);

    kconvW<<<cdiv(4 * 128 * 16, TB), TB>>>(Wv0, We0, Wv1, We1, Wh);
    kzero_counts<<<cdiv(E + N + 2 * C, TB), TB>>>(cd, cs, cc1, cc2, E, N, C);
    kcountall<<<cdiv(NNZ + E + N, TB), TB>>>(src, dst, he_c, nc_c, cs, cd, cc1, cc2,
                                             NNZ, E, N);
    // G1 = v2e layer 0 -> T fp32 raw + T16 (launch index 3 for ncu capture)
    kgemm_tc<<<GT, 256, SM_TOT>>>(x, Wh + 0 * 8192, bv0, pa, T, T16, 0, N);
    kscanA<<<nbtot, 1024>>>(cd, cs, od, os, bsum, nbd, E, N);
    kscanB<<<1, 1024>>>(bsum, bscan, nbd, nbtot, NNZ);
    kscanC<<<nbtot, 1024>>>(od, os, bscan, cd, cs, nbd, E, N, NNZ);
    kfill<<<cdiv(NNZ, TB), TB>>>(src, dst, od, os, cd, cs, pd, ps, NNZ);
    kinvall<<<cdiv(E + N + 2 * C, TB), TB>>>(od, os, cc1, cc2, invd, invs, ic1, ic2,
                                             E, N, C);

    // ---- layer 0 ----
    kagg_e<<<cdiv((long)E * 32, TB), TB>>>(T16, pd, od, invd, pa, E16, nullptr, E);
    kagg_n<<<cdiv((long)N * 32, TB), TB>>>(T, E16, ps, os, invs, pa, N);
    // G2 = e2v layer 0 -> HB = prelu(A@We0+be0)
    kgemm_tc<<<GT, 256, SM_TOT>>>(T, Wh + 1 * 8192, be0, pa, HB, nullptr, 1, N);

    // ---- layer 1 ----
    kgemm_tc<<<GT, 256, SM_TOT>>>(HB, Wh + 2 * 8192, bv1, pa, T, T16, 0, N);
    kagg_e<<<cdiv((long)E * 32, TB), TB>>>(T16, pd, od, invd, pa, E16, out_e, E);
    kagg_n<<<cdiv((long)N * 32, TB), TB>>>(T, E16, ps, os, invs, pa, N);
    // G4 = e2v layer 1 -> out_n = prelu(n), T16 = raw n fp16
    kgemm_tc<<<GT, 256, SM_TOT>>>(T, Wh + 3 * 8192, be1, pa, out_n, T16, 1, N);

    // components
    kzero4<<<cdiv((long)C * 32, TB), TB>>>((float4*)CE, (long)C * 32);
    kzero4<<<cdiv((long)C * 32, TB), TB>>>((float4*)CN, (long)C * 32);
    kscatterc<<<cdiv((long)E, 8), TB>>>(E16, he_e, he_c, ic1, CE, E);
    kscatterc<<<cdiv((long)N, 8), TB>>>(T16, nc_n, nc_c, ic2, CN, N);
    kgemm2<<<cdiv(C, 64), TB>>>(CE, (const float*)d_in[wi + 12], (const float*)d_in[wi + 13],
                                nullptr, CT, nullptr, pa, C);
    kgemm2<<<cdiv(C, 64), TB>>>(CN, (const float*)d_in[wi + 14], (const float*)d_in[wi + 15],
                                CT, nullptr, out_c, pa, C);
}

// round 10
// speedup vs baseline: 1.7346x; 1.1125x over previous
#include <cuda_runtime.h>
#include <cuda_fp16.h>
#include <cuda_bf16.h>
#include <mma.h>
#include <cstdint>
#include <cstddef>

#define D 128
using namespace nvcuda;

// ---------------- static scratch (device globals) ---------------------------
static __device__ unsigned g_T16[100000 * 64];   // v2e transform output (fp16 rows)
static __device__ unsigned g_A16[100000 * 64];   // aggregated node features (fp16)
static __device__ unsigned g_H16[100000 * 64];   // h = prelu(n) layer 0 (fp16)
static __device__ unsigned g_E16[50000  * 64];   // e fp16 rows
static __device__ float    g_c1 [2048   * 128];
static __device__ float    g_c2 [2048   * 128];
static __device__ float    g_c3 [2048   * 128];
static __device__ unsigned g_Wh [4 * 128 * 64];  // 4 W, fp16 [128][128]
static __device__ float g_invdst[50016];
static __device__ float g_invsrc[100016];
static __device__ float g_invc1[2048];
static __device__ float g_invc2[2048];
static __device__ int   g_cd [50016];
static __device__ int   g_cs [100016];
static __device__ int   g_cc1[2048];
static __device__ int   g_cc2[2048];
static __device__ int   g_offs_d[50024];
static __device__ int   g_offs_s[100024];
static __device__ int   g_perm_d[1600128];
static __device__ int   g_perm_s[1600128];
static __device__ int   g_bsum [1024];
static __device__ int   g_bscan[1024];

// ---------------- helpers ----------------------------------------------------
__device__ __forceinline__ unsigned long long pk2(float v) {
    unsigned long long r; unsigned u = __float_as_uint(v);
    asm("mov.b64 %0, {%1,%1};" : "=l"(r) : "r"(u));
    return r;
}
__device__ __forceinline__ void fma2(unsigned long long& d, unsigned long long a,
                                     unsigned long long b) {
    asm("fma.rn.f32x2 %0, %1, %2, %0;" : "+l"(d) : "l"(a), "l"(b));
}
__device__ __forceinline__ float2 up2(unsigned long long v) {
    unsigned lo, hi;
    asm("mov.b64 {%0,%1}, %2;" : "=r"(lo), "=r"(hi) : "l"(v));
    return make_float2(__uint_as_float(lo), __uint_as_float(hi));
}
__device__ __forceinline__ float prelu1(float v, float a) { return v >= 0.f ? v : a * v; }
__device__ __forceinline__ float4 prelu4(float4 v, float a) {
    return make_float4(prelu1(v.x, a), prelu1(v.y, a), prelu1(v.z, a), prelu1(v.w, a));
}
__device__ __forceinline__ void add4(float4& a, float4 b) {
    a.x += b.x; a.y += b.y; a.z += b.z; a.w += b.w;
}
__device__ __forceinline__ void addh(float4& a, uint2 v) {
    __half2 h0 = *reinterpret_cast<__half2*>(&v.x);
    __half2 h1 = *reinterpret_cast<__half2*>(&v.y);
    float2 f0 = __half22float2(h0), f1 = __half22float2(h1);
    a.x += f0.x; a.y += f0.y; a.z += f1.x; a.w += f1.y;
}
__device__ __forceinline__ uint2 h4(float4 v) {
    __half2 h0 = __float22half2_rn(make_float2(v.x, v.y));
    __half2 h1 = __float22half2_rn(make_float2(v.z, v.w));
    uint2 r;
    r.x = *reinterpret_cast<unsigned*>(&h0);
    r.y = *reinterpret_cast<unsigned*>(&h1);
    return r;
}

// ---------------- W convert: Wh[w] = fp16 [128][128] -------------------------
__global__ void kconvW(const float* __restrict__ W0, const float* __restrict__ W1,
                       const float* __restrict__ W2, const float* __restrict__ W3,
                       unsigned* __restrict__ Wh) {
    int idx = blockIdx.x * blockDim.x + threadIdx.x;
    if (idx >= 4 * 128 * 16) return;
    int w = idx >> 11;
    int rem = idx & 2047;
    int kk = rem >> 4, g = rem & 15;
    const float* W = (w == 0) ? W0 : (w == 1) ? W1 : (w == 2) ? W2 : W3;
    float4 x0 = __ldg((const float4*)(W + (size_t)kk * D + g * 8));
    float4 x1 = __ldg((const float4*)(W + (size_t)kk * D + g * 8 + 4));
    uint2 p0 = h4(x0), p1 = h4(x1);
    ((uint4*)(Wh + (size_t)w * 128 * 64))[kk * 16 + g] = make_uint4(p0.x, p0.y, p1.x, p1.y);
}

// ---------------- WMMA GEMM: Y[M x 128] = X @ W + b (fp16) -------------------
// Input either fp32 (X32) or fp16 (X16). Outputs: out_h16 (raw or prelu),
// out_f32 (raw or prelu), both optional. CTA 64x128, 8 warps, 4 CTAs/SM.
#define AS_LD 136
#define BS_LD 136
#define CS_LD 132
#define SM_AS  (64 * AS_LD * 2)               // 17408
#define SM_TOT (SM_AS + 128 * BS_LD * 2)      // 52224

__global__ __launch_bounds__(256, 4) void kgemm_tc(const float* __restrict__ X32,
                                                   const unsigned* __restrict__ X16,
                                                   const unsigned* __restrict__ Wh,
                                                   const float* __restrict__ bias,
                                                   const float* __restrict__ pa,
                                                   float* __restrict__ out_f32,
                                                   int prelu_f32,
                                                   unsigned* __restrict__ out_h16,
                                                   int prelu_h16, int M) {
    extern __shared__ char smem[];
    __half* As = (__half*)smem;                  // 64 x AS_LD
    __half* Bs = (__half*)(smem + SM_AS);        // 128 x BS_LD
    float* Cs = (float*)smem;                    // reuse smem: 64 x CS_LD
    const int tid = threadIdx.x;
    const int wid = tid >> 5;
    const int m0 = blockIdx.x * 64;

    // stage A
    if (X16) {
        for (int idx = tid; idx < 64 * 16; idx += 256) {
            int r = idx >> 4, g = idx & 15;
            int gr = m0 + r;
            uint4 v = make_uint4(0, 0, 0, 0);
            if (gr < M) v = ((const uint4*)(X16 + (size_t)gr * 64))[g];
            *(uint4*)(As + (size_t)r * AS_LD + g * 8) = v;
        }
    } else {
        for (int idx = tid; idx < 64 * 16; idx += 256) {
            int r = idx >> 4, g = idx & 15;
            int gr = m0 + r;
            float4 x0 = make_float4(0.f, 0.f, 0.f, 0.f), x1 = x0;
            if (gr < M) {
                x0 = __ldg((const float4*)(X32 + (size_t)gr * D + g * 8));
                x1 = __ldg((const float4*)(X32 + (size_t)gr * D + g * 8 + 4));
            }
            uint2 p0 = h4(x0), p1 = h4(x1);
            *(uint4*)(As + (size_t)r * AS_LD + g * 8) = make_uint4(p0.x, p0.y, p1.x, p1.y);
        }
    }
    // stage B: fp16 weights
    for (int idx = tid; idx < 128 * 16; idx += 256) {
        int kk = idx >> 4, g = idx & 15;
        uint4 v = __ldg((const uint4*)Wh + kk * 16 + g);
        *(uint4*)(Bs + (size_t)kk * BS_LD + g * 8) = v;
    }
    __syncthreads();

    const int row0 = (wid >> 2) * 32;
    const int n0   = (wid & 3) * 32;
    wmma::fragment<wmma::accumulator, 16, 16, 16, float> acc[2][2];
#pragma unroll
    for (int i = 0; i < 2; i++)
#pragma unroll
        for (int j = 0; j < 2; j++) wmma::fill_fragment(acc[i][j], 0.f);

#pragma unroll
    for (int k = 0; k < 8; k++) {
        wmma::fragment<wmma::matrix_a, 16, 16, 16, __half, wmma::row_major> af[2];
        wmma::fragment<wmma::matrix_b, 16, 16, 16, __half, wmma::row_major> bf[2];
#pragma unroll
        for (int i = 0; i < 2; i++)
            wmma::load_matrix_sync(af[i], As + (size_t)(row0 + i * 16) * AS_LD + k * 16, AS_LD);
#pragma unroll
        for (int j = 0; j < 2; j++)
            wmma::load_matrix_sync(bf[j], Bs + (size_t)(k * 16) * BS_LD + n0 + j * 16, BS_LD);
#pragma unroll
        for (int i = 0; i < 2; i++)
#pragma unroll
            for (int j = 0; j < 2; j++)
                wmma::mma_sync(acc[i][j], af[i], bf[j], acc[i][j]);
    }
    __syncthreads();
#pragma unroll
    for (int i = 0; i < 2; i++)
#pragma unroll
        for (int j = 0; j < 2; j++)
            wmma::store_matrix_sync(Cs + (size_t)(row0 + i * 16) * CS_LD + n0 + j * 16,
                                    acc[i][j], CS_LD, wmma::mem_row_major);
    __syncthreads();

    // epilogue: each thread one quarter-row (32 cols)
    {
        int r = tid >> 2, h = (tid & 3) * 32;
        int gr = m0 + r;
        if (gr < M) {
            float a = __ldg(pa);
#pragma unroll
            for (int q = 0; q < 8; q++) {
                int c = h + q * 4;
                float4 v = *(float4*)(Cs + (size_t)r * CS_LD + c);
                float4 bb = __ldg((const float4*)(bias + c));
                add4(v, bb);
                if (out_h16) {
                    float4 o = prelu_h16 ? prelu4(v, a) : v;
                    *(uint2*)(out_h16 + (size_t)gr * 64 + c / 2) = h4(o);
                }
                if (out_f32) {
                    float4 o = prelu_f32 ? prelu4(v, a) : v;
                    *(float4*)(out_f32 + (size_t)gr * D + c) = o;
                }
            }
        }
    }
}

// ---------------- setup kernels ----------------------------------------------
__global__ void kzero_counts(int* cd, int* cs, int* cc1, int* cc2, int E, int N, int C) {
    int i = blockIdx.x * blockDim.x + threadIdx.x;
    int tot = E + N + 2 * C;
    if (i >= tot) return;
    if (i < E) cd[i] = 0;
    else if (i < E + N) cs[i - E] = 0;
    else if (i < E + N + C) cc1[i - E - N] = 0;
    else cc2[i - E - N - C] = 0;
}

__global__ void kcountall(const int* __restrict__ src, const int* __restrict__ dst,
                          const int* __restrict__ he_c, const int* __restrict__ nc_c,
                          int* cs, int* cd, int* cc1, int* cc2,
                          int nnz, int E, int N) {
    int i = blockIdx.x * blockDim.x + threadIdx.x;
    if (i < nnz) {
        atomicAdd(&cd[dst[i]], 1);
        atomicAdd(&cs[src[i]], 1);
    } else if (i < nnz + E) {
        atomicAdd(&cc1[he_c[i - nnz]], 1);
    } else if (i < nnz + E + N) {
        atomicAdd(&cc2[nc_c[i - nnz - E]], 1);
    }
}

__global__ __launch_bounds__(1024) void kscanA(const int* __restrict__ cd,
                                               const int* __restrict__ cs,
                                               int* od, int* os, int* bsum,
                                               int nbd, int E, int N) {
    __shared__ int sh[1024];
    const int b = blockIdx.x, t = threadIdx.x;
    const bool isD = b < nbd;
    const int* in = isD ? cd : cs;
    int* out = isD ? od : os;
    const int n = isD ? E : N;
    const int i = (isD ? b : b - nbd) * 1024 + t;
    int v = (i < n) ? in[i] : 0;
    sh[t] = v;
    __syncthreads();
    for (int off = 1; off < 1024; off <<= 1) {
        int x = (t >= off) ? sh[t - off] : 0;
        __syncthreads();
        sh[t] += x;
        __syncthreads();
    }
    if (i < n) out[i] = sh[t] - v;
    if (t == 1023) bsum[b] = sh[1023];
}

__global__ __launch_bounds__(1024) void kscanB(const int* __restrict__ bsum,
                                               int* bscan, int nbd, int nbtot, int nnz) {
    __shared__ int sh[1024];
    int t = threadIdx.x;
    int v = (t < nbtot) ? bsum[t] : 0;
    sh[t] = v;
    __syncthreads();
    for (int off = 1; off < 1024; off <<= 1) {
        int x = (t >= off) ? sh[t - off] : 0;
        __syncthreads();
        sh[t] += x;
        __syncthreads();
    }
    if (t < nbtot) {
        int excl = sh[t] - v;
        bscan[t] = (t >= nbd) ? excl - nnz : excl;
    }
}

__global__ __launch_bounds__(1024) void kscanC(int* od, int* os,
                                               const int* __restrict__ bscan,
                                               int* cd, int* cs,
                                               int nbd, int E, int N, int nnz) {
    const int b = blockIdx.x, t = threadIdx.x;
    const bool isD = b < nbd;
    const int i = (isD ? b : b - nbd) * 1024 + t;
    if (isD) {
        if (i < E) { od[i] += bscan[b]; cd[i] = 0; }
        if (b == 0 && t == 0) od[E] = nnz;
    } else {
        if (i < N) { os[i] += bscan[b]; cs[i] = 0; }
        if (i == 0) os[N] = nnz;
    }
}

__global__ void kfill(const int* __restrict__ src, const int* __restrict__ dst,
                      const int* __restrict__ od, const int* __restrict__ os,
                      int* cur_d, int* cur_s, int* perm_d, int* perm_s, int nnz) {
    int k = blockIdx.x * blockDim.x + threadIdx.x;
    if (k >= nnz) return;
    int s = __ldg(&src[k]), d = __ldg(&dst[k]);
    int pd = atomicAdd(&cur_d[d], 1);
    perm_d[__ldg(&od[d]) + pd] = s;
    int ps = atomicAdd(&cur_s[s], 1);
    perm_s[__ldg(&os[s]) + ps] = d;
}

__global__ void kinvall(const int* __restrict__ od, const int* __restrict__ os,
                        const int* __restrict__ cc1, const int* __restrict__ cc2,
                        float* invd, float* invs, float* ic1, float* ic2,
                        int E, int N, int C) {
    int i = blockIdx.x * blockDim.x + threadIdx.x;
    if (i < E) {
        int c = od[i + 1] - od[i];
        invd[i] = 1.f / (float)(c > 0 ? c : 1);
    } else if (i < E + N) {
        int j = i - E;
        int c = os[j + 1] - os[j] + 1;
        invs[j] = 1.f / (float)c;
    } else if (i < E + N + C) {
        int c = cc1[i - E - N];
        ic1[i - E - N] = 1.f / (float)(c > 0 ? c : 1);
    } else if (i < E + N + 2 * C) {
        int c = cc2[i - E - N - C];
        ic2[i - E - N - C] = 1.f / (float)(c > 0 ? c : 1);
    }
}

__global__ void kzero4(float4* p, long n4) {
    long i = (long)blockIdx.x * blockDim.x + threadIdx.x;
    if (i < n4) p[i] = make_float4(0.f, 0.f, 0.f, 0.f);
}

// ---------------- SIMT GEMM (small C-row GEMMs) ------------------------------
__global__ __launch_bounds__(256) void kgemm2(const float* __restrict__ X,
                                              const float* __restrict__ W,
                                              const float* __restrict__ b,
                                              const float* __restrict__ addin,
                                              float* __restrict__ Yraw,
                                              float* __restrict__ Ypre,
                                              const float* __restrict__ pa, int M) {
    __shared__ float As[64][128];
    const int m0 = blockIdx.x * 64;
    const int t = threadIdx.x;
    {
        const int c4 = t & 31;
        const int r0 = t >> 5;
#pragma unroll
        for (int s = 0; s < 8; s++) {
            int r = r0 + 8 * s;
            int gr = m0 + r;
            float4 v = make_float4(0.f, 0.f, 0.f, 0.f);
            if (gr < M) v = ((const float4*)(X + (size_t)gr * D))[c4];
            ((float4*)(&As[r][0]))[c4] = v;
        }
    }
    __syncthreads();
    const int cg = (t & 15) * 8;
    const int rg = (t >> 4) * 4;
    unsigned long long acc[4][4];
#pragma unroll
    for (int i = 0; i < 4; i++)
#pragma unroll
        for (int j = 0; j < 4; j++) acc[i][j] = 0ULL;
#pragma unroll 4
    for (int k = 0; k < D; k += 4) {
        float4 a[4];
#pragma unroll
        for (int i = 0; i < 4; i++) a[i] = *(const float4*)&As[rg + i][k];
#pragma unroll
        for (int kk = 0; kk < 4; kk++) {
            const ulonglong2 w0 = *reinterpret_cast<const ulonglong2*>(&W[(k + kk) * D + cg]);
            const ulonglong2 w1 = *reinterpret_cast<const ulonglong2*>(&W[(k + kk) * D + cg + 4]);
#pragma unroll
            for (int i = 0; i < 4; i++) {
                float av = (kk == 0) ? a[i].x : (kk == 1) ? a[i].y
                         : (kk == 2) ? a[i].z : a[i].w;
                unsigned long long av2 = pk2(av);
                fma2(acc[i][0], av2, w0.x);
                fma2(acc[i][1], av2, w0.y);
                fma2(acc[i][2], av2, w1.x);
                fma2(acc[i][3], av2, w1.y);
            }
        }
    }
    const float4 b0 = __ldg((const float4*)&b[cg]);
    const float4 b1 = __ldg((const float4*)&b[cg + 4]);
    const float a = __ldg(pa);
#pragma unroll
    for (int i = 0; i < 4; i++) {
        int gr = m0 + rg + i;
        if (gr >= M) continue;
        float2 p0 = up2(acc[i][0]), p1 = up2(acc[i][1]);
        float2 p2 = up2(acc[i][2]), p3 = up2(acc[i][3]);
        float4 o0 = make_float4(p0.x + b0.x, p0.y + b0.y, p1.x + b0.z, p1.y + b0.w);
        float4 o1 = make_float4(p2.x + b1.x, p2.y + b1.y, p3.x + b1.z, p3.y + b1.w);
        if (addin) {
            const float4* ar = (const float4*)(addin + (size_t)gr * D);
            add4(o0, ar[cg / 4]); add4(o1, ar[cg / 4 + 1]);
        }
        if (Yraw) {
            float4* yr = (float4*)(Yraw + (size_t)gr * D);
            yr[cg / 4] = o0; yr[cg / 4 + 1] = o1;
        }
        if (Ypre) {
            float4* yp = (float4*)(Ypre + (size_t)gr * D);
            yp[cg / 4] = prelu4(o0, a); yp[cg / 4 + 1] = prelu4(o1, a);
        }
    }
}

// ---------------- CSR aggregation (warp per segment, fp16) -------------------
__global__ __launch_bounds__(256) void kagg_e(const unsigned* __restrict__ T16,
                                              const int* __restrict__ perm,
                                              const int* __restrict__ offs,
                                              const float* __restrict__ invd,
                                              const float* __restrict__ pa,
                                              unsigned* __restrict__ EB16,
                                              float* __restrict__ out_e, int E) {
    int w = (blockIdx.x * blockDim.x + threadIdx.x) >> 5;
    int lane = threadIdx.x & 31;
    if (w >= E) return;
    int beg = __ldg(&offs[w]), end = __ldg(&offs[w + 1]);
    float4 a0 = {0,0,0,0}, a1 = {0,0,0,0}, a2 = {0,0,0,0}, a3 = {0,0,0,0};
    int p = beg;
    for (; p + 4 <= end; p += 4) {
        int s0 = __ldg(&perm[p]),     s1 = __ldg(&perm[p + 1]);
        int s2 = __ldg(&perm[p + 2]), s3 = __ldg(&perm[p + 3]);
        addh(a0, __ldg((const uint2*)(T16 + (size_t)s0 * 64) + lane));
        addh(a1, __ldg((const uint2*)(T16 + (size_t)s1 * 64) + lane));
        addh(a2, __ldg((const uint2*)(T16 + (size_t)s2 * 64) + lane));
        addh(a3, __ldg((const uint2*)(T16 + (size_t)s3 * 64) + lane));
    }
    for (; p < end; p++)
        addh(a0, __ldg((const uint2*)(T16 + (size_t)__ldg(&perm[p]) * 64) + lane));
    add4(a0, a1); add4(a2, a3); add4(a0, a2);
    float iv = __ldg(&invd[w]);
    float a = __ldg(pa);
    a0.x *= iv; a0.y *= iv; a0.z *= iv; a0.w *= iv;
    float4 r = prelu4(a0, a);
    ((uint2*)(EB16 + (size_t)w * 64))[lane] = h4(r);
    if (out_e) ((float4*)out_e)[(size_t)w * 32 + lane] = r;
}

// A16[i] = fp16( (sum_{p} EB16[perm[p]] + prelu(T16[i])) * invs[i] )
__global__ __launch_bounds__(256) void kagg_n(const unsigned* __restrict__ T16,
                                              const unsigned* __restrict__ EB16,
                                              const int* __restrict__ perm,
                                              const int* __restrict__ offs,
                                              const float* __restrict__ invs,
                                              const float* __restrict__ pa,
                                              unsigned* __restrict__ A16, int N) {
    int w = (blockIdx.x * blockDim.x + threadIdx.x) >> 5;
    int lane = threadIdx.x & 31;
    if (w >= N) return;
    int beg = __ldg(&offs[w]), end = __ldg(&offs[w + 1]);
    float4 a0 = {0,0,0,0}, a1 = {0,0,0,0}, a2 = {0,0,0,0}, a3 = {0,0,0,0};
    int p = beg;
    for (; p + 4 <= end; p += 4) {
        int s0 = __ldg(&perm[p]),     s1 = __ldg(&perm[p + 1]);
        int s2 = __ldg(&perm[p + 2]), s3 = __ldg(&perm[p + 3]);
        addh(a0, __ldg((const uint2*)(EB16 + (size_t)s0 * 64) + lane));
        addh(a1, __ldg((const uint2*)(EB16 + (size_t)s1 * 64) + lane));
        addh(a2, __ldg((const uint2*)(EB16 + (size_t)s2 * 64) + lane));
        addh(a3, __ldg((const uint2*)(EB16 + (size_t)s3 * 64) + lane));
    }
    for (; p < end; p++)
        addh(a0, __ldg((const uint2*)(EB16 + (size_t)__ldg(&perm[p]) * 64) + lane));
    add4(a0, a1); add4(a2, a3); add4(a0, a2);
    float a = __ldg(pa);
    float4 t = {0,0,0,0};
    addh(t, __ldg((const uint2*)(T16 + (size_t)w * 64) + lane));
    add4(a0, prelu4(t, a));
    float iv = __ldg(&invs[w]);
    a0.x *= iv; a0.y *= iv; a0.z *= iv; a0.w *= iv;
    ((uint2*)(A16 + (size_t)w * 64))[lane] = h4(a0);
}

// ---------------- component scatter (atomic; fp16 gather) --------------------
__device__ __forceinline__ void red4(float* a, float4 v) {
    asm volatile("red.global.add.v4.f32 [%0], {%1,%2,%3,%4};"
                 :: "l"(a), "f"(v.x), "f"(v.y), "f"(v.z), "f"(v.w)
                 : "memory");
}

__global__ void kscatterc(const unsigned* __restrict__ P16, const int* __restrict__ rows,
                          const int* __restrict__ comp, const float* __restrict__ inv,
                          float* __restrict__ csum, int n) {
    int w = (blockIdx.x * blockDim.x + threadIdx.x) >> 5;
    int lane = threadIdx.x & 31;
    if (w >= n) return;
    int r = __ldg(&rows[w]);
    int c = __ldg(&comp[w]);
    float sc = __ldg(&inv[c]);
    float4 v = {0,0,0,0};
    addh(v, __ldg((const uint2*)(P16 + (size_t)r * 64) + lane));
    v.x *= sc; v.y *= sc; v.z *= sc; v.w *= sc;
    red4(csum + (size_t)c * D + lane * 4, v);
}

// ---------------- host driver ------------------------------------------------
static inline int cdiv(long a, long b) { return (int)((a + b - 1) / b); }

extern "C" void kernel_launch(void* const* d_in, const int* in_sizes, int n_in,
                              void* d_out, int out_size) {
    const float* x   = (const float*)d_in[0];
    const int*   hei = (const int*)d_in[1];
    const int*   hci = (const int*)d_in[2];
    const int*   nci = (const int*)d_in[3];

    const int NNZ = in_sizes[1] / 2;
    const int E   = in_sizes[2] / 2;
    const int N   = in_sizes[0] / D;
    const int C   = out_size / D - N - E;

    int wi = -1;
    for (int i = 4; i < n_in; i++) {
        if (in_sizes[i] == D * D) { wi = i; break; }
    }
    const float* pa = (const float*)d_in[wi - 1];

    const int* src  = hei;
    const int* dst  = hei + NNZ;
    const int* he_e = hci;
    const int* he_c = hci + E;
    const int* nc_n = nci;
    const int* nc_c = nci + N;

    float *CE, *CN, *CT, *invd, *invs, *ic1, *ic2;
    unsigned *T16, *A16, *H16, *E16, *Wh;
    int *cd, *cs, *cc1, *cc2, *od, *os, *pd, *ps, *bsum, *bscan;
    cudaGetSymbolAddress((void**)&T16,  g_T16);
    cudaGetSymbolAddress((void**)&A16,  g_A16);
    cudaGetSymbolAddress((void**)&H16,  g_H16);
    cudaGetSymbolAddress((void**)&E16,  g_E16);
    cudaGetSymbolAddress((void**)&CE,   g_c1);
    cudaGetSymbolAddress((void**)&CN,   g_c2);
    cudaGetSymbolAddress((void**)&CT,   g_c3);
    cudaGetSymbolAddress((void**)&Wh,   g_Wh);
    cudaGetSymbolAddress((void**)&invd, g_invdst);
    cudaGetSymbolAddress((void**)&invs, g_invsrc);
    cudaGetSymbolAddress((void**)&ic1,  g_invc1);
    cudaGetSymbolAddress((void**)&ic2,  g_invc2);
    cudaGetSymbolAddress((void**)&cd,   g_cd);
    cudaGetSymbolAddress((void**)&cs,   g_cs);
    cudaGetSymbolAddress((void**)&cc1,  g_cc1);
    cudaGetSymbolAddress((void**)&cc2,  g_cc2);
    cudaGetSymbolAddress((void**)&od,   g_offs_d);
    cudaGetSymbolAddress((void**)&os,   g_offs_s);
    cudaGetSymbolAddress((void**)&pd,   g_perm_d);
    cudaGetSymbolAddress((void**)&ps,   g_perm_s);
    cudaGetSymbolAddress((void**)&bsum, g_bsum);
    cudaGetSymbolAddress((void**)&bscan,g_bscan);

    float* out   = (float*)d_out;
    float* out_n = out;
    float* out_e = out + (size_t)N * D;
    float* out_c = out + (size_t)(N + E) * D;

    const int TB = 256;
    const int nbd = cdiv(E, 1024);
    const int nbs = cdiv(N, 1024);
    const int nbtot = nbd + nbs;
    const int GT = cdiv(N, 64);

    const float* Wv0 = (const float*)d_in[wi + 0];
    const float* bv0 = (const float*)d_in[wi + 1];
    const float* We0 = (const float*)d_in[wi + 2];
    const float* be0 = (const float*)d_in[wi + 3];
    const float* Wv1 = (const float*)d_in[wi + 8];
    const float* bv1 = (const float*)d_in[wi + 9];
    const float* We1 = (const float*)d_in[wi + 10];
    const float* be1 = (const float*)d_in[wi + 11];

    cudaFuncSetAttribute(kgemm_tc, cudaFuncAttributeMaxDynamicSharedMemorySize, SM_TOT);

    kconvW<<<cdiv(4 * 128 * 16, TB), TB>>>(Wv0, We0, Wv1, We1, Wh);
    kzero_counts<<<cdiv(E + N + 2 * C, TB), TB>>>(cd, cs, cc1, cc2, E, N, C);
    kcountall<<<cdiv(NNZ + E + N, TB), TB>>>(src, dst, he_c, nc_c, cs, cd, cc1, cc2,
                                             NNZ, E, N);
    // G1 = v2e layer 0 (fp32 input) -> T16 raw (launch index 3 for ncu)
    kgemm_tc<<<GT, 256, SM_TOT>>>(x, nullptr, Wh + 0 * 8192, bv0, pa,
                                  nullptr, 0, T16, 0, N);
    kscanA<<<nbtot, 1024>>>(cd, cs, od, os, bsum, nbd, E, N);
    kscanB<<<1, 1024>>>(bsum, bscan, nbd, nbtot, NNZ);
    kscanC<<<nbtot, 1024>>>(od, os, bscan, cd, cs, nbd, E, N, NNZ);
    kfill<<<cdiv(NNZ, TB), TB>>>(src, dst, od, os, cd, cs, pd, ps, NNZ);
    kinvall<<<cdiv(E + N + 2 * C, TB), TB>>>(od, os, cc1, cc2, invd, invs, ic1, ic2,
                                             E, N, C);

    // ---- layer 0 ----
    kagg_e<<<cdiv((long)E * 32, TB), TB>>>(T16, pd, od, invd, pa, E16, nullptr, E);
    kagg_n<<<cdiv((long)N * 32, TB), TB>>>(T16, E16, ps, os, invs, pa, A16, N);
    // G2 = e2v layer 0 -> H16 = prelu(A@We0+be0) fp16
    kgemm_tc<<<GT, 256, SM_TOT>>>(nullptr, A16, Wh + 1 * 8192, be0, pa,
                                  nullptr, 0, H16, 1, N);

    // ---- layer 1 ----
    // G3 = v2e layer 1 -> T16 raw
    kgemm_tc<<<GT, 256, SM_TOT>>>(nullptr, H16, Wh + 2 * 8192, bv1, pa,
                                  nullptr, 0, T16, 0, N);
    kagg_e<<<cdiv((long)E * 32, TB), TB>>>(T16, pd, od, invd, pa, E16, out_e, E);
    kagg_n<<<cdiv((long)N * 32, TB), TB>>>(T16, E16, ps, os, invs, pa, A16, N);
    // G4 = e2v layer 1 -> out_n fp32 prelu + T16 = raw n fp16
    kgemm_tc<<<GT, 256, SM_TOT>>>(nullptr, A16, Wh + 3 * 8192, be1, pa,
                                  out_n, 1, T16, 0, N);

    // components
    kzero4<<<cdiv((long)C * 32, TB), TB>>>((float4*)CE, (long)C * 32);
    kzero4<<<cdiv((long)C * 32, TB), TB>>>((float4*)CN, (long)C * 32);
    kscatterc<<<cdiv((long)E, 8), TB>>>(E16, he_e, he_c, ic1, CE, E);
    kscatterc<<<cdiv((long)N, 8), TB>>>(T16, nc_n, nc_c, ic2, CN, N);
    kgemm2<<<cdiv(C, 64), TB>>>(CE, (const float*)d_in[wi + 12], (const float*)d_in[wi + 13],
                                nullptr, CT, nullptr, pa, C);
    kgemm2<<<cdiv(C, 64), TB>>>(CN, (const float*)d_in[wi + 14], (const float*)d_in[wi + 15],
                                CT, nullptr, out_c, pa, C);
}

// round 11
// speedup vs baseline: 1.8704x; 1.0783x over previous
#include <cuda_runtime.h>
#include <cuda_fp16.h>
#include <cuda_bf16.h>
#include <mma.h>
#include <cstdint>
#include <cstddef>

#define D 128
using namespace nvcuda;

// ---------------- static scratch (device globals) ---------------------------
static __device__ unsigned g_T16[100000 * 64];   // v2e transform output (fp16 rows)
static __device__ unsigned g_A16[100000 * 64];   // aggregated node features (fp16)
static __device__ unsigned g_H16[100000 * 64];   // h = prelu(n) layer 0 (fp16)
static __device__ unsigned g_E16[50000  * 64];   // e fp16 rows
static __device__ float    g_c1 [2048   * 128];
static __device__ float    g_c2 [2048   * 128];
static __device__ float    g_c3 [2048   * 128];
static __device__ unsigned g_Wh [4 * 128 * 64];  // 4 W, fp16 [128][128]
static __device__ float g_invdst[50016];
static __device__ float g_invsrc[100016];
static __device__ float g_invc1[2048];
static __device__ float g_invc2[2048];
static __device__ int   g_cd [50016];
static __device__ int   g_cs [100016];
static __device__ int   g_cc1[2048];
static __device__ int   g_cc2[2048];
static __device__ int   g_offs_d[50024];
static __device__ int   g_offs_s[100024];
static __device__ int   g_perm_d[1600128];
static __device__ int   g_perm_s[1600128];
static __device__ int   g_bsum [1024];
static __device__ int   g_bscan[1024];

// ---------------- helpers ----------------------------------------------------
__device__ __forceinline__ unsigned long long pk2(float v) {
    unsigned long long r; unsigned u = __float_as_uint(v);
    asm("mov.b64 %0, {%1,%1};" : "=l"(r) : "r"(u));
    return r;
}
__device__ __forceinline__ void fma2(unsigned long long& d, unsigned long long a,
                                     unsigned long long b) {
    asm("fma.rn.f32x2 %0, %1, %2, %0;" : "+l"(d) : "l"(a), "l"(b));
}
__device__ __forceinline__ float2 up2(unsigned long long v) {
    unsigned lo, hi;
    asm("mov.b64 {%0,%1}, %2;" : "=r"(lo), "=r"(hi) : "l"(v));
    return make_float2(__uint_as_float(lo), __uint_as_float(hi));
}
__device__ __forceinline__ float prelu1(float v, float a) { return v >= 0.f ? v : a * v; }
__device__ __forceinline__ float4 prelu4(float4 v, float a) {
    return make_float4(prelu1(v.x, a), prelu1(v.y, a), prelu1(v.z, a), prelu1(v.w, a));
}
__device__ __forceinline__ void add4(float4& a, float4 b) {
    a.x += b.x; a.y += b.y; a.z += b.z; a.w += b.w;
}
// accumulate 8 halves (uint4) into two float4s
__device__ __forceinline__ void addh8(float4& a, float4& b, uint4 v) {
    __half2 h0 = *reinterpret_cast<__half2*>(&v.x);
    __half2 h1 = *reinterpret_cast<__half2*>(&v.y);
    __half2 h2 = *reinterpret_cast<__half2*>(&v.z);
    __half2 h3 = *reinterpret_cast<__half2*>(&v.w);
    float2 f0 = __half22float2(h0), f1 = __half22float2(h1);
    float2 f2 = __half22float2(h2), f3 = __half22float2(h3);
    a.x += f0.x; a.y += f0.y; a.z += f1.x; a.w += f1.y;
    b.x += f2.x; b.y += f2.y; b.z += f3.x; b.w += f3.y;
}
__device__ __forceinline__ uint2 h4(float4 v) {
    __half2 h0 = __float22half2_rn(make_float2(v.x, v.y));
    __half2 h1 = __float22half2_rn(make_float2(v.z, v.w));
    uint2 r;
    r.x = *reinterpret_cast<unsigned*>(&h0);
    r.y = *reinterpret_cast<unsigned*>(&h1);
    return r;
}
__device__ __forceinline__ void cpasync16(void* smem_dst, const void* gsrc) {
    unsigned sa = (unsigned)__cvta_generic_to_shared(smem_dst);
    asm volatile("cp.async.cg.shared.global [%0], [%1], 16;" :: "r"(sa), "l"(gsrc));
}

// ---------------- W convert: Wh[w] = fp16 [128][128] -------------------------
__global__ void kconvW(const float* __restrict__ W0, const float* __restrict__ W1,
                       const float* __restrict__ W2, const float* __restrict__ W3,
                       unsigned* __restrict__ Wh) {
    int idx = blockIdx.x * blockDim.x + threadIdx.x;
    if (idx >= 4 * 128 * 16) return;
    int w = idx >> 11;
    int rem = idx & 2047;
    int kk = rem >> 4, g = rem & 15;
    const float* W = (w == 0) ? W0 : (w == 1) ? W1 : (w == 2) ? W2 : W3;
    float4 x0 = __ldg((const float4*)(W + (size_t)kk * D + g * 8));
    float4 x1 = __ldg((const float4*)(W + (size_t)kk * D + g * 8 + 4));
    uint2 p0 = h4(x0), p1 = h4(x1);
    ((uint4*)(Wh + (size_t)w * 128 * 64))[kk * 16 + g] = make_uint4(p0.x, p0.y, p1.x, p1.y);
}

// ---------------- WMMA GEMM: Y[M x 128] = X @ W + b (fp16) -------------------
// CTA 128x128, 16 warps (512 thr), warp tile 32x32, 2 CTAs/SM, cp.async staging.
#define AS_LD 136
#define BS_LD 136
#define CS_LD 132
#define SM_AS  (128 * AS_LD * 2)              // 34816
#define SM_TOT (SM_AS + 128 * BS_LD * 2)      // 69632

__global__ __launch_bounds__(512, 2) void kgemm_tc(const float* __restrict__ X32,
                                                   const unsigned* __restrict__ X16,
                                                   const unsigned* __restrict__ Wh,
                                                   const float* __restrict__ bias,
                                                   const float* __restrict__ pa,
                                                   float* __restrict__ out_f32,
                                                   int prelu_f32,
                                                   unsigned* __restrict__ out_h16,
                                                   int prelu_h16, int M) {
    extern __shared__ char smem[];
    __half* As = (__half*)smem;                  // 128 x AS_LD
    __half* Bs = (__half*)(smem + SM_AS);        // 128 x BS_LD
    float* Cs = (float*)smem;                    // reuse smem: 128 x CS_LD
    const int tid = threadIdx.x;
    const int wid = tid >> 5;
    const int m0 = blockIdx.x * 128;

    // stage A (4 chunks/thread)
    if (X16) {
#pragma unroll
        for (int it = 0; it < 4; it++) {
            int idx = tid + it * 512;
            int r = idx >> 4, g = idx & 15;
            int gr = m0 + r;
            void* dst = As + (size_t)r * AS_LD + g * 8;
            if (gr < M) cpasync16(dst, (const uint4*)(X16 + (size_t)gr * 64) + g);
            else        *(uint4*)dst = make_uint4(0, 0, 0, 0);
        }
    } else {
#pragma unroll
        for (int it = 0; it < 4; it++) {
            int idx = tid + it * 512;
            int r = idx >> 4, g = idx & 15;
            int gr = m0 + r;
            float4 x0 = make_float4(0.f, 0.f, 0.f, 0.f), x1 = x0;
            if (gr < M) {
                x0 = __ldg((const float4*)(X32 + (size_t)gr * D + g * 8));
                x1 = __ldg((const float4*)(X32 + (size_t)gr * D + g * 8 + 4));
            }
            uint2 p0 = h4(x0), p1 = h4(x1);
            *(uint4*)(As + (size_t)r * AS_LD + g * 8) = make_uint4(p0.x, p0.y, p1.x, p1.y);
        }
    }
    // stage B (4 chunks/thread)
#pragma unroll
    for (int it = 0; it < 4; it++) {
        int idx = tid + it * 512;
        int kk = idx >> 4, g = idx & 15;
        cpasync16(Bs + (size_t)kk * BS_LD + g * 8, (const uint4*)Wh + kk * 16 + g);
    }
    asm volatile("cp.async.commit_group;" ::: "memory");
    asm volatile("cp.async.wait_group 0;" ::: "memory");
    __syncthreads();

    // 16 warps: 4 m-strips x 4 n-strips, warp tile 32x32
    const int row0 = (wid & 3) * 32;
    const int n0   = (wid >> 2) * 32;
    wmma::fragment<wmma::accumulator, 16, 16, 16, float> acc[2][2];
#pragma unroll
    for (int i = 0; i < 2; i++)
#pragma unroll
        for (int j = 0; j < 2; j++) wmma::fill_fragment(acc[i][j], 0.f);

#pragma unroll
    for (int k = 0; k < 8; k++) {
        wmma::fragment<wmma::matrix_a, 16, 16, 16, __half, wmma::row_major> af[2];
        wmma::fragment<wmma::matrix_b, 16, 16, 16, __half, wmma::row_major> bf[2];
#pragma unroll
        for (int i = 0; i < 2; i++)
            wmma::load_matrix_sync(af[i], As + (size_t)(row0 + i * 16) * AS_LD + k * 16, AS_LD);
#pragma unroll
        for (int j = 0; j < 2; j++)
            wmma::load_matrix_sync(bf[j], Bs + (size_t)(k * 16) * BS_LD + n0 + j * 16, BS_LD);
#pragma unroll
        for (int i = 0; i < 2; i++)
#pragma unroll
            for (int j = 0; j < 2; j++)
                wmma::mma_sync(acc[i][j], af[i], bf[j], acc[i][j]);
    }
    __syncthreads();
#pragma unroll
    for (int i = 0; i < 2; i++)
#pragma unroll
        for (int j = 0; j < 2; j++)
            wmma::store_matrix_sync(Cs + (size_t)(row0 + i * 16) * CS_LD + n0 + j * 16,
                                    acc[i][j], CS_LD, wmma::mem_row_major);
    __syncthreads();

    // epilogue: each thread one quarter-row (32 cols)
    {
        int r = tid >> 2, h = (tid & 3) * 32;
        int gr = m0 + r;
        if (gr < M) {
            float a = __ldg(pa);
#pragma unroll
            for (int q = 0; q < 8; q++) {
                int c = h + q * 4;
                float4 v = *(float4*)(Cs + (size_t)r * CS_LD + c);
                float4 bb = __ldg((const float4*)(bias + c));
                add4(v, bb);
                if (out_h16) {
                    float4 o = prelu_h16 ? prelu4(v, a) : v;
                    *(uint2*)(out_h16 + (size_t)gr * 64 + c / 2) = h4(o);
                }
                if (out_f32) {
                    float4 o = prelu_f32 ? prelu4(v, a) : v;
                    *(float4*)(out_f32 + (size_t)gr * D + c) = o;
                }
            }
        }
    }
}

// ---------------- setup kernels ----------------------------------------------
__global__ void kzero_counts(int* cd, int* cs, int* cc1, int* cc2, int E, int N, int C) {
    int i = blockIdx.x * blockDim.x + threadIdx.x;
    int tot = E + N + 2 * C;
    if (i >= tot) return;
    if (i < E) cd[i] = 0;
    else if (i < E + N) cs[i - E] = 0;
    else if (i < E + N + C) cc1[i - E - N] = 0;
    else cc2[i - E - N - C] = 0;
}

__global__ void kcountall(const int* __restrict__ src, const int* __restrict__ dst,
                          const int* __restrict__ he_c, const int* __restrict__ nc_c,
                          int* cs, int* cd, int* cc1, int* cc2,
                          int nnz, int E, int N) {
    int i = blockIdx.x * blockDim.x + threadIdx.x;
    if (i < nnz) {
        atomicAdd(&cd[dst[i]], 1);
        atomicAdd(&cs[src[i]], 1);
    } else if (i < nnz + E) {
        atomicAdd(&cc1[he_c[i - nnz]], 1);
    } else if (i < nnz + E + N) {
        atomicAdd(&cc2[nc_c[i - nnz - E]], 1);
    }
}

__global__ __launch_bounds__(1024) void kscanA(const int* __restrict__ cd,
                                               const int* __restrict__ cs,
                                               int* od, int* os, int* bsum,
                                               int nbd, int E, int N) {
    __shared__ int sh[1024];
    const int b = blockIdx.x, t = threadIdx.x;
    const bool isD = b < nbd;
    const int* in = isD ? cd : cs;
    int* out = isD ? od : os;
    const int n = isD ? E : N;
    const int i = (isD ? b : b - nbd) * 1024 + t;
    int v = (i < n) ? in[i] : 0;
    sh[t] = v;
    __syncthreads();
    for (int off = 1; off < 1024; off <<= 1) {
        int x = (t >= off) ? sh[t - off] : 0;
        __syncthreads();
        sh[t] += x;
        __syncthreads();
    }
    if (i < n) out[i] = sh[t] - v;
    if (t == 1023) bsum[b] = sh[1023];
}

__global__ __launch_bounds__(1024) void kscanB(const int* __restrict__ bsum,
                                               int* bscan, int nbd, int nbtot, int nnz) {
    __shared__ int sh[1024];
    int t = threadIdx.x;
    int v = (t < nbtot) ? bsum[t] : 0;
    sh[t] = v;
    __syncthreads();
    for (int off = 1; off < 1024; off <<= 1) {
        int x = (t >= off) ? sh[t - off] : 0;
        __syncthreads();
        sh[t] += x;
        __syncthreads();
    }
    if (t < nbtot) {
        int excl = sh[t] - v;
        bscan[t] = (t >= nbd) ? excl - nnz : excl;
    }
}

__global__ __launch_bounds__(1024) void kscanC(int* od, int* os,
                                               const int* __restrict__ bscan,
                                               int* cd, int* cs,
                                               int nbd, int E, int N, int nnz) {
    const int b = blockIdx.x, t = threadIdx.x;
    const bool isD = b < nbd;
    const int i = (isD ? b : b - nbd) * 1024 + t;
    if (isD) {
        if (i < E) { od[i] += bscan[b]; cd[i] = 0; }
        if (b == 0 && t == 0) od[E] = nnz;
    } else {
        if (i < N) { os[i] += bscan[b]; cs[i] = 0; }
        if (i == 0) os[N] = nnz;
    }
}

__global__ void kfill(const int* __restrict__ src, const int* __restrict__ dst,
                      const int* __restrict__ od, const int* __restrict__ os,
                      int* cur_d, int* cur_s, int* perm_d, int* perm_s, int nnz) {
    int k = blockIdx.x * blockDim.x + threadIdx.x;
    if (k >= nnz) return;
    int s = __ldg(&src[k]), d = __ldg(&dst[k]);
    int pd = atomicAdd(&cur_d[d], 1);
    perm_d[__ldg(&od[d]) + pd] = s;
    int ps = atomicAdd(&cur_s[s], 1);
    perm_s[__ldg(&os[s]) + ps] = d;
}

__global__ void kinvall(const int* __restrict__ od, const int* __restrict__ os,
                        const int* __restrict__ cc1, const int* __restrict__ cc2,
                        float* invd, float* invs, float* ic1, float* ic2,
                        int E, int N, int C) {
    int i = blockIdx.x * blockDim.x + threadIdx.x;
    if (i < E) {
        int c = od[i + 1] - od[i];
        invd[i] = 1.f / (float)(c > 0 ? c : 1);
    } else if (i < E + N) {
        int j = i - E;
        int c = os[j + 1] - os[j] + 1;
        invs[j] = 1.f / (float)c;
    } else if (i < E + N + C) {
        int c = cc1[i - E - N];
        ic1[i - E - N] = 1.f / (float)(c > 0 ? c : 1);
    } else if (i < E + N + 2 * C) {
        int c = cc2[i - E - N - C];
        ic2[i - E - N - C] = 1.f / (float)(c > 0 ? c : 1);
    }
}

__global__ void kzero4(float4* p, long n4) {
    long i = (long)blockIdx.x * blockDim.x + threadIdx.x;
    if (i < n4) p[i] = make_float4(0.f, 0.f, 0.f, 0.f);
}

// ---------------- SIMT GEMM (small C-row GEMMs) ------------------------------
__global__ __launch_bounds__(256) void kgemm2(const float* __restrict__ X,
                                              const float* __restrict__ W,
                                              const float* __restrict__ b,
                                              const float* __restrict__ addin,
                                              float* __restrict__ Yraw,
                                              float* __restrict__ Ypre,
                                              const float* __restrict__ pa, int M) {
    __shared__ float As[64][128];
    const int m0 = blockIdx.x * 64;
    const int t = threadIdx.x;
    {
        const int c4 = t & 31;
        const int r0 = t >> 5;
#pragma unroll
        for (int s = 0; s < 8; s++) {
            int r = r0 + 8 * s;
            int gr = m0 + r;
            float4 v = make_float4(0.f, 0.f, 0.f, 0.f);
            if (gr < M) v = ((const float4*)(X + (size_t)gr * D))[c4];
            ((float4*)(&As[r][0]))[c4] = v;
        }
    }
    __syncthreads();
    const int cg = (t & 15) * 8;
    const int rg = (t >> 4) * 4;
    unsigned long long acc[4][4];
#pragma unroll
    for (int i = 0; i < 4; i++)
#pragma unroll
        for (int j = 0; j < 4; j++) acc[i][j] = 0ULL;
#pragma unroll 4
    for (int k = 0; k < D; k += 4) {
        float4 a[4];
#pragma unroll
        for (int i = 0; i < 4; i++) a[i] = *(const float4*)&As[rg + i][k];
#pragma unroll
        for (int kk = 0; kk < 4; kk++) {
            const ulonglong2 w0 = *reinterpret_cast<const ulonglong2*>(&W[(k + kk) * D + cg]);
            const ulonglong2 w1 = *reinterpret_cast<const ulonglong2*>(&W[(k + kk) * D + cg + 4]);
#pragma unroll
            for (int i = 0; i < 4; i++) {
                float av = (kk == 0) ? a[i].x : (kk == 1) ? a[i].y
                         : (kk == 2) ? a[i].z : a[i].w;
                unsigned long long av2 = pk2(av);
                fma2(acc[i][0], av2, w0.x);
                fma2(acc[i][1], av2, w0.y);
                fma2(acc[i][2], av2, w1.x);
                fma2(acc[i][3], av2, w1.y);
            }
        }
    }
    const float4 b0 = __ldg((const float4*)&b[cg]);
    const float4 b1 = __ldg((const float4*)&b[cg + 4]);
    const float a = __ldg(pa);
#pragma unroll
    for (int i = 0; i < 4; i++) {
        int gr = m0 + rg + i;
        if (gr >= M) continue;
        float2 p0 = up2(acc[i][0]), p1 = up2(acc[i][1]);
        float2 p2 = up2(acc[i][2]), p3 = up2(acc[i][3]);
        float4 o0 = make_float4(p0.x + b0.x, p0.y + b0.y, p1.x + b0.z, p1.y + b0.w);
        float4 o1 = make_float4(p2.x + b1.x, p2.y + b1.y, p3.x + b1.z, p3.y + b1.w);
        if (addin) {
            const float4* ar = (const float4*)(addin + (size_t)gr * D);
            add4(o0, ar[cg / 4]); add4(o1, ar[cg / 4 + 1]);
        }
        if (Yraw) {
            float4* yr = (float4*)(Yraw + (size_t)gr * D);
            yr[cg / 4] = o0; yr[cg / 4 + 1] = o1;
        }
        if (Ypre) {
            float4* yp = (float4*)(Ypre + (size_t)gr * D);
            yp[cg / 4] = prelu4(o0, a); yp[cg / 4 + 1] = prelu4(o1, a);
        }
    }
}

// ---------------- CSR aggregation (HALF-warp per segment, uint4 gather) ------
__global__ __launch_bounds__(256) void kagg_e(const unsigned* __restrict__ T16,
                                              const int* __restrict__ perm,
                                              const int* __restrict__ offs,
                                              const float* __restrict__ invd,
                                              const float* __restrict__ pa,
                                              unsigned* __restrict__ EB16,
                                              float* __restrict__ out_e, int E) {
    int seg = (blockIdx.x * blockDim.x + threadIdx.x) >> 4;
    int l = threadIdx.x & 15;
    if (seg >= E) return;
    int beg = __ldg(&offs[seg]), end = __ldg(&offs[seg + 1]);
    float4 s0 = {0,0,0,0}, s1 = {0,0,0,0}, t0 = {0,0,0,0}, t1 = {0,0,0,0};
    float4 u0 = {0,0,0,0}, u1 = {0,0,0,0}, v0 = {0,0,0,0}, v1 = {0,0,0,0};
    int p = beg;
    for (; p + 4 <= end; p += 4) {
        int r0 = __ldg(&perm[p]),     r1 = __ldg(&perm[p + 1]);
        int r2 = __ldg(&perm[p + 2]), r3 = __ldg(&perm[p + 3]);
        addh8(s0, s1, __ldg((const uint4*)(T16 + (size_t)r0 * 64) + l));
        addh8(t0, t1, __ldg((const uint4*)(T16 + (size_t)r1 * 64) + l));
        addh8(u0, u1, __ldg((const uint4*)(T16 + (size_t)r2 * 64) + l));
        addh8(v0, v1, __ldg((const uint4*)(T16 + (size_t)r3 * 64) + l));
    }
    for (; p < end; p++)
        addh8(s0, s1, __ldg((const uint4*)(T16 + (size_t)__ldg(&perm[p]) * 64) + l));
    add4(s0, t0); add4(u0, v0); add4(s0, u0);
    add4(s1, t1); add4(u1, v1); add4(s1, u1);
    float iv = __ldg(&invd[seg]);
    float a = __ldg(pa);
    s0.x *= iv; s0.y *= iv; s0.z *= iv; s0.w *= iv;
    s1.x *= iv; s1.y *= iv; s1.z *= iv; s1.w *= iv;
    float4 r0 = prelu4(s0, a), r1 = prelu4(s1, a);
    uint2 q0 = h4(r0), q1 = h4(r1);
    ((uint4*)(EB16 + (size_t)seg * 64))[l] = make_uint4(q0.x, q0.y, q1.x, q1.y);
    if (out_e) {
        ((float4*)out_e)[(size_t)seg * 32 + l * 2]     = r0;
        ((float4*)out_e)[(size_t)seg * 32 + l * 2 + 1] = r1;
    }
}

// A16[i] = fp16( (sum EB16[perm[p]] + prelu(T16[i])) * invs[i] )
__global__ __launch_bounds__(256) void kagg_n(const unsigned* __restrict__ T16,
                                              const unsigned* __restrict__ EB16,
                                              const int* __restrict__ perm,
                                              const int* __restrict__ offs,
                                              const float* __restrict__ invs,
                                              const float* __restrict__ pa,
                                              unsigned* __restrict__ A16, int N) {
    int seg = (blockIdx.x * blockDim.x + threadIdx.x) >> 4;
    int l = threadIdx.x & 15;
    if (seg >= N) return;
    int beg = __ldg(&offs[seg]), end = __ldg(&offs[seg + 1]);
    float4 s0 = {0,0,0,0}, s1 = {0,0,0,0}, t0 = {0,0,0,0}, t1 = {0,0,0,0};
    float4 u0 = {0,0,0,0}, u1 = {0,0,0,0}, v0 = {0,0,0,0}, v1 = {0,0,0,0};
    int p = beg;
    for (; p + 4 <= end; p += 4) {
        int r0 = __ldg(&perm[p]),     r1 = __ldg(&perm[p + 1]);
        int r2 = __ldg(&perm[p + 2]), r3 = __ldg(&perm[p + 3]);
        addh8(s0, s1, __ldg((const uint4*)(EB16 + (size_t)r0 * 64) + l));
        addh8(t0, t1, __ldg((const uint4*)(EB16 + (size_t)r1 * 64) + l));
        addh8(u0, u1, __ldg((const uint4*)(EB16 + (size_t)r2 * 64) + l));
        addh8(v0, v1, __ldg((const uint4*)(EB16 + (size_t)r3 * 64) + l));
    }
    for (; p < end; p++)
        addh8(s0, s1, __ldg((const uint4*)(EB16 + (size_t)__ldg(&perm[p]) * 64) + l));
    add4(s0, t0); add4(u0, v0); add4(s0, u0);
    add4(s1, t1); add4(u1, v1); add4(s1, u1);
    float a = __ldg(pa);
    // analytic self loop: + prelu(T16[seg])
    float4 w0 = {0,0,0,0}, w1 = {0,0,0,0};
    addh8(w0, w1, __ldg((const uint4*)(T16 + (size_t)seg * 64) + l));
    add4(s0, prelu4(w0, a));
    add4(s1, prelu4(w1, a));
    float iv = __ldg(&invs[seg]);
    s0.x *= iv; s0.y *= iv; s0.z *= iv; s0.w *= iv;
    s1.x *= iv; s1.y *= iv; s1.z *= iv; s1.w *= iv;
    uint2 q0 = h4(s0), q1 = h4(s1);
    ((uint4*)(A16 + (size_t)seg * 64))[l] = make_uint4(q0.x, q0.y, q1.x, q1.y);
}

// ---------------- component scatter (HALF-warp per incidence) ----------------
__device__ __forceinline__ void red4(float* a, float4 v) {
    asm volatile("red.global.add.v4.f32 [%0], {%1,%2,%3,%4};"
                 :: "l"(a), "f"(v.x), "f"(v.y), "f"(v.z), "f"(v.w)
                 : "memory");
}

__global__ void kscatterc(const unsigned* __restrict__ P16, const int* __restrict__ rows,
                          const int* __restrict__ comp, const float* __restrict__ inv,
                          float* __restrict__ csum, int n) {
    int idx = (blockIdx.x * blockDim.x + threadIdx.x) >> 4;
    int l = threadIdx.x & 15;
    if (idx >= n) return;
    int r = __ldg(&rows[idx]);
    int c = __ldg(&comp[idx]);
    float sc = __ldg(&inv[c]);
    float4 v0 = {0,0,0,0}, v1 = {0,0,0,0};
    addh8(v0, v1, __ldg((const uint4*)(P16 + (size_t)r * 64) + l));
    v0.x *= sc; v0.y *= sc; v0.z *= sc; v0.w *= sc;
    v1.x *= sc; v1.y *= sc; v1.z *= sc; v1.w *= sc;
    red4(csum + (size_t)c * D + l * 8,     v0);
    red4(csum + (size_t)c * D + l * 8 + 4, v1);
}

// ---------------- host driver ------------------------------------------------
static inline int cdiv(long a, long b) { return (int)((a + b - 1) / b); }

extern "C" void kernel_launch(void* const* d_in, const int* in_sizes, int n_in,
                              void* d_out, int out_size) {
    const float* x   = (const float*)d_in[0];
    const int*   hei = (const int*)d_in[1];
    const int*   hci = (const int*)d_in[2];
    const int*   nci = (const int*)d_in[3];

    const int NNZ = in_sizes[1] / 2;
    const int E   = in_sizes[2] / 2;
    const int N   = in_sizes[0] / D;
    const int C   = out_size / D - N - E;

    int wi = -1;
    for (int i = 4; i < n_in; i++) {
        if (in_sizes[i] == D * D) { wi = i; break; }
    }
    const float* pa = (const float*)d_in[wi - 1];

    const int* src  = hei;
    const int* dst  = hei + NNZ;
    const int* he_e = hci;
    const int* he_c = hci + E;
    const int* nc_n = nci;
    const int* nc_c = nci + N;

    float *CE, *CN, *CT, *invd, *invs, *ic1, *ic2;
    unsigned *T16, *A16, *H16, *E16, *Wh;
    int *cd, *cs, *cc1, *cc2, *od, *os, *pd, *ps, *bsum, *bscan;
    cudaGetSymbolAddress((void**)&T16,  g_T16);
    cudaGetSymbolAddress((void**)&A16,  g_A16);
    cudaGetSymbolAddress((void**)&H16,  g_H16);
    cudaGetSymbolAddress((void**)&E16,  g_E16);
    cudaGetSymbolAddress((void**)&CE,   g_c1);
    cudaGetSymbolAddress((void**)&CN,   g_c2);
    cudaGetSymbolAddress((void**)&CT,   g_c3);
    cudaGetSymbolAddress((void**)&Wh,   g_Wh);
    cudaGetSymbolAddress((void**)&invd, g_invdst);
    cudaGetSymbolAddress((void**)&invs, g_invsrc);
    cudaGetSymbolAddress((void**)&ic1,  g_invc1);
    cudaGetSymbolAddress((void**)&ic2,  g_invc2);
    cudaGetSymbolAddress((void**)&cd,   g_cd);
    cudaGetSymbolAddress((void**)&cs,   g_cs);
    cudaGetSymbolAddress((void**)&cc1,  g_cc1);
    cudaGetSymbolAddress((void**)&cc2,  g_cc2);
    cudaGetSymbolAddress((void**)&od,   g_offs_d);
    cudaGetSymbolAddress((void**)&os,   g_offs_s);
    cudaGetSymbolAddress((void**)&pd,   g_perm_d);
    cudaGetSymbolAddress((void**)&ps,   g_perm_s);
    cudaGetSymbolAddress((void**)&bsum, g_bsum);
    cudaGetSymbolAddress((void**)&bscan,g_bscan);

    float* out   = (float*)d_out;
    float* out_n = out;
    float* out_e = out + (size_t)N * D;
    float* out_c = out + (size_t)(N + E) * D;

    const int TB = 256;
    const int nbd = cdiv(E, 1024);
    const int nbs = cdiv(N, 1024);
    const int nbtot = nbd + nbs;
    const int GT = cdiv(N, 128);

    const float* Wv0 = (const float*)d_in[wi + 0];
    const float* bv0 = (const float*)d_in[wi + 1];
    const float* We0 = (const float*)d_in[wi + 2];
    const float* be0 = (const float*)d_in[wi + 3];
    const float* Wv1 = (const float*)d_in[wi + 8];
    const float* bv1 = (const float*)d_in[wi + 9];
    const float* We1 = (const float*)d_in[wi + 10];
    const float* be1 = (const float*)d_in[wi + 11];

    cudaFuncSetAttribute(kgemm_tc, cudaFuncAttributeMaxDynamicSharedMemorySize, SM_TOT);

    kconvW<<<cdiv(4 * 128 * 16, TB), TB>>>(Wv0, We0, Wv1, We1, Wh);
    kzero_counts<<<cdiv(E + N + 2 * C, TB), TB>>>(cd, cs, cc1, cc2, E, N, C);
    kcountall<<<cdiv(NNZ + E + N, TB), TB>>>(src, dst, he_c, nc_c, cs, cd, cc1, cc2,
                                             NNZ, E, N);
    // G1 = v2e layer 0 (fp32 input) -> T16 raw (launch index 3 for ncu)
    kgemm_tc<<<GT, 512, SM_TOT>>>(x, nullptr, Wh + 0 * 8192, bv0, pa,
                                  nullptr, 0, T16, 0, N);
    kscanA<<<nbtot, 1024>>>(cd, cs, od, os, bsum, nbd, E, N);
    kscanB<<<1, 1024>>>(bsum, bscan, nbd, nbtot, NNZ);
    kscanC<<<nbtot, 1024>>>(od, os, bscan, cd, cs, nbd, E, N, NNZ);
    kfill<<<cdiv(NNZ, TB), TB>>>(src, dst, od, os, cd, cs, pd, ps, NNZ);
    kinvall<<<cdiv(E + N + 2 * C, TB), TB>>>(od, os, cc1, cc2, invd, invs, ic1, ic2,
                                             E, N, C);

    // ---- layer 0 ----
    kagg_e<<<cdiv((long)E * 16, TB), TB>>>(T16, pd, od, invd, pa, E16, nullptr, E);
    kagg_n<<<cdiv((long)N * 16, TB), TB>>>(T16, E16, ps, os, invs, pa, A16, N);
    // G2 = e2v layer 0 -> H16 = prelu(A@We0+be0) fp16
    kgemm_tc<<<GT, 512, SM_TOT>>>(nullptr, A16, Wh + 1 * 8192, be0, pa,
                                  nullptr, 0, H16, 1, N);

    // ---- layer 1 ----
    kgemm_tc<<<GT, 512, SM_TOT>>>(nullptr, H16, Wh + 2 * 8192, bv1, pa,
                                  nullptr, 0, T16, 0, N);
    kagg_e<<<cdiv((long)E * 16, TB), TB>>>(T16, pd, od, invd, pa, E16, out_e, E);
    kagg_n<<<cdiv((long)N * 16, TB), TB>>>(T16, E16, ps, os, invs, pa, A16, N);
    // G4 = e2v layer 1 -> out_n fp32 prelu + T16 = raw n fp16
    kgemm_tc<<<GT, 512, SM_TOT>>>(nullptr, A16, Wh + 3 * 8192, be1, pa,
                                  out_n, 1, T16, 0, N);

    // components
    kzero4<<<cdiv((long)C * 32, TB), TB>>>((float4*)CE, (long)C * 32);
    kzero4<<<cdiv((long)C * 32, TB), TB>>>((float4*)CN, (long)C * 32);
    kscatterc<<<cdiv((long)E * 16, TB), TB>>>(E16, he_e, he_c, ic1, CE, E);
    kscatterc<<<cdiv((long)N * 16, TB), TB>>>(T16, nc_n, nc_c, ic2, CN, N);
    kgemm2<<<cdiv(C, 64), TB>>>(CE, (const float*)d_in[wi + 12], (const float*)d_in[wi + 13],
                                nullptr, CT, nullptr, pa, C);
    kgemm2<<<cdiv(C, 64), TB>>>(CN, (const float*)d_in[wi + 14], (const float*)d_in[wi + 15],
                                CT, nullptr, out_c, pa, C);
}

// round 12
// speedup vs baseline: 2.1455x; 1.1471x over previous
#include <cuda_runtime.h>
#include <cuda_fp16.h>
#include <cuda_bf16.h>
#include <mma.h>
#include <cstdint>
#include <cstddef>

#define D 128
using namespace nvcuda;

// ---------------- static scratch (device globals) ---------------------------
static __device__ unsigned g_T16[100000 * 64];   // v2e transform output (fp16 rows)
static __device__ unsigned g_A16[100000 * 64];   // aggregated node features (fp16)
static __device__ unsigned g_H16[100000 * 64];   // h = prelu(n) layer 0 (fp16)
static __device__ unsigned g_E16[50000  * 64];   // e fp16 rows
static __device__ float    g_c1 [2048   * 128];
static __device__ float    g_c2 [2048   * 128];
static __device__ float    g_c3 [2048   * 128];
static __device__ unsigned g_Wh [4 * 128 * 64];  // 4 W, fp16 [128][128]
static __device__ float g_invdst[50016];
static __device__ float g_invsrc[100016];
static __device__ float g_invc1[2048];
static __device__ float g_invc2[2048];
static __device__ int   g_cd [50016];
static __device__ int   g_cs [100016];
static __device__ int   g_cc1[2048];
static __device__ int   g_cc2[2048];
static __device__ int   g_offs_d[50024];
static __device__ int   g_offs_s[100024];
static __device__ int   g_perm_d[1600128];
static __device__ int   g_perm_s[1600128];
static __device__ int   g_bsum [1024];
static __device__ int   g_bscan[1024];

// ---------------- helpers ----------------------------------------------------
__device__ __forceinline__ unsigned long long pk2(float v) {
    unsigned long long r; unsigned u = __float_as_uint(v);
    asm("mov.b64 %0, {%1,%1};" : "=l"(r) : "r"(u));
    return r;
}
__device__ __forceinline__ void fma2(unsigned long long& d, unsigned long long a,
                                     unsigned long long b) {
    asm("fma.rn.f32x2 %0, %1, %2, %0;" : "+l"(d) : "l"(a), "l"(b));
}
__device__ __forceinline__ float2 up2(unsigned long long v) {
    unsigned lo, hi;
    asm("mov.b64 {%0,%1}, %2;" : "=r"(lo), "=r"(hi) : "l"(v));
    return make_float2(__uint_as_float(lo), __uint_as_float(hi));
}
__device__ __forceinline__ float prelu1(float v, float a) { return v >= 0.f ? v : a * v; }
__device__ __forceinline__ float4 prelu4(float4 v, float a) {
    return make_float4(prelu1(v.x, a), prelu1(v.y, a), prelu1(v.z, a), prelu1(v.w, a));
}
__device__ __forceinline__ void add4(float4& a, float4 b) {
    a.x += b.x; a.y += b.y; a.z += b.z; a.w += b.w;
}
// accumulate 8 halves (uint4) into two float4s
__device__ __forceinline__ void addh8(float4& a, float4& b, uint4 v) {
    __half2 h0 = *reinterpret_cast<__half2*>(&v.x);
    __half2 h1 = *reinterpret_cast<__half2*>(&v.y);
    __half2 h2 = *reinterpret_cast<__half2*>(&v.z);
    __half2 h3 = *reinterpret_cast<__half2*>(&v.w);
    float2 f0 = __half22float2(h0), f1 = __half22float2(h1);
    float2 f2 = __half22float2(h2), f3 = __half22float2(h3);
    a.x += f0.x; a.y += f0.y; a.z += f1.x; a.w += f1.y;
    b.x += f2.x; b.y += f2.y; b.z += f3.x; b.w += f3.y;
}
__device__ __forceinline__ uint2 h4(float4 v) {
    __half2 h0 = __float22half2_rn(make_float2(v.x, v.y));
    __half2 h1 = __float22half2_rn(make_float2(v.z, v.w));
    uint2 r;
    r.x = *reinterpret_cast<unsigned*>(&h0);
    r.y = *reinterpret_cast<unsigned*>(&h1);
    return r;
}
__device__ __forceinline__ void cpasync16(void* smem_dst, const void* gsrc) {
    unsigned sa = (unsigned)__cvta_generic_to_shared(smem_dst);
    asm volatile("cp.async.cg.shared.global [%0], [%1], 16;" :: "r"(sa), "l"(gsrc));
}

// ---------------- W convert: Wh[w] = fp16 [128][128] -------------------------
__global__ void kconvW(const float* __restrict__ W0, const float* __restrict__ W1,
                       const float* __restrict__ W2, const float* __restrict__ W3,
                       unsigned* __restrict__ Wh) {
    int idx = blockIdx.x * blockDim.x + threadIdx.x;
    if (idx >= 4 * 128 * 16) return;
    int w = idx >> 11;
    int rem = idx & 2047;
    int kk = rem >> 4, g = rem & 15;
    const float* W = (w == 0) ? W0 : (w == 1) ? W1 : (w == 2) ? W2 : W3;
    float4 x0 = __ldg((const float4*)(W + (size_t)kk * D + g * 8));
    float4 x1 = __ldg((const float4*)(W + (size_t)kk * D + g * 8 + 4));
    uint2 p0 = h4(x0), p1 = h4(x1);
    ((uint4*)(Wh + (size_t)w * 128 * 64))[kk * 16 + g] = make_uint4(p0.x, p0.y, p1.x, p1.y);
}

// ---------------- WMMA GEMM: Y[M x 128] = X @ W + b (fp16) -------------------
// CTA 128x128, 16 warps (512 thr), warp tile 32x32, 2 CTAs/SM, cp.async staging.
// Epilogue directly from accumulator fragments (sm_80+ HMMA layout).
#define AS_LD 136
#define BS_LD 136
#define SM_AS  (128 * AS_LD * 2)              // 34816
#define SM_TOT (SM_AS + 128 * BS_LD * 2)      // 69632

__global__ __launch_bounds__(512, 2) void kgemm_tc(const float* __restrict__ X32,
                                                   const unsigned* __restrict__ X16,
                                                   const unsigned* __restrict__ Wh,
                                                   const float* __restrict__ bias,
                                                   const float* __restrict__ pa,
                                                   float* __restrict__ out_f32,
                                                   int prelu_f32,
                                                   unsigned* __restrict__ out_h16,
                                                   int prelu_h16, int M) {
    extern __shared__ char smem[];
    __half* As = (__half*)smem;                  // 128 x AS_LD
    __half* Bs = (__half*)(smem + SM_AS);        // 128 x BS_LD
    const int tid = threadIdx.x;
    const int wid = tid >> 5;
    const int m0 = blockIdx.x * 128;

    // stage A (4 chunks/thread)
    if (X16) {
#pragma unroll
        for (int it = 0; it < 4; it++) {
            int idx = tid + it * 512;
            int r = idx >> 4, g = idx & 15;
            int gr = m0 + r;
            void* dst = As + (size_t)r * AS_LD + g * 8;
            if (gr < M) cpasync16(dst, (const uint4*)(X16 + (size_t)gr * 64) + g);
            else        *(uint4*)dst = make_uint4(0, 0, 0, 0);
        }
    } else {
#pragma unroll
        for (int it = 0; it < 4; it++) {
            int idx = tid + it * 512;
            int r = idx >> 4, g = idx & 15;
            int gr = m0 + r;
            float4 x0 = make_float4(0.f, 0.f, 0.f, 0.f), x1 = x0;
            if (gr < M) {
                x0 = __ldg((const float4*)(X32 + (size_t)gr * D + g * 8));
                x1 = __ldg((const float4*)(X32 + (size_t)gr * D + g * 8 + 4));
            }
            uint2 p0 = h4(x0), p1 = h4(x1);
            *(uint4*)(As + (size_t)r * AS_LD + g * 8) = make_uint4(p0.x, p0.y, p1.x, p1.y);
        }
    }
    // stage B (4 chunks/thread)
#pragma unroll
    for (int it = 0; it < 4; it++) {
        int idx = tid + it * 512;
        int kk = idx >> 4, g = idx & 15;
        cpasync16(Bs + (size_t)kk * BS_LD + g * 8, (const uint4*)Wh + kk * 16 + g);
    }
    asm volatile("cp.async.commit_group;" ::: "memory");
    asm volatile("cp.async.wait_group 0;" ::: "memory");
    __syncthreads();

    // 16 warps: 4 m-strips x 4 n-strips, warp tile 32x32
    const int row0 = (wid & 3) * 32;
    const int n0   = (wid >> 2) * 32;
    wmma::fragment<wmma::accumulator, 16, 16, 16, float> acc[2][2];
#pragma unroll
    for (int i = 0; i < 2; i++)
#pragma unroll
        for (int j = 0; j < 2; j++) wmma::fill_fragment(acc[i][j], 0.f);

#pragma unroll
    for (int k = 0; k < 8; k++) {
        wmma::fragment<wmma::matrix_a, 16, 16, 16, __half, wmma::row_major> af[2];
        wmma::fragment<wmma::matrix_b, 16, 16, 16, __half, wmma::row_major> bf[2];
#pragma unroll
        for (int i = 0; i < 2; i++)
            wmma::load_matrix_sync(af[i], As + (size_t)(row0 + i * 16) * AS_LD + k * 16, AS_LD);
#pragma unroll
        for (int j = 0; j < 2; j++)
            wmma::load_matrix_sync(bf[j], Bs + (size_t)(k * 16) * BS_LD + n0 + j * 16, BS_LD);
#pragma unroll
        for (int i = 0; i < 2; i++)
#pragma unroll
            for (int j = 0; j < 2; j++)
                wmma::mma_sync(acc[i][j], af[i], bf[j], acc[i][j]);
    }

    // epilogue: direct from accumulator fragments (sm_80+ layout):
    // element e of lane L: row = (L>>2) + (e&2 ? 8:0), col = (L&3)*2 + (e&1) + (e&4 ? 8:0)
    {
        const float a = __ldg(pa);
        const int lane = tid & 31;
        const int g8  = lane >> 2;
        const int tg2 = (lane & 3) * 2;
#pragma unroll
        for (int i = 0; i < 2; i++) {
#pragma unroll
            for (int j = 0; j < 2; j++) {
                const int rb = m0 + row0 + i * 16;
                const int cb = n0 + j * 16;
#pragma unroll
                for (int e = 0; e < 8; e += 2) {
                    int r = rb + g8 + ((e & 2) ? 8 : 0);
                    int c = cb + tg2 + ((e & 4) ? 8 : 0);
                    if (r < M) {
                        float2 bb = __ldg((const float2*)(bias + c));
                        float vx = acc[i][j].x[e]     + bb.x;
                        float vy = acc[i][j].x[e + 1] + bb.y;
                        if (out_h16) {
                            float ox = prelu_h16 ? prelu1(vx, a) : vx;
                            float oy = prelu_h16 ? prelu1(vy, a) : vy;
                            __half2 hv = __floats2half2_rn(ox, oy);
                            *(unsigned*)(out_h16 + (size_t)r * 64 + (c >> 1)) =
                                *reinterpret_cast<unsigned*>(&hv);
                        }
                        if (out_f32) {
                            float ox = prelu_f32 ? prelu1(vx, a) : vx;
                            float oy = prelu_f32 ? prelu1(vy, a) : vy;
                            *(float2*)(out_f32 + (size_t)r * D + c) = make_float2(ox, oy);
                        }
                    }
                }
            }
        }
    }
}

// ---------------- setup kernels ----------------------------------------------
__global__ void kzero_counts(int* cd, int* cs, int* cc1, int* cc2, int E, int N, int C) {
    int i = blockIdx.x * blockDim.x + threadIdx.x;
    int tot = E + N + 2 * C;
    if (i >= tot) return;
    if (i < E) cd[i] = 0;
    else if (i < E + N) cs[i - E] = 0;
    else if (i < E + N + C) cc1[i - E - N] = 0;
    else cc2[i - E - N - C] = 0;
}

__global__ void kcountall(const int* __restrict__ src, const int* __restrict__ dst,
                          const int* __restrict__ he_c, const int* __restrict__ nc_c,
                          int* cs, int* cd, int* cc1, int* cc2,
                          int nnz, int E, int N) {
    int i = blockIdx.x * blockDim.x + threadIdx.x;
    if (i < nnz) {
        atomicAdd(&cd[dst[i]], 1);
        atomicAdd(&cs[src[i]], 1);
    } else if (i < nnz + E) {
        atomicAdd(&cc1[he_c[i - nnz]], 1);
    } else if (i < nnz + E + N) {
        atomicAdd(&cc2[nc_c[i - nnz - E]], 1);
    }
}

__global__ __launch_bounds__(1024) void kscanA(const int* __restrict__ cd,
                                               const int* __restrict__ cs,
                                               int* od, int* os, int* bsum,
                                               int nbd, int E, int N) {
    __shared__ int sh[1024];
    const int b = blockIdx.x, t = threadIdx.x;
    const bool isD = b < nbd;
    const int* in = isD ? cd : cs;
    int* out = isD ? od : os;
    const int n = isD ? E : N;
    const int i = (isD ? b : b - nbd) * 1024 + t;
    int v = (i < n) ? in[i] : 0;
    sh[t] = v;
    __syncthreads();
    for (int off = 1; off < 1024; off <<= 1) {
        int x = (t >= off) ? sh[t - off] : 0;
        __syncthreads();
        sh[t] += x;
        __syncthreads();
    }
    if (i < n) out[i] = sh[t] - v;
    if (t == 1023) bsum[b] = sh[1023];
}

__global__ __launch_bounds__(1024) void kscanB(const int* __restrict__ bsum,
                                               int* bscan, int nbd, int nbtot, int nnz) {
    __shared__ int sh[1024];
    int t = threadIdx.x;
    int v = (t < nbtot) ? bsum[t] : 0;
    sh[t] = v;
    __syncthreads();
    for (int off = 1; off < 1024; off <<= 1) {
        int x = (t >= off) ? sh[t - off] : 0;
        __syncthreads();
        sh[t] += x;
        __syncthreads();
    }
    if (t < nbtot) {
        int excl = sh[t] - v;
        bscan[t] = (t >= nbd) ? excl - nnz : excl;
    }
}

__global__ __launch_bounds__(1024) void kscanC(int* od, int* os,
                                               const int* __restrict__ bscan,
                                               int* cd, int* cs,
                                               int nbd, int E, int N, int nnz) {
    const int b = blockIdx.x, t = threadIdx.x;
    const bool isD = b < nbd;
    const int i = (isD ? b : b - nbd) * 1024 + t;
    if (isD) {
        if (i < E) { od[i] += bscan[b]; cd[i] = 0; }
        if (b == 0 && t == 0) od[E] = nnz;
    } else {
        if (i < N) { os[i] += bscan[b]; cs[i] = 0; }
        if (i == 0) os[N] = nnz;
    }
}

__global__ void kfill(const int* __restrict__ src, const int* __restrict__ dst,
                      const int* __restrict__ od, const int* __restrict__ os,
                      int* cur_d, int* cur_s, int* perm_d, int* perm_s, int nnz) {
    int k = blockIdx.x * blockDim.x + threadIdx.x;
    if (k >= nnz) return;
    int s = __ldg(&src[k]), d = __ldg(&dst[k]);
    int pd = atomicAdd(&cur_d[d], 1);
    perm_d[__ldg(&od[d]) + pd] = s;
    int ps = atomicAdd(&cur_s[s], 1);
    perm_s[__ldg(&os[s]) + ps] = d;
}

__global__ void kinvall(const int* __restrict__ od, const int* __restrict__ os,
                        const int* __restrict__ cc1, const int* __restrict__ cc2,
                        float* invd, float* invs, float* ic1, float* ic2,
                        int E, int N, int C) {
    int i = blockIdx.x * blockDim.x + threadIdx.x;
    if (i < E) {
        int c = od[i + 1] - od[i];
        invd[i] = 1.f / (float)(c > 0 ? c : 1);
    } else if (i < E + N) {
        int j = i - E;
        int c = os[j + 1] - os[j] + 1;
        invs[j] = 1.f / (float)c;
    } else if (i < E + N + C) {
        int c = cc1[i - E - N];
        ic1[i - E - N] = 1.f / (float)(c > 0 ? c : 1);
    } else if (i < E + N + 2 * C) {
        int c = cc2[i - E - N - C];
        ic2[i - E - N - C] = 1.f / (float)(c > 0 ? c : 1);
    }
}

__global__ void kzero4(float4* p, long n4) {
    long i = (long)blockIdx.x * blockDim.x + threadIdx.x;
    if (i < n4) p[i] = make_float4(0.f, 0.f, 0.f, 0.f);
}

// ---------------- SIMT GEMM (small C-row GEMMs) ------------------------------
__global__ __launch_bounds__(256) void kgemm2(const float* __restrict__ X,
                                              const float* __restrict__ W,
                                              const float* __restrict__ b,
                                              const float* __restrict__ addin,
                                              float* __restrict__ Yraw,
                                              float* __restrict__ Ypre,
                                              const float* __restrict__ pa, int M) {
    __shared__ float As[64][128];
    const int m0 = blockIdx.x * 64;
    const int t = threadIdx.x;
    {
        const int c4 = t & 31;
        const int r0 = t >> 5;
#pragma unroll
        for (int s = 0; s < 8; s++) {
            int r = r0 + 8 * s;
            int gr = m0 + r;
            float4 v = make_float4(0.f, 0.f, 0.f, 0.f);
            if (gr < M) v = ((const float4*)(X + (size_t)gr * D))[c4];
            ((float4*)(&As[r][0]))[c4] = v;
        }
    }
    __syncthreads();
    const int cg = (t & 15) * 8;
    const int rg = (t >> 4) * 4;
    unsigned long long acc[4][4];
#pragma unroll
    for (int i = 0; i < 4; i++)
#pragma unroll
        for (int j = 0; j < 4; j++) acc[i][j] = 0ULL;
#pragma unroll 4
    for (int k = 0; k < D; k += 4) {
        float4 a[4];
#pragma unroll
        for (int i = 0; i < 4; i++) a[i] = *(const float4*)&As[rg + i][k];
#pragma unroll
        for (int kk = 0; kk < 4; kk++) {
            const ulonglong2 w0 = *reinterpret_cast<const ulonglong2*>(&W[(k + kk) * D + cg]);
            const ulonglong2 w1 = *reinterpret_cast<const ulonglong2*>(&W[(k + kk) * D + cg + 4]);
#pragma unroll
            for (int i = 0; i < 4; i++) {
                float av = (kk == 0) ? a[i].x : (kk == 1) ? a[i].y
                         : (kk == 2) ? a[i].z : a[i].w;
                unsigned long long av2 = pk2(av);
                fma2(acc[i][0], av2, w0.x);
                fma2(acc[i][1], av2, w0.y);
                fma2(acc[i][2], av2, w1.x);
                fma2(acc[i][3], av2, w1.y);
            }
        }
    }
    const float4 b0 = __ldg((const float4*)&b[cg]);
    const float4 b1 = __ldg((const float4*)&b[cg + 4]);
    const float a = __ldg(pa);
#pragma unroll
    for (int i = 0; i < 4; i++) {
        int gr = m0 + rg + i;
        if (gr >= M) continue;
        float2 p0 = up2(acc[i][0]), p1 = up2(acc[i][1]);
        float2 p2 = up2(acc[i][2]), p3 = up2(acc[i][3]);
        float4 o0 = make_float4(p0.x + b0.x, p0.y + b0.y, p1.x + b0.z, p1.y + b0.w);
        float4 o1 = make_float4(p2.x + b1.x, p2.y + b1.y, p3.x + b1.z, p3.y + b1.w);
        if (addin) {
            const float4* ar = (const float4*)(addin + (size_t)gr * D);
            add4(o0, ar[cg / 4]); add4(o1, ar[cg / 4 + 1]);
        }
        if (Yraw) {
            float4* yr = (float4*)(Yraw + (size_t)gr * D);
            yr[cg / 4] = o0; yr[cg / 4 + 1] = o1;
        }
        if (Ypre) {
            float4* yp = (float4*)(Ypre + (size_t)gr * D);
            yp[cg / 4] = prelu4(o0, a); yp[cg / 4 + 1] = prelu4(o1, a);
        }
    }
}

// ---------------- CSR aggregation (HALF-warp per segment, uint4 gather) ------
__global__ __launch_bounds__(256) void kagg_e(const unsigned* __restrict__ T16,
                                              const int* __restrict__ perm,
                                              const int* __restrict__ offs,
                                              const float* __restrict__ invd,
                                              const float* __restrict__ pa,
                                              unsigned* __restrict__ EB16,
                                              float* __restrict__ out_e, int E) {
    int seg = (blockIdx.x * blockDim.x + threadIdx.x) >> 4;
    int l = threadIdx.x & 15;
    if (seg >= E) return;
    int beg = __ldg(&offs[seg]), end = __ldg(&offs[seg + 1]);
    float4 s0 = {0,0,0,0}, s1 = {0,0,0,0}, t0 = {0,0,0,0}, t1 = {0,0,0,0};
    float4 u0 = {0,0,0,0}, u1 = {0,0,0,0}, v0 = {0,0,0,0}, v1 = {0,0,0,0};
    int p = beg;
    for (; p + 4 <= end; p += 4) {
        int r0 = __ldg(&perm[p]),     r1 = __ldg(&perm[p + 1]);
        int r2 = __ldg(&perm[p + 2]), r3 = __ldg(&perm[p + 3]);
        addh8(s0, s1, __ldg((const uint4*)(T16 + (size_t)r0 * 64) + l));
        addh8(t0, t1, __ldg((const uint4*)(T16 + (size_t)r1 * 64) + l));
        addh8(u0, u1, __ldg((const uint4*)(T16 + (size_t)r2 * 64) + l));
        addh8(v0, v1, __ldg((const uint4*)(T16 + (size_t)r3 * 64) + l));
    }
    for (; p < end; p++)
        addh8(s0, s1, __ldg((const uint4*)(T16 + (size_t)__ldg(&perm[p]) * 64) + l));
    add4(s0, t0); add4(u0, v0); add4(s0, u0);
    add4(s1, t1); add4(u1, v1); add4(s1, u1);
    float iv = __ldg(&invd[seg]);
    float a = __ldg(pa);
    s0.x *= iv; s0.y *= iv; s0.z *= iv; s0.w *= iv;
    s1.x *= iv; s1.y *= iv; s1.z *= iv; s1.w *= iv;
    float4 r0 = prelu4(s0, a), r1 = prelu4(s1, a);
    uint2 q0 = h4(r0), q1 = h4(r1);
    ((uint4*)(EB16 + (size_t)seg * 64))[l] = make_uint4(q0.x, q0.y, q1.x, q1.y);
    if (out_e) {
        ((float4*)out_e)[(size_t)seg * 32 + l * 2]     = r0;
        ((float4*)out_e)[(size_t)seg * 32 + l * 2 + 1] = r1;
    }
}

// A16[i] = fp16( (sum EB16[perm[p]] + prelu(T16[i])) * invs[i] )
__global__ __launch_bounds__(256) void kagg_n(const unsigned* __restrict__ T16,
                                              const unsigned* __restrict__ EB16,
                                              const int* __restrict__ perm,
                                              const int* __restrict__ offs,
                                              const float* __restrict__ invs,
                                              const float* __restrict__ pa,
                                              unsigned* __restrict__ A16, int N) {
    int seg = (blockIdx.x * blockDim.x + threadIdx.x) >> 4;
    int l = threadIdx.x & 15;
    if (seg >= N) return;
    int beg = __ldg(&offs[seg]), end = __ldg(&offs[seg + 1]);
    float4 s0 = {0,0,0,0}, s1 = {0,0,0,0}, t0 = {0,0,0,0}, t1 = {0,0,0,0};
    float4 u0 = {0,0,0,0}, u1 = {0,0,0,0}, v0 = {0,0,0,0}, v1 = {0,0,0,0};
    int p = beg;
    for (; p + 4 <= end; p += 4) {
        int r0 = __ldg(&perm[p]),     r1 = __ldg(&perm[p + 1]);
        int r2 = __ldg(&perm[p + 2]), r3 = __ldg(&perm[p + 3]);
        addh8(s0, s1, __ldg((const uint4*)(EB16 + (size_t)r0 * 64) + l));
        addh8(t0, t1, __ldg((const uint4*)(EB16 + (size_t)r1 * 64) + l));
        addh8(u0, u1, __ldg((const uint4*)(EB16 + (size_t)r2 * 64) + l));
        addh8(v0, v1, __ldg((const uint4*)(EB16 + (size_t)r3 * 64) + l));
    }
    for (; p < end; p++)
        addh8(s0, s1, __ldg((const uint4*)(EB16 + (size_t)__ldg(&perm[p]) * 64) + l));
    add4(s0, t0); add4(u0, v0); add4(s0, u0);
    add4(s1, t1); add4(u1, v1); add4(s1, u1);
    float a = __ldg(pa);
    float4 w0 = {0,0,0,0}, w1 = {0,0,0,0};
    addh8(w0, w1, __ldg((const uint4*)(T16 + (size_t)seg * 64) + l));
    add4(s0, prelu4(w0, a));
    add4(s1, prelu4(w1, a));
    float iv = __ldg(&invs[seg]);
    s0.x *= iv; s0.y *= iv; s0.z *= iv; s0.w *= iv;
    s1.x *= iv; s1.y *= iv; s1.z *= iv; s1.w *= iv;
    uint2 q0 = h4(s0), q1 = h4(s1);
    ((uint4*)(A16 + (size_t)seg * 64))[l] = make_uint4(q0.x, q0.y, q1.x, q1.y);
}

// ---------------- component scatter (HALF-warp per incidence) ----------------
__device__ __forceinline__ void red4(float* a, float4 v) {
    asm volatile("red.global.add.v4.f32 [%0], {%1,%2,%3,%4};"
                 :: "l"(a), "f"(v.x), "f"(v.y), "f"(v.z), "f"(v.w)
                 : "memory");
}

__global__ void kscatterc(const unsigned* __restrict__ P16, const int* __restrict__ rows,
                          const int* __restrict__ comp, const float* __restrict__ inv,
                          float* __restrict__ csum, int n) {
    int idx = (blockIdx.x * blockDim.x + threadIdx.x) >> 4;
    int l = threadIdx.x & 15;
    if (idx >= n) return;
    int r = __ldg(&rows[idx]);
    int c = __ldg(&comp[idx]);
    float sc = __ldg(&inv[c]);
    float4 v0 = {0,0,0,0}, v1 = {0,0,0,0};
    addh8(v0, v1, __ldg((const uint4*)(P16 + (size_t)r * 64) + l));
    v0.x *= sc; v0.y *= sc; v0.z *= sc; v0.w *= sc;
    v1.x *= sc; v1.y *= sc; v1.z *= sc; v1.w *= sc;
    red4(csum + (size_t)c * D + l * 8,     v0);
    red4(csum + (size_t)c * D + l * 8 + 4, v1);
}

// ---------------- host driver ------------------------------------------------
static inline int cdiv(long a, long b) { return (int)((a + b - 1) / b); }

extern "C" void kernel_launch(void* const* d_in, const int* in_sizes, int n_in,
                              void* d_out, int out_size) {
    const float* x   = (const float*)d_in[0];
    const int*   hei = (const int*)d_in[1];
    const int*   hci = (const int*)d_in[2];
    const int*   nci = (const int*)d_in[3];

    const int NNZ = in_sizes[1] / 2;
    const int E   = in_sizes[2] / 2;
    const int N   = in_sizes[0] / D;
    const int C   = out_size / D - N - E;

    int wi = -1;
    for (int i = 4; i < n_in; i++) {
        if (in_sizes[i] == D * D) { wi = i; break; }
    }
    const float* pa = (const float*)d_in[wi - 1];

    const int* src  = hei;
    const int* dst  = hei + NNZ;
    const int* he_e = hci;
    const int* he_c = hci + E;
    const int* nc_n = nci;
    const int* nc_c = nci + N;

    float *CE, *CN, *CT, *invd, *invs, *ic1, *ic2;
    unsigned *T16, *A16, *H16, *E16, *Wh;
    int *cd, *cs, *cc1, *cc2, *od, *os, *pd, *ps, *bsum, *bscan;
    cudaGetSymbolAddress((void**)&T16,  g_T16);
    cudaGetSymbolAddress((void**)&A16,  g_A16);
    cudaGetSymbolAddress((void**)&H16,  g_H16);
    cudaGetSymbolAddress((void**)&E16,  g_E16);
    cudaGetSymbolAddress((void**)&CE,   g_c1);
    cudaGetSymbolAddress((void**)&CN,   g_c2);
    cudaGetSymbolAddress((void**)&CT,   g_c3);
    cudaGetSymbolAddress((void**)&Wh,   g_Wh);
    cudaGetSymbolAddress((void**)&invd, g_invdst);
    cudaGetSymbolAddress((void**)&invs, g_invsrc);
    cudaGetSymbolAddress((void**)&ic1,  g_invc1);
    cudaGetSymbolAddress((void**)&ic2,  g_invc2);
    cudaGetSymbolAddress((void**)&cd,   g_cd);
    cudaGetSymbolAddress((void**)&cs,   g_cs);
    cudaGetSymbolAddress((void**)&cc1,  g_cc1);
    cudaGetSymbolAddress((void**)&cc2,  g_cc2);
    cudaGetSymbolAddress((void**)&od,   g_offs_d);
    cudaGetSymbolAddress((void**)&os,   g_offs_s);
    cudaGetSymbolAddress((void**)&pd,   g_perm_d);
    cudaGetSymbolAddress((void**)&ps,   g_perm_s);
    cudaGetSymbolAddress((void**)&bsum, g_bsum);
    cudaGetSymbolAddress((void**)&bscan,g_bscan);

    float* out   = (float*)d_out;
    float* out_n = out;
    float* out_e = out + (size_t)N * D;
    float* out_c = out + (size_t)(N + E) * D;

    const int TB = 256;
    const int nbd = cdiv(E, 1024);
    const int nbs = cdiv(N, 1024);
    const int nbtot = nbd + nbs;
    const int GT = cdiv(N, 128);

    const float* Wv0 = (const float*)d_in[wi + 0];
    const float* bv0 = (const float*)d_in[wi + 1];
    const float* We0 = (const float*)d_in[wi + 2];
    const float* be0 = (const float*)d_in[wi + 3];
    const float* Wv1 = (const float*)d_in[wi + 8];
    const float* bv1 = (const float*)d_in[wi + 9];
    const float* We1 = (const float*)d_in[wi + 10];
    const float* be1 = (const float*)d_in[wi + 11];

    cudaFuncSetAttribute(kgemm_tc, cudaFuncAttributeMaxDynamicSharedMemorySize, SM_TOT);

    kconvW<<<cdiv(4 * 128 * 16, TB), TB>>>(Wv0, We0, Wv1, We1, Wh);
    kzero_counts<<<cdiv(E + N + 2 * C, TB), TB>>>(cd, cs, cc1, cc2, E, N, C);
    kcountall<<<cdiv(NNZ + E + N, TB), TB>>>(src, dst, he_c, nc_c, cs, cd, cc1, cc2,
                                             NNZ, E, N);
    // G1 = v2e layer 0 (fp32 input) -> T16 raw (launch index 3 for ncu)
    kgemm_tc<<<GT, 512, SM_TOT>>>(x, nullptr, Wh + 0 * 8192, bv0, pa,
                                  nullptr, 0, T16, 0, N);
    kscanA<<<nbtot, 1024>>>(cd, cs, od, os, bsum, nbd, E, N);
    kscanB<<<1, 1024>>>(bsum, bscan, nbd, nbtot, NNZ);
    kscanC<<<nbtot, 1024>>>(od, os, bscan, cd, cs, nbd, E, N, NNZ);
    kfill<<<cdiv(NNZ, TB), TB>>>(src, dst, od, os, cd, cs, pd, ps, NNZ);
    kinvall<<<cdiv(E + N + 2 * C, TB), TB>>>(od, os, cc1, cc2, invd, invs, ic1, ic2,
                                             E, N, C);

    // ---- layer 0 ----
    kagg_e<<<cdiv((long)E * 16, TB), TB>>>(T16, pd, od, invd, pa, E16, nullptr, E);
    kagg_n<<<cdiv((long)N * 16, TB), TB>>>(T16, E16, ps, os, invs, pa, A16, N);
    // G2 = e2v layer 0 -> H16 = prelu(A@We0+be0) fp16
    kgemm_tc<<<GT, 512, SM_TOT>>>(nullptr, A16, Wh + 1 * 8192, be0, pa,
                                  nullptr, 0, H16, 1, N);

    // ---- layer 1 ----
    kgemm_tc<<<GT, 512, SM_TOT>>>(nullptr, H16, Wh + 2 * 8192, bv1, pa,
                                  nullptr, 0, T16, 0, N);
    kagg_e<<<cdiv((long)E * 16, TB), TB>>>(T16, pd, od, invd, pa, E16, out_e, E);
    kagg_n<<<cdiv((long)N * 16, TB), TB>>>(T16, E16, ps, os, invs, pa, A16, N);
    // G4 = e2v layer 1 -> out_n fp32 prelu + T16 = raw n fp16
    kgemm_tc<<<GT, 512, SM_TOT>>>(nullptr, A16, Wh + 3 * 8192, be1, pa,
                                  out_n, 1, T16, 0, N);

    // components
    kzero4<<<cdiv((long)C * 32, TB), TB>>>((float4*)CE, (long)C * 32);
    kzero4<<<cdiv((long)C * 32, TB), TB>>>((float4*)CN, (long)C * 32);
    kscatterc<<<cdiv((long)E * 16, TB), TB>>>(E16, he_e, he_c, ic1, CE, E);
    kscatterc<<<cdiv((long)N * 16, TB), TB>>>(T16, nc_n, nc_c, ic2, CN, N);
    kgemm2<<<cdiv(C, 64), TB>>>(CE, (const float*)d_in[wi + 12], (const float*)d_in[wi + 13],
                                nullptr, CT, nullptr, pa, C);
    kgemm2<<<cdiv(C, 64), TB>>>(CN, (const float*)d_in[wi + 14], (const float*)d_in[wi + 15],
                                CT, nullptr, out_c, pa, C);
}

// round 13
// speedup vs baseline: 2.2395x; 1.0438x over previous
#include <cuda_runtime.h>
#include <cuda_fp16.h>
#include <cuda_bf16.h>
#include <mma.h>
#include <cstdint>
#include <cstddef>

#define D 128
using namespace nvcuda;

// ---------------- static scratch (device globals) ---------------------------
static __device__ unsigned g_T16[100000 * 64];   // v2e transform output (fp16 rows)
static __device__ unsigned g_A16[100000 * 64];   // aggregated node features (fp16)
static __device__ unsigned g_H16[100000 * 64];   // h = prelu(n) layer 0 (fp16)
static __device__ unsigned g_E16[50000  * 64];   // e fp16 rows
static __device__ float    g_c1 [2048   * 128];
static __device__ float    g_c2 [2048   * 128];
static __device__ float    g_c3 [2048   * 128];
static __device__ unsigned g_Wh [4 * 128 * 64];  // 4 W, fp16 [128][128]
static __device__ float g_invdst[50016];
static __device__ float g_invsrc[100016];
static __device__ float g_invc1[2048];
static __device__ float g_invc2[2048];
static __device__ int   g_cd [50016];
static __device__ int   g_cs [100016];
static __device__ int   g_cc1[2048];
static __device__ int   g_cc2[2048];
static __device__ int   g_offs_d[50024];
static __device__ int   g_offs_s[100024];
static __device__ int   g_perm_d[1600128];
static __device__ int   g_perm_s[1600128];
static __device__ int   g_bsum [1024];
static __device__ int   g_bscan[1024];

// ---------------- helpers ----------------------------------------------------
__device__ __forceinline__ unsigned long long pk2(float v) {
    unsigned long long r; unsigned u = __float_as_uint(v);
    asm("mov.b64 %0, {%1,%1};" : "=l"(r) : "r"(u));
    return r;
}
__device__ __forceinline__ void fma2(unsigned long long& d, unsigned long long a,
                                     unsigned long long b) {
    asm("fma.rn.f32x2 %0, %1, %2, %0;" : "+l"(d) : "l"(a), "l"(b));
}
__device__ __forceinline__ float2 up2(unsigned long long v) {
    unsigned lo, hi;
    asm("mov.b64 {%0,%1}, %2;" : "=r"(lo), "=r"(hi) : "l"(v));
    return make_float2(__uint_as_float(lo), __uint_as_float(hi));
}
__device__ __forceinline__ float prelu1(float v, float a) { return v >= 0.f ? v : a * v; }
__device__ __forceinline__ float4 prelu4(float4 v, float a) {
    return make_float4(prelu1(v.x, a), prelu1(v.y, a), prelu1(v.z, a), prelu1(v.w, a));
}
__device__ __forceinline__ void add4(float4& a, float4 b) {
    a.x += b.x; a.y += b.y; a.z += b.z; a.w += b.w;
}
__device__ __forceinline__ void addh8(float4& a, float4& b, uint4 v) {
    __half2 h0 = *reinterpret_cast<__half2*>(&v.x);
    __half2 h1 = *reinterpret_cast<__half2*>(&v.y);
    __half2 h2 = *reinterpret_cast<__half2*>(&v.z);
    __half2 h3 = *reinterpret_cast<__half2*>(&v.w);
    float2 f0 = __half22float2(h0), f1 = __half22float2(h1);
    float2 f2 = __half22float2(h2), f3 = __half22float2(h3);
    a.x += f0.x; a.y += f0.y; a.z += f1.x; a.w += f1.y;
    b.x += f2.x; b.y += f2.y; b.z += f3.x; b.w += f3.y;
}
__device__ __forceinline__ uint2 h4(float4 v) {
    __half2 h0 = __float22half2_rn(make_float2(v.x, v.y));
    __half2 h1 = __float22half2_rn(make_float2(v.z, v.w));
    uint2 r;
    r.x = *reinterpret_cast<unsigned*>(&h0);
    r.y = *reinterpret_cast<unsigned*>(&h1);
    return r;
}
__device__ __forceinline__ void cpasync16(void* smem_dst, const void* gsrc) {
    unsigned sa = (unsigned)__cvta_generic_to_shared(smem_dst);
    asm volatile("cp.async.cg.shared.global [%0], [%1], 16;" :: "r"(sa), "l"(gsrc));
}
__device__ __forceinline__ void red4(float* a, float4 v) {
    asm volatile("red.global.add.v4.f32 [%0], {%1,%2,%3,%4};"
                 :: "l"(a), "f"(v.x), "f"(v.y), "f"(v.z), "f"(v.w)
                 : "memory");
}
__device__ __forceinline__ void red2(float* a, float x, float y) {
    asm volatile("red.global.add.v2.f32 [%0], {%1,%2};"
                 :: "l"(a), "f"(x), "f"(y) : "memory");
}

// ---------------- W convert: Wh[w] = fp16 [128][128] -------------------------
__global__ void kconvW(const float* __restrict__ W0, const float* __restrict__ W1,
                       const float* __restrict__ W2, const float* __restrict__ W3,
                       unsigned* __restrict__ Wh) {
    int idx = blockIdx.x * blockDim.x + threadIdx.x;
    if (idx >= 4 * 128 * 16) return;
    int w = idx >> 11;
    int rem = idx & 2047;
    int kk = rem >> 4, g = rem & 15;
    const float* W = (w == 0) ? W0 : (w == 1) ? W1 : (w == 2) ? W2 : W3;
    float4 x0 = __ldg((const float4*)(W + (size_t)kk * D + g * 8));
    float4 x1 = __ldg((const float4*)(W + (size_t)kk * D + g * 8 + 4));
    uint2 p0 = h4(x0), p1 = h4(x1);
    ((uint4*)(Wh + (size_t)w * 128 * 64))[kk * 16 + g] = make_uint4(p0.x, p0.y, p1.x, p1.y);
}

// ---------------- WMMA GEMM: Y[M x 128] = X @ W + b (fp16) -------------------
// CTA 128x128, 16 warps, 2 CTAs/SM, cp.async staging, fragment-direct epilogue.
// Optional fused node->component scatter: csum[comp[r]] += raw * cinv[comp[r]].
#define AS_LD 136
#define BS_LD 136
#define SM_AS  (128 * AS_LD * 2)
#define SM_TOT (SM_AS + 128 * BS_LD * 2)

__global__ __launch_bounds__(512, 2) void kgemm_tc(const float* __restrict__ X32,
                                                   const unsigned* __restrict__ X16,
                                                   const unsigned* __restrict__ Wh,
                                                   const float* __restrict__ bias,
                                                   const float* __restrict__ pa,
                                                   float* __restrict__ out_f32,
                                                   int prelu_f32,
                                                   unsigned* __restrict__ out_h16,
                                                   int prelu_h16,
                                                   const int* __restrict__ ncomp,
                                                   const float* __restrict__ cinv,
                                                   float* __restrict__ csum, int M) {
    extern __shared__ char smem[];
    __half* As = (__half*)smem;                  // 128 x AS_LD
    __half* Bs = (__half*)(smem + SM_AS);        // 128 x BS_LD
    const int tid = threadIdx.x;
    const int wid = tid >> 5;
    const int m0 = blockIdx.x * 128;

    if (X16) {
#pragma unroll
        for (int it = 0; it < 4; it++) {
            int idx = tid + it * 512;
            int r = idx >> 4, g = idx & 15;
            int gr = m0 + r;
            void* dst = As + (size_t)r * AS_LD + g * 8;
            if (gr < M) cpasync16(dst, (const uint4*)(X16 + (size_t)gr * 64) + g);
            else        *(uint4*)dst = make_uint4(0, 0, 0, 0);
        }
    } else {
#pragma unroll
        for (int it = 0; it < 4; it++) {
            int idx = tid + it * 512;
            int r = idx >> 4, g = idx & 15;
            int gr = m0 + r;
            float4 x0 = make_float4(0.f, 0.f, 0.f, 0.f), x1 = x0;
            if (gr < M) {
                x0 = __ldg((const float4*)(X32 + (size_t)gr * D + g * 8));
                x1 = __ldg((const float4*)(X32 + (size_t)gr * D + g * 8 + 4));
            }
            uint2 p0 = h4(x0), p1 = h4(x1);
            *(uint4*)(As + (size_t)r * AS_LD + g * 8) = make_uint4(p0.x, p0.y, p1.x, p1.y);
        }
    }
#pragma unroll
    for (int it = 0; it < 4; it++) {
        int idx = tid + it * 512;
        int kk = idx >> 4, g = idx & 15;
        cpasync16(Bs + (size_t)kk * BS_LD + g * 8, (const uint4*)Wh + kk * 16 + g);
    }
    asm volatile("cp.async.commit_group;" ::: "memory");
    asm volatile("cp.async.wait_group 0;" ::: "memory");
    __syncthreads();

    const int row0 = (wid & 3) * 32;
    const int n0   = (wid >> 2) * 32;
    wmma::fragment<wmma::accumulator, 16, 16, 16, float> acc[2][2];
#pragma unroll
    for (int i = 0; i < 2; i++)
#pragma unroll
        for (int j = 0; j < 2; j++) wmma::fill_fragment(acc[i][j], 0.f);

#pragma unroll
    for (int k = 0; k < 8; k++) {
        wmma::fragment<wmma::matrix_a, 16, 16, 16, __half, wmma::row_major> af[2];
        wmma::fragment<wmma::matrix_b, 16, 16, 16, __half, wmma::row_major> bf[2];
#pragma unroll
        for (int i = 0; i < 2; i++)
            wmma::load_matrix_sync(af[i], As + (size_t)(row0 + i * 16) * AS_LD + k * 16, AS_LD);
#pragma unroll
        for (int j = 0; j < 2; j++)
            wmma::load_matrix_sync(bf[j], Bs + (size_t)(k * 16) * BS_LD + n0 + j * 16, BS_LD);
#pragma unroll
        for (int i = 0; i < 2; i++)
#pragma unroll
            for (int j = 0; j < 2; j++)
                wmma::mma_sync(acc[i][j], af[i], bf[j], acc[i][j]);
    }

    // epilogue direct from fragments: elem e of lane L ->
    // row = (L>>2) + (e&2 ? 8:0), col = (L&3)*2 + (e&1) + (e&4 ? 8:0)
    {
        const float a = __ldg(pa);
        const int lane = tid & 31;
        const int g8  = lane >> 2;
        const int tg2 = (lane & 3) * 2;
#pragma unroll
        for (int i = 0; i < 2; i++) {
#pragma unroll
            for (int j = 0; j < 2; j++) {
                const int rb = m0 + row0 + i * 16;
                const int cb = n0 + j * 16;
#pragma unroll
                for (int e = 0; e < 8; e += 2) {
                    int r = rb + g8 + ((e & 2) ? 8 : 0);
                    int c = cb + tg2 + ((e & 4) ? 8 : 0);
                    if (r < M) {
                        float2 bb = __ldg((const float2*)(bias + c));
                        float vx = acc[i][j].x[e]     + bb.x;
                        float vy = acc[i][j].x[e + 1] + bb.y;
                        if (out_h16) {
                            float ox = prelu_h16 ? prelu1(vx, a) : vx;
                            float oy = prelu_h16 ? prelu1(vy, a) : vy;
                            __half2 hv = __floats2half2_rn(ox, oy);
                            *(unsigned*)(out_h16 + (size_t)r * 64 + (c >> 1)) =
                                *reinterpret_cast<unsigned*>(&hv);
                        }
                        if (out_f32) {
                            float ox = prelu_f32 ? prelu1(vx, a) : vx;
                            float oy = prelu_f32 ? prelu1(vy, a) : vy;
                            *(float2*)(out_f32 + (size_t)r * D + c) = make_float2(ox, oy);
                        }
                        if (csum) {   // fused node->component mean contribution
                            int cc = __ldg(&ncomp[r]);
                            float sc = __ldg(&cinv[cc]);
                            red2(csum + (size_t)cc * D + c, vx * sc, vy * sc);
                        }
                    }
                }
            }
        }
    }
}

// ---------------- setup kernels ----------------------------------------------
__global__ void kzero_counts(int* cd, int* cs, int* cc1, int* cc2, int E, int N, int C) {
    int i = blockIdx.x * blockDim.x + threadIdx.x;
    int tot = E + N + 2 * C;
    if (i >= tot) return;
    if (i < E) cd[i] = 0;
    else if (i < E + N) cs[i - E] = 0;
    else if (i < E + N + C) cc1[i - E - N] = 0;
    else cc2[i - E - N - C] = 0;
}

__global__ void kcountall(const int* __restrict__ src, const int* __restrict__ dst,
                          const int* __restrict__ he_c, const int* __restrict__ nc_c,
                          int* cs, int* cd, int* cc1, int* cc2,
                          int nnz, int E, int N) {
    int i = blockIdx.x * blockDim.x + threadIdx.x;
    if (i < nnz) {
        atomicAdd(&cd[dst[i]], 1);
        atomicAdd(&cs[src[i]], 1);
    } else if (i < nnz + E) {
        atomicAdd(&cc1[he_c[i - nnz]], 1);
    } else if (i < nnz + E + N) {
        atomicAdd(&cc2[nc_c[i - nnz - E]], 1);
    }
}

__global__ __launch_bounds__(1024) void kscanA(const int* __restrict__ cd,
                                               const int* __restrict__ cs,
                                               int* od, int* os, int* bsum,
                                               int nbd, int E, int N) {
    __shared__ int sh[1024];
    const int b = blockIdx.x, t = threadIdx.x;
    const bool isD = b < nbd;
    const int* in = isD ? cd : cs;
    int* out = isD ? od : os;
    const int n = isD ? E : N;
    const int i = (isD ? b : b - nbd) * 1024 + t;
    int v = (i < n) ? in[i] : 0;
    sh[t] = v;
    __syncthreads();
    for (int off = 1; off < 1024; off <<= 1) {
        int x = (t >= off) ? sh[t - off] : 0;
        __syncthreads();
        sh[t] += x;
        __syncthreads();
    }
    if (i < n) out[i] = sh[t] - v;
    if (t == 1023) bsum[b] = sh[1023];
}

__global__ __launch_bounds__(1024) void kscanB(const int* __restrict__ bsum,
                                               int* bscan, int nbd, int nbtot, int nnz) {
    __shared__ int sh[1024];
    int t = threadIdx.x;
    int v = (t < nbtot) ? bsum[t] : 0;
    sh[t] = v;
    __syncthreads();
    for (int off = 1; off < 1024; off <<= 1) {
        int x = (t >= off) ? sh[t - off] : 0;
        __syncthreads();
        sh[t] += x;
        __syncthreads();
    }
    if (t < nbtot) {
        int excl = sh[t] - v;
        bscan[t] = (t >= nbd) ? excl - nnz : excl;
    }
}

__global__ __launch_bounds__(1024) void kscanC(int* od, int* os,
                                               const int* __restrict__ bscan,
                                               int* cd, int* cs,
                                               int nbd, int E, int N, int nnz) {
    const int b = blockIdx.x, t = threadIdx.x;
    const bool isD = b < nbd;
    const int i = (isD ? b : b - nbd) * 1024 + t;
    if (isD) {
        if (i < E) { od[i] += bscan[b]; cd[i] = 0; }
        if (b == 0 && t == 0) od[E] = nnz;
    } else {
        if (i < N) { os[i] += bscan[b]; cs[i] = 0; }
        if (i == 0) os[N] = nnz;
    }
}

__global__ void kfill(const int* __restrict__ src, const int* __restrict__ dst,
                      const int* __restrict__ od, const int* __restrict__ os,
                      int* cur_d, int* cur_s, int* perm_d, int* perm_s, int nnz) {
    int k = blockIdx.x * blockDim.x + threadIdx.x;
    if (k >= nnz) return;
    int s = __ldg(&src[k]), d = __ldg(&dst[k]);
    int pd = atomicAdd(&cur_d[d], 1);
    perm_d[__ldg(&od[d]) + pd] = s;
    int ps = atomicAdd(&cur_s[s], 1);
    perm_s[__ldg(&os[s]) + ps] = d;
}

__global__ void kinvall(const int* __restrict__ od, const int* __restrict__ os,
                        const int* __restrict__ cc1, const int* __restrict__ cc2,
                        float* invd, float* invs, float* ic1, float* ic2,
                        int E, int N, int C) {
    int i = blockIdx.x * blockDim.x + threadIdx.x;
    if (i < E) {
        int c = od[i + 1] - od[i];
        invd[i] = 1.f / (float)(c > 0 ? c : 1);
    } else if (i < E + N) {
        int j = i - E;
        int c = os[j + 1] - os[j] + 1;
        invs[j] = 1.f / (float)c;
    } else if (i < E + N + C) {
        int c = cc1[i - E - N];
        ic1[i - E - N] = 1.f / (float)(c > 0 ? c : 1);
    } else if (i < E + N + 2 * C) {
        int c = cc2[i - E - N - C];
        ic2[i - E - N - C] = 1.f / (float)(c > 0 ? c : 1);
    }
}

__global__ void kzero4(float4* p, long n4) {
    long i = (long)blockIdx.x * blockDim.x + threadIdx.x;
    if (i < n4) p[i] = make_float4(0.f, 0.f, 0.f, 0.f);
}

// ---------------- SIMT GEMM (small C-row GEMMs) ------------------------------
__global__ __launch_bounds__(256) void kgemm2(const float* __restrict__ X,
                                              const float* __restrict__ W,
                                              const float* __restrict__ b,
                                              const float* __restrict__ addin,
                                              float* __restrict__ Yraw,
                                              float* __restrict__ Ypre,
                                              const float* __restrict__ pa, int M) {
    __shared__ float As[64][128];
    const int m0 = blockIdx.x * 64;
    const int t = threadIdx.x;
    {
        const int c4 = t & 31;
        const int r0 = t >> 5;
#pragma unroll
        for (int s = 0; s < 8; s++) {
            int r = r0 + 8 * s;
            int gr = m0 + r;
            float4 v = make_float4(0.f, 0.f, 0.f, 0.f);
            if (gr < M) v = ((const float4*)(X + (size_t)gr * D))[c4];
            ((float4*)(&As[r][0]))[c4] = v;
        }
    }
    __syncthreads();
    const int cg = (t & 15) * 8;
    const int rg = (t >> 4) * 4;
    unsigned long long acc[4][4];
#pragma unroll
    for (int i = 0; i < 4; i++)
#pragma unroll
        for (int j = 0; j < 4; j++) acc[i][j] = 0ULL;
#pragma unroll 4
    for (int k = 0; k < D; k += 4) {
        float4 a[4];
#pragma unroll
        for (int i = 0; i < 4; i++) a[i] = *(const float4*)&As[rg + i][k];
#pragma unroll
        for (int kk = 0; kk < 4; kk++) {
            const ulonglong2 w0 = *reinterpret_cast<const ulonglong2*>(&W[(k + kk) * D + cg]);
            const ulonglong2 w1 = *reinterpret_cast<const ulonglong2*>(&W[(k + kk) * D + cg + 4]);
#pragma unroll
            for (int i = 0; i < 4; i++) {
                float av = (kk == 0) ? a[i].x : (kk == 1) ? a[i].y
                         : (kk == 2) ? a[i].z : a[i].w;
                unsigned long long av2 = pk2(av);
                fma2(acc[i][0], av2, w0.x);
                fma2(acc[i][1], av2, w0.y);
                fma2(acc[i][2], av2, w1.x);
                fma2(acc[i][3], av2, w1.y);
            }
        }
    }
    const float4 b0 = __ldg((const float4*)&b[cg]);
    const float4 b1 = __ldg((const float4*)&b[cg + 4]);
    const float a = __ldg(pa);
#pragma unroll
    for (int i = 0; i < 4; i++) {
        int gr = m0 + rg + i;
        if (gr >= M) continue;
        float2 p0 = up2(acc[i][0]), p1 = up2(acc[i][1]);
        float2 p2 = up2(acc[i][2]), p3 = up2(acc[i][3]);
        float4 o0 = make_float4(p0.x + b0.x, p0.y + b0.y, p1.x + b0.z, p1.y + b0.w);
        float4 o1 = make_float4(p2.x + b1.x, p2.y + b1.y, p3.x + b1.z, p3.y + b1.w);
        if (addin) {
            const float4* ar = (const float4*)(addin + (size_t)gr * D);
            add4(o0, ar[cg / 4]); add4(o1, ar[cg / 4 + 1]);
        }
        if (Yraw) {
            float4* yr = (float4*)(Yraw + (size_t)gr * D);
            yr[cg / 4] = o0; yr[cg / 4 + 1] = o1;
        }
        if (Ypre) {
            float4* yp = (float4*)(Ypre + (size_t)gr * D);
            yp[cg / 4] = prelu4(o0, a); yp[cg / 4 + 1] = prelu4(o1, a);
        }
    }
}

// ---------------- CSR aggregation (half-warp/segment, 8-deep MLP batches) ----
__global__ __launch_bounds__(256) void kagg_e(const unsigned* __restrict__ T16,
                                              const int* __restrict__ perm,
                                              const int* __restrict__ offs,
                                              const float* __restrict__ invd,
                                              const float* __restrict__ pa,
                                              unsigned* __restrict__ EB16,
                                              float* __restrict__ out_e,
                                              const int* __restrict__ ecomp,
                                              const float* __restrict__ cinv,
                                              float* __restrict__ csum, int E) {
    int seg = (blockIdx.x * blockDim.x + threadIdx.x) >> 4;
    int l = threadIdx.x & 15;
    if (seg >= E) return;
    int beg = __ldg(&offs[seg]), end = __ldg(&offs[seg + 1]);
    float4 s0 = {0,0,0,0}, s1 = {0,0,0,0}, t0 = {0,0,0,0}, t1 = {0,0,0,0};
    float4 u0 = {0,0,0,0}, u1 = {0,0,0,0}, v0 = {0,0,0,0}, v1 = {0,0,0,0};
    int p = beg;
    for (; p + 8 <= end; p += 8) {
        uint4 vv[8];
#pragma unroll
        for (int q = 0; q < 8; q++)
            vv[q] = __ldg((const uint4*)(T16 + (size_t)__ldg(&perm[p + q]) * 64) + l);
        addh8(s0, s1, vv[0]); addh8(t0, t1, vv[1]);
        addh8(u0, u1, vv[2]); addh8(v0, v1, vv[3]);
        addh8(s0, s1, vv[4]); addh8(t0, t1, vv[5]);
        addh8(u0, u1, vv[6]); addh8(v0, v1, vv[7]);
    }
    for (; p + 4 <= end; p += 4) {
        uint4 vv[4];
#pragma unroll
        for (int q = 0; q < 4; q++)
            vv[q] = __ldg((const uint4*)(T16 + (size_t)__ldg(&perm[p + q]) * 64) + l);
        addh8(s0, s1, vv[0]); addh8(t0, t1, vv[1]);
        addh8(u0, u1, vv[2]); addh8(v0, v1, vv[3]);
    }
    for (; p < end; p++)
        addh8(s0, s1, __ldg((const uint4*)(T16 + (size_t)__ldg(&perm[p]) * 64) + l));
    add4(s0, t0); add4(u0, v0); add4(s0, u0);
    add4(s1, t1); add4(u1, v1); add4(s1, u1);
    float iv = __ldg(&invd[seg]);
    float a = __ldg(pa);
    s0.x *= iv; s0.y *= iv; s0.z *= iv; s0.w *= iv;
    s1.x *= iv; s1.y *= iv; s1.z *= iv; s1.w *= iv;
    float4 r0 = prelu4(s0, a), r1 = prelu4(s1, a);
    uint2 q0 = h4(r0), q1 = h4(r1);
    ((uint4*)(EB16 + (size_t)seg * 64))[l] = make_uint4(q0.x, q0.y, q1.x, q1.y);
    if (out_e) {
        ((float4*)out_e)[(size_t)seg * 32 + l * 2]     = r0;
        ((float4*)out_e)[(size_t)seg * 32 + l * 2 + 1] = r1;
    }
    if (csum) {   // fused edge->component mean contribution
        int cc = __ldg(&ecomp[seg]);
        float sc = __ldg(&cinv[cc]);
        float4 w0 = make_float4(r0.x * sc, r0.y * sc, r0.z * sc, r0.w * sc);
        float4 w1 = make_float4(r1.x * sc, r1.y * sc, r1.z * sc, r1.w * sc);
        red4(csum + (size_t)cc * D + l * 8,     w0);
        red4(csum + (size_t)cc * D + l * 8 + 4, w1);
    }
}

// A16[i] = fp16( (sum EB16[perm[p]] + prelu(T16[i])) * invs[i] )
__global__ __launch_bounds__(256) void kagg_n(const unsigned* __restrict__ T16,
                                              const unsigned* __restrict__ EB16,
                                              const int* __restrict__ perm,
                                              const int* __restrict__ offs,
                                              const float* __restrict__ invs,
                                              const float* __restrict__ pa,
                                              unsigned* __restrict__ A16, int N) {
    int seg = (blockIdx.x * blockDim.x + threadIdx.x) >> 4;
    int l = threadIdx.x & 15;
    if (seg >= N) return;
    int beg = __ldg(&offs[seg]), end = __ldg(&offs[seg + 1]);
    float4 s0 = {0,0,0,0}, s1 = {0,0,0,0}, t0 = {0,0,0,0}, t1 = {0,0,0,0};
    float4 u0 = {0,0,0,0}, u1 = {0,0,0,0}, v0 = {0,0,0,0}, v1 = {0,0,0,0};
    int p = beg;
    for (; p + 8 <= end; p += 8) {
        uint4 vv[8];
#pragma unroll
        for (int q = 0; q < 8; q++)
            vv[q] = __ldg((const uint4*)(EB16 + (size_t)__ldg(&perm[p + q]) * 64) + l);
        addh8(s0, s1, vv[0]); addh8(t0, t1, vv[1]);
        addh8(u0, u1, vv[2]); addh8(v0, v1, vv[3]);
        addh8(s0, s1, vv[4]); addh8(t0, t1, vv[5]);
        addh8(u0, u1, vv[6]); addh8(v0, v1, vv[7]);
    }
    for (; p + 4 <= end; p += 4) {
        uint4 vv[4];
#pragma unroll
        for (int q = 0; q < 4; q++)
            vv[q] = __ldg((const uint4*)(EB16 + (size_t)__ldg(&perm[p + q]) * 64) + l);
        addh8(s0, s1, vv[0]); addh8(t0, t1, vv[1]);
        addh8(u0, u1, vv[2]); addh8(v0, v1, vv[3]);
    }
    for (; p < end; p++)
        addh8(s0, s1, __ldg((const uint4*)(EB16 + (size_t)__ldg(&perm[p]) * 64) + l));
    add4(s0, t0); add4(u0, v0); add4(s0, u0);
    add4(s1, t1); add4(u1, v1); add4(s1, u1);
    float a = __ldg(pa);
    float4 w0 = {0,0,0,0}, w1 = {0,0,0,0};
    addh8(w0, w1, __ldg((const uint4*)(T16 + (size_t)seg * 64) + l));
    add4(s0, prelu4(w0, a));
    add4(s1, prelu4(w1, a));
    float iv = __ldg(&invs[seg]);
    s0.x *= iv; s0.y *= iv; s0.z *= iv; s0.w *= iv;
    s1.x *= iv; s1.y *= iv; s1.z *= iv; s1.w *= iv;
    uint2 q0 = h4(s0), q1 = h4(s1);
    ((uint4*)(A16 + (size_t)seg * 64))[l] = make_uint4(q0.x, q0.y, q1.x, q1.y);
}

// ---------------- host driver ------------------------------------------------
static inline int cdiv(long a, long b) { return (int)((a + b - 1) / b); }

extern "C" void kernel_launch(void* const* d_in, const int* in_sizes, int n_in,
                              void* d_out, int out_size) {
    const float* x   = (const float*)d_in[0];
    const int*   hei = (const int*)d_in[1];
    const int*   hci = (const int*)d_in[2];
    const int*   nci = (const int*)d_in[3];

    const int NNZ = in_sizes[1] / 2;
    const int E   = in_sizes[2] / 2;
    const int N   = in_sizes[0] / D;
    const int C   = out_size / D - N - E;

    int wi = -1;
    for (int i = 4; i < n_in; i++) {
        if (in_sizes[i] == D * D) { wi = i; break; }
    }
    const float* pa = (const float*)d_in[wi - 1];

    const int* src  = hei;
    const int* dst  = hei + NNZ;
    const int* he_c = hci + E;
    const int* nc_c = nci + N;

    float *CE, *CN, *CT, *invd, *invs, *ic1, *ic2;
    unsigned *T16, *A16, *H16, *E16, *Wh;
    int *cd, *cs, *cc1, *cc2, *od, *os, *pd, *ps, *bsum, *bscan;
    cudaGetSymbolAddress((void**)&T16,  g_T16);
    cudaGetSymbolAddress((void**)&A16,  g_A16);
    cudaGetSymbolAddress((void**)&H16,  g_H16);
    cudaGetSymbolAddress((void**)&E16,  g_E16);
    cudaGetSymbolAddress((void**)&CE,   g_c1);
    cudaGetSymbolAddress((void**)&CN,   g_c2);
    cudaGetSymbolAddress((void**)&CT,   g_c3);
    cudaGetSymbolAddress((void**)&Wh,   g_Wh);
    cudaGetSymbolAddress((void**)&invd, g_invdst);
    cudaGetSymbolAddress((void**)&invs, g_invsrc);
    cudaGetSymbolAddress((void**)&ic1,  g_invc1);
    cudaGetSymbolAddress((void**)&ic2,  g_invc2);
    cudaGetSymbolAddress((void**)&cd,   g_cd);
    cudaGetSymbolAddress((void**)&cs,   g_cs);
    cudaGetSymbolAddress((void**)&cc1,  g_cc1);
    cudaGetSymbolAddress((void**)&cc2,  g_cc2);
    cudaGetSymbolAddress((void**)&od,   g_offs_d);
    cudaGetSymbolAddress((void**)&os,   g_offs_s);
    cudaGetSymbolAddress((void**)&pd,   g_perm_d);
    cudaGetSymbolAddress((void**)&ps,   g_perm_s);
    cudaGetSymbolAddress((void**)&bsum, g_bsum);
    cudaGetSymbolAddress((void**)&bscan,g_bscan);

    float* out   = (float*)d_out;
    float* out_n = out;
    float* out_e = out + (size_t)N * D;
    float* out_c = out + (size_t)(N + E) * D;

    const int TB = 256;
    const int nbd = cdiv(E, 1024);
    const int nbs = cdiv(N, 1024);
    const int nbtot = nbd + nbs;
    const int GT = cdiv(N, 128);

    const float* bv0 = (const float*)d_in[wi + 1];
    const float* be0 = (const float*)d_in[wi + 3];
    const float* bv1 = (const float*)d_in[wi + 9];
    const float* be1 = (const float*)d_in[wi + 11];

    cudaFuncSetAttribute(kgemm_tc, cudaFuncAttributeMaxDynamicSharedMemorySize, SM_TOT);

    kconvW<<<cdiv(4 * 128 * 16, TB), TB>>>((const float*)d_in[wi + 0], (const float*)d_in[wi + 2],
                                           (const float*)d_in[wi + 8], (const float*)d_in[wi + 10], Wh);
    kzero_counts<<<cdiv(E + N + 2 * C, TB), TB>>>(cd, cs, cc1, cc2, E, N, C);
    kcountall<<<cdiv(NNZ + E + N, TB), TB>>>(src, dst, he_c, nc_c, cs, cd, cc1, cc2,
                                             NNZ, E, N);
    // G1 = v2e layer 0 (fp32 input) -> T16 raw (launch index 3 for ncu)
    kgemm_tc<<<GT, 512, SM_TOT>>>(x, nullptr, Wh + 0 * 8192, bv0, pa,
                                  nullptr, 0, T16, 0, nullptr, nullptr, nullptr, N);
    kscanA<<<nbtot, 1024>>>(cd, cs, od, os, bsum, nbd, E, N);
    kscanB<<<1, 1024>>>(bsum, bscan, nbd, nbtot, NNZ);
    kscanC<<<nbtot, 1024>>>(od, os, bscan, cd, cs, nbd, E, N, NNZ);
    kfill<<<cdiv(NNZ, TB), TB>>>(src, dst, od, os, cd, cs, pd, ps, NNZ);
    kinvall<<<cdiv(E + N + 2 * C, TB), TB>>>(od, os, cc1, cc2, invd, invs, ic1, ic2,
                                             E, N, C);
    kzero4<<<cdiv((long)C * 32, TB), TB>>>((float4*)CE, (long)C * 32);
    kzero4<<<cdiv((long)C * 32, TB), TB>>>((float4*)CN, (long)C * 32);

    // ---- layer 0 ----
    kagg_e<<<cdiv((long)E * 16, TB), TB>>>(T16, pd, od, invd, pa, E16, nullptr,
                                           nullptr, nullptr, nullptr, E);
    kagg_n<<<cdiv((long)N * 16, TB), TB>>>(T16, E16, ps, os, invs, pa, A16, N);
    // G2 = e2v layer 0 -> H16 = prelu(A@We0+be0) fp16
    kgemm_tc<<<GT, 512, SM_TOT>>>(nullptr, A16, Wh + 1 * 8192, be0, pa,
                                  nullptr, 0, H16, 1, nullptr, nullptr, nullptr, N);

    // ---- layer 1 ----
    kgemm_tc<<<GT, 512, SM_TOT>>>(nullptr, H16, Wh + 2 * 8192, bv1, pa,
                                  nullptr, 0, T16, 0, nullptr, nullptr, nullptr, N);
    // kagg_e layer 1: writes out_e + fused edge->component scatter into CE
    kagg_e<<<cdiv((long)E * 16, TB), TB>>>(T16, pd, od, invd, pa, E16, out_e,
                                           he_c, ic1, CE, E);
    kagg_n<<<cdiv((long)N * 16, TB), TB>>>(T16, E16, ps, os, invs, pa, A16, N);
    // G4 = e2v layer 1 -> out_n fp32 prelu + fused node->component scatter into CN
    kgemm_tc<<<GT, 512, SM_TOT>>>(nullptr, A16, Wh + 3 * 8192, be1, pa,
                                  out_n, 1, nullptr, 0, nc_c, ic2, CN, N);

    // components: small GEMMs on aggregated C rows
    kgemm2<<<cdiv(C, 64), TB>>>(CE, (const float*)d_in[wi + 12], (const float*)d_in[wi + 13],
                                nullptr, CT, nullptr, pa, C);
    kgemm2<<<cdiv(C, 64), TB>>>(CN, (const float*)d_in[wi + 14], (const float*)d_in[wi + 15],
                                CT, nullptr, out_c, pa, C);
}

// round 14
// speedup vs baseline: 2.3498x; 1.0493x over previous
#include <cuda_runtime.h>
#include <cuda_fp16.h>
#include <cuda_bf16.h>
#include <mma.h>
#include <cstdint>
#include <cstddef>

#define D 128
using namespace nvcuda;

// ---------------- static scratch (device globals) ---------------------------
static __device__ unsigned g_T16[100000 * 64];   // v2e transform output (fp16 rows)
static __device__ unsigned g_A16[100000 * 64];   // aggregated node features (fp16)
static __device__ unsigned g_E16[50000  * 64];   // e fp16 rows
static __device__ float    g_c1 [2048   * 128];
static __device__ float    g_c2 [2048   * 128];
static __device__ float    g_c3 [2048   * 128];
static __device__ unsigned g_Wh [4 * 128 * 64];  // 4 W, fp16 [128][128]
static __device__ float g_invdst[50016];
static __device__ float g_invsrc[100016];
static __device__ float g_invc1[2048];
static __device__ float g_invc2[2048];
static __device__ int   g_cd [50016];
static __device__ int   g_cs [100016];
static __device__ int   g_cc1[2048];
static __device__ int   g_cc2[2048];
static __device__ int   g_offs_d[50024];
static __device__ int   g_offs_s[100024];
static __device__ int   g_perm_d[1600128];
static __device__ int   g_perm_s[1600128];
static __device__ int   g_bsum [1024];
static __device__ int   g_bscan[1024];

// ---------------- helpers ----------------------------------------------------
__device__ __forceinline__ unsigned long long pk2(float v) {
    unsigned long long r; unsigned u = __float_as_uint(v);
    asm("mov.b64 %0, {%1,%1};" : "=l"(r) : "r"(u));
    return r;
}
__device__ __forceinline__ void fma2(unsigned long long& d, unsigned long long a,
                                     unsigned long long b) {
    asm("fma.rn.f32x2 %0, %1, %2, %0;" : "+l"(d) : "l"(a), "l"(b));
}
__device__ __forceinline__ float2 up2(unsigned long long v) {
    unsigned lo, hi;
    asm("mov.b64 {%0,%1}, %2;" : "=r"(lo), "=r"(hi) : "l"(v));
    return make_float2(__uint_as_float(lo), __uint_as_float(hi));
}
__device__ __forceinline__ float prelu1(float v, float a) { return v >= 0.f ? v : a * v; }
__device__ __forceinline__ float4 prelu4(float4 v, float a) {
    return make_float4(prelu1(v.x, a), prelu1(v.y, a), prelu1(v.z, a), prelu1(v.w, a));
}
__device__ __forceinline__ void add4(float4& a, float4 b) {
    a.x += b.x; a.y += b.y; a.z += b.z; a.w += b.w;
}
__device__ __forceinline__ void addh8(float4& a, float4& b, uint4 v) {
    __half2 h0 = *reinterpret_cast<__half2*>(&v.x);
    __half2 h1 = *reinterpret_cast<__half2*>(&v.y);
    __half2 h2 = *reinterpret_cast<__half2*>(&v.z);
    __half2 h3 = *reinterpret_cast<__half2*>(&v.w);
    float2 f0 = __half22float2(h0), f1 = __half22float2(h1);
    float2 f2 = __half22float2(h2), f3 = __half22float2(h3);
    a.x += f0.x; a.y += f0.y; a.z += f1.x; a.w += f1.y;
    b.x += f2.x; b.y += f2.y; b.z += f3.x; b.w += f3.y;
}
__device__ __forceinline__ uint2 h4(float4 v) {
    __half2 h0 = __float22half2_rn(make_float2(v.x, v.y));
    __half2 h1 = __float22half2_rn(make_float2(v.z, v.w));
    uint2 r;
    r.x = *reinterpret_cast<unsigned*>(&h0);
    r.y = *reinterpret_cast<unsigned*>(&h1);
    return r;
}
__device__ __forceinline__ void cpasync16(void* smem_dst, const void* gsrc) {
    unsigned sa = (unsigned)__cvta_generic_to_shared(smem_dst);
    asm volatile("cp.async.cg.shared.global [%0], [%1], 16;" :: "r"(sa), "l"(gsrc));
}
__device__ __forceinline__ void red4(float* a, float4 v) {
    asm volatile("red.global.add.v4.f32 [%0], {%1,%2,%3,%4};"
                 :: "l"(a), "f"(v.x), "f"(v.y), "f"(v.z), "f"(v.w)
                 : "memory");
}
__device__ __forceinline__ void red2(float* a, float x, float y) {
    asm volatile("red.global.add.v2.f32 [%0], {%1,%2};"
                 :: "l"(a), "f"(x), "f"(y) : "memory");
}

// ---------------- setup 0: W convert + zero count arrays ---------------------
__global__ void ksetup0(const float* __restrict__ W0, const float* __restrict__ W1,
                        const float* __restrict__ W2, const float* __restrict__ W3,
                        unsigned* __restrict__ Wh,
                        int* cd, int* cs, int* cc1, int* cc2, int E, int N, int C) {
    int idx = blockIdx.x * blockDim.x + threadIdx.x;
    if (idx < 4 * 128 * 16) {
        int w = idx >> 11;
        int rem = idx & 2047;
        int kk = rem >> 4, g = rem & 15;
        const float* W = (w == 0) ? W0 : (w == 1) ? W1 : (w == 2) ? W2 : W3;
        float4 x0 = __ldg((const float4*)(W + (size_t)kk * D + g * 8));
        float4 x1 = __ldg((const float4*)(W + (size_t)kk * D + g * 8 + 4));
        uint2 p0 = h4(x0), p1 = h4(x1);
        ((uint4*)(Wh + (size_t)w * 128 * 64))[kk * 16 + g] = make_uint4(p0.x, p0.y, p1.x, p1.y);
        return;
    }
    int i = idx - 4 * 128 * 16;
    if (i < E) cd[i] = 0;
    else if (i < E + N) cs[i - E] = 0;
    else if (i < E + N + C) cc1[i - E - N] = 0;
    else if (i < E + N + 2 * C) cc2[i - E - N - C] = 0;
}

__global__ void kcountall(const int* __restrict__ src, const int* __restrict__ dst,
                          const int* __restrict__ he_c, const int* __restrict__ nc_c,
                          int* cs, int* cd, int* cc1, int* cc2,
                          int nnz, int E, int N) {
    int i = blockIdx.x * blockDim.x + threadIdx.x;
    if (i < nnz) {
        atomicAdd(&cd[dst[i]], 1);
        atomicAdd(&cs[src[i]], 1);
    } else if (i < nnz + E) {
        atomicAdd(&cc1[he_c[i - nnz]], 1);
    } else if (i < nnz + E + N) {
        atomicAdd(&cc2[nc_c[i - nnz - E]], 1);
    }
}

__global__ __launch_bounds__(1024) void kscanA(const int* __restrict__ cd,
                                               const int* __restrict__ cs,
                                               int* od, int* os, int* bsum,
                                               int nbd, int E, int N) {
    __shared__ int sh[1024];
    const int b = blockIdx.x, t = threadIdx.x;
    const bool isD = b < nbd;
    const int* in = isD ? cd : cs;
    int* out = isD ? od : os;
    const int n = isD ? E : N;
    const int i = (isD ? b : b - nbd) * 1024 + t;
    int v = (i < n) ? in[i] : 0;
    sh[t] = v;
    __syncthreads();
    for (int off = 1; off < 1024; off <<= 1) {
        int x = (t >= off) ? sh[t - off] : 0;
        __syncthreads();
        sh[t] += x;
        __syncthreads();
    }
    if (i < n) out[i] = sh[t] - v;
    if (t == 1023) bsum[b] = sh[1023];
}

__global__ __launch_bounds__(1024) void kscanB(const int* __restrict__ bsum,
                                               int* bscan, int nbd, int nbtot, int nnz) {
    __shared__ int sh[1024];
    int t = threadIdx.x;
    int v = (t < nbtot) ? bsum[t] : 0;
    sh[t] = v;
    __syncthreads();
    for (int off = 1; off < 1024; off <<= 1) {
        int x = (t >= off) ? sh[t - off] : 0;
        __syncthreads();
        sh[t] += x;
        __syncthreads();
    }
    if (t < nbtot) {
        int excl = sh[t] - v;
        bscan[t] = (t >= nbd) ? excl - nnz : excl;
    }
}

// add block offsets; init fill cursors = start offsets
__global__ __launch_bounds__(1024) void kscanC(int* od, int* os,
                                               const int* __restrict__ bscan,
                                               int* cd, int* cs,
                                               int nbd, int E, int N, int nnz) {
    const int b = blockIdx.x, t = threadIdx.x;
    const bool isD = b < nbd;
    const int i = (isD ? b : b - nbd) * 1024 + t;
    if (isD) {
        if (i < E) { int o = od[i] + bscan[b]; od[i] = o; cd[i] = o; }
        if (b == 0 && t == 0) od[E] = nnz;
    } else {
        if (i < N) { int o = os[i] + bscan[b]; os[i] = o; cs[i] = o; }
        if (i == 0) os[N] = nnz;
    }
}

__global__ void kfill(const int* __restrict__ src, const int* __restrict__ dst,
                      int* cur_d, int* cur_s, int* perm_d, int* perm_s, int nnz) {
    int k = blockIdx.x * blockDim.x + threadIdx.x;
    if (k >= nnz) return;
    int s = __ldg(&src[k]), d = __ldg(&dst[k]);
    perm_d[atomicAdd(&cur_d[d], 1)] = s;
    perm_s[atomicAdd(&cur_s[s], 1)] = d;
}

// inverses + zero component accumulators
__global__ void kinvzero(const int* __restrict__ od, const int* __restrict__ os,
                         const int* __restrict__ cc1, const int* __restrict__ cc2,
                         float* invd, float* invs, float* ic1, float* ic2,
                         float4* CE4, float4* CN4, int E, int N, int C) {
    int i = blockIdx.x * blockDim.x + threadIdx.x;
    if (i < E) {
        int c = od[i + 1] - od[i];
        invd[i] = 1.f / (float)(c > 0 ? c : 1);
    } else if (i < E + N) {
        int j = i - E;
        int c = os[j + 1] - os[j] + 1;
        invs[j] = 1.f / (float)c;
    } else if (i < E + N + C) {
        int c = cc1[i - E - N];
        ic1[i - E - N] = 1.f / (float)(c > 0 ? c : 1);
    } else if (i < E + N + 2 * C) {
        int c = cc2[i - E - N - C];
        ic2[i - E - N - C] = 1.f / (float)(c > 0 ? c : 1);
    } else {
        int j = i - (E + N + 2 * C);
        int z = C * 32;
        if (j < z) CE4[j] = make_float4(0.f, 0.f, 0.f, 0.f);
        else if (j < 2 * z) CN4[j - z] = make_float4(0.f, 0.f, 0.f, 0.f);
    }
}

// ---------------- WMMA GEMM (single): Y = X @ W + b --------------------------
#define AS_LD 136
#define BS_LD 136
#define SM_AS  (128 * AS_LD * 2)
#define SM_TOT (SM_AS + 128 * BS_LD * 2)
#define SM3_TOT (3 * SM_AS)

__global__ __launch_bounds__(512, 2) void kgemm_tc(const float* __restrict__ X32,
                                                   const unsigned* __restrict__ X16,
                                                   const unsigned* __restrict__ Wh,
                                                   const float* __restrict__ bias,
                                                   const float* __restrict__ pa,
                                                   float* __restrict__ out_f32,
                                                   int prelu_f32,
                                                   unsigned* __restrict__ out_h16,
                                                   int prelu_h16,
                                                   const int* __restrict__ ncomp,
                                                   const float* __restrict__ cinv,
                                                   float* __restrict__ csum, int M) {
    extern __shared__ char smem[];
    __half* As = (__half*)smem;
    __half* Bs = (__half*)(smem + SM_AS);
    const int tid = threadIdx.x;
    const int wid = tid >> 5;
    const int m0 = blockIdx.x * 128;

    if (X16) {
#pragma unroll
        for (int it = 0; it < 4; it++) {
            int idx = tid + it * 512;
            int r = idx >> 4, g = idx & 15;
            int gr = m0 + r;
            void* dst = As + (size_t)r * AS_LD + g * 8;
            if (gr < M) cpasync16(dst, (const uint4*)(X16 + (size_t)gr * 64) + g);
            else        *(uint4*)dst = make_uint4(0, 0, 0, 0);
        }
    } else {
#pragma unroll
        for (int it = 0; it < 4; it++) {
            int idx = tid + it * 512;
            int r = idx >> 4, g = idx & 15;
            int gr = m0 + r;
            float4 x0 = make_float4(0.f, 0.f, 0.f, 0.f), x1 = x0;
            if (gr < M) {
                x0 = __ldg((const float4*)(X32 + (size_t)gr * D + g * 8));
                x1 = __ldg((const float4*)(X32 + (size_t)gr * D + g * 8 + 4));
            }
            uint2 p0 = h4(x0), p1 = h4(x1);
            *(uint4*)(As + (size_t)r * AS_LD + g * 8) = make_uint4(p0.x, p0.y, p1.x, p1.y);
        }
    }
#pragma unroll
    for (int it = 0; it < 4; it++) {
        int idx = tid + it * 512;
        int kk = idx >> 4, g = idx & 15;
        cpasync16(Bs + (size_t)kk * BS_LD + g * 8, (const uint4*)Wh + kk * 16 + g);
    }
    asm volatile("cp.async.commit_group;" ::: "memory");
    asm volatile("cp.async.wait_group 0;" ::: "memory");
    __syncthreads();

    const int row0 = (wid & 3) * 32;
    const int n0   = (wid >> 2) * 32;
    wmma::fragment<wmma::accumulator, 16, 16, 16, float> acc[2][2];
#pragma unroll
    for (int i = 0; i < 2; i++)
#pragma unroll
        for (int j = 0; j < 2; j++) wmma::fill_fragment(acc[i][j], 0.f);

#pragma unroll
    for (int k = 0; k < 8; k++) {
        wmma::fragment<wmma::matrix_a, 16, 16, 16, __half, wmma::row_major> af[2];
        wmma::fragment<wmma::matrix_b, 16, 16, 16, __half, wmma::row_major> bf[2];
#pragma unroll
        for (int i = 0; i < 2; i++)
            wmma::load_matrix_sync(af[i], As + (size_t)(row0 + i * 16) * AS_LD + k * 16, AS_LD);
#pragma unroll
        for (int j = 0; j < 2; j++)
            wmma::load_matrix_sync(bf[j], Bs + (size_t)(k * 16) * BS_LD + n0 + j * 16, BS_LD);
#pragma unroll
        for (int i = 0; i < 2; i++)
#pragma unroll
            for (int j = 0; j < 2; j++)
                wmma::mma_sync(acc[i][j], af[i], bf[j], acc[i][j]);
    }

    {
        const float a = __ldg(pa);
        const int lane = tid & 31;
        const int g8  = lane >> 2;
        const int tg2 = (lane & 3) * 2;
#pragma unroll
        for (int i = 0; i < 2; i++) {
#pragma unroll
            for (int j = 0; j < 2; j++) {
                const int rb = m0 + row0 + i * 16;
                const int cb = n0 + j * 16;
#pragma unroll
                for (int e = 0; e < 8; e += 2) {
                    int r = rb + g8 + ((e & 2) ? 8 : 0);
                    int c = cb + tg2 + ((e & 4) ? 8 : 0);
                    if (r < M) {
                        float2 bb = __ldg((const float2*)(bias + c));
                        float vx = acc[i][j].x[e]     + bb.x;
                        float vy = acc[i][j].x[e + 1] + bb.y;
                        if (out_h16) {
                            float ox = prelu_h16 ? prelu1(vx, a) : vx;
                            float oy = prelu_h16 ? prelu1(vy, a) : vy;
                            __half2 hv = __floats2half2_rn(ox, oy);
                            *(unsigned*)(out_h16 + (size_t)r * 64 + (c >> 1)) =
                                *reinterpret_cast<unsigned*>(&hv);
                        }
                        if (out_f32) {
                            float ox = prelu_f32 ? prelu1(vx, a) : vx;
                            float oy = prelu_f32 ? prelu1(vy, a) : vy;
                            *(float2*)(out_f32 + (size_t)r * D + c) = make_float2(ox, oy);
                        }
                        if (csum) {
                            int cc = __ldg(&ncomp[r]);
                            float sc = __ldg(&cinv[cc]);
                            red2(csum + (size_t)cc * D + c, vx * sc, vy * sc);
                        }
                    }
                }
            }
        }
    }
}

// ---------------- WMMA double GEMM: out = (prelu(X@W1+b1))@W2 + b2 ----------
__global__ __launch_bounds__(512, 2) void kgemm_fused(const unsigned* __restrict__ X16,
                                                      const unsigned* __restrict__ Wh1,
                                                      const float* __restrict__ b1,
                                                      const unsigned* __restrict__ Wh2,
                                                      const float* __restrict__ b2,
                                                      const float* __restrict__ pa,
                                                      unsigned* __restrict__ out_h16,
                                                      int M) {
    extern __shared__ char smem[];
    __half* As = (__half*)smem;
    __half* B1 = (__half*)(smem + SM_AS);
    __half* B2 = (__half*)(smem + 2 * SM_AS);
    const int tid = threadIdx.x;
    const int wid = tid >> 5;
    const int m0 = blockIdx.x * 128;

#pragma unroll
    for (int it = 0; it < 4; it++) {
        int idx = tid + it * 512;
        int r = idx >> 4, g = idx & 15;
        int gr = m0 + r;
        void* dst = As + (size_t)r * AS_LD + g * 8;
        if (gr < M) cpasync16(dst, (const uint4*)(X16 + (size_t)gr * 64) + g);
        else        *(uint4*)dst = make_uint4(0, 0, 0, 0);
    }
#pragma unroll
    for (int it = 0; it < 4; it++) {
        int idx = tid + it * 512;
        int kk = idx >> 4, g = idx & 15;
        cpasync16(B1 + (size_t)kk * BS_LD + g * 8, (const uint4*)Wh1 + kk * 16 + g);
        cpasync16(B2 + (size_t)kk * BS_LD + g * 8, (const uint4*)Wh2 + kk * 16 + g);
    }
    asm volatile("cp.async.commit_group;" ::: "memory");
    asm volatile("cp.async.wait_group 0;" ::: "memory");
    __syncthreads();

    const int row0 = (wid & 3) * 32;
    const int n0   = (wid >> 2) * 32;
    const int lane = tid & 31;
    const int g8  = lane >> 2;
    const int tg2 = (lane & 3) * 2;
    const float a = __ldg(pa);

    wmma::fragment<wmma::accumulator, 16, 16, 16, float> acc[2][2];
#pragma unroll
    for (int i = 0; i < 2; i++)
#pragma unroll
        for (int j = 0; j < 2; j++) wmma::fill_fragment(acc[i][j], 0.f);

#pragma unroll
    for (int k = 0; k < 8; k++) {
        wmma::fragment<wmma::matrix_a, 16, 16, 16, __half, wmma::row_major> af[2];
        wmma::fragment<wmma::matrix_b, 16, 16, 16, __half, wmma::row_major> bf[2];
#pragma unroll
        for (int i = 0; i < 2; i++)
            wmma::load_matrix_sync(af[i], As + (size_t)(row0 + i * 16) * AS_LD + k * 16, AS_LD);
#pragma unroll
        for (int j = 0; j < 2; j++)
            wmma::load_matrix_sync(bf[j], B1 + (size_t)(k * 16) * BS_LD + n0 + j * 16, BS_LD);
#pragma unroll
        for (int i = 0; i < 2; i++)
#pragma unroll
            for (int j = 0; j < 2; j++)
                wmma::mma_sync(acc[i][j], af[i], bf[j], acc[i][j]);
    }
    __syncthreads();   // everyone done reading As

    // write H = prelu(acc + b1) into As (fp16), fragment-direct
#pragma unroll
    for (int i = 0; i < 2; i++) {
#pragma unroll
        for (int j = 0; j < 2; j++) {
            const int rl = row0 + i * 16;
            const int cb = n0 + j * 16;
#pragma unroll
            for (int e = 0; e < 8; e += 2) {
                int r = rl + g8 + ((e & 2) ? 8 : 0);
                int c = cb + tg2 + ((e & 4) ? 8 : 0);
                float2 bb = __ldg((const float2*)(b1 + c));
                float vx = prelu1(acc[i][j].x[e]     + bb.x, a);
                float vy = prelu1(acc[i][j].x[e + 1] + bb.y, a);
                __half2 hv = __floats2half2_rn(vx, vy);
                *(unsigned*)(As + (size_t)r * AS_LD + c) = *reinterpret_cast<unsigned*>(&hv);
            }
        }
    }
    __syncthreads();

    // second GEMM: T = H @ W2 + b2 (raw fp16 out)
#pragma unroll
    for (int i = 0; i < 2; i++)
#pragma unroll
        for (int j = 0; j < 2; j++) wmma::fill_fragment(acc[i][j], 0.f);
#pragma unroll
    for (int k = 0; k < 8; k++) {
        wmma::fragment<wmma::matrix_a, 16, 16, 16, __half, wmma::row_major> af[2];
        wmma::fragment<wmma::matrix_b, 16, 16, 16, __half, wmma::row_major> bf[2];
#pragma unroll
        for (int i = 0; i < 2; i++)
            wmma::load_matrix_sync(af[i], As + (size_t)(row0 + i * 16) * AS_LD + k * 16, AS_LD);
#pragma unroll
        for (int j = 0; j < 2; j++)
            wmma::load_matrix_sync(bf[j], B2 + (size_t)(k * 16) * BS_LD + n0 + j * 16, BS_LD);
#pragma unroll
        for (int i = 0; i < 2; i++)
#pragma unroll
            for (int j = 0; j < 2; j++)
                wmma::mma_sync(acc[i][j], af[i], bf[j], acc[i][j]);
    }
#pragma unroll
    for (int i = 0; i < 2; i++) {
#pragma unroll
        for (int j = 0; j < 2; j++) {
            const int rb = m0 + row0 + i * 16;
            const int cb = n0 + j * 16;
#pragma unroll
            for (int e = 0; e < 8; e += 2) {
                int r = rb + g8 + ((e & 2) ? 8 : 0);
                int c = cb + tg2 + ((e & 4) ? 8 : 0);
                if (r < M) {
                    float2 bb = __ldg((const float2*)(b2 + c));
                    __half2 hv = __floats2half2_rn(acc[i][j].x[e] + bb.x,
                                                   acc[i][j].x[e + 1] + bb.y);
                    *(unsigned*)(out_h16 + (size_t)r * 64 + (c >> 1)) =
                        *reinterpret_cast<unsigned*>(&hv);
                }
            }
        }
    }
}

// ---------------- SIMT GEMM (small C-row GEMMs) ------------------------------
__global__ __launch_bounds__(256) void kgemm2(const float* __restrict__ X,
                                              const float* __restrict__ W,
                                              const float* __restrict__ b,
                                              const float* __restrict__ addin,
                                              float* __restrict__ Yraw,
                                              float* __restrict__ Ypre,
                                              const float* __restrict__ pa, int M) {
    __shared__ float As[64][128];
    const int m0 = blockIdx.x * 64;
    const int t = threadIdx.x;
    {
        const int c4 = t & 31;
        const int r0 = t >> 5;
#pragma unroll
        for (int s = 0; s < 8; s++) {
            int r = r0 + 8 * s;
            int gr = m0 + r;
            float4 v = make_float4(0.f, 0.f, 0.f, 0.f);
            if (gr < M) v = ((const float4*)(X + (size_t)gr * D))[c4];
            ((float4*)(&As[r][0]))[c4] = v;
        }
    }
    __syncthreads();
    const int cg = (t & 15) * 8;
    const int rg = (t >> 4) * 4;
    unsigned long long acc[4][4];
#pragma unroll
    for (int i = 0; i < 4; i++)
#pragma unroll
        for (int j = 0; j < 4; j++) acc[i][j] = 0ULL;
#pragma unroll 4
    for (int k = 0; k < D; k += 4) {
        float4 a[4];
#pragma unroll
        for (int i = 0; i < 4; i++) a[i] = *(const float4*)&As[rg + i][k];
#pragma unroll
        for (int kk = 0; kk < 4; kk++) {
            const ulonglong2 w0 = *reinterpret_cast<const ulonglong2*>(&W[(k + kk) * D + cg]);
            const ulonglong2 w1 = *reinterpret_cast<const ulonglong2*>(&W[(k + kk) * D + cg + 4]);
#pragma unroll
            for (int i = 0; i < 4; i++) {
                float av = (kk == 0) ? a[i].x : (kk == 1) ? a[i].y
                         : (kk == 2) ? a[i].z : a[i].w;
                unsigned long long av2 = pk2(av);
                fma2(acc[i][0], av2, w0.x);
                fma2(acc[i][1], av2, w0.y);
                fma2(acc[i][2], av2, w1.x);
                fma2(acc[i][3], av2, w1.y);
            }
        }
    }
    const float4 b0 = __ldg((const float4*)&b[cg]);
    const float4 b1 = __ldg((const float4*)&b[cg + 4]);
    const float a = __ldg(pa);
#pragma unroll
    for (int i = 0; i < 4; i++) {
        int gr = m0 + rg + i;
        if (gr >= M) continue;
        float2 p0 = up2(acc[i][0]), p1 = up2(acc[i][1]);
        float2 p2 = up2(acc[i][2]), p3 = up2(acc[i][3]);
        float4 o0 = make_float4(p0.x + b0.x, p0.y + b0.y, p1.x + b0.z, p1.y + b0.w);
        float4 o1 = make_float4(p2.x + b1.x, p2.y + b1.y, p3.x + b1.z, p3.y + b1.w);
        if (addin) {
            const float4* ar = (const float4*)(addin + (size_t)gr * D);
            add4(o0, ar[cg / 4]); add4(o1, ar[cg / 4 + 1]);
        }
        if (Yraw) {
            float4* yr = (float4*)(Yraw + (size_t)gr * D);
            yr[cg / 4] = o0; yr[cg / 4 + 1] = o1;
        }
        if (Ypre) {
            float4* yp = (float4*)(Ypre + (size_t)gr * D);
            yp[cg / 4] = prelu4(o0, a); yp[cg / 4 + 1] = prelu4(o1, a);
        }
    }
}

// ---------------- CSR aggregation (half-warp/segment, 8-deep MLP batches) ----
__global__ __launch_bounds__(256) void kagg_e(const unsigned* __restrict__ T16,
                                              const int* __restrict__ perm,
                                              const int* __restrict__ offs,
                                              const float* __restrict__ invd,
                                              const float* __restrict__ pa,
                                              unsigned* __restrict__ EB16,
                                              float* __restrict__ out_e,
                                              const int* __restrict__ ecomp,
                                              const float* __restrict__ cinv,
                                              float* __restrict__ csum, int E) {
    int seg = (blockIdx.x * blockDim.x + threadIdx.x) >> 4;
    int l = threadIdx.x & 15;
    if (seg >= E) return;
    int beg = __ldg(&offs[seg]), end = __ldg(&offs[seg + 1]);
    float4 s0 = {0,0,0,0}, s1 = {0,0,0,0}, t0 = {0,0,0,0}, t1 = {0,0,0,0};
    float4 u0 = {0,0,0,0}, u1 = {0,0,0,0}, v0 = {0,0,0,0}, v1 = {0,0,0,0};
    int p = beg;
    for (; p + 8 <= end; p += 8) {
        uint4 vv[8];
#pragma unroll
        for (int q = 0; q < 8; q++)
            vv[q] = __ldg((const uint4*)(T16 + (size_t)__ldg(&perm[p + q]) * 64) + l);
        addh8(s0, s1, vv[0]); addh8(t0, t1, vv[1]);
        addh8(u0, u1, vv[2]); addh8(v0, v1, vv[3]);
        addh8(s0, s1, vv[4]); addh8(t0, t1, vv[5]);
        addh8(u0, u1, vv[6]); addh8(v0, v1, vv[7]);
    }
    for (; p + 4 <= end; p += 4) {
        uint4 vv[4];
#pragma unroll
        for (int q = 0; q < 4; q++)
            vv[q] = __ldg((const uint4*)(T16 + (size_t)__ldg(&perm[p + q]) * 64) + l);
        addh8(s0, s1, vv[0]); addh8(t0, t1, vv[1]);
        addh8(u0, u1, vv[2]); addh8(v0, v1, vv[3]);
    }
    for (; p < end; p++)
        addh8(s0, s1, __ldg((const uint4*)(T16 + (size_t)__ldg(&perm[p]) * 64) + l));
    add4(s0, t0); add4(u0, v0); add4(s0, u0);
    add4(s1, t1); add4(u1, v1); add4(s1, u1);
    float iv = __ldg(&invd[seg]);
    float a = __ldg(pa);
    s0.x *= iv; s0.y *= iv; s0.z *= iv; s0.w *= iv;
    s1.x *= iv; s1.y *= iv; s1.z *= iv; s1.w *= iv;
    float4 r0 = prelu4(s0, a), r1 = prelu4(s1, a);
    uint2 q0 = h4(r0), q1 = h4(r1);
    ((uint4*)(EB16 + (size_t)seg * 64))[l] = make_uint4(q0.x, q0.y, q1.x, q1.y);
    if (out_e) {
        ((float4*)out_e)[(size_t)seg * 32 + l * 2]     = r0;
        ((float4*)out_e)[(size_t)seg * 32 + l * 2 + 1] = r1;
    }
    if (csum) {
        int cc = __ldg(&ecomp[seg]);
        float sc = __ldg(&cinv[cc]);
        float4 w0 = make_float4(r0.x * sc, r0.y * sc, r0.z * sc, r0.w * sc);
        float4 w1 = make_float4(r1.x * sc, r1.y * sc, r1.z * sc, r1.w * sc);
        red4(csum + (size_t)cc * D + l * 8,     w0);
        red4(csum + (size_t)cc * D + l * 8 + 4, w1);
    }
}

__global__ __launch_bounds__(256) void kagg_n(const unsigned* __restrict__ T16,
                                              const unsigned* __restrict__ EB16,
                                              const int* __restrict__ perm,
                                              const int* __restrict__ offs,
                                              const float* __restrict__ invs,
                                              const float* __restrict__ pa,
                                              unsigned* __restrict__ A16, int N) {
    int seg = (blockIdx.x * blockDim.x + threadIdx.x) >> 4;
    int l = threadIdx.x & 15;
    if (seg >= N) return;
    int beg = __ldg(&offs[seg]), end = __ldg(&offs[seg + 1]);
    float4 s0 = {0,0,0,0}, s1 = {0,0,0,0}, t0 = {0,0,0,0}, t1 = {0,0,0,0};
    float4 u0 = {0,0,0,0}, u1 = {0,0,0,0}, v0 = {0,0,0,0}, v1 = {0,0,0,0};
    int p = beg;
    for (; p + 8 <= end; p += 8) {
        uint4 vv[8];
#pragma unroll
        for (int q = 0; q < 8; q++)
            vv[q] = __ldg((const uint4*)(EB16 + (size_t)__ldg(&perm[p + q]) * 64) + l);
        addh8(s0, s1, vv[0]); addh8(t0, t1, vv[1]);
        addh8(u0, u1, vv[2]); addh8(v0, v1, vv[3]);
        addh8(s0, s1, vv[4]); addh8(t0, t1, vv[5]);
        addh8(u0, u1, vv[6]); addh8(v0, v1, vv[7]);
    }
    for (; p + 4 <= end; p += 4) {
        uint4 vv[4];
#pragma unroll
        for (int q = 0; q < 4; q++)
            vv[q] = __ldg((const uint4*)(EB16 + (size_t)__ldg(&perm[p + q]) * 64) + l);
        addh8(s0, s1, vv[0]); addh8(t0, t1, vv[1]);
        addh8(u0, u1, vv[2]); addh8(v0, v1, vv[3]);
    }
    for (; p < end; p++)
        addh8(s0, s1, __ldg((const uint4*)(EB16 + (size_t)__ldg(&perm[p]) * 64) + l));
    add4(s0, t0); add4(u0, v0); add4(s0, u0);
    add4(s1, t1); add4(u1, v1); add4(s1, u1);
    float a = __ldg(pa);
    float4 w0 = {0,0,0,0}, w1 = {0,0,0,0};
    addh8(w0, w1, __ldg((const uint4*)(T16 + (size_t)seg * 64) + l));
    add4(s0, prelu4(w0, a));
    add4(s1, prelu4(w1, a));
    float iv = __ldg(&invs[seg]);
    s0.x *= iv; s0.y *= iv; s0.z *= iv; s0.w *= iv;
    s1.x *= iv; s1.y *= iv; s1.z *= iv; s1.w *= iv;
    uint2 q0 = h4(s0), q1 = h4(s1);
    ((uint4*)(A16 + (size_t)seg * 64))[l] = make_uint4(q0.x, q0.y, q1.x, q1.y);
}

// ---------------- host driver ------------------------------------------------
static inline int cdiv(long a, long b) { return (int)((a + b - 1) / b); }

extern "C" void kernel_launch(void* const* d_in, const int* in_sizes, int n_in,
                              void* d_out, int out_size) {
    const float* x   = (const float*)d_in[0];
    const int*   hei = (const int*)d_in[1];
    const int*   hci = (const int*)d_in[2];
    const int*   nci = (const int*)d_in[3];

    const int NNZ = in_sizes[1] / 2;
    const int E   = in_sizes[2] / 2;
    const int N   = in_sizes[0] / D;
    const int C   = out_size / D - N - E;

    int wi = -1;
    for (int i = 4; i < n_in; i++) {
        if (in_sizes[i] == D * D) { wi = i; break; }
    }
    const float* pa = (const float*)d_in[wi - 1];

    const int* src  = hei;
    const int* dst  = hei + NNZ;
    const int* he_c = hci + E;
    const int* nc_c = nci + N;

    float *CE, *CN, *CT, *invd, *invs, *ic1, *ic2;
    unsigned *T16, *A16, *E16, *Wh;
    int *cd, *cs, *cc1, *cc2, *od, *os, *pd, *ps, *bsum, *bscan;
    cudaGetSymbolAddress((void**)&T16,  g_T16);
    cudaGetSymbolAddress((void**)&A16,  g_A16);
    cudaGetSymbolAddress((void**)&E16,  g_E16);
    cudaGetSymbolAddress((void**)&CE,   g_c1);
    cudaGetSymbolAddress((void**)&CN,   g_c2);
    cudaGetSymbolAddress((void**)&CT,   g_c3);
    cudaGetSymbolAddress((void**)&Wh,   g_Wh);
    cudaGetSymbolAddress((void**)&invd, g_invdst);
    cudaGetSymbolAddress((void**)&invs, g_invsrc);
    cudaGetSymbolAddress((void**)&ic1,  g_invc1);
    cudaGetSymbolAddress((void**)&ic2,  g_invc2);
    cudaGetSymbolAddress((void**)&cd,   g_cd);
    cudaGetSymbolAddress((void**)&cs,   g_cs);
    cudaGetSymbolAddress((void**)&cc1,  g_cc1);
    cudaGetSymbolAddress((void**)&cc2,  g_cc2);
    cudaGetSymbolAddress((void**)&od,   g_offs_d);
    cudaGetSymbolAddress((void**)&os,   g_offs_s);
    cudaGetSymbolAddress((void**)&pd,   g_perm_d);
    cudaGetSymbolAddress((void**)&ps,   g_perm_s);
    cudaGetSymbolAddress((void**)&bsum, g_bsum);
    cudaGetSymbolAddress((void**)&bscan,g_bscan);

    float* out   = (float*)d_out;
    float* out_n = out;
    float* out_e = out + (size_t)N * D;
    float* out_c = out + (size_t)(N + E) * D;

    const int TB = 256;
    const int nbd = cdiv(E, 1024);
    const int nbs = cdiv(N, 1024);
    const int nbtot = nbd + nbs;
    const int GT = cdiv(N, 128);

    const float* bv0 = (const float*)d_in[wi + 1];
    const float* be0 = (const float*)d_in[wi + 3];
    const float* bv1 = (const float*)d_in[wi + 9];
    const float* be1 = (const float*)d_in[wi + 11];

    cudaFuncSetAttribute(kgemm_tc, cudaFuncAttributeMaxDynamicSharedMemorySize, SM_TOT);
    cudaFuncSetAttribute(kgemm_fused, cudaFuncAttributeMaxDynamicSharedMemorySize, SM3_TOT);

    ksetup0<<<cdiv(4 * 128 * 16 + E + N + 2 * C, TB), TB>>>(
        (const float*)d_in[wi + 0], (const float*)d_in[wi + 2],
        (const float*)d_in[wi + 8], (const float*)d_in[wi + 10], Wh,
        cd, cs, cc1, cc2, E, N, C);
    kcountall<<<cdiv(NNZ + E + N, TB), TB>>>(src, dst, he_c, nc_c, cs, cd, cc1, cc2,
                                             NNZ, E, N);
    // G1 = v2e layer 0 (fp32 input) -> T16 raw
    kgemm_tc<<<GT, 512, SM_TOT>>>(x, nullptr, Wh + 0 * 8192, bv0, pa,
                                  nullptr, 0, T16, 0, nullptr, nullptr, nullptr, N);
    kscanA<<<nbtot, 1024>>>(cd, cs, od, os, bsum, nbd, E, N);
    kscanB<<<1, 1024>>>(bsum, bscan, nbd, nbtot, NNZ);
    kscanC<<<nbtot, 1024>>>(od, os, bscan, cd, cs, nbd, E, N, NNZ);
    kfill<<<cdiv(NNZ, TB), TB>>>(src, dst, cd, cs, pd, ps, NNZ);
    kinvzero<<<cdiv(E + N + 2 * C + 2 * C * 32, TB), TB>>>(od, os, cc1, cc2,
                                                           invd, invs, ic1, ic2,
                                                           (float4*)CE, (float4*)CN,
                                                           E, N, C);

    // ---- layer 0 ----
    kagg_e<<<cdiv((long)E * 16, TB), TB>>>(T16, pd, od, invd, pa, E16, nullptr,
                                           nullptr, nullptr, nullptr, E);
    kagg_n<<<cdiv((long)N * 16, TB), TB>>>(T16, E16, ps, os, invs, pa, A16, N);
    // G2+G3 fused: T16 = prelu(A@We0+be0) @ Wv1 + bv1
    kgemm_fused<<<GT, 512, SM3_TOT>>>(A16, Wh + 1 * 8192, be0,
                                      Wh + 2 * 8192, bv1, pa, T16, N);

    // ---- layer 1 ----
    kagg_e<<<cdiv((long)E * 16, TB), TB>>>(T16, pd, od, invd, pa, E16, out_e,
                                           he_c, ic1, CE, E);
    kagg_n<<<cdiv((long)N * 16, TB), TB>>>(T16, E16, ps, os, invs, pa, A16, N);
    // G4 = e2v layer 1 -> out_n fp32 prelu + fused node->component scatter
    kgemm_tc<<<GT, 512, SM_TOT>>>(nullptr, A16, Wh + 3 * 8192, be1, pa,
                                  out_n, 1, nullptr, 0, nc_c, ic2, CN, N);

    // components
    kgemm2<<<cdiv(C, 64), TB>>>(CE, (const float*)d_in[wi + 12], (const float*)d_in[wi + 13],
                                nullptr, CT, nullptr, pa, C);
    kgemm2<<<cdiv(C, 64), TB>>>(CN, (const float*)d_in[wi + 14], (const float*)d_in[wi + 15],
                                CT, nullptr, out_c, pa, C);
}

// round 15
// speedup vs baseline: 2.5618x; 1.0902x over previous
#include <cuda_runtime.h>
#include <cuda_fp16.h>
#include <cuda_bf16.h>
#include <mma.h>
#include <cstdint>
#include <cstddef>

#define D 128
using namespace nvcuda;

// ---------------- static scratch (device globals) ---------------------------
static __device__ unsigned g_T16[100000 * 64];   // v2e transform output (fp16 rows)
static __device__ unsigned g_A16[100000 * 64];   // aggregated node features (fp16)
static __device__ unsigned g_E16[50000  * 64];   // e fp16 rows
static __device__ float    g_c1 [2048   * 128];
static __device__ float    g_c2 [2048   * 128];
static __device__ float    g_c3 [2048   * 128];
static __device__ unsigned g_Wh [4 * 128 * 64];  // 4 W, fp16 [128][128]
static __device__ float g_invdst[50016];
static __device__ float g_invsrc[100016];
static __device__ float g_invc1[2048];
static __device__ float g_invc2[2048];
static __device__ int   g_cd [50016];
static __device__ int   g_cs [100016];
static __device__ int   g_cc1[2048];
static __device__ int   g_cc2[2048];
static __device__ int   g_offs_d[50024];
static __device__ int   g_offs_s[100024];
static __device__ int   g_perm_d[1600128];
static __device__ int   g_perm_s[1600128];
static __device__ int   g_bsum [1024];
static __device__ int   g_bscan[1024];

// ---------------- helpers ----------------------------------------------------
__device__ __forceinline__ unsigned long long pk2(float v) {
    unsigned long long r; unsigned u = __float_as_uint(v);
    asm("mov.b64 %0, {%1,%1};" : "=l"(r) : "r"(u));
    return r;
}
__device__ __forceinline__ void fma2(unsigned long long& d, unsigned long long a,
                                     unsigned long long b) {
    asm("fma.rn.f32x2 %0, %1, %2, %0;" : "+l"(d) : "l"(a), "l"(b));
}
__device__ __forceinline__ float2 up2(unsigned long long v) {
    unsigned lo, hi;
    asm("mov.b64 {%0,%1}, %2;" : "=r"(lo), "=r"(hi) : "l"(v));
    return make_float2(__uint_as_float(lo), __uint_as_float(hi));
}
__device__ __forceinline__ float prelu1(float v, float a) { return v >= 0.f ? v : a * v; }
__device__ __forceinline__ float4 prelu4(float4 v, float a) {
    return make_float4(prelu1(v.x, a), prelu1(v.y, a), prelu1(v.z, a), prelu1(v.w, a));
}
__device__ __forceinline__ void add4(float4& a, float4 b) {
    a.x += b.x; a.y += b.y; a.z += b.z; a.w += b.w;
}
__device__ __forceinline__ void addh8(float4& a, float4& b, uint4 v) {
    __half2 h0 = *reinterpret_cast<__half2*>(&v.x);
    __half2 h1 = *reinterpret_cast<__half2*>(&v.y);
    __half2 h2 = *reinterpret_cast<__half2*>(&v.z);
    __half2 h3 = *reinterpret_cast<__half2*>(&v.w);
    float2 f0 = __half22float2(h0), f1 = __half22float2(h1);
    float2 f2 = __half22float2(h2), f3 = __half22float2(h3);
    a.x += f0.x; a.y += f0.y; a.z += f1.x; a.w += f1.y;
    b.x += f2.x; b.y += f2.y; b.z += f3.x; b.w += f3.y;
}
__device__ __forceinline__ uint2 h4(float4 v) {
    __half2 h0 = __float22half2_rn(make_float2(v.x, v.y));
    __half2 h1 = __float22half2_rn(make_float2(v.z, v.w));
    uint2 r;
    r.x = *reinterpret_cast<unsigned*>(&h0);
    r.y = *reinterpret_cast<unsigned*>(&h1);
    return r;
}
__device__ __forceinline__ void cpasync16(void* smem_dst, const void* gsrc) {
    unsigned sa = (unsigned)__cvta_generic_to_shared(smem_dst);
    asm volatile("cp.async.cg.shared.global [%0], [%1], 16;" :: "r"(sa), "l"(gsrc));
}
__device__ __forceinline__ void red4(float* a, float4 v) {
    asm volatile("red.global.add.v4.f32 [%0], {%1,%2,%3,%4};"
                 :: "l"(a), "f"(v.x), "f"(v.y), "f"(v.z), "f"(v.w)
                 : "memory");
}
__device__ __forceinline__ void red2(float* a, float x, float y) {
    asm volatile("red.global.add.v2.f32 [%0], {%1,%2};"
                 :: "l"(a), "f"(x), "f"(y) : "memory");
}

// ---------------- setup 0: W convert + zero count arrays ---------------------
__global__ void ksetup0(const float* __restrict__ W0, const float* __restrict__ W1,
                        const float* __restrict__ W2, const float* __restrict__ W3,
                        unsigned* __restrict__ Wh,
                        int* cd, int* cs, int* cc1, int* cc2, int E, int N, int C) {
    int idx = blockIdx.x * blockDim.x + threadIdx.x;
    if (idx < 4 * 128 * 16) {
        int w = idx >> 11;
        int rem = idx & 2047;
        int kk = rem >> 4, g = rem & 15;
        const float* W = (w == 0) ? W0 : (w == 1) ? W1 : (w == 2) ? W2 : W3;
        float4 x0 = __ldg((const float4*)(W + (size_t)kk * D + g * 8));
        float4 x1 = __ldg((const float4*)(W + (size_t)kk * D + g * 8 + 4));
        uint2 p0 = h4(x0), p1 = h4(x1);
        ((uint4*)(Wh + (size_t)w * 128 * 64))[kk * 16 + g] = make_uint4(p0.x, p0.y, p1.x, p1.y);
        return;
    }
    int i = idx - 4 * 128 * 16;
    if (i < E) cd[i] = 0;
    else if (i < E + N) cs[i - E] = 0;
    else if (i < E + N + C) cc1[i - E - N] = 0;
    else if (i < E + N + 2 * C) cc2[i - E - N - C] = 0;
}

__global__ void kcountall(const int* __restrict__ src, const int* __restrict__ dst,
                          const int* __restrict__ he_c, const int* __restrict__ nc_c,
                          int* cs, int* cd, int* cc1, int* cc2,
                          int nnz, int E, int N) {
    int i = blockIdx.x * blockDim.x + threadIdx.x;
    if (i < nnz) {
        atomicAdd(&cd[dst[i]], 1);
        atomicAdd(&cs[src[i]], 1);
    } else if (i < nnz + E) {
        atomicAdd(&cc1[he_c[i - nnz]], 1);
    } else if (i < nnz + E + N) {
        atomicAdd(&cc2[nc_c[i - nnz - E]], 1);
    }
}

__global__ __launch_bounds__(1024) void kscanA(const int* __restrict__ cd,
                                               const int* __restrict__ cs,
                                               int* od, int* os, int* bsum,
                                               int nbd, int E, int N) {
    __shared__ int sh[1024];
    const int b = blockIdx.x, t = threadIdx.x;
    const bool isD = b < nbd;
    const int* in = isD ? cd : cs;
    int* out = isD ? od : os;
    const int n = isD ? E : N;
    const int i = (isD ? b : b - nbd) * 1024 + t;
    int v = (i < n) ? in[i] : 0;
    sh[t] = v;
    __syncthreads();
    for (int off = 1; off < 1024; off <<= 1) {
        int x = (t >= off) ? sh[t - off] : 0;
        __syncthreads();
        sh[t] += x;
        __syncthreads();
    }
    if (i < n) out[i] = sh[t] - v;
    if (t == 1023) bsum[b] = sh[1023];
}

__global__ __launch_bounds__(1024) void kscanB(const int* __restrict__ bsum,
                                               int* bscan, int nbd, int nbtot, int nnz) {
    __shared__ int sh[1024];
    int t = threadIdx.x;
    int v = (t < nbtot) ? bsum[t] : 0;
    sh[t] = v;
    __syncthreads();
    for (int off = 1; off < 1024; off <<= 1) {
        int x = (t >= off) ? sh[t - off] : 0;
        __syncthreads();
        sh[t] += x;
        __syncthreads();
    }
    if (t < nbtot) {
        int excl = sh[t] - v;
        bscan[t] = (t >= nbd) ? excl - nnz : excl;
    }
}

// add block offsets; init fill cursors = start offsets
__global__ __launch_bounds__(1024) void kscanC(int* od, int* os,
                                               const int* __restrict__ bscan,
                                               int* cd, int* cs,
                                               int nbd, int E, int N, int nnz) {
    const int b = blockIdx.x, t = threadIdx.x;
    const bool isD = b < nbd;
    const int i = (isD ? b : b - nbd) * 1024 + t;
    if (isD) {
        if (i < E) { int o = od[i] + bscan[b]; od[i] = o; cd[i] = o; }
        if (b == 0 && t == 0) od[E] = nnz;
    } else {
        if (i < N) { int o = os[i] + bscan[b]; os[i] = o; cs[i] = o; }
        if (i == 0) os[N] = nnz;
    }
}

__global__ void kfill(const int* __restrict__ src, const int* __restrict__ dst,
                      int* cur_d, int* cur_s, int* perm_d, int* perm_s, int nnz) {
    int k = blockIdx.x * blockDim.x + threadIdx.x;
    if (k >= nnz) return;
    int s = __ldg(&src[k]), d = __ldg(&dst[k]);
    perm_d[atomicAdd(&cur_d[d], 1)] = s;
    perm_s[atomicAdd(&cur_s[s], 1)] = d;
}

// inverses + zero component accumulators
__global__ void kinvzero(const int* __restrict__ od, const int* __restrict__ os,
                         const int* __restrict__ cc1, const int* __restrict__ cc2,
                         float* invd, float* invs, float* ic1, float* ic2,
                         float4* CE4, float4* CN4, int E, int N, int C) {
    int i = blockIdx.x * blockDim.x + threadIdx.x;
    if (i < E) {
        int c = od[i + 1] - od[i];
        invd[i] = 1.f / (float)(c > 0 ? c : 1);
    } else if (i < E + N) {
        int j = i - E;
        int c = os[j + 1] - os[j] + 1;
        invs[j] = 1.f / (float)c;
    } else if (i < E + N + C) {
        int c = cc1[i - E - N];
        ic1[i - E - N] = 1.f / (float)(c > 0 ? c : 1);
    } else if (i < E + N + 2 * C) {
        int c = cc2[i - E - N - C];
        ic2[i - E - N - C] = 1.f / (float)(c > 0 ? c : 1);
    } else {
        int j = i - (E + N + 2 * C);
        int z = C * 32;
        if (j < z) CE4[j] = make_float4(0.f, 0.f, 0.f, 0.f);
        else if (j < 2 * z) CN4[j - z] = make_float4(0.f, 0.f, 0.f, 0.f);
    }
}

// ---------------- WMMA GEMM (single): Y = X @ W + b --------------------------
#define AS_LD 136
#define BS_LD 136
#define SM_AS  (128 * AS_LD * 2)
#define SM_TOT (SM_AS + 128 * BS_LD * 2)
#define SM3_TOT (3 * SM_AS)

__global__ __launch_bounds__(512, 2) void kgemm_tc(const float* __restrict__ X32,
                                                   const unsigned* __restrict__ X16,
                                                   const unsigned* __restrict__ Wh,
                                                   const float* __restrict__ bias,
                                                   const float* __restrict__ pa,
                                                   float* __restrict__ out_f32,
                                                   int prelu_f32,
                                                   unsigned* __restrict__ out_h16,
                                                   int prelu_h16,
                                                   const int* __restrict__ ncomp,
                                                   const float* __restrict__ cinv,
                                                   float* __restrict__ csum, int M) {
    extern __shared__ char smem[];
    __half* As = (__half*)smem;
    __half* Bs = (__half*)(smem + SM_AS);
    const int tid = threadIdx.x;
    const int wid = tid >> 5;
    const int m0 = blockIdx.x * 128;

    if (X16) {
#pragma unroll
        for (int it = 0; it < 4; it++) {
            int idx = tid + it * 512;
            int r = idx >> 4, g = idx & 15;
            int gr = m0 + r;
            void* dst = As + (size_t)r * AS_LD + g * 8;
            if (gr < M) cpasync16(dst, (const uint4*)(X16 + (size_t)gr * 64) + g);
            else        *(uint4*)dst = make_uint4(0, 0, 0, 0);
        }
    } else {
#pragma unroll
        for (int it = 0; it < 4; it++) {
            int idx = tid + it * 512;
            int r = idx >> 4, g = idx & 15;
            int gr = m0 + r;
            float4 x0 = make_float4(0.f, 0.f, 0.f, 0.f), x1 = x0;
            if (gr < M) {
                x0 = __ldg((const float4*)(X32 + (size_t)gr * D + g * 8));
                x1 = __ldg((const float4*)(X32 + (size_t)gr * D + g * 8 + 4));
            }
            uint2 p0 = h4(x0), p1 = h4(x1);
            *(uint4*)(As + (size_t)r * AS_LD + g * 8) = make_uint4(p0.x, p0.y, p1.x, p1.y);
        }
    }
#pragma unroll
    for (int it = 0; it < 4; it++) {
        int idx = tid + it * 512;
        int kk = idx >> 4, g = idx & 15;
        cpasync16(Bs + (size_t)kk * BS_LD + g * 8, (const uint4*)Wh + kk * 16 + g);
    }
    asm volatile("cp.async.commit_group;" ::: "memory");
    asm volatile("cp.async.wait_group 0;" ::: "memory");
    __syncthreads();

    const int row0 = (wid & 3) * 32;
    const int n0   = (wid >> 2) * 32;
    wmma::fragment<wmma::accumulator, 16, 16, 16, float> acc[2][2];
#pragma unroll
    for (int i = 0; i < 2; i++)
#pragma unroll
        for (int j = 0; j < 2; j++) wmma::fill_fragment(acc[i][j], 0.f);

#pragma unroll
    for (int k = 0; k < 8; k++) {
        wmma::fragment<wmma::matrix_a, 16, 16, 16, __half, wmma::row_major> af[2];
        wmma::fragment<wmma::matrix_b, 16, 16, 16, __half, wmma::row_major> bf[2];
#pragma unroll
        for (int i = 0; i < 2; i++)
            wmma::load_matrix_sync(af[i], As + (size_t)(row0 + i * 16) * AS_LD + k * 16, AS_LD);
#pragma unroll
        for (int j = 0; j < 2; j++)
            wmma::load_matrix_sync(bf[j], Bs + (size_t)(k * 16) * BS_LD + n0 + j * 16, BS_LD);
#pragma unroll
        for (int i = 0; i < 2; i++)
#pragma unroll
            for (int j = 0; j < 2; j++)
                wmma::mma_sync(acc[i][j], af[i], bf[j], acc[i][j]);
    }

    {
        const float a = __ldg(pa);
        const int lane = tid & 31;
        const int g8  = lane >> 2;
        const int tg2 = (lane & 3) * 2;
#pragma unroll
        for (int i = 0; i < 2; i++) {
#pragma unroll
            for (int j = 0; j < 2; j++) {
                const int rb = m0 + row0 + i * 16;
                const int cb = n0 + j * 16;
#pragma unroll
                for (int e = 0; e < 8; e += 2) {
                    int r = rb + g8 + ((e & 2) ? 8 : 0);
                    int c = cb + tg2 + ((e & 4) ? 8 : 0);
                    if (r < M) {
                        float2 bb = __ldg((const float2*)(bias + c));
                        float vx = acc[i][j].x[e]     + bb.x;
                        float vy = acc[i][j].x[e + 1] + bb.y;
                        if (out_h16) {
                            float ox = prelu_h16 ? prelu1(vx, a) : vx;
                            float oy = prelu_h16 ? prelu1(vy, a) : vy;
                            __half2 hv = __floats2half2_rn(ox, oy);
                            *(unsigned*)(out_h16 + (size_t)r * 64 + (c >> 1)) =
                                *reinterpret_cast<unsigned*>(&hv);
                        }
                        if (out_f32) {
                            float ox = prelu_f32 ? prelu1(vx, a) : vx;
                            float oy = prelu_f32 ? prelu1(vy, a) : vy;
                            *(float2*)(out_f32 + (size_t)r * D + c) = make_float2(ox, oy);
                        }
                        if (csum) {
                            int cc = __ldg(&ncomp[r]);
                            float sc = __ldg(&cinv[cc]);
                            red2(csum + (size_t)cc * D + c, vx * sc, vy * sc);
                        }
                    }
                }
            }
        }
    }
}

// ---------------- WMMA double GEMM: out = (prelu(X@W1+b1))@W2 + b2 ----------
__global__ __launch_bounds__(512, 2) void kgemm_fused(const unsigned* __restrict__ X16,
                                                      const unsigned* __restrict__ Wh1,
                                                      const float* __restrict__ b1,
                                                      const unsigned* __restrict__ Wh2,
                                                      const float* __restrict__ b2,
                                                      const float* __restrict__ pa,
                                                      unsigned* __restrict__ out_h16,
                                                      int M) {
    extern __shared__ char smem[];
    __half* As = (__half*)smem;
    __half* B1 = (__half*)(smem + SM_AS);
    __half* B2 = (__half*)(smem + 2 * SM_AS);
    const int tid = threadIdx.x;
    const int wid = tid >> 5;
    const int m0 = blockIdx.x * 128;

#pragma unroll
    for (int it = 0; it < 4; it++) {
        int idx = tid + it * 512;
        int r = idx >> 4, g = idx & 15;
        int gr = m0 + r;
        void* dst = As + (size_t)r * AS_LD + g * 8;
        if (gr < M) cpasync16(dst, (const uint4*)(X16 + (size_t)gr * 64) + g);
        else        *(uint4*)dst = make_uint4(0, 0, 0, 0);
    }
#pragma unroll
    for (int it = 0; it < 4; it++) {
        int idx = tid + it * 512;
        int kk = idx >> 4, g = idx & 15;
        cpasync16(B1 + (size_t)kk * BS_LD + g * 8, (const uint4*)Wh1 + kk * 16 + g);
        cpasync16(B2 + (size_t)kk * BS_LD + g * 8, (const uint4*)Wh2 + kk * 16 + g);
    }
    asm volatile("cp.async.commit_group;" ::: "memory");
    asm volatile("cp.async.wait_group 0;" ::: "memory");
    __syncthreads();

    const int row0 = (wid & 3) * 32;
    const int n0   = (wid >> 2) * 32;
    const int lane = tid & 31;
    const int g8  = lane >> 2;
    const int tg2 = (lane & 3) * 2;
    const float a = __ldg(pa);

    wmma::fragment<wmma::accumulator, 16, 16, 16, float> acc[2][2];
#pragma unroll
    for (int i = 0; i < 2; i++)
#pragma unroll
        for (int j = 0; j < 2; j++) wmma::fill_fragment(acc[i][j], 0.f);

#pragma unroll
    for (int k = 0; k < 8; k++) {
        wmma::fragment<wmma::matrix_a, 16, 16, 16, __half, wmma::row_major> af[2];
        wmma::fragment<wmma::matrix_b, 16, 16, 16, __half, wmma::row_major> bf[2];
#pragma unroll
        for (int i = 0; i < 2; i++)
            wmma::load_matrix_sync(af[i], As + (size_t)(row0 + i * 16) * AS_LD + k * 16, AS_LD);
#pragma unroll
        for (int j = 0; j < 2; j++)
            wmma::load_matrix_sync(bf[j], B1 + (size_t)(k * 16) * BS_LD + n0 + j * 16, BS_LD);
#pragma unroll
        for (int i = 0; i < 2; i++)
#pragma unroll
            for (int j = 0; j < 2; j++)
                wmma::mma_sync(acc[i][j], af[i], bf[j], acc[i][j]);
    }
    __syncthreads();   // everyone done reading As

#pragma unroll
    for (int i = 0; i < 2; i++) {
#pragma unroll
        for (int j = 0; j < 2; j++) {
            const int rl = row0 + i * 16;
            const int cb = n0 + j * 16;
#pragma unroll
            for (int e = 0; e < 8; e += 2) {
                int r = rl + g8 + ((e & 2) ? 8 : 0);
                int c = cb + tg2 + ((e & 4) ? 8 : 0);
                float2 bb = __ldg((const float2*)(b1 + c));
                float vx = prelu1(acc[i][j].x[e]     + bb.x, a);
                float vy = prelu1(acc[i][j].x[e + 1] + bb.y, a);
                __half2 hv = __floats2half2_rn(vx, vy);
                *(unsigned*)(As + (size_t)r * AS_LD + c) = *reinterpret_cast<unsigned*>(&hv);
            }
        }
    }
    __syncthreads();

#pragma unroll
    for (int i = 0; i < 2; i++)
#pragma unroll
        for (int j = 0; j < 2; j++) wmma::fill_fragment(acc[i][j], 0.f);
#pragma unroll
    for (int k = 0; k < 8; k++) {
        wmma::fragment<wmma::matrix_a, 16, 16, 16, __half, wmma::row_major> af[2];
        wmma::fragment<wmma::matrix_b, 16, 16, 16, __half, wmma::row_major> bf[2];
#pragma unroll
        for (int i = 0; i < 2; i++)
            wmma::load_matrix_sync(af[i], As + (size_t)(row0 + i * 16) * AS_LD + k * 16, AS_LD);
#pragma unroll
        for (int j = 0; j < 2; j++)
            wmma::load_matrix_sync(bf[j], B2 + (size_t)(k * 16) * BS_LD + n0 + j * 16, BS_LD);
#pragma unroll
        for (int i = 0; i < 2; i++)
#pragma unroll
            for (int j = 0; j < 2; j++)
                wmma::mma_sync(acc[i][j], af[i], bf[j], acc[i][j]);
    }
#pragma unroll
    for (int i = 0; i < 2; i++) {
#pragma unroll
        for (int j = 0; j < 2; j++) {
            const int rb = m0 + row0 + i * 16;
            const int cb = n0 + j * 16;
#pragma unroll
            for (int e = 0; e < 8; e += 2) {
                int r = rb + g8 + ((e & 2) ? 8 : 0);
                int c = cb + tg2 + ((e & 4) ? 8 : 0);
                if (r < M) {
                    float2 bb = __ldg((const float2*)(b2 + c));
                    __half2 hv = __floats2half2_rn(acc[i][j].x[e] + bb.x,
                                                   acc[i][j].x[e + 1] + bb.y);
                    *(unsigned*)(out_h16 + (size_t)r * 64 + (c >> 1)) =
                        *reinterpret_cast<unsigned*>(&hv);
                }
            }
        }
    }
}

// ---------------- SIMT GEMM (small C-row GEMMs) ------------------------------
__global__ __launch_bounds__(256) void kgemm2(const float* __restrict__ X,
                                              const float* __restrict__ W,
                                              const float* __restrict__ b,
                                              const float* __restrict__ addin,
                                              float* __restrict__ Yraw,
                                              float* __restrict__ Ypre,
                                              const float* __restrict__ pa, int M) {
    __shared__ float As[64][128];
    const int m0 = blockIdx.x * 64;
    const int t = threadIdx.x;
    {
        const int c4 = t & 31;
        const int r0 = t >> 5;
#pragma unroll
        for (int s = 0; s < 8; s++) {
            int r = r0 + 8 * s;
            int gr = m0 + r;
            float4 v = make_float4(0.f, 0.f, 0.f, 0.f);
            if (gr < M) v = ((const float4*)(X + (size_t)gr * D))[c4];
            ((float4*)(&As[r][0]))[c4] = v;
        }
    }
    __syncthreads();
    const int cg = (t & 15) * 8;
    const int rg = (t >> 4) * 4;
    unsigned long long acc[4][4];
#pragma unroll
    for (int i = 0; i < 4; i++)
#pragma unroll
        for (int j = 0; j < 4; j++) acc[i][j] = 0ULL;
#pragma unroll 4
    for (int k = 0; k < D; k += 4) {
        float4 a[4];
#pragma unroll
        for (int i = 0; i < 4; i++) a[i] = *(const float4*)&As[rg + i][k];
#pragma unroll
        for (int kk = 0; kk < 4; kk++) {
            const ulonglong2 w0 = *reinterpret_cast<const ulonglong2*>(&W[(k + kk) * D + cg]);
            const ulonglong2 w1 = *reinterpret_cast<const ulonglong2*>(&W[(k + kk) * D + cg + 4]);
#pragma unroll
            for (int i = 0; i < 4; i++) {
                float av = (kk == 0) ? a[i].x : (kk == 1) ? a[i].y
                         : (kk == 2) ? a[i].z : a[i].w;
                unsigned long long av2 = pk2(av);
                fma2(acc[i][0], av2, w0.x);
                fma2(acc[i][1], av2, w0.y);
                fma2(acc[i][2], av2, w1.x);
                fma2(acc[i][3], av2, w1.y);
            }
        }
    }
    const float4 b0 = __ldg((const float4*)&b[cg]);
    const float4 b1 = __ldg((const float4*)&b[cg + 4]);
    const float a = __ldg(pa);
#pragma unroll
    for (int i = 0; i < 4; i++) {
        int gr = m0 + rg + i;
        if (gr >= M) continue;
        float2 p0 = up2(acc[i][0]), p1 = up2(acc[i][1]);
        float2 p2 = up2(acc[i][2]), p3 = up2(acc[i][3]);
        float4 o0 = make_float4(p0.x + b0.x, p0.y + b0.y, p1.x + b0.z, p1.y + b0.w);
        float4 o1 = make_float4(p2.x + b1.x, p2.y + b1.y, p3.x + b1.z, p3.y + b1.w);
        if (addin) {
            const float4* ar = (const float4*)(addin + (size_t)gr * D);
            add4(o0, ar[cg / 4]); add4(o1, ar[cg / 4 + 1]);
        }
        if (Yraw) {
            float4* yr = (float4*)(Yraw + (size_t)gr * D);
            yr[cg / 4] = o0; yr[cg / 4 + 1] = o1;
        }
        if (Ypre) {
            float4* yp = (float4*)(Ypre + (size_t)gr * D);
            yp[cg / 4] = prelu4(o0, a); yp[cg / 4 + 1] = prelu4(o1, a);
        }
    }
}

// ---------------- CSR aggregation (half-warp/segment, 8-deep MLP batches) ----
__global__ __launch_bounds__(256) void kagg_e(const unsigned* __restrict__ T16,
                                              const int* __restrict__ perm,
                                              const int* __restrict__ offs,
                                              const float* __restrict__ invd,
                                              const float* __restrict__ pa,
                                              unsigned* __restrict__ EB16,
                                              float* __restrict__ out_e,
                                              const int* __restrict__ ecomp,
                                              const float* __restrict__ cinv,
                                              float* __restrict__ csum, int E) {
    int seg = (blockIdx.x * blockDim.x + threadIdx.x) >> 4;
    int l = threadIdx.x & 15;
    if (seg >= E) return;
    int beg = __ldg(&offs[seg]), end = __ldg(&offs[seg + 1]);
    float4 s0 = {0,0,0,0}, s1 = {0,0,0,0}, t0 = {0,0,0,0}, t1 = {0,0,0,0};
    float4 u0 = {0,0,0,0}, u1 = {0,0,0,0}, v0 = {0,0,0,0}, v1 = {0,0,0,0};
    int p = beg;
    for (; p + 8 <= end; p += 8) {
        uint4 vv[8];
#pragma unroll
        for (int q = 0; q < 8; q++)
            vv[q] = __ldg((const uint4*)(T16 + (size_t)__ldg(&perm[p + q]) * 64) + l);
        addh8(s0, s1, vv[0]); addh8(t0, t1, vv[1]);
        addh8(u0, u1, vv[2]); addh8(v0, v1, vv[3]);
        addh8(s0, s1, vv[4]); addh8(t0, t1, vv[5]);
        addh8(u0, u1, vv[6]); addh8(v0, v1, vv[7]);
    }
    for (; p + 4 <= end; p += 4) {
        uint4 vv[4];
#pragma unroll
        for (int q = 0; q < 4; q++)
            vv[q] = __ldg((const uint4*)(T16 + (size_t)__ldg(&perm[p + q]) * 64) + l);
        addh8(s0, s1, vv[0]); addh8(t0, t1, vv[1]);
        addh8(u0, u1, vv[2]); addh8(v0, v1, vv[3]);
    }
    for (; p < end; p++)
        addh8(s0, s1, __ldg((const uint4*)(T16 + (size_t)__ldg(&perm[p]) * 64) + l));
    add4(s0, t0); add4(u0, v0); add4(s0, u0);
    add4(s1, t1); add4(u1, v1); add4(s1, u1);
    float iv = __ldg(&invd[seg]);
    float a = __ldg(pa);
    s0.x *= iv; s0.y *= iv; s0.z *= iv; s0.w *= iv;
    s1.x *= iv; s1.y *= iv; s1.z *= iv; s1.w *= iv;
    float4 r0 = prelu4(s0, a), r1 = prelu4(s1, a);
    uint2 q0 = h4(r0), q1 = h4(r1);
    ((uint4*)(EB16 + (size_t)seg * 64))[l] = make_uint4(q0.x, q0.y, q1.x, q1.y);
    if (out_e) {
        ((float4*)out_e)[(size_t)seg * 32 + l * 2]     = r0;
        ((float4*)out_e)[(size_t)seg * 32 + l * 2 + 1] = r1;
    }
    if (csum) {
        int cc = __ldg(&ecomp[seg]);
        float sc = __ldg(&cinv[cc]);
        float4 w0 = make_float4(r0.x * sc, r0.y * sc, r0.z * sc, r0.w * sc);
        float4 w1 = make_float4(r1.x * sc, r1.y * sc, r1.z * sc, r1.w * sc);
        red4(csum + (size_t)cc * D + l * 8,     w0);
        red4(csum + (size_t)cc * D + l * 8 + 4, w1);
    }
}

__global__ __launch_bounds__(256) void kagg_n(const unsigned* __restrict__ T16,
                                              const unsigned* __restrict__ EB16,
                                              const int* __restrict__ perm,
                                              const int* __restrict__ offs,
                                              const float* __restrict__ invs,
                                              const float* __restrict__ pa,
                                              unsigned* __restrict__ A16, int N) {
    int seg = (blockIdx.x * blockDim.x + threadIdx.x) >> 4;
    int l = threadIdx.x & 15;
    if (seg >= N) return;
    int beg = __ldg(&offs[seg]), end = __ldg(&offs[seg + 1]);
    float4 s0 = {0,0,0,0}, s1 = {0,0,0,0}, t0 = {0,0,0,0}, t1 = {0,0,0,0};
    float4 u0 = {0,0,0,0}, u1 = {0,0,0,0}, v0 = {0,0,0,0}, v1 = {0,0,0,0};
    int p = beg;
    for (; p + 8 <= end; p += 8) {
        uint4 vv[8];
#pragma unroll
        for (int q = 0; q < 8; q++)
            vv[q] = __ldg((const uint4*)(EB16 + (size_t)__ldg(&perm[p + q]) * 64) + l);
        addh8(s0, s1, vv[0]); addh8(t0, t1, vv[1]);
        addh8(u0, u1, vv[2]); addh8(v0, v1, vv[3]);
        addh8(s0, s1, vv[4]); addh8(t0, t1, vv[5]);
        addh8(u0, u1, vv[6]); addh8(v0, v1, vv[7]);
    }
    for (; p + 4 <= end; p += 4) {
        uint4 vv[4];
#pragma unroll
        for (int q = 0; q < 4; q++)
            vv[q] = __ldg((const uint4*)(EB16 + (size_t)__ldg(&perm[p + q]) * 64) + l);
        addh8(s0, s1, vv[0]); addh8(t0, t1, vv[1]);
        addh8(u0, u1, vv[2]); addh8(v0, v1, vv[3]);
    }
    for (; p < end; p++)
        addh8(s0, s1, __ldg((const uint4*)(EB16 + (size_t)__ldg(&perm[p]) * 64) + l));
    add4(s0, t0); add4(u0, v0); add4(s0, u0);
    add4(s1, t1); add4(u1, v1); add4(s1, u1);
    float a = __ldg(pa);
    float4 w0 = {0,0,0,0}, w1 = {0,0,0,0};
    addh8(w0, w1, __ldg((const uint4*)(T16 + (size_t)seg * 64) + l));
    add4(s0, prelu4(w0, a));
    add4(s1, prelu4(w1, a));
    float iv = __ldg(&invs[seg]);
    s0.x *= iv; s0.y *= iv; s0.z *= iv; s0.w *= iv;
    s1.x *= iv; s1.y *= iv; s1.z *= iv; s1.w *= iv;
    uint2 q0 = h4(s0), q1 = h4(s1);
    ((uint4*)(A16 + (size_t)seg * 64))[l] = make_uint4(q0.x, q0.y, q1.x, q1.y);
}

// ---------------- host driver ------------------------------------------------
static inline int cdiv(long a, long b) { return (int)((a + b - 1) / b); }

extern "C" void kernel_launch(void* const* d_in, const int* in_sizes, int n_in,
                              void* d_out, int out_size) {
    const float* x   = (const float*)d_in[0];
    const int*   hei = (const int*)d_in[1];
    const int*   hci = (const int*)d_in[2];
    const int*   nci = (const int*)d_in[3];

    const int NNZ = in_sizes[1] / 2;
    const int E   = in_sizes[2] / 2;
    const int N   = in_sizes[0] / D;
    const int C   = out_size / D - N - E;

    int wi = -1;
    for (int i = 4; i < n_in; i++) {
        if (in_sizes[i] == D * D) { wi = i; break; }
    }
    const float* pa = (const float*)d_in[wi - 1];

    const int* src  = hei;
    const int* dst  = hei + NNZ;
    const int* he_c = hci + E;
    const int* nc_c = nci + N;

    float *CE, *CN, *CT, *invd, *invs, *ic1, *ic2;
    unsigned *T16, *A16, *E16, *Wh;
    int *cd, *cs, *cc1, *cc2, *od, *os, *pd, *ps, *bsum, *bscan;
    cudaGetSymbolAddress((void**)&T16,  g_T16);
    cudaGetSymbolAddress((void**)&A16,  g_A16);
    cudaGetSymbolAddress((void**)&E16,  g_E16);
    cudaGetSymbolAddress((void**)&CE,   g_c1);
    cudaGetSymbolAddress((void**)&CN,   g_c2);
    cudaGetSymbolAddress((void**)&CT,   g_c3);
    cudaGetSymbolAddress((void**)&Wh,   g_Wh);
    cudaGetSymbolAddress((void**)&invd, g_invdst);
    cudaGetSymbolAddress((void**)&invs, g_invsrc);
    cudaGetSymbolAddress((void**)&ic1,  g_invc1);
    cudaGetSymbolAddress((void**)&ic2,  g_invc2);
    cudaGetSymbolAddress((void**)&cd,   g_cd);
    cudaGetSymbolAddress((void**)&cs,   g_cs);
    cudaGetSymbolAddress((void**)&cc1,  g_cc1);
    cudaGetSymbolAddress((void**)&cc2,  g_cc2);
    cudaGetSymbolAddress((void**)&od,   g_offs_d);
    cudaGetSymbolAddress((void**)&os,   g_offs_s);
    cudaGetSymbolAddress((void**)&pd,   g_perm_d);
    cudaGetSymbolAddress((void**)&ps,   g_perm_s);
    cudaGetSymbolAddress((void**)&bsum, g_bsum);
    cudaGetSymbolAddress((void**)&bscan,g_bscan);

    float* out   = (float*)d_out;
    float* out_n = out;
    float* out_e = out + (size_t)N * D;
    float* out_c = out + (size_t)(N + E) * D;

    const int TB = 256;
    const int nbd = cdiv(E, 1024);
    const int nbs = cdiv(N, 1024);
    const int nbtot = nbd + nbs;
    const int GT = cdiv(N, 128);

    const float* bv0 = (const float*)d_in[wi + 1];
    const float* be0 = (const float*)d_in[wi + 3];
    const float* bv1 = (const float*)d_in[wi + 9];
    const float* be1 = (const float*)d_in[wi + 11];

    cudaFuncSetAttribute(kgemm_tc, cudaFuncAttributeMaxDynamicSharedMemorySize, SM_TOT);
    cudaFuncSetAttribute(kgemm_fused, cudaFuncAttributeMaxDynamicSharedMemorySize, SM3_TOT);

    // persistent side stream + events for forked graph capture
    static cudaStream_t s2 = nullptr;
    static cudaEvent_t evA = nullptr, evB = nullptr, evC = nullptr, evD = nullptr;
    if (!s2) {
        cudaStreamCreateWithFlags(&s2, cudaStreamNonBlocking);
        cudaEventCreateWithFlags(&evA, cudaEventDisableTiming);
        cudaEventCreateWithFlags(&evB, cudaEventDisableTiming);
        cudaEventCreateWithFlags(&evC, cudaEventDisableTiming);
        cudaEventCreateWithFlags(&evD, cudaEventDisableTiming);
    }

    ksetup0<<<cdiv(4 * 128 * 16 + E + N + 2 * C, TB), TB>>>(
        (const float*)d_in[wi + 0], (const float*)d_in[wi + 2],
        (const float*)d_in[wi + 8], (const float*)d_in[wi + 10], Wh,
        cd, cs, cc1, cc2, E, N, C);

    // ---- fork 1: CSR build on s2  ||  G1 on main ----
    cudaEventRecord(evA, 0);
    cudaStreamWaitEvent(s2, evA, 0);
    kcountall<<<cdiv(NNZ + E + N, TB), TB, 0, s2>>>(src, dst, he_c, nc_c,
                                                    cs, cd, cc1, cc2, NNZ, E, N);
    kscanA<<<nbtot, 1024, 0, s2>>>(cd, cs, od, os, bsum, nbd, E, N);
    kscanB<<<1, 1024, 0, s2>>>(bsum, bscan, nbd, nbtot, NNZ);
    kscanC<<<nbtot, 1024, 0, s2>>>(od, os, bscan, cd, cs, nbd, E, N, NNZ);
    kfill<<<cdiv(NNZ, TB), TB, 0, s2>>>(src, dst, cd, cs, pd, ps, NNZ);
    kinvzero<<<cdiv(E + N + 2 * C + 2 * C * 32, TB), TB, 0, s2>>>(
        od, os, cc1, cc2, invd, invs, ic1, ic2, (float4*)CE, (float4*)CN, E, N, C);
    cudaEventRecord(evB, s2);

    // G1 = v2e layer 0 (fp32 input) -> T16 raw (main stream, parallel with CSR)
    kgemm_tc<<<GT, 512, SM_TOT>>>(x, nullptr, Wh + 0 * 8192, bv0, pa,
                                  nullptr, 0, T16, 0, nullptr, nullptr, nullptr, N);
    cudaStreamWaitEvent(0, evB, 0);   // join

    // ---- layer 0 ----
    kagg_e<<<cdiv((long)E * 16, TB), TB>>>(T16, pd, od, invd, pa, E16, nullptr,
                                           nullptr, nullptr, nullptr, E);
    kagg_n<<<cdiv((long)N * 16, TB), TB>>>(T16, E16, ps, os, invs, pa, A16, N);
    // G2+G3 fused: T16 = prelu(A@We0+be0) @ Wv1 + bv1
    kgemm_fused<<<GT, 512, SM3_TOT>>>(A16, Wh + 1 * 8192, be0,
                                      Wh + 2 * 8192, bv1, pa, T16, N);

    // ---- layer 1 ----
    kagg_e<<<cdiv((long)E * 16, TB), TB>>>(T16, pd, od, invd, pa, E16, out_e,
                                           he_c, ic1, CE, E);
    // ---- fork 2: CE component GEMM on s2  ||  kagg_n + G4 on main ----
    cudaEventRecord(evC, 0);
    cudaStreamWaitEvent(s2, evC, 0);
    kgemm2<<<cdiv(C, 64), TB, 0, s2>>>(CE, (const float*)d_in[wi + 12],
                                       (const float*)d_in[wi + 13],
                                       nullptr, CT, nullptr, pa, C);
    cudaEventRecord(evD, s2);

    kagg_n<<<cdiv((long)N * 16, TB), TB>>>(T16, E16, ps, os, invs, pa, A16, N);
    // G4 = e2v layer 1 -> out_n fp32 prelu + fused node->component scatter
    kgemm_tc<<<GT, 512, SM_TOT>>>(nullptr, A16, Wh + 3 * 8192, be1, pa,
                                  out_n, 1, nullptr, 0, nc_c, ic2, CN, N);
    cudaStreamWaitEvent(0, evD, 0);   // join

    kgemm2<<<cdiv(C, 64), TB>>>(CN, (const float*)d_in[wi + 14], (const float*)d_in[wi + 15],
                                CT, nullptr, out_c, pa, C);
}

// round 16
// speedup vs baseline: 2.6422x; 1.0314x over previous
#include <cuda_runtime.h>
#include <cuda_fp16.h>
#include <cuda_bf16.h>
#include <mma.h>
#include <cstdint>
#include <cstddef>

#define D 128
using namespace nvcuda;

// ---------------- static scratch (device globals) ---------------------------
static __device__ unsigned g_T16[100000 * 64];   // v2e transform output (fp16 rows)
static __device__ unsigned g_E16[50000  * 64];   // e fp16 rows
static __device__ float    g_c1 [2048   * 128];
static __device__ float    g_c2 [2048   * 128];
static __device__ float    g_c3 [2048   * 128];
static __device__ unsigned g_Wh [4 * 128 * 64];  // 4 W, fp16 [128][128]
static __device__ float g_invdst[50016];
static __device__ float g_invsrc[100016];
static __device__ float g_invc1[2048];
static __device__ float g_invc2[2048];
static __device__ int   g_cd [50016];
static __device__ int   g_cs [100016];
static __device__ int   g_cc1[2048];
static __device__ int   g_cc2[2048];
static __device__ int   g_offs_d[50024];
static __device__ int   g_offs_s[100024];
static __device__ int   g_perm_d[1600128];
static __device__ int   g_perm_s[1600128];
static __device__ int   g_bsum [1024];
static __device__ int   g_bscan[1024];

// ---------------- helpers ----------------------------------------------------
__device__ __forceinline__ unsigned long long pk2(float v) {
    unsigned long long r; unsigned u = __float_as_uint(v);
    asm("mov.b64 %0, {%1,%1};" : "=l"(r) : "r"(u));
    return r;
}
__device__ __forceinline__ void fma2(unsigned long long& d, unsigned long long a,
                                     unsigned long long b) {
    asm("fma.rn.f32x2 %0, %1, %2, %0;" : "+l"(d) : "l"(a), "l"(b));
}
__device__ __forceinline__ float2 up2(unsigned long long v) {
    unsigned lo, hi;
    asm("mov.b64 {%0,%1}, %2;" : "=r"(lo), "=r"(hi) : "l"(v));
    return make_float2(__uint_as_float(lo), __uint_as_float(hi));
}
__device__ __forceinline__ float prelu1(float v, float a) { return v >= 0.f ? v : a * v; }
__device__ __forceinline__ float4 prelu4(float4 v, float a) {
    return make_float4(prelu1(v.x, a), prelu1(v.y, a), prelu1(v.z, a), prelu1(v.w, a));
}
__device__ __forceinline__ void add4(float4& a, float4 b) {
    a.x += b.x; a.y += b.y; a.z += b.z; a.w += b.w;
}
__device__ __forceinline__ void addh8(float4& a, float4& b, uint4 v) {
    __half2 h0 = *reinterpret_cast<__half2*>(&v.x);
    __half2 h1 = *reinterpret_cast<__half2*>(&v.y);
    __half2 h2 = *reinterpret_cast<__half2*>(&v.z);
    __half2 h3 = *reinterpret_cast<__half2*>(&v.w);
    float2 f0 = __half22float2(h0), f1 = __half22float2(h1);
    float2 f2 = __half22float2(h2), f3 = __half22float2(h3);
    a.x += f0.x; a.y += f0.y; a.z += f1.x; a.w += f1.y;
    b.x += f2.x; b.y += f2.y; b.z += f3.x; b.w += f3.y;
}
__device__ __forceinline__ uint2 h4(float4 v) {
    __half2 h0 = __float22half2_rn(make_float2(v.x, v.y));
    __half2 h1 = __float22half2_rn(make_float2(v.z, v.w));
    uint2 r;
    r.x = *reinterpret_cast<unsigned*>(&h0);
    r.y = *reinterpret_cast<unsigned*>(&h1);
    return r;
}
__device__ __forceinline__ void cpasync16(void* smem_dst, const void* gsrc) {
    unsigned sa = (unsigned)__cvta_generic_to_shared(smem_dst);
    asm volatile("cp.async.cg.shared.global [%0], [%1], 16;" :: "r"(sa), "l"(gsrc));
}
__device__ __forceinline__ void red4(float* a, float4 v) {
    asm volatile("red.global.add.v4.f32 [%0], {%1,%2,%3,%4};"
                 :: "l"(a), "f"(v.x), "f"(v.y), "f"(v.z), "f"(v.w)
                 : "memory");
}
__device__ __forceinline__ void red2(float* a, float x, float y) {
    asm volatile("red.global.add.v2.f32 [%0], {%1,%2};"
                 :: "l"(a), "f"(x), "f"(y) : "memory");
}

#define AS_LD 136
#define BS_LD 136
#define SM_AS  (128 * AS_LD * 2)
#define SM_TOT (SM_AS + 128 * BS_LD * 2)
#define SM3_TOT (3 * SM_AS)

// aggregate node segment seg (kagg_n math, verbatim) -> uint4 of 8 fp16
__device__ __forceinline__ uint4 agg_node_seg(const unsigned* __restrict__ T16,
                                              const unsigned* __restrict__ EB16,
                                              const int* __restrict__ perm,
                                              const int* __restrict__ offs,
                                              const float* __restrict__ invs,
                                              float a, int seg, int l) {
    int beg = __ldg(&offs[seg]), end = __ldg(&offs[seg + 1]);
    float4 s0 = {0,0,0,0}, s1 = {0,0,0,0}, t0 = {0,0,0,0}, t1 = {0,0,0,0};
    float4 u0 = {0,0,0,0}, u1 = {0,0,0,0}, v0 = {0,0,0,0}, v1 = {0,0,0,0};
    int p = beg;
    for (; p + 8 <= end; p += 8) {
        uint4 vv[8];
#pragma unroll
        for (int q = 0; q < 8; q++)
            vv[q] = __ldg((const uint4*)(EB16 + (size_t)__ldg(&perm[p + q]) * 64) + l);
        addh8(s0, s1, vv[0]); addh8(t0, t1, vv[1]);
        addh8(u0, u1, vv[2]); addh8(v0, v1, vv[3]);
        addh8(s0, s1, vv[4]); addh8(t0, t1, vv[5]);
        addh8(u0, u1, vv[6]); addh8(v0, v1, vv[7]);
    }
    for (; p + 4 <= end; p += 4) {
        uint4 vv[4];
#pragma unroll
        for (int q = 0; q < 4; q++)
            vv[q] = __ldg((const uint4*)(EB16 + (size_t)__ldg(&perm[p + q]) * 64) + l);
        addh8(s0, s1, vv[0]); addh8(t0, t1, vv[1]);
        addh8(u0, u1, vv[2]); addh8(v0, v1, vv[3]);
    }
    for (; p < end; p++)
        addh8(s0, s1, __ldg((const uint4*)(EB16 + (size_t)__ldg(&perm[p]) * 64) + l));
    add4(s0, t0); add4(u0, v0); add4(s0, u0);
    add4(s1, t1); add4(u1, v1); add4(s1, u1);
    float4 w0 = {0,0,0,0}, w1 = {0,0,0,0};
    addh8(w0, w1, __ldg((const uint4*)(T16 + (size_t)seg * 64) + l));
    add4(s0, prelu4(w0, a));
    add4(s1, prelu4(w1, a));
    float iv = __ldg(&invs[seg]);
    s0.x *= iv; s0.y *= iv; s0.z *= iv; s0.w *= iv;
    s1.x *= iv; s1.y *= iv; s1.z *= iv; s1.w *= iv;
    uint2 q0 = h4(s0), q1 = h4(s1);
    return make_uint4(q0.x, q0.y, q1.x, q1.y);
}

// ---------------- setup 0: W convert + zero count arrays ---------------------
__global__ void ksetup0(const float* __restrict__ W0, const float* __restrict__ W1,
                        const float* __restrict__ W2, const float* __restrict__ W3,
                        unsigned* __restrict__ Wh,
                        int* cd, int* cs, int* cc1, int* cc2, int E, int N, int C) {
    int idx = blockIdx.x * blockDim.x + threadIdx.x;
    if (idx < 4 * 128 * 16) {
        int w = idx >> 11;
        int rem = idx & 2047;
        int kk = rem >> 4, g = rem & 15;
        const float* W = (w == 0) ? W0 : (w == 1) ? W1 : (w == 2) ? W2 : W3;
        float4 x0 = __ldg((const float4*)(W + (size_t)kk * D + g * 8));
        float4 x1 = __ldg((const float4*)(W + (size_t)kk * D + g * 8 + 4));
        uint2 p0 = h4(x0), p1 = h4(x1);
        ((uint4*)(Wh + (size_t)w * 128 * 64))[kk * 16 + g] = make_uint4(p0.x, p0.y, p1.x, p1.y);
        return;
    }
    int i = idx - 4 * 128 * 16;
    if (i < E) cd[i] = 0;
    else if (i < E + N) cs[i - E] = 0;
    else if (i < E + N + C) cc1[i - E - N] = 0;
    else if (i < E + N + 2 * C) cc2[i - E - N - C] = 0;
}

__global__ void kcountall(const int* __restrict__ src, const int* __restrict__ dst,
                          const int* __restrict__ he_c, const int* __restrict__ nc_c,
                          int* cs, int* cd, int* cc1, int* cc2,
                          int nnz, int E, int N) {
    int i = blockIdx.x * blockDim.x + threadIdx.x;
    if (i < nnz) {
        atomicAdd(&cd[dst[i]], 1);
        atomicAdd(&cs[src[i]], 1);
    } else if (i < nnz + E) {
        atomicAdd(&cc1[he_c[i - nnz]], 1);
    } else if (i < nnz + E + N) {
        atomicAdd(&cc2[nc_c[i - nnz - E]], 1);
    }
}

__global__ __launch_bounds__(1024) void kscanA(const int* __restrict__ cd,
                                               const int* __restrict__ cs,
                                               int* od, int* os, int* bsum,
                                               int nbd, int E, int N) {
    __shared__ int sh[1024];
    const int b = blockIdx.x, t = threadIdx.x;
    const bool isD = b < nbd;
    const int* in = isD ? cd : cs;
    int* out = isD ? od : os;
    const int n = isD ? E : N;
    const int i = (isD ? b : b - nbd) * 1024 + t;
    int v = (i < n) ? in[i] : 0;
    sh[t] = v;
    __syncthreads();
    for (int off = 1; off < 1024; off <<= 1) {
        int x = (t >= off) ? sh[t - off] : 0;
        __syncthreads();
        sh[t] += x;
        __syncthreads();
    }
    if (i < n) out[i] = sh[t] - v;
    if (t == 1023) bsum[b] = sh[1023];
}

__global__ __launch_bounds__(1024) void kscanB(const int* __restrict__ bsum,
                                               int* bscan, int nbd, int nbtot, int nnz) {
    __shared__ int sh[1024];
    int t = threadIdx.x;
    int v = (t < nbtot) ? bsum[t] : 0;
    sh[t] = v;
    __syncthreads();
    for (int off = 1; off < 1024; off <<= 1) {
        int x = (t >= off) ? sh[t - off] : 0;
        __syncthreads();
        sh[t] += x;
        __syncthreads();
    }
    if (t < nbtot) {
        int excl = sh[t] - v;
        bscan[t] = (t >= nbd) ? excl - nnz : excl;
    }
}

__global__ __launch_bounds__(1024) void kscanC(int* od, int* os,
                                               const int* __restrict__ bscan,
                                               int* cd, int* cs,
                                               int nbd, int E, int N, int nnz) {
    const int b = blockIdx.x, t = threadIdx.x;
    const bool isD = b < nbd;
    const int i = (isD ? b : b - nbd) * 1024 + t;
    if (isD) {
        if (i < E) { int o = od[i] + bscan[b]; od[i] = o; cd[i] = o; }
        if (b == 0 && t == 0) od[E] = nnz;
    } else {
        if (i < N) { int o = os[i] + bscan[b]; os[i] = o; cs[i] = o; }
        if (i == 0) os[N] = nnz;
    }
}

// fill perms + inverses + zero component accumulators (independent ranges)
__global__ void kfillinv(const int* __restrict__ src, const int* __restrict__ dst,
                         int* cur_d, int* cur_s, int* perm_d, int* perm_s,
                         const int* __restrict__ od, const int* __restrict__ os,
                         const int* __restrict__ cc1, const int* __restrict__ cc2,
                         float* invd, float* invs, float* ic1, float* ic2,
                         float4* CE4, float4* CN4, int nnz, int E, int N, int C) {
    int k = blockIdx.x * blockDim.x + threadIdx.x;
    if (k < nnz) {
        int s = __ldg(&src[k]), d = __ldg(&dst[k]);
        perm_d[atomicAdd(&cur_d[d], 1)] = s;
        perm_s[atomicAdd(&cur_s[s], 1)] = d;
        return;
    }
    int i = k - nnz;
    if (i < E) {
        int c = od[i + 1] - od[i];
        invd[i] = 1.f / (float)(c > 0 ? c : 1);
    } else if (i < E + N) {
        int j = i - E;
        int c = os[j + 1] - os[j] + 1;
        invs[j] = 1.f / (float)c;
    } else if (i < E + N + C) {
        int c = cc1[i - E - N];
        ic1[i - E - N] = 1.f / (float)(c > 0 ? c : 1);
    } else if (i < E + N + 2 * C) {
        int c = cc2[i - E - N - C];
        ic2[i - E - N - C] = 1.f / (float)(c > 0 ? c : 1);
    } else {
        int j = i - (E + N + 2 * C);
        int z = C * 32;
        if (j < z) CE4[j] = make_float4(0.f, 0.f, 0.f, 0.f);
        else if (j < 2 * z) CN4[j - z] = make_float4(0.f, 0.f, 0.f, 0.f);
    }
}

// ---------------- WMMA GEMM (single, fp32 or fp16 input) ---------------------
__global__ __launch_bounds__(512, 2) void kgemm_tc(const float* __restrict__ X32,
                                                   const unsigned* __restrict__ Wh,
                                                   const float* __restrict__ bias,
                                                   const float* __restrict__ pa,
                                                   unsigned* __restrict__ out_h16,
                                                   int M) {
    extern __shared__ char smem[];
    __half* As = (__half*)smem;
    __half* Bs = (__half*)(smem + SM_AS);
    const int tid = threadIdx.x;
    const int wid = tid >> 5;
    const int m0 = blockIdx.x * 128;

#pragma unroll
    for (int it = 0; it < 4; it++) {
        int idx = tid + it * 512;
        int kk = idx >> 4, g = idx & 15;
        cpasync16(Bs + (size_t)kk * BS_LD + g * 8, (const uint4*)Wh + kk * 16 + g);
    }
    asm volatile("cp.async.commit_group;" ::: "memory");
#pragma unroll
    for (int it = 0; it < 4; it++) {
        int idx = tid + it * 512;
        int r = idx >> 4, g = idx & 15;
        int gr = m0 + r;
        float4 x0 = make_float4(0.f, 0.f, 0.f, 0.f), x1 = x0;
        if (gr < M) {
            x0 = __ldg((const float4*)(X32 + (size_t)gr * D + g * 8));
            x1 = __ldg((const float4*)(X32 + (size_t)gr * D + g * 8 + 4));
        }
        uint2 p0 = h4(x0), p1 = h4(x1);
        *(uint4*)(As + (size_t)r * AS_LD + g * 8) = make_uint4(p0.x, p0.y, p1.x, p1.y);
    }
    asm volatile("cp.async.wait_group 0;" ::: "memory");
    __syncthreads();

    const int row0 = (wid & 3) * 32;
    const int n0   = (wid >> 2) * 32;
    wmma::fragment<wmma::accumulator, 16, 16, 16, float> acc[2][2];
#pragma unroll
    for (int i = 0; i < 2; i++)
#pragma unroll
        for (int j = 0; j < 2; j++) wmma::fill_fragment(acc[i][j], 0.f);
#pragma unroll
    for (int k = 0; k < 8; k++) {
        wmma::fragment<wmma::matrix_a, 16, 16, 16, __half, wmma::row_major> af[2];
        wmma::fragment<wmma::matrix_b, 16, 16, 16, __half, wmma::row_major> bf[2];
#pragma unroll
        for (int i = 0; i < 2; i++)
            wmma::load_matrix_sync(af[i], As + (size_t)(row0 + i * 16) * AS_LD + k * 16, AS_LD);
#pragma unroll
        for (int j = 0; j < 2; j++)
            wmma::load_matrix_sync(bf[j], Bs + (size_t)(k * 16) * BS_LD + n0 + j * 16, BS_LD);
#pragma unroll
        for (int i = 0; i < 2; i++)
#pragma unroll
            for (int j = 0; j < 2; j++)
                wmma::mma_sync(acc[i][j], af[i], bf[j], acc[i][j]);
    }
    {
        const int lane = tid & 31;
        const int g8  = lane >> 2;
        const int tg2 = (lane & 3) * 2;
#pragma unroll
        for (int i = 0; i < 2; i++) {
#pragma unroll
            for (int j = 0; j < 2; j++) {
                const int rb = m0 + row0 + i * 16;
                const int cb = n0 + j * 16;
#pragma unroll
                for (int e = 0; e < 8; e += 2) {
                    int r = rb + g8 + ((e & 2) ? 8 : 0);
                    int c = cb + tg2 + ((e & 4) ? 8 : 0);
                    if (r < M) {
                        float2 bb = __ldg((const float2*)(bias + c));
                        __half2 hv = __floats2half2_rn(acc[i][j].x[e] + bb.x,
                                                       acc[i][j].x[e + 1] + bb.y);
                        *(unsigned*)(out_h16 + (size_t)r * 64 + (c >> 1)) =
                            *reinterpret_cast<unsigned*>(&hv);
                    }
                }
            }
        }
    }
}

// ---------------- fused: node-agg + double GEMM (layer 0) --------------------
// T16out = (prelu(Agg @ W1 + b1)) @ W2 + b2
__global__ __launch_bounds__(512, 2) void kagg_gemm2(const unsigned* __restrict__ T16,
                                                     const unsigned* __restrict__ EB16,
                                                     const int* __restrict__ perm,
                                                     const int* __restrict__ offs,
                                                     const float* __restrict__ invs,
                                                     const unsigned* __restrict__ Wh1,
                                                     const float* __restrict__ b1,
                                                     const unsigned* __restrict__ Wh2,
                                                     const float* __restrict__ b2,
                                                     const float* __restrict__ pa,
                                                     unsigned* __restrict__ out_h16,
                                                     int M) {
    extern __shared__ char smem[];
    __half* As = (__half*)smem;
    __half* B1 = (__half*)(smem + SM_AS);
    __half* B2 = (__half*)(smem + 2 * SM_AS);
    const int tid = threadIdx.x;
    const int wid = tid >> 5;
    const int m0 = blockIdx.x * 128;
    const float a = __ldg(pa);

#pragma unroll
    for (int it = 0; it < 4; it++) {
        int idx = tid + it * 512;
        int kk = idx >> 4, g = idx & 15;
        cpasync16(B1 + (size_t)kk * BS_LD + g * 8, (const uint4*)Wh1 + kk * 16 + g);
        cpasync16(B2 + (size_t)kk * BS_LD + g * 8, (const uint4*)Wh2 + kk * 16 + g);
    }
    asm volatile("cp.async.commit_group;" ::: "memory");

    // aggregate this CTA's 128 segments straight into As
    {
        const int hw = tid >> 4, l = tid & 15;
#pragma unroll
        for (int q = 0; q < 4; q++) {
            int r = q * 32 + hw;
            int seg = m0 + r;
            uint4 outv = make_uint4(0, 0, 0, 0);
            if (seg < M)
                outv = agg_node_seg(T16, EB16, perm, offs, invs, a, seg, l);
            *(uint4*)(As + (size_t)r * AS_LD + l * 8) = outv;
        }
    }
    asm volatile("cp.async.wait_group 0;" ::: "memory");
    __syncthreads();

    const int row0 = (wid & 3) * 32;
    const int n0   = (wid >> 2) * 32;
    const int lane = tid & 31;
    const int g8  = lane >> 2;
    const int tg2 = (lane & 3) * 2;

    wmma::fragment<wmma::accumulator, 16, 16, 16, float> acc[2][2];
#pragma unroll
    for (int i = 0; i < 2; i++)
#pragma unroll
        for (int j = 0; j < 2; j++) wmma::fill_fragment(acc[i][j], 0.f);
#pragma unroll
    for (int k = 0; k < 8; k++) {
        wmma::fragment<wmma::matrix_a, 16, 16, 16, __half, wmma::row_major> af[2];
        wmma::fragment<wmma::matrix_b, 16, 16, 16, __half, wmma::row_major> bf[2];
#pragma unroll
        for (int i = 0; i < 2; i++)
            wmma::load_matrix_sync(af[i], As + (size_t)(row0 + i * 16) * AS_LD + k * 16, AS_LD);
#pragma unroll
        for (int j = 0; j < 2; j++)
            wmma::load_matrix_sync(bf[j], B1 + (size_t)(k * 16) * BS_LD + n0 + j * 16, BS_LD);
#pragma unroll
        for (int i = 0; i < 2; i++)
#pragma unroll
            for (int j = 0; j < 2; j++)
                wmma::mma_sync(acc[i][j], af[i], bf[j], acc[i][j]);
    }
    __syncthreads();

    // H = prelu(acc + b1) back into As (fp16), fragment-direct
#pragma unroll
    for (int i = 0; i < 2; i++) {
#pragma unroll
        for (int j = 0; j < 2; j++) {
            const int rl = row0 + i * 16;
            const int cb = n0 + j * 16;
#pragma unroll
            for (int e = 0; e < 8; e += 2) {
                int r = rl + g8 + ((e & 2) ? 8 : 0);
                int c = cb + tg2 + ((e & 4) ? 8 : 0);
                float2 bb = __ldg((const float2*)(b1 + c));
                float vx = prelu1(acc[i][j].x[e]     + bb.x, a);
                float vy = prelu1(acc[i][j].x[e + 1] + bb.y, a);
                __half2 hv = __floats2half2_rn(vx, vy);
                *(unsigned*)(As + (size_t)r * AS_LD + c) = *reinterpret_cast<unsigned*>(&hv);
            }
        }
    }
    __syncthreads();

#pragma unroll
    for (int i = 0; i < 2; i++)
#pragma unroll
        for (int j = 0; j < 2; j++) wmma::fill_fragment(acc[i][j], 0.f);
#pragma unroll
    for (int k = 0; k < 8; k++) {
        wmma::fragment<wmma::matrix_a, 16, 16, 16, __half, wmma::row_major> af[2];
        wmma::fragment<wmma::matrix_b, 16, 16, 16, __half, wmma::row_major> bf[2];
#pragma unroll
        for (int i = 0; i < 2; i++)
            wmma::load_matrix_sync(af[i], As + (size_t)(row0 + i * 16) * AS_LD + k * 16, AS_LD);
#pragma unroll
        for (int j = 0; j < 2; j++)
            wmma::load_matrix_sync(bf[j], B2 + (size_t)(k * 16) * BS_LD + n0 + j * 16, BS_LD);
#pragma unroll
        for (int i = 0; i < 2; i++)
#pragma unroll
            for (int j = 0; j < 2; j++)
                wmma::mma_sync(acc[i][j], af[i], bf[j], acc[i][j]);
    }
#pragma unroll
    for (int i = 0; i < 2; i++) {
#pragma unroll
        for (int j = 0; j < 2; j++) {
            const int rb = m0 + row0 + i * 16;
            const int cb = n0 + j * 16;
#pragma unroll
            for (int e = 0; e < 8; e += 2) {
                int r = rb + g8 + ((e & 2) ? 8 : 0);
                int c = cb + tg2 + ((e & 4) ? 8 : 0);
                if (r < M) {
                    float2 bb = __ldg((const float2*)(b2 + c));
                    __half2 hv = __floats2half2_rn(acc[i][j].x[e] + bb.x,
                                                   acc[i][j].x[e + 1] + bb.y);
                    *(unsigned*)(out_h16 + (size_t)r * 64 + (c >> 1)) =
                        *reinterpret_cast<unsigned*>(&hv);
                }
            }
        }
    }
}

// ---------------- fused: node-agg + single GEMM (layer 1: G4) ----------------
// out_f32 = prelu(Agg @ W + b); csum[comp[r]] += raw * cinv[comp[r]]
__global__ __launch_bounds__(512, 2) void kagg_gemm1(const unsigned* __restrict__ T16,
                                                     const unsigned* __restrict__ EB16,
                                                     const int* __restrict__ perm,
                                                     const int* __restrict__ offs,
                                                     const float* __restrict__ invs,
                                                     const unsigned* __restrict__ Wh,
                                                     const float* __restrict__ bias,
                                                     const float* __restrict__ pa,
                                                     float* __restrict__ out_f32,
                                                     const int* __restrict__ ncomp,
                                                     const float* __restrict__ cinv,
                                                     float* __restrict__ csum, int M) {
    extern __shared__ char smem[];
    __half* As = (__half*)smem;
    __half* Bs = (__half*)(smem + SM_AS);
    const int tid = threadIdx.x;
    const int wid = tid >> 5;
    const int m0 = blockIdx.x * 128;
    const float a = __ldg(pa);

#pragma unroll
    for (int it = 0; it < 4; it++) {
        int idx = tid + it * 512;
        int kk = idx >> 4, g = idx & 15;
        cpasync16(Bs + (size_t)kk * BS_LD + g * 8, (const uint4*)Wh + kk * 16 + g);
    }
    asm volatile("cp.async.commit_group;" ::: "memory");

    {
        const int hw = tid >> 4, l = tid & 15;
#pragma unroll
        for (int q = 0; q < 4; q++) {
            int r = q * 32 + hw;
            int seg = m0 + r;
            uint4 outv = make_uint4(0, 0, 0, 0);
            if (seg < M)
                outv = agg_node_seg(T16, EB16, perm, offs, invs, a, seg, l);
            *(uint4*)(As + (size_t)r * AS_LD + l * 8) = outv;
        }
    }
    asm volatile("cp.async.wait_group 0;" ::: "memory");
    __syncthreads();

    const int row0 = (wid & 3) * 32;
    const int n0   = (wid >> 2) * 32;
    wmma::fragment<wmma::accumulator, 16, 16, 16, float> acc[2][2];
#pragma unroll
    for (int i = 0; i < 2; i++)
#pragma unroll
        for (int j = 0; j < 2; j++) wmma::fill_fragment(acc[i][j], 0.f);
#pragma unroll
    for (int k = 0; k < 8; k++) {
        wmma::fragment<wmma::matrix_a, 16, 16, 16, __half, wmma::row_major> af[2];
        wmma::fragment<wmma::matrix_b, 16, 16, 16, __half, wmma::row_major> bf[2];
#pragma unroll
        for (int i = 0; i < 2; i++)
            wmma::load_matrix_sync(af[i], As + (size_t)(row0 + i * 16) * AS_LD + k * 16, AS_LD);
#pragma unroll
        for (int j = 0; j < 2; j++)
            wmma::load_matrix_sync(bf[j], Bs + (size_t)(k * 16) * BS_LD + n0 + j * 16, BS_LD);
#pragma unroll
        for (int i = 0; i < 2; i++)
#pragma unroll
            for (int j = 0; j < 2; j++)
                wmma::mma_sync(acc[i][j], af[i], bf[j], acc[i][j]);
    }
    {
        const int lane = tid & 31;
        const int g8  = lane >> 2;
        const int tg2 = (lane & 3) * 2;
#pragma unroll
        for (int i = 0; i < 2; i++) {
#pragma unroll
            for (int j = 0; j < 2; j++) {
                const int rb = m0 + row0 + i * 16;
                const int cb = n0 + j * 16;
#pragma unroll
                for (int e = 0; e < 8; e += 2) {
                    int r = rb + g8 + ((e & 2) ? 8 : 0);
                    int c = cb + tg2 + ((e & 4) ? 8 : 0);
                    if (r < M) {
                        float2 bb = __ldg((const float2*)(bias + c));
                        float vx = acc[i][j].x[e]     + bb.x;
                        float vy = acc[i][j].x[e + 1] + bb.y;
                        *(float2*)(out_f32 + (size_t)r * D + c) =
                            make_float2(prelu1(vx, a), prelu1(vy, a));
                        int cc = __ldg(&ncomp[r]);
                        float sc = __ldg(&cinv[cc]);
                        red2(csum + (size_t)cc * D + c, vx * sc, vy * sc);
                    }
                }
            }
        }
    }
}

// ---------------- SIMT GEMM (small C-row GEMMs) ------------------------------
__global__ __launch_bounds__(256) void kgemm2(const float* __restrict__ X,
                                              const float* __restrict__ W,
                                              const float* __restrict__ b,
                                              const float* __restrict__ addin,
                                              float* __restrict__ Yraw,
                                              float* __restrict__ Ypre,
                                              const float* __restrict__ pa, int M) {
    __shared__ float As[64][128];
    const int m0 = blockIdx.x * 64;
    const int t = threadIdx.x;
    {
        const int c4 = t & 31;
        const int r0 = t >> 5;
#pragma unroll
        for (int s = 0; s < 8; s++) {
            int r = r0 + 8 * s;
            int gr = m0 + r;
            float4 v = make_float4(0.f, 0.f, 0.f, 0.f);
            if (gr < M) v = ((const float4*)(X + (size_t)gr * D))[c4];
            ((float4*)(&As[r][0]))[c4] = v;
        }
    }
    __syncthreads();
    const int cg = (t & 15) * 8;
    const int rg = (t >> 4) * 4;
    unsigned long long acc[4][4];
#pragma unroll
    for (int i = 0; i < 4; i++)
#pragma unroll
        for (int j = 0; j < 4; j++) acc[i][j] = 0ULL;
#pragma unroll 4
    for (int k = 0; k < D; k += 4) {
        float4 a[4];
#pragma unroll
        for (int i = 0; i < 4; i++) a[i] = *(const float4*)&As[rg + i][k];
#pragma unroll
        for (int kk = 0; kk < 4; kk++) {
            const ulonglong2 w0 = *reinterpret_cast<const ulonglong2*>(&W[(k + kk) * D + cg]);
            const ulonglong2 w1 = *reinterpret_cast<const ulonglong2*>(&W[(k + kk) * D + cg + 4]);
#pragma unroll
            for (int i = 0; i < 4; i++) {
                float av = (kk == 0) ? a[i].x : (kk == 1) ? a[i].y
                         : (kk == 2) ? a[i].z : a[i].w;
                unsigned long long av2 = pk2(av);
                fma2(acc[i][0], av2, w0.x);
                fma2(acc[i][1], av2, w0.y);
                fma2(acc[i][2], av2, w1.x);
                fma2(acc[i][3], av2, w1.y);
            }
        }
    }
    const float4 b0 = __ldg((const float4*)&b[cg]);
    const float4 b1 = __ldg((const float4*)&b[cg + 4]);
    const float a = __ldg(pa);
#pragma unroll
    for (int i = 0; i < 4; i++) {
        int gr = m0 + rg + i;
        if (gr >= M) continue;
        float2 p0 = up2(acc[i][0]), p1 = up2(acc[i][1]);
        float2 p2 = up2(acc[i][2]), p3 = up2(acc[i][3]);
        float4 o0 = make_float4(p0.x + b0.x, p0.y + b0.y, p1.x + b0.z, p1.y + b0.w);
        float4 o1 = make_float4(p2.x + b1.x, p2.y + b1.y, p3.x + b1.z, p3.y + b1.w);
        if (addin) {
            const float4* ar = (const float4*)(addin + (size_t)gr * D);
            add4(o0, ar[cg / 4]); add4(o1, ar[cg / 4 + 1]);
        }
        if (Yraw) {
            float4* yr = (float4*)(Yraw + (size_t)gr * D);
            yr[cg / 4] = o0; yr[cg / 4 + 1] = o1;
        }
        if (Ypre) {
            float4* yp = (float4*)(Ypre + (size_t)gr * D);
            yp[cg / 4] = prelu4(o0, a); yp[cg / 4 + 1] = prelu4(o1, a);
        }
    }
}

// ---------------- CSR edge aggregation (half-warp/segment) -------------------
__global__ __launch_bounds__(256) void kagg_e(const unsigned* __restrict__ T16,
                                              const int* __restrict__ perm,
                                              const int* __restrict__ offs,
                                              const float* __restrict__ invd,
                                              const float* __restrict__ pa,
                                              unsigned* __restrict__ EB16,
                                              float* __restrict__ out_e,
                                              const int* __restrict__ ecomp,
                                              const float* __restrict__ cinv,
                                              float* __restrict__ csum, int E) {
    int seg = (blockIdx.x * blockDim.x + threadIdx.x) >> 4;
    int l = threadIdx.x & 15;
    if (seg >= E) return;
    int beg = __ldg(&offs[seg]), end = __ldg(&offs[seg + 1]);
    float4 s0 = {0,0,0,0}, s1 = {0,0,0,0}, t0 = {0,0,0,0}, t1 = {0,0,0,0};
    float4 u0 = {0,0,0,0}, u1 = {0,0,0,0}, v0 = {0,0,0,0}, v1 = {0,0,0,0};
    int p = beg;
    for (; p + 8 <= end; p += 8) {
        uint4 vv[8];
#pragma unroll
        for (int q = 0; q < 8; q++)
            vv[q] = __ldg((const uint4*)(T16 + (size_t)__ldg(&perm[p + q]) * 64) + l);
        addh8(s0, s1, vv[0]); addh8(t0, t1, vv[1]);
        addh8(u0, u1, vv[2]); addh8(v0, v1, vv[3]);
        addh8(s0, s1, vv[4]); addh8(t0, t1, vv[5]);
        addh8(u0, u1, vv[6]); addh8(v0, v1, vv[7]);
    }
    for (; p + 4 <= end; p += 4) {
        uint4 vv[4];
#pragma unroll
        for (int q = 0; q < 4; q++)
            vv[q] = __ldg((const uint4*)(T16 + (size_t)__ldg(&perm[p + q]) * 64) + l);
        addh8(s0, s1, vv[0]); addh8(t0, t1, vv[1]);
        addh8(u0, u1, vv[2]); addh8(v0, v1, vv[3]);
    }
    for (; p < end; p++)
        addh8(s0, s1, __ldg((const uint4*)(T16 + (size_t)__ldg(&perm[p]) * 64) + l));
    add4(s0, t0); add4(u0, v0); add4(s0, u0);
    add4(s1, t1); add4(u1, v1); add4(s1, u1);
    float iv = __ldg(&invd[seg]);
    float a = __ldg(pa);
    s0.x *= iv; s0.y *= iv; s0.z *= iv; s0.w *= iv;
    s1.x *= iv; s1.y *= iv; s1.z *= iv; s1.w *= iv;
    float4 r0 = prelu4(s0, a), r1 = prelu4(s1, a);
    uint2 q0 = h4(r0), q1 = h4(r1);
    ((uint4*)(EB16 + (size_t)seg * 64))[l] = make_uint4(q0.x, q0.y, q1.x, q1.y);
    if (out_e) {
        ((float4*)out_e)[(size_t)seg * 32 + l * 2]     = r0;
        ((float4*)out_e)[(size_t)seg * 32 + l * 2 + 1] = r1;
    }
    if (csum) {
        int cc = __ldg(&ecomp[seg]);
        float sc = __ldg(&cinv[cc]);
        float4 w0 = make_float4(r0.x * sc, r0.y * sc, r0.z * sc, r0.w * sc);
        float4 w1 = make_float4(r1.x * sc, r1.y * sc, r1.z * sc, r1.w * sc);
        red4(csum + (size_t)cc * D + l * 8,     w0);
        red4(csum + (size_t)cc * D + l * 8 + 4, w1);
    }
}

// ---------------- host driver ------------------------------------------------
static inline int cdiv(long a, long b) { return (int)((a + b - 1) / b); }

extern "C" void kernel_launch(void* const* d_in, const int* in_sizes, int n_in,
                              void* d_out, int out_size) {
    const float* x   = (const float*)d_in[0];
    const int*   hei = (const int*)d_in[1];
    const int*   hci = (const int*)d_in[2];
    const int*   nci = (const int*)d_in[3];

    const int NNZ = in_sizes[1] / 2;
    const int E   = in_sizes[2] / 2;
    const int N   = in_sizes[0] / D;
    const int C   = out_size / D - N - E;

    int wi = -1;
    for (int i = 4; i < n_in; i++) {
        if (in_sizes[i] == D * D) { wi = i; break; }
    }
    const float* pa = (const float*)d_in[wi - 1];

    const int* src  = hei;
    const int* dst  = hei + NNZ;
    const int* he_c = hci + E;
    const int* nc_c = nci + N;

    float *CE, *CN, *CT, *invd, *invs, *ic1, *ic2;
    unsigned *T16, *E16, *Wh;
    int *cd, *cs, *cc1, *cc2, *od, *os, *pd, *ps, *bsum, *bscan;
    cudaGetSymbolAddress((void**)&T16,  g_T16);
    cudaGetSymbolAddress((void**)&E16,  g_E16);
    cudaGetSymbolAddress((void**)&CE,   g_c1);
    cudaGetSymbolAddress((void**)&CN,   g_c2);
    cudaGetSymbolAddress((void**)&CT,   g_c3);
    cudaGetSymbolAddress((void**)&Wh,   g_Wh);
    cudaGetSymbolAddress((void**)&invd, g_invdst);
    cudaGetSymbolAddress((void**)&invs, g_invsrc);
    cudaGetSymbolAddress((void**)&ic1,  g_invc1);
    cudaGetSymbolAddress((void**)&ic2,  g_invc2);
    cudaGetSymbolAddress((void**)&cd,   g_cd);
    cudaGetSymbolAddress((void**)&cs,   g_cs);
    cudaGetSymbolAddress((void**)&cc1,  g_cc1);
    cudaGetSymbolAddress((void**)&cc2,  g_cc2);
    cudaGetSymbolAddress((void**)&od,   g_offs_d);
    cudaGetSymbolAddress((void**)&os,   g_offs_s);
    cudaGetSymbolAddress((void**)&pd,   g_perm_d);
    cudaGetSymbolAddress((void**)&ps,   g_perm_s);
    cudaGetSymbolAddress((void**)&bsum, g_bsum);
    cudaGetSymbolAddress((void**)&bscan,g_bscan);

    float* out   = (float*)d_out;
    float* out_n = out;
    float* out_e = out + (size_t)N * D;
    float* out_c = out + (size_t)(N + E) * D;

    const int TB = 256;
    const int nbd = cdiv(E, 1024);
    const int nbs = cdiv(N, 1024);
    const int nbtot = nbd + nbs;
    const int GT = cdiv(N, 128);

    const float* bv0 = (const float*)d_in[wi + 1];
    const float* be0 = (const float*)d_in[wi + 3];
    const float* bv1 = (const float*)d_in[wi + 9];
    const float* be1 = (const float*)d_in[wi + 11];

    cudaFuncSetAttribute(kgemm_tc,   cudaFuncAttributeMaxDynamicSharedMemorySize, SM_TOT);
    cudaFuncSetAttribute(kagg_gemm1, cudaFuncAttributeMaxDynamicSharedMemorySize, SM_TOT);
    cudaFuncSetAttribute(kagg_gemm2, cudaFuncAttributeMaxDynamicSharedMemorySize, SM3_TOT);

    static cudaStream_t s2 = nullptr;
    static cudaEvent_t evA = nullptr, evB = nullptr, evC = nullptr, evD = nullptr;
    if (!s2) {
        cudaStreamCreateWithFlags(&s2, cudaStreamNonBlocking);
        cudaEventCreateWithFlags(&evA, cudaEventDisableTiming);
        cudaEventCreateWithFlags(&evB, cudaEventDisableTiming);
        cudaEventCreateWithFlags(&evC, cudaEventDisableTiming);
        cudaEventCreateWithFlags(&evD, cudaEventDisableTiming);
    }

    ksetup0<<<cdiv(4 * 128 * 16 + E + N + 2 * C, TB), TB>>>(
        (const float*)d_in[wi + 0], (const float*)d_in[wi + 2],
        (const float*)d_in[wi + 8], (const float*)d_in[wi + 10], Wh,
        cd, cs, cc1, cc2, E, N, C);

    // ---- fork 1: CSR build on s2  ||  G1 on main ----
    cudaEventRecord(evA, 0);
    cudaStreamWaitEvent(s2, evA, 0);
    kcountall<<<cdiv(NNZ + E + N, TB), TB, 0, s2>>>(src, dst, he_c, nc_c,
                                                    cs, cd, cc1, cc2, NNZ, E, N);
    kscanA<<<nbtot, 1024, 0, s2>>>(cd, cs, od, os, bsum, nbd, E, N);
    kscanB<<<1, 1024, 0, s2>>>(bsum, bscan, nbd, nbtot, NNZ);
    kscanC<<<nbtot, 1024, 0, s2>>>(od, os, bscan, cd, cs, nbd, E, N, NNZ);
    kfillinv<<<cdiv((long)NNZ + E + N + 2 * C + 2 * C * 32, TB), TB, 0, s2>>>(
        src, dst, cd, cs, pd, ps, od, os, cc1, cc2,
        invd, invs, ic1, ic2, (float4*)CE, (float4*)CN, NNZ, E, N, C);
    cudaEventRecord(evB, s2);

    // G1 = v2e layer 0 (fp32 input) -> T16 raw
    kgemm_tc<<<GT, 512, SM_TOT>>>(x, Wh + 0 * 8192, bv0, pa, T16, N);
    cudaStreamWaitEvent(0, evB, 0);   // join

    // ---- layer 0 ----
    kagg_e<<<cdiv((long)E * 16, TB), TB>>>(T16, pd, od, invd, pa, E16, nullptr,
                                           nullptr, nullptr, nullptr, E);
    // fused node-agg + G2 + G3 -> T16
    kagg_gemm2<<<GT, 512, SM3_TOT>>>(T16, E16, ps, os, invs,
                                     Wh + 1 * 8192, be0, Wh + 2 * 8192, bv1,
                                     pa, T16, N);

    // ---- layer 1 ----
    kagg_e<<<cdiv((long)E * 16, TB), TB>>>(T16, pd, od, invd, pa, E16, out_e,
                                           he_c, ic1, CE, E);
    // ---- fork 2: CE component GEMM on s2  ||  fused agg+G4 on main ----
    cudaEventRecord(evC, 0);
    cudaStreamWaitEvent(s2, evC, 0);
    kgemm2<<<cdiv(C, 64), TB, 0, s2>>>(CE, (const float*)d_in[wi + 12],
                                       (const float*)d_in[wi + 13],
                                       nullptr, CT, nullptr, pa, C);
    cudaEventRecord(evD, s2);

    kagg_gemm1<<<GT, 512, SM_TOT>>>(T16, E16, ps, os, invs,
                                    Wh + 3 * 8192, be1, pa, out_n,
                                    nc_c, ic2, CN, N);
    cudaStreamWaitEvent(0, evD, 0);   // join

    kgemm2<<<cdiv(C, 64), TB>>>(CN, (const float*)d_in[wi + 14], (const float*)d_in[wi + 15],
                                CT, nullptr, out_c, pa, C);
}

// round 17
// speedup vs baseline: 2.7892x; 1.0556x over previous
#include <cuda_runtime.h>
#include <cuda_fp16.h>
#include <cuda_bf16.h>
#include <mma.h>
#include <cstdint>
#include <cstddef>

#define D 128
using namespace nvcuda;

// ---------------- static scratch (device globals; zero-initialized) ----------
static __device__ unsigned g_T16[100000 * 64];
static __device__ unsigned g_E16[50000  * 64];
static __device__ float    g_c1 [2048   * 128];
static __device__ float    g_c2 [2048   * 128];
static __device__ float    g_c3 [2048   * 128];
static __device__ unsigned g_Wh [5 * 128 * 64];   // 5 fp16 weight slots
static __device__ float g_invdst[50016];
static __device__ float g_invsrc[100016];
static __device__ float g_invc1[2048];
static __device__ float g_invc2[2048];
static __device__ int   g_cd [50016];      // pre-zeroed invariant (kzerocnt)
static __device__ int   g_cs [100016];
static __device__ int   g_cc1[2048];
static __device__ int   g_cc2[2048];
static __device__ int   g_offs_d[50024];
static __device__ int   g_offs_s[100024];
static __device__ int   g_perm_d[1600128];
static __device__ int   g_perm_s[1600128];
static __device__ int   g_bsum [1024];

// ---------------- helpers ----------------------------------------------------
__device__ __forceinline__ unsigned long long pk2(float v) {
    unsigned long long r; unsigned u = __float_as_uint(v);
    asm("mov.b64 %0, {%1,%1};" : "=l"(r) : "r"(u));
    return r;
}
__device__ __forceinline__ void fma2(unsigned long long& d, unsigned long long a,
                                     unsigned long long b) {
    asm("fma.rn.f32x2 %0, %1, %2, %0;" : "+l"(d) : "l"(a), "l"(b));
}
__device__ __forceinline__ float2 up2(unsigned long long v) {
    unsigned lo, hi;
    asm("mov.b64 {%0,%1}, %2;" : "=r"(lo), "=r"(hi) : "l"(v));
    return make_float2(__uint_as_float(lo), __uint_as_float(hi));
}
__device__ __forceinline__ float prelu1(float v, float a) { return v >= 0.f ? v : a * v; }
__device__ __forceinline__ float4 prelu4(float4 v, float a) {
    return make_float4(prelu1(v.x, a), prelu1(v.y, a), prelu1(v.z, a), prelu1(v.w, a));
}
__device__ __forceinline__ void add4(float4& a, float4 b) {
    a.x += b.x; a.y += b.y; a.z += b.z; a.w += b.w;
}
__device__ __forceinline__ void addh8(float4& a, float4& b, uint4 v) {
    __half2 h0 = *reinterpret_cast<__half2*>(&v.x);
    __half2 h1 = *reinterpret_cast<__half2*>(&v.y);
    __half2 h2 = *reinterpret_cast<__half2*>(&v.z);
    __half2 h3 = *reinterpret_cast<__half2*>(&v.w);
    float2 f0 = __half22float2(h0), f1 = __half22float2(h1);
    float2 f2 = __half22float2(h2), f3 = __half22float2(h3);
    a.x += f0.x; a.y += f0.y; a.z += f1.x; a.w += f1.y;
    b.x += f2.x; b.y += f2.y; b.z += f3.x; b.w += f3.y;
}
__device__ __forceinline__ uint2 h4(float4 v) {
    __half2 h0 = __float22half2_rn(make_float2(v.x, v.y));
    __half2 h1 = __float22half2_rn(make_float2(v.z, v.w));
    uint2 r;
    r.x = *reinterpret_cast<unsigned*>(&h0);
    r.y = *reinterpret_cast<unsigned*>(&h1);
    return r;
}
__device__ __forceinline__ void cpasync16(void* smem_dst, const void* gsrc) {
    unsigned sa = (unsigned)__cvta_generic_to_shared(smem_dst);
    asm volatile("cp.async.cg.shared.global [%0], [%1], 16;" :: "r"(sa), "l"(gsrc));
}
__device__ __forceinline__ void red4(float* a, float4 v) {
    asm volatile("red.global.add.v4.f32 [%0], {%1,%2,%3,%4};"
                 :: "l"(a), "f"(v.x), "f"(v.y), "f"(v.z), "f"(v.w)
                 : "memory");
}
__device__ __forceinline__ void red2(float* a, float x, float y) {
    asm volatile("red.global.add.v2.f32 [%0], {%1,%2};"
                 :: "l"(a), "f"(x), "f"(y) : "memory");
}

#define AS_LD 136
#define BS_LD 136
#define SM_AS  (128 * AS_LD * 2)
#define SM_TOT (SM_AS + 128 * BS_LD * 2)
#define SM3_TOT (3 * SM_AS)

// aggregate node segment (kagg_n math, verbatim) -> uint4 of 8 fp16
__device__ __forceinline__ uint4 agg_node_seg(const unsigned* __restrict__ T16,
                                              const unsigned* __restrict__ EB16,
                                              const int* __restrict__ perm,
                                              const int* __restrict__ offs,
                                              const float* __restrict__ invs,
                                              float a, int seg, int l) {
    int beg = __ldg(&offs[seg]), end = __ldg(&offs[seg + 1]);
    float4 s0 = {0,0,0,0}, s1 = {0,0,0,0}, t0 = {0,0,0,0}, t1 = {0,0,0,0};
    float4 u0 = {0,0,0,0}, u1 = {0,0,0,0}, v0 = {0,0,0,0}, v1 = {0,0,0,0};
    int p = beg;
    for (; p + 8 <= end; p += 8) {
        uint4 vv[8];
#pragma unroll
        for (int q = 0; q < 8; q++)
            vv[q] = __ldg((const uint4*)(EB16 + (size_t)__ldg(&perm[p + q]) * 64) + l);
        addh8(s0, s1, vv[0]); addh8(t0, t1, vv[1]);
        addh8(u0, u1, vv[2]); addh8(v0, v1, vv[3]);
        addh8(s0, s1, vv[4]); addh8(t0, t1, vv[5]);
        addh8(u0, u1, vv[6]); addh8(v0, v1, vv[7]);
    }
    for (; p + 4 <= end; p += 4) {
        uint4 vv[4];
#pragma unroll
        for (int q = 0; q < 4; q++)
            vv[q] = __ldg((const uint4*)(EB16 + (size_t)__ldg(&perm[p + q]) * 64) + l);
        addh8(s0, s1, vv[0]); addh8(t0, t1, vv[1]);
        addh8(u0, u1, vv[2]); addh8(v0, v1, vv[3]);
    }
    for (; p < end; p++)
        addh8(s0, s1, __ldg((const uint4*)(EB16 + (size_t)__ldg(&perm[p]) * 64) + l));
    add4(s0, t0); add4(u0, v0); add4(s0, u0);
    add4(s1, t1); add4(u1, v1); add4(s1, u1);
    float4 w0 = {0,0,0,0}, w1 = {0,0,0,0};
    addh8(w0, w1, __ldg((const uint4*)(T16 + (size_t)seg * 64) + l));
    add4(s0, prelu4(w0, a));
    add4(s1, prelu4(w1, a));
    float iv = __ldg(&invs[seg]);
    s0.x *= iv; s0.y *= iv; s0.z *= iv; s0.w *= iv;
    s1.x *= iv; s1.y *= iv; s1.z *= iv; s1.w *= iv;
    uint2 q0 = h4(s0), q1 = h4(s1);
    return make_uint4(q0.x, q0.y, q1.x, q1.y);
}

// ---------------- W convert (5 matrices) -------------------------------------
__global__ void ksetupW(const float* __restrict__ W0, const float* __restrict__ W1,
                        const float* __restrict__ W2, const float* __restrict__ W3,
                        const float* __restrict__ W4, unsigned* __restrict__ Wh) {
    int idx = blockIdx.x * blockDim.x + threadIdx.x;
    if (idx >= 5 * 128 * 16) return;
    int w = idx >> 11;
    int rem = idx & 2047;
    int kk = rem >> 4, g = rem & 15;
    const float* W = (w == 0) ? W0 : (w == 1) ? W1 : (w == 2) ? W2
                   : (w == 3) ? W3 : W4;
    float4 x0 = __ldg((const float4*)(W + (size_t)kk * D + g * 8));
    float4 x1 = __ldg((const float4*)(W + (size_t)kk * D + g * 8 + 4));
    uint2 p0 = h4(x0), p1 = h4(x1);
    ((uint4*)(Wh + (size_t)w * 128 * 64))[kk * 16 + g] = make_uint4(p0.x, p0.y, p1.x, p1.y);
}

// counts into PRE-ZEROED arrays
__global__ void kcountall(const int* __restrict__ src, const int* __restrict__ dst,
                          const int* __restrict__ he_c, const int* __restrict__ nc_c,
                          int* cs, int* cd, int* cc1, int* cc2,
                          int nnz, int E, int N) {
    int i = blockIdx.x * blockDim.x + threadIdx.x;
    if (i < nnz) {
        atomicAdd(&cd[dst[i]], 1);
        atomicAdd(&cs[src[i]], 1);
    } else if (i < nnz + E) {
        atomicAdd(&cc1[he_c[i - nnz]], 1);
    } else if (i < nnz + E + N) {
        atomicAdd(&cc2[nc_c[i - nnz - E]], 1);
    }
}

__global__ __launch_bounds__(1024) void kscanA(const int* __restrict__ cd,
                                               const int* __restrict__ cs,
                                               int* od, int* os, int* bsum,
                                               int nbd, int E, int N) {
    __shared__ int sh[1024];
    const int b = blockIdx.x, t = threadIdx.x;
    const bool isD = b < nbd;
    const int* in = isD ? cd : cs;
    int* out = isD ? od : os;
    const int n = isD ? E : N;
    const int i = (isD ? b : b - nbd) * 1024 + t;
    int v = (i < n) ? in[i] : 0;
    sh[t] = v;
    __syncthreads();
    for (int off = 1; off < 1024; off <<= 1) {
        int x = (t >= off) ? sh[t - off] : 0;
        __syncthreads();
        sh[t] += x;
        __syncthreads();
    }
    if (i < n) out[i] = sh[t] - v;
    if (t == 1023) bsum[b] = sh[1023];
}

// inline block prefix (replaces kscanB+kscanC); cursors = start offsets
__global__ __launch_bounds__(1024) void kscanC2(int* od, int* os,
                                                const int* __restrict__ bsum,
                                                int* cd, int* cs,
                                                int nbd, int E, int N, int nnz) {
    __shared__ int spref;
    const int b = blockIdx.x, t = threadIdx.x;
    const bool isD = b < nbd;
    if (t < 32) {
        int lo = isD ? 0 : nbd;
        int acc = 0;
        for (int j = lo + t; j < b; j += 32) acc += __ldg(&bsum[j]);
#pragma unroll
        for (int o = 16; o; o >>= 1) acc += __shfl_down_sync(0xffffffffu, acc, o);
        if (t == 0) spref = acc;
    }
    __syncthreads();
    const int pref = spref;
    const int i = (isD ? b : b - nbd) * 1024 + t;
    if (isD) {
        if (i < E) { int o = od[i] + pref; od[i] = o; cd[i] = o; }
        if (b == 0 && t == 0) od[E] = nnz;
    } else {
        if (i < N) { int o = os[i] + pref; os[i] = o; cs[i] = o; }
        if (i == 0) os[N] = nnz;
    }
}

__global__ void kfillinv(const int* __restrict__ src, const int* __restrict__ dst,
                         int* cur_d, int* cur_s, int* perm_d, int* perm_s,
                         const int* __restrict__ od, const int* __restrict__ os,
                         const int* __restrict__ cc1, const int* __restrict__ cc2,
                         float* invd, float* invs, float* ic1, float* ic2,
                         float4* CE4, float4* CN4, int nnz, int E, int N, int C) {
    int k = blockIdx.x * blockDim.x + threadIdx.x;
    if (k < nnz) {
        int s = __ldg(&src[k]), d = __ldg(&dst[k]);
        perm_d[atomicAdd(&cur_d[d], 1)] = s;
        perm_s[atomicAdd(&cur_s[s], 1)] = d;
        return;
    }
    int i = k - nnz;
    if (i < E) {
        int c = od[i + 1] - od[i];
        invd[i] = 1.f / (float)(c > 0 ? c : 1);
    } else if (i < E + N) {
        int j = i - E;
        int c = os[j + 1] - os[j] + 1;
        invs[j] = 1.f / (float)c;
    } else if (i < E + N + C) {
        int c = cc1[i - E - N];
        ic1[i - E - N] = 1.f / (float)(c > 0 ? c : 1);
    } else if (i < E + N + 2 * C) {
        int c = cc2[i - E - N - C];
        ic2[i - E - N - C] = 1.f / (float)(c > 0 ? c : 1);
    } else {
        int j = i - (E + N + 2 * C);
        int z = C * 32;
        if (j < z) CE4[j] = make_float4(0.f, 0.f, 0.f, 0.f);
        else if (j < 2 * z) CN4[j - z] = make_float4(0.f, 0.f, 0.f, 0.f);
    }
}

// restore counter-zero invariant for next replay
__global__ void kzerocnt(int* cd, int* cs, int* cc1, int* cc2, int E, int N, int C) {
    int i = blockIdx.x * blockDim.x + threadIdx.x;
    if (i < E) cd[i] = 0;
    else if (i < E + N) cs[i - E] = 0;
    else if (i < E + N + C) cc1[i - E - N] = 0;
    else if (i < E + N + 2 * C) cc2[i - E - N - C] = 0;
}

// ---------------- WMMA GEMM (fp32 in) -> fp16 out ----------------------------
__global__ __launch_bounds__(512, 2) void kgemm_tc(const float* __restrict__ X32,
                                                   const unsigned* __restrict__ Wh,
                                                   const float* __restrict__ bias,
                                                   const float* __restrict__ pa,
                                                   unsigned* __restrict__ out_h16,
                                                   int M) {
    extern __shared__ char smem[];
    __half* As = (__half*)smem;
    __half* Bs = (__half*)(smem + SM_AS);
    const int tid = threadIdx.x;
    const int wid = tid >> 5;
    const int m0 = blockIdx.x * 128;

#pragma unroll
    for (int it = 0; it < 4; it++) {
        int idx = tid + it * 512;
        int kk = idx >> 4, g = idx & 15;
        cpasync16(Bs + (size_t)kk * BS_LD + g * 8, (const uint4*)Wh + kk * 16 + g);
    }
    asm volatile("cp.async.commit_group;" ::: "memory");
#pragma unroll
    for (int it = 0; it < 4; it++) {
        int idx = tid + it * 512;
        int r = idx >> 4, g = idx & 15;
        int gr = m0 + r;
        float4 x0 = make_float4(0.f, 0.f, 0.f, 0.f), x1 = x0;
        if (gr < M) {
            x0 = __ldg((const float4*)(X32 + (size_t)gr * D + g * 8));
            x1 = __ldg((const float4*)(X32 + (size_t)gr * D + g * 8 + 4));
        }
        uint2 p0 = h4(x0), p1 = h4(x1);
        *(uint4*)(As + (size_t)r * AS_LD + g * 8) = make_uint4(p0.x, p0.y, p1.x, p1.y);
    }
    asm volatile("cp.async.wait_group 0;" ::: "memory");
    __syncthreads();

    const int row0 = (wid & 3) * 32;
    const int n0   = (wid >> 2) * 32;
    wmma::fragment<wmma::accumulator, 16, 16, 16, float> acc[2][2];
#pragma unroll
    for (int i = 0; i < 2; i++)
#pragma unroll
        for (int j = 0; j < 2; j++) wmma::fill_fragment(acc[i][j], 0.f);
#pragma unroll
    for (int k = 0; k < 8; k++) {
        wmma::fragment<wmma::matrix_a, 16, 16, 16, __half, wmma::row_major> af[2];
        wmma::fragment<wmma::matrix_b, 16, 16, 16, __half, wmma::row_major> bf[2];
#pragma unroll
        for (int i = 0; i < 2; i++)
            wmma::load_matrix_sync(af[i], As + (size_t)(row0 + i * 16) * AS_LD + k * 16, AS_LD);
#pragma unroll
        for (int j = 0; j < 2; j++)
            wmma::load_matrix_sync(bf[j], Bs + (size_t)(k * 16) * BS_LD + n0 + j * 16, BS_LD);
#pragma unroll
        for (int i = 0; i < 2; i++)
#pragma unroll
            for (int j = 0; j < 2; j++)
                wmma::mma_sync(acc[i][j], af[i], bf[j], acc[i][j]);
    }
    {
        const int lane = tid & 31;
        const int g8  = lane >> 2;
        const int tg2 = (lane & 3) * 2;
#pragma unroll
        for (int i = 0; i < 2; i++) {
#pragma unroll
            for (int j = 0; j < 2; j++) {
                const int rb = m0 + row0 + i * 16;
                const int cb = n0 + j * 16;
#pragma unroll
                for (int e = 0; e < 8; e += 2) {
                    int r = rb + g8 + ((e & 2) ? 8 : 0);
                    int c = cb + tg2 + ((e & 4) ? 8 : 0);
                    if (r < M) {
                        float2 bb = __ldg((const float2*)(bias + c));
                        __half2 hv = __floats2half2_rn(acc[i][j].x[e] + bb.x,
                                                       acc[i][j].x[e + 1] + bb.y);
                        *(unsigned*)(out_h16 + (size_t)r * 64 + (c >> 1)) =
                            *reinterpret_cast<unsigned*>(&hv);
                    }
                }
            }
        }
    }
}

// ---------------- WMMA GEMM (fp32 in, fp32 addin, fp32 prelu out) ------------
__global__ __launch_bounds__(512, 2) void kgemm_cn(const float* __restrict__ X32,
                                                   const unsigned* __restrict__ Wh,
                                                   const float* __restrict__ bias,
                                                   const float* __restrict__ addin,
                                                   const float* __restrict__ pa,
                                                   float* __restrict__ out_f32,
                                                   int M) {
    extern __shared__ char smem[];
    __half* As = (__half*)smem;
    __half* Bs = (__half*)(smem + SM_AS);
    const int tid = threadIdx.x;
    const int wid = tid >> 5;
    const int m0 = blockIdx.x * 128;

#pragma unroll
    for (int it = 0; it < 4; it++) {
        int idx = tid + it * 512;
        int kk = idx >> 4, g = idx & 15;
        cpasync16(Bs + (size_t)kk * BS_LD + g * 8, (const uint4*)Wh + kk * 16 + g);
    }
    asm volatile("cp.async.commit_group;" ::: "memory");
#pragma unroll
    for (int it = 0; it < 4; it++) {
        int idx = tid + it * 512;
        int r = idx >> 4, g = idx & 15;
        int gr = m0 + r;
        float4 x0 = make_float4(0.f, 0.f, 0.f, 0.f), x1 = x0;
        if (gr < M) {
            x0 = __ldg((const float4*)(X32 + (size_t)gr * D + g * 8));
            x1 = __ldg((const float4*)(X32 + (size_t)gr * D + g * 8 + 4));
        }
        uint2 p0 = h4(x0), p1 = h4(x1);
        *(uint4*)(As + (size_t)r * AS_LD + g * 8) = make_uint4(p0.x, p0.y, p1.x, p1.y);
    }
    asm volatile("cp.async.wait_group 0;" ::: "memory");
    __syncthreads();

    const int row0 = (wid & 3) * 32;
    const int n0   = (wid >> 2) * 32;
    wmma::fragment<wmma::accumulator, 16, 16, 16, float> acc[2][2];
#pragma unroll
    for (int i = 0; i < 2; i++)
#pragma unroll
        for (int j = 0; j < 2; j++) wmma::fill_fragment(acc[i][j], 0.f);
#pragma unroll
    for (int k = 0; k < 8; k++) {
        wmma::fragment<wmma::matrix_a, 16, 16, 16, __half, wmma::row_major> af[2];
        wmma::fragment<wmma::matrix_b, 16, 16, 16, __half, wmma::row_major> bf[2];
#pragma unroll
        for (int i = 0; i < 2; i++)
            wmma::load_matrix_sync(af[i], As + (size_t)(row0 + i * 16) * AS_LD + k * 16, AS_LD);
#pragma unroll
        for (int j = 0; j < 2; j++)
            wmma::load_matrix_sync(bf[j], Bs + (size_t)(k * 16) * BS_LD + n0 + j * 16, BS_LD);
#pragma unroll
        for (int i = 0; i < 2; i++)
#pragma unroll
            for (int j = 0; j < 2; j++)
                wmma::mma_sync(acc[i][j], af[i], bf[j], acc[i][j]);
    }
    {
        const float a = __ldg(pa);
        const int lane = tid & 31;
        const int g8  = lane >> 2;
        const int tg2 = (lane & 3) * 2;
#pragma unroll
        for (int i = 0; i < 2; i++) {
#pragma unroll
            for (int j = 0; j < 2; j++) {
                const int rb = m0 + row0 + i * 16;
                const int cb = n0 + j * 16;
#pragma unroll
                for (int e = 0; e < 8; e += 2) {
                    int r = rb + g8 + ((e & 2) ? 8 : 0);
                    int c = cb + tg2 + ((e & 4) ? 8 : 0);
                    if (r < M) {
                        float2 bb = __ldg((const float2*)(bias + c));
                        float2 ad = __ldg((const float2*)(addin + (size_t)r * D + c));
                        float vx = acc[i][j].x[e]     + bb.x + ad.x;
                        float vy = acc[i][j].x[e + 1] + bb.y + ad.y;
                        *(float2*)(out_f32 + (size_t)r * D + c) =
                            make_float2(prelu1(vx, a), prelu1(vy, a));
                    }
                }
            }
        }
    }
}

// ---------------- fused: node-agg + double GEMM (layer 0) --------------------
__global__ __launch_bounds__(512, 2) void kagg_gemm2(const unsigned* __restrict__ T16,
                                                     const unsigned* __restrict__ EB16,
                                                     const int* __restrict__ perm,
                                                     const int* __restrict__ offs,
                                                     const float* __restrict__ invs,
                                                     const unsigned* __restrict__ Wh1,
                                                     const float* __restrict__ b1,
                                                     const unsigned* __restrict__ Wh2,
                                                     const float* __restrict__ b2,
                                                     const float* __restrict__ pa,
                                                     unsigned* __restrict__ out_h16,
                                                     int M) {
    extern __shared__ char smem[];
    __half* As = (__half*)smem;
    __half* B1 = (__half*)(smem + SM_AS);
    __half* B2 = (__half*)(smem + 2 * SM_AS);
    const int tid = threadIdx.x;
    const int wid = tid >> 5;
    const int m0 = blockIdx.x * 128;
    const float a = __ldg(pa);

#pragma unroll
    for (int it = 0; it < 4; it++) {
        int idx = tid + it * 512;
        int kk = idx >> 4, g = idx & 15;
        cpasync16(B1 + (size_t)kk * BS_LD + g * 8, (const uint4*)Wh1 + kk * 16 + g);
        cpasync16(B2 + (size_t)kk * BS_LD + g * 8, (const uint4*)Wh2 + kk * 16 + g);
    }
    asm volatile("cp.async.commit_group;" ::: "memory");

    {
        const int hw = tid >> 4, l = tid & 15;
#pragma unroll
        for (int q = 0; q < 4; q++) {
            int r = q * 32 + hw;
            int seg = m0 + r;
            uint4 outv = make_uint4(0, 0, 0, 0);
            if (seg < M)
                outv = agg_node_seg(T16, EB16, perm, offs, invs, a, seg, l);
            *(uint4*)(As + (size_t)r * AS_LD + l * 8) = outv;
        }
    }
    asm volatile("cp.async.wait_group 0;" ::: "memory");
    __syncthreads();

    const int row0 = (wid & 3) * 32;
    const int n0   = (wid >> 2) * 32;
    const int lane = tid & 31;
    const int g8  = lane >> 2;
    const int tg2 = (lane & 3) * 2;

    wmma::fragment<wmma::accumulator, 16, 16, 16, float> acc[2][2];
#pragma unroll
    for (int i = 0; i < 2; i++)
#pragma unroll
        for (int j = 0; j < 2; j++) wmma::fill_fragment(acc[i][j], 0.f);
#pragma unroll
    for (int k = 0; k < 8; k++) {
        wmma::fragment<wmma::matrix_a, 16, 16, 16, __half, wmma::row_major> af[2];
        wmma::fragment<wmma::matrix_b, 16, 16, 16, __half, wmma::row_major> bf[2];
#pragma unroll
        for (int i = 0; i < 2; i++)
            wmma::load_matrix_sync(af[i], As + (size_t)(row0 + i * 16) * AS_LD + k * 16, AS_LD);
#pragma unroll
        for (int j = 0; j < 2; j++)
            wmma::load_matrix_sync(bf[j], B1 + (size_t)(k * 16) * BS_LD + n0 + j * 16, BS_LD);
#pragma unroll
        for (int i = 0; i < 2; i++)
#pragma unroll
            for (int j = 0; j < 2; j++)
                wmma::mma_sync(acc[i][j], af[i], bf[j], acc[i][j]);
    }
    __syncthreads();

#pragma unroll
    for (int i = 0; i < 2; i++) {
#pragma unroll
        for (int j = 0; j < 2; j++) {
            const int rl = row0 + i * 16;
            const int cb = n0 + j * 16;
#pragma unroll
            for (int e = 0; e < 8; e += 2) {
                int r = rl + g8 + ((e & 2) ? 8 : 0);
                int c = cb + tg2 + ((e & 4) ? 8 : 0);
                float2 bb = __ldg((const float2*)(b1 + c));
                float vx = prelu1(acc[i][j].x[e]     + bb.x, a);
                float vy = prelu1(acc[i][j].x[e + 1] + bb.y, a);
                __half2 hv = __floats2half2_rn(vx, vy);
                *(unsigned*)(As + (size_t)r * AS_LD + c) = *reinterpret_cast<unsigned*>(&hv);
            }
        }
    }
    __syncthreads();

#pragma unroll
    for (int i = 0; i < 2; i++)
#pragma unroll
        for (int j = 0; j < 2; j++) wmma::fill_fragment(acc[i][j], 0.f);
#pragma unroll
    for (int k = 0; k < 8; k++) {
        wmma::fragment<wmma::matrix_a, 16, 16, 16, __half, wmma::row_major> af[2];
        wmma::fragment<wmma::matrix_b, 16, 16, 16, __half, wmma::row_major> bf[2];
#pragma unroll
        for (int i = 0; i < 2; i++)
            wmma::load_matrix_sync(af[i], As + (size_t)(row0 + i * 16) * AS_LD + k * 16, AS_LD);
#pragma unroll
        for (int j = 0; j < 2; j++)
            wmma::load_matrix_sync(bf[j], B2 + (size_t)(k * 16) * BS_LD + n0 + j * 16, BS_LD);
#pragma unroll
        for (int i = 0; i < 2; i++)
#pragma unroll
            for (int j = 0; j < 2; j++)
                wmma::mma_sync(acc[i][j], af[i], bf[j], acc[i][j]);
    }
#pragma unroll
    for (int i = 0; i < 2; i++) {
#pragma unroll
        for (int j = 0; j < 2; j++) {
            const int rb = m0 + row0 + i * 16;
            const int cb = n0 + j * 16;
#pragma unroll
            for (int e = 0; e < 8; e += 2) {
                int r = rb + g8 + ((e & 2) ? 8 : 0);
                int c = cb + tg2 + ((e & 4) ? 8 : 0);
                if (r < M) {
                    float2 bb = __ldg((const float2*)(b2 + c));
                    __half2 hv = __floats2half2_rn(acc[i][j].x[e] + bb.x,
                                                   acc[i][j].x[e + 1] + bb.y);
                    *(unsigned*)(out_h16 + (size_t)r * 64 + (c >> 1)) =
                        *reinterpret_cast<unsigned*>(&hv);
                }
            }
        }
    }
}

// ---------------- fused: node-agg + single GEMM (layer 1: G4) ----------------
__global__ __launch_bounds__(512, 2) void kagg_gemm1(const unsigned* __restrict__ T16,
                                                     const unsigned* __restrict__ EB16,
                                                     const int* __restrict__ perm,
                                                     const int* __restrict__ offs,
                                                     const float* __restrict__ invs,
                                                     const unsigned* __restrict__ Wh,
                                                     const float* __restrict__ bias,
                                                     const float* __restrict__ pa,
                                                     float* __restrict__ out_f32,
                                                     const int* __restrict__ ncomp,
                                                     const float* __restrict__ cinv,
                                                     float* __restrict__ csum, int M) {
    extern __shared__ char smem[];
    __half* As = (__half*)smem;
    __half* Bs = (__half*)(smem + SM_AS);
    const int tid = threadIdx.x;
    const int wid = tid >> 5;
    const int m0 = blockIdx.x * 128;
    const float a = __ldg(pa);

#pragma unroll
    for (int it = 0; it < 4; it++) {
        int idx = tid + it * 512;
        int kk = idx >> 4, g = idx & 15;
        cpasync16(Bs + (size_t)kk * BS_LD + g * 8, (const uint4*)Wh + kk * 16 + g);
    }
    asm volatile("cp.async.commit_group;" ::: "memory");

    {
        const int hw = tid >> 4, l = tid & 15;
#pragma unroll
        for (int q = 0; q < 4; q++) {
            int r = q * 32 + hw;
            int seg = m0 + r;
            uint4 outv = make_uint4(0, 0, 0, 0);
            if (seg < M)
                outv = agg_node_seg(T16, EB16, perm, offs, invs, a, seg, l);
            *(uint4*)(As + (size_t)r * AS_LD + l * 8) = outv;
        }
    }
    asm volatile("cp.async.wait_group 0;" ::: "memory");
    __syncthreads();

    const int row0 = (wid & 3) * 32;
    const int n0   = (wid >> 2) * 32;
    wmma::fragment<wmma::accumulator, 16, 16, 16, float> acc[2][2];
#pragma unroll
    for (int i = 0; i < 2; i++)
#pragma unroll
        for (int j = 0; j < 2; j++) wmma::fill_fragment(acc[i][j], 0.f);
#pragma unroll
    for (int k = 0; k < 8; k++) {
        wmma::fragment<wmma::matrix_a, 16, 16, 16, __half, wmma::row_major> af[2];
        wmma::fragment<wmma::matrix_b, 16, 16, 16, __half, wmma::row_major> bf[2];
#pragma unroll
        for (int i = 0; i < 2; i++)
            wmma::load_matrix_sync(af[i], As + (size_t)(row0 + i * 16) * AS_LD + k * 16, AS_LD);
#pragma unroll
        for (int j = 0; j < 2; j++)
            wmma::load_matrix_sync(bf[j], Bs + (size_t)(k * 16) * BS_LD + n0 + j * 16, BS_LD);
#pragma unroll
        for (int i = 0; i < 2; i++)
#pragma unroll
            for (int j = 0; j < 2; j++)
                wmma::mma_sync(acc[i][j], af[i], bf[j], acc[i][j]);
    }
    {
        const int lane = tid & 31;
        const int g8  = lane >> 2;
        const int tg2 = (lane & 3) * 2;
#pragma unroll
        for (int i = 0; i < 2; i++) {
#pragma unroll
            for (int j = 0; j < 2; j++) {
                const int rb = m0 + row0 + i * 16;
                const int cb = n0 + j * 16;
#pragma unroll
                for (int e = 0; e < 8; e += 2) {
                    int r = rb + g8 + ((e & 2) ? 8 : 0);
                    int c = cb + tg2 + ((e & 4) ? 8 : 0);
                    if (r < M) {
                        float2 bb = __ldg((const float2*)(bias + c));
                        float vx = acc[i][j].x[e]     + bb.x;
                        float vy = acc[i][j].x[e + 1] + bb.y;
                        *(float2*)(out_f32 + (size_t)r * D + c) =
                            make_float2(prelu1(vx, a), prelu1(vy, a));
                        int cc = __ldg(&ncomp[r]);
                        float sc = __ldg(&cinv[cc]);
                        red2(csum + (size_t)cc * D + c, vx * sc, vy * sc);
                    }
                }
            }
        }
    }
}

// ---------------- SIMT GEMM (CE component GEMM, off critical path) -----------
__global__ __launch_bounds__(256) void kgemm2(const float* __restrict__ X,
                                              const float* __restrict__ W,
                                              const float* __restrict__ b,
                                              float* __restrict__ Yraw, int M) {
    __shared__ float As[64][128];
    const int m0 = blockIdx.x * 64;
    const int t = threadIdx.x;
    {
        const int c4 = t & 31;
        const int r0 = t >> 5;
#pragma unroll
        for (int s = 0; s < 8; s++) {
            int r = r0 + 8 * s;
            int gr = m0 + r;
            float4 v = make_float4(0.f, 0.f, 0.f, 0.f);
            if (gr < M) v = ((const float4*)(X + (size_t)gr * D))[c4];
            ((float4*)(&As[r][0]))[c4] = v;
        }
    }
    __syncthreads();
    const int cg = (t & 15) * 8;
    const int rg = (t >> 4) * 4;
    unsigned long long acc[4][4];
#pragma unroll
    for (int i = 0; i < 4; i++)
#pragma unroll
        for (int j = 0; j < 4; j++) acc[i][j] = 0ULL;
#pragma unroll 4
    for (int k = 0; k < D; k += 4) {
        float4 a[4];
#pragma unroll
        for (int i = 0; i < 4; i++) a[i] = *(const float4*)&As[rg + i][k];
#pragma unroll
        for (int kk = 0; kk < 4; kk++) {
            const ulonglong2 w0 = *reinterpret_cast<const ulonglong2*>(&W[(k + kk) * D + cg]);
            const ulonglong2 w1 = *reinterpret_cast<const ulonglong2*>(&W[(k + kk) * D + cg + 4]);
#pragma unroll
            for (int i = 0; i < 4; i++) {
                float av = (kk == 0) ? a[i].x : (kk == 1) ? a[i].y
                         : (kk == 2) ? a[i].z : a[i].w;
                unsigned long long av2 = pk2(av);
                fma2(acc[i][0], av2, w0.x);
                fma2(acc[i][1], av2, w0.y);
                fma2(acc[i][2], av2, w1.x);
                fma2(acc[i][3], av2, w1.y);
            }
        }
    }
    const float4 b0 = __ldg((const float4*)&b[cg]);
    const float4 b1 = __ldg((const float4*)&b[cg + 4]);
#pragma unroll
    for (int i = 0; i < 4; i++) {
        int gr = m0 + rg + i;
        if (gr >= M) continue;
        float2 p0 = up2(acc[i][0]), p1 = up2(acc[i][1]);
        float2 p2 = up2(acc[i][2]), p3 = up2(acc[i][3]);
        float4 o0 = make_float4(p0.x + b0.x, p0.y + b0.y, p1.x + b0.z, p1.y + b0.w);
        float4 o1 = make_float4(p2.x + b1.x, p2.y + b1.y, p3.x + b1.z, p3.y + b1.w);
        float4* yr = (float4*)(Yraw + (size_t)gr * D);
        yr[cg / 4] = o0; yr[cg / 4 + 1] = o1;
    }
}

// ---------------- CSR edge aggregation (half-warp/segment) -------------------
__global__ __launch_bounds__(256) void kagg_e(const unsigned* __restrict__ T16,
                                              const int* __restrict__ perm,
                                              const int* __restrict__ offs,
                                              const float* __restrict__ invd,
                                              const float* __restrict__ pa,
                                              unsigned* __restrict__ EB16,
                                              float* __restrict__ out_e,
                                              const int* __restrict__ ecomp,
                                              const float* __restrict__ cinv,
                                              float* __restrict__ csum, int E) {
    int seg = (blockIdx.x * blockDim.x + threadIdx.x) >> 4;
    int l = threadIdx.x & 15;
    if (seg >= E) return;
    int beg = __ldg(&offs[seg]), end = __ldg(&offs[seg + 1]);
    float4 s0 = {0,0,0,0}, s1 = {0,0,0,0}, t0 = {0,0,0,0}, t1 = {0,0,0,0};
    float4 u0 = {0,0,0,0}, u1 = {0,0,0,0}, v0 = {0,0,0,0}, v1 = {0,0,0,0};
    int p = beg;
    for (; p + 8 <= end; p += 8) {
        uint4 vv[8];
#pragma unroll
        for (int q = 0; q < 8; q++)
            vv[q] = __ldg((const uint4*)(T16 + (size_t)__ldg(&perm[p + q]) * 64) + l);
        addh8(s0, s1, vv[0]); addh8(t0, t1, vv[1]);
        addh8(u0, u1, vv[2]); addh8(v0, v1, vv[3]);
        addh8(s0, s1, vv[4]); addh8(t0, t1, vv[5]);
        addh8(u0, u1, vv[6]); addh8(v0, v1, vv[7]);
    }
    for (; p + 4 <= end; p += 4) {
        uint4 vv[4];
#pragma unroll
        for (int q = 0; q < 4; q++)
            vv[q] = __ldg((const uint4*)(T16 + (size_t)__ldg(&perm[p + q]) * 64) + l);
        addh8(s0, s1, vv[0]); addh8(t0, t1, vv[1]);
        addh8(u0, u1, vv[2]); addh8(v0, v1, vv[3]);
    }
    for (; p < end; p++)
        addh8(s0, s1, __ldg((const uint4*)(T16 + (size_t)__ldg(&perm[p]) * 64) + l));
    add4(s0, t0); add4(u0, v0); add4(s0, u0);
    add4(s1, t1); add4(u1, v1); add4(s1, u1);
    float iv = __ldg(&invd[seg]);
    float a = __ldg(pa);
    s0.x *= iv; s0.y *= iv; s0.z *= iv; s0.w *= iv;
    s1.x *= iv; s1.y *= iv; s1.z *= iv; s1.w *= iv;
    float4 r0 = prelu4(s0, a), r1 = prelu4(s1, a);
    uint2 q0 = h4(r0), q1 = h4(r1);
    ((uint4*)(EB16 + (size_t)seg * 64))[l] = make_uint4(q0.x, q0.y, q1.x, q1.y);
    if (out_e) {
        ((float4*)out_e)[(size_t)seg * 32 + l * 2]     = r0;
        ((float4*)out_e)[(size_t)seg * 32 + l * 2 + 1] = r1;
    }
    if (csum) {
        int cc = __ldg(&ecomp[seg]);
        float sc = __ldg(&cinv[cc]);
        float4 w0 = make_float4(r0.x * sc, r0.y * sc, r0.z * sc, r0.w * sc);
        float4 w1 = make_float4(r1.x * sc, r1.y * sc, r1.z * sc, r1.w * sc);
        red4(csum + (size_t)cc * D + l * 8,     w0);
        red4(csum + (size_t)cc * D + l * 8 + 4, w1);
    }
}

// ---------------- host driver ------------------------------------------------
static inline int cdiv(long a, long b) { return (int)((a + b - 1) / b); }

extern "C" void kernel_launch(void* const* d_in, const int* in_sizes, int n_in,
                              void* d_out, int out_size) {
    const float* x   = (const float*)d_in[0];
    const int*   hei = (const int*)d_in[1];
    const int*   hci = (const int*)d_in[2];
    const int*   nci = (const int*)d_in[3];

    const int NNZ = in_sizes[1] / 2;
    const int E   = in_sizes[2] / 2;
    const int N   = in_sizes[0] / D;
    const int C   = out_size / D - N - E;

    int wi = -1;
    for (int i = 4; i < n_in; i++) {
        if (in_sizes[i] == D * D) { wi = i; break; }
    }
    const float* pa = (const float*)d_in[wi - 1];

    const int* src  = hei;
    const int* dst  = hei + NNZ;
    const int* he_c = hci + E;
    const int* nc_c = nci + N;

    float *CE, *CN, *CT, *invd, *invs, *ic1, *ic2;
    unsigned *T16, *E16, *Wh;
    int *cd, *cs, *cc1, *cc2, *od, *os, *pd, *ps, *bsum;
    cudaGetSymbolAddress((void**)&T16,  g_T16);
    cudaGetSymbolAddress((void**)&E16,  g_E16);
    cudaGetSymbolAddress((void**)&CE,   g_c1);
    cudaGetSymbolAddress((void**)&CN,   g_c2);
    cudaGetSymbolAddress((void**)&CT,   g_c3);
    cudaGetSymbolAddress((void**)&Wh,   g_Wh);
    cudaGetSymbolAddress((void**)&invd, g_invdst);
    cudaGetSymbolAddress((void**)&invs, g_invsrc);
    cudaGetSymbolAddress((void**)&ic1,  g_invc1);
    cudaGetSymbolAddress((void**)&ic2,  g_invc2);
    cudaGetSymbolAddress((void**)&cd,   g_cd);
    cudaGetSymbolAddress((void**)&cs,   g_cs);
    cudaGetSymbolAddress((void**)&cc1,  g_cc1);
    cudaGetSymbolAddress((void**)&cc2,  g_cc2);
    cudaGetSymbolAddress((void**)&od,   g_offs_d);
    cudaGetSymbolAddress((void**)&os,   g_offs_s);
    cudaGetSymbolAddress((void**)&pd,   g_perm_d);
    cudaGetSymbolAddress((void**)&ps,   g_perm_s);
    cudaGetSymbolAddress((void**)&bsum, g_bsum);

    float* out   = (float*)d_out;
    float* out_n = out;
    float* out_e = out + (size_t)N * D;
    float* out_c = out + (size_t)(N + E) * D;

    const int TB = 256;
    const int nbd = cdiv(E, 1024);
    const int nbs = cdiv(N, 1024);
    const int nbtot = nbd + nbs;
    const int GT = cdiv(N, 128);

    const float* bv0 = (const float*)d_in[wi + 1];
    const float* be0 = (const float*)d_in[wi + 3];
    const float* bv1 = (const float*)d_in[wi + 9];
    const float* be1 = (const float*)d_in[wi + 11];

    cudaFuncSetAttribute(kgemm_tc,   cudaFuncAttributeMaxDynamicSharedMemorySize, SM_TOT);
    cudaFuncSetAttribute(kgemm_cn,   cudaFuncAttributeMaxDynamicSharedMemorySize, SM_TOT);
    cudaFuncSetAttribute(kagg_gemm1, cudaFuncAttributeMaxDynamicSharedMemorySize, SM_TOT);
    cudaFuncSetAttribute(kagg_gemm2, cudaFuncAttributeMaxDynamicSharedMemorySize, SM3_TOT);

    static cudaStream_t s2 = nullptr;
    static cudaEvent_t evA = nullptr, evB = nullptr, evC = nullptr, evD = nullptr;
    if (!s2) {
        cudaStreamCreateWithFlags(&s2, cudaStreamNonBlocking);
        cudaEventCreateWithFlags(&evA, cudaEventDisableTiming);
        cudaEventCreateWithFlags(&evB, cudaEventDisableTiming);
        cudaEventCreateWithFlags(&evC, cudaEventDisableTiming);
        cudaEventCreateWithFlags(&evD, cudaEventDisableTiming);
    }

    // ---- fork 1 at t=0: CSR build on s2 (counters pre-zeroed)  ||  W+G1 ----
    cudaEventRecord(evA, 0);
    cudaStreamWaitEvent(s2, evA, 0);
    kcountall<<<cdiv(NNZ + E + N, TB), TB, 0, s2>>>(src, dst, he_c, nc_c,
                                                    cs, cd, cc1, cc2, NNZ, E, N);
    kscanA<<<nbtot, 1024, 0, s2>>>(cd, cs, od, os, bsum, nbd, E, N);
    kscanC2<<<nbtot, 1024, 0, s2>>>(od, os, bsum, cd, cs, nbd, E, N, NNZ);
    kfillinv<<<cdiv((long)NNZ + E + N + 2 * C + 2 * C * 32, TB), TB, 0, s2>>>(
        src, dst, cd, cs, pd, ps, od, os, cc1, cc2,
        invd, invs, ic1, ic2, (float4*)CE, (float4*)CN, NNZ, E, N, C);
    kzerocnt<<<cdiv(E + N + 2 * C, TB), TB, 0, s2>>>(cd, cs, cc1, cc2, E, N, C);
    cudaEventRecord(evB, s2);

    // main: W convert (5 mats incl Wnc), then G1
    ksetupW<<<cdiv(5 * 128 * 16, TB), TB>>>(
        (const float*)d_in[wi + 0], (const float*)d_in[wi + 2],
        (const float*)d_in[wi + 8], (const float*)d_in[wi + 10],
        (const float*)d_in[wi + 14], Wh);
    kgemm_tc<<<GT, 512, SM_TOT>>>(x, Wh + 0 * 8192, bv0, pa, T16, N);
    cudaStreamWaitEvent(0, evB, 0);

    // ---- layer 0 ----
    kagg_e<<<cdiv((long)E * 16, TB), TB>>>(T16, pd, od, invd, pa, E16, nullptr,
                                           nullptr, nullptr, nullptr, E);
    kagg_gemm2<<<GT, 512, SM3_TOT>>>(T16, E16, ps, os, invs,
                                     Wh + 1 * 8192, be0, Wh + 2 * 8192, bv1,
                                     pa, T16, N);

    // ---- layer 1 ----
    kagg_e<<<cdiv((long)E * 16, TB), TB>>>(T16, pd, od, invd, pa, E16, out_e,
                                           he_c, ic1, CE, E);
    cudaEventRecord(evC, 0);
    cudaStreamWaitEvent(s2, evC, 0);
    kgemm2<<<cdiv(C, 64), TB, 0, s2>>>(CE, (const float*)d_in[wi + 12],
                                       (const float*)d_in[wi + 13], CT, C);
    cudaEventRecord(evD, s2);

    kagg_gemm1<<<GT, 512, SM_TOT>>>(T16, E16, ps, os, invs,
                                    Wh + 3 * 8192, be1, pa, out_n,
                                    nc_c, ic2, CN, N);
    cudaStreamWaitEvent(0, evD, 0);

    // out_c = prelu(CN @ Wnc + bnc + CT)   (WMMA, Wnc = slot 4)
    kgemm_cn<<<cdiv(C, 128), 512, SM_TOT>>>(CN, Wh + 4 * 8192,
                                            (const float*)d_in[wi + 15], CT, pa,
                                            out_c, C);
}